// round 5
// baseline (speedup 1.0000x reference)
#include <cuda_runtime.h>
#include <cstdint>
#include <math.h>

// ---------------- problem constants ----------------
#define BATCH 16384
#define ZD 32
#define NE 512
#define GAMMA 0.99f
#define ONE_M_GAMMA 0.01f
#define BETA 1.0f

#define OFF_SCAL (BATCH * 784)   // x_rec size
// d_out layout: [x_rec (B*784)][quant][commit][perplexity][emb_new (512*32)]

// ---------------- scratch ----------------
__device__ float g_h1[BATCH * 16 * 14 * 14];
__device__ float g_h2[BATCH * 32 * 7 * 7];
__device__ float g_a [BATCH * 224];
__device__ float g_z [BATCH * ZD];
__device__ int   g_idx[BATCH];
__device__ float g_enorm[NE];
__device__ float g_counts[NE];
__device__ float g_sums[NE * ZD];
__device__ float g_loss[1];

// ---------------- tf32 mma helpers ----------------
__device__ __forceinline__ float to_tf32(float x) {
    float y;
    asm("cvt.rna.tf32.f32 %0, %1;" : "=f"(y) : "f"(x));
    return y;
}

__device__ __forceinline__ void split_tf32(float v, unsigned& hi, unsigned& lo) {
    float h;
    asm("cvt.rna.tf32.f32 %0, %1;" : "=f"(h) : "f"(v));
    float l = v - h;
    float l2;
    asm("cvt.rna.tf32.f32 %0, %1;" : "=f"(l2) : "f"(l));
    hi = __float_as_uint(h);
    lo = __float_as_uint(l2);
}

__device__ __forceinline__ void split_tf32_f(float v, float& hi, float& lo) {
    asm("cvt.rna.tf32.f32 %0, %1;" : "=f"(hi) : "f"(v));
    float l = v - hi;
    asm("cvt.rna.tf32.f32 %0, %1;" : "=f"(lo) : "f"(l));
}

__device__ __forceinline__ void mma_tf32(float* d, const unsigned* a,
                                         unsigned b0, unsigned b1) {
    asm volatile(
        "mma.sync.aligned.m16n8k8.row.col.f32.tf32.tf32.f32 "
        "{%0,%1,%2,%3}, {%4,%5,%6,%7}, {%8,%9}, {%0,%1,%2,%3};\n"
        : "+f"(d[0]), "+f"(d[1]), "+f"(d[2]), "+f"(d[3])
        : "r"(a[0]), "r"(a[1]), "r"(a[2]), "r"(a[3]), "r"(b0), "r"(b1));
}

// 3-pass split mma: acc += a*b with ~fp32 accuracy
__device__ __forceinline__ void mma3(float* d, const unsigned* ah, const unsigned* al,
                                     unsigned bh0, unsigned bh1,
                                     unsigned bl0, unsigned bl1) {
    mma_tf32(d, ah, bl0, bl1);
    mma_tf32(d, al, bh0, bh1);
    mma_tf32(d, ah, bh0, bh1);
}

// ======================================================================
// conv1: x[B,1,28,28] -> relu -> h1[B,16,14,14]   (k4 s2 p1)  fp32
// ======================================================================
__global__ void conv1_kernel(const float* __restrict__ x,
                             const float* __restrict__ w,
                             const float* __restrict__ bias,
                             float* __restrict__ out) {
    __shared__ float img[784];
    __shared__ float ws[256];
    int b = blockIdx.x, t = threadIdx.x;
    const float* ip = x + (size_t)b * 784;
    for (int i = t; i < 784; i += 256) img[i] = ip[i];
    if (t < 256) ws[t] = w[t];
    __syncthreads();
    float* op = out + (size_t)b * 3136;
    for (int o = t; o < 3136; o += 256) {
        int oc = o / 196, s = o % 196, oy = s / 14, ox = s % 14;
        float acc = bias[oc];
        const float* wp = ws + oc * 16;
        #pragma unroll
        for (int ky = 0; ky < 4; ky++) {
            int iy = 2 * oy - 1 + ky;
            if ((unsigned)iy < 28u) {
                #pragma unroll
                for (int kx = 0; kx < 4; kx++) {
                    int ix = 2 * ox - 1 + kx;
                    if ((unsigned)ix < 28u)
                        acc += img[iy * 28 + ix] * wp[ky * 4 + kx];
                }
            }
        }
        op[o] = fmaxf(acc, 0.f);
    }
}

// ======================================================================
// conv2 3xTF32 shift-GEMM: h1[B,16,14,14] -> h2[B,32,7,7] (k4 s2 p1)
// 4 img/CTA, 256 thr. Weights PRE-SPLIT into hi/lo planes at staging.
// ======================================================================
#define C2_IMSZ 4608                   // 256 pos * 18 pitch
#define C2_ZOFF (4 * C2_IMSZ)          // 18432 (5th block = zeros)
#define C2_XIN  (5 * C2_IMSZ)          // 23040
#define C2_WH   C2_XIN                 // 23040
#define C2_WL   (C2_WH + 16 * 16 * 36) // 32256
#define C2_TOT  (C2_WL + 16 * 16 * 36) // 41472
#define C2_SMEM (C2_TOT * 4)           // 165888 B

__global__ void __launch_bounds__(256) conv2_tc3(
        const float* __restrict__ in,
        const float* __restrict__ w,
        const float* __restrict__ bias,
        float* __restrict__ out) {
    extern __shared__ float sm[];
    float* xin = sm;
    float* wth = sm + C2_WH;
    float* wtl = sm + C2_WL;
    int t = threadIdx.x;
    int b0 = blockIdx.x * 4;

    for (int i = t; i < C2_XIN; i += 256) xin[i] = 0.f;
    __syncthreads();
    for (int i = t; i < 4 * 3136; i += 256) {
        int img = i / 3136, j = i % 3136;
        int ic = j / 196, p = j % 196, iy = p / 14, ix = p % 14;
        xin[img * C2_IMSZ + ((iy + 1) * 16 + (ix + 1)) * 18 + ic] =
            in[(size_t)(b0 + img) * 3136 + j];
    }
    for (int i = t; i < 8192; i += 256) {           // [oc][ic][s] -> [s][ic][oc]
        int oc = i / 256, r = i % 256, ic = r / 16, s = r % 16;
        float h, l;
        split_tf32_f(w[i], h, l);
        wth[s * 576 + ic * 36 + oc] = h;
        wtl[s * 576 + ic * 36 + oc] = l;
    }
    __syncthreads();

    int lane = t & 31, wrp = t >> 5;
    int grp = lane >> 2, tig = lane & 3;
    int wm = wrp * 32;

    int rb[2][2];
    #pragma unroll
    for (int mi = 0; mi < 2; mi++)
        #pragma unroll
        for (int h = 0; h < 2; h++) {
            int r = wm + mi * 16 + grp + h * 8;
            int img = r >> 6, p = r & 63;
            rb[mi][h] = (p < 49)
                ? img * C2_IMSZ + ((p / 7) * 32 + (p % 7) * 2) * 18
                : C2_ZOFF;
        }

    float acc[2][4][4];
    #pragma unroll
    for (int mi = 0; mi < 2; mi++)
        #pragma unroll
        for (int ni = 0; ni < 4; ni++)
            #pragma unroll
            for (int c = 0; c < 4; c++) acc[mi][ni][c] = 0.f;

    #pragma unroll
    for (int ky = 0; ky < 4; ky++) {
        #pragma unroll
        for (int kx = 0; kx < 4; kx++) {
            int soff = (ky * 16 + kx) * 18;
            const float* wsh = wth + (ky * 4 + kx) * 576;
            const float* wsl = wtl + (ky * 4 + kx) * 576;
            #pragma unroll
            for (int kk = 0; kk < 2; kk++) {
                int kb = kk * 8;
                unsigned ah[2][4], al[2][4];
                #pragma unroll
                for (int mi = 0; mi < 2; mi++) {
                    split_tf32(xin[rb[mi][0] + soff + kb + tig],     ah[mi][0], al[mi][0]);
                    split_tf32(xin[rb[mi][1] + soff + kb + tig],     ah[mi][1], al[mi][1]);
                    split_tf32(xin[rb[mi][0] + soff + kb + tig + 4], ah[mi][2], al[mi][2]);
                    split_tf32(xin[rb[mi][1] + soff + kb + tig + 4], ah[mi][3], al[mi][3]);
                }
                #pragma unroll
                for (int ni = 0; ni < 4; ni++) {
                    unsigned bh0 = __float_as_uint(wsh[(kb + tig) * 36 + ni * 8 + grp]);
                    unsigned bh1 = __float_as_uint(wsh[(kb + tig + 4) * 36 + ni * 8 + grp]);
                    unsigned bl0 = __float_as_uint(wsl[(kb + tig) * 36 + ni * 8 + grp]);
                    unsigned bl1 = __float_as_uint(wsl[(kb + tig + 4) * 36 + ni * 8 + grp]);
                    mma3(acc[0][ni], ah[0], al[0], bh0, bh1, bl0, bl1);
                    mma3(acc[1][ni], ah[1], al[1], bh0, bh1, bl0, bl1);
                }
            }
        }
    }

    #pragma unroll
    for (int mi = 0; mi < 2; mi++) {
        #pragma unroll
        for (int ni = 0; ni < 4; ni++) {
            #pragma unroll
            for (int ci = 0; ci < 4; ci++) {
                int r = wm + mi * 16 + grp + ((ci >= 2) ? 8 : 0);
                int img = r >> 6, p = r & 63;
                if (p < 49) {
                    int oc = ni * 8 + tig * 2 + (ci & 1);
                    out[(size_t)(b0 + img) * 1568 + oc * 49 + p] =
                        acc[mi][ni][ci] + __ldg(bias + oc);
                }
            }
        }
    }
}

// ======================================================================
// res stack 3xTF32 (encoder): y = relu(x + w2*relu(w1*relu(x)))
// 2 img/CTA, 256 thr (8 warps x 16 rows). Weights PRE-SPLIT hi/lo.
// ======================================================================
#define R3_XIN   5832                    // 2 * 81*36
#define R3_W1H   R3_XIN                  // 5832   [s][ic][68]
#define R3_W1L   (R3_W1H + 9 * 32 * 68)  // 25416  [s][ic][66]
#define R3_W2H   (R3_W1L + 9 * 32 * 66)  // 44424  [ic][36]
#define R3_W2L   (R3_W2H + 64 * 36)      // 46728
#define R3_RS    (R3_W2L + 64 * 36)      // 49032  [128][68]
#define R3_TOT   (R3_RS + 128 * 68)      // 57736
#define R3_SMEM  (R3_TOT * 4)            // 230944 B

__global__ void __launch_bounds__(256) res_tc3(
        float* __restrict__ buf,
        const float* __restrict__ pw1,
        const float* __restrict__ pw2) {
    extern __shared__ float sm[];
    float* xin = sm;
    float* w1h = sm + R3_W1H;
    float* w1l = sm + R3_W1L;
    float* w2h = sm + R3_W2H;
    float* w2l = sm + R3_W2L;
    float* rs  = sm + R3_RS;
    int t = threadIdx.x;
    int b0 = blockIdx.x * 2;

    for (int i = t; i < R3_XIN; i += 256) xin[i] = 0.f;
    __syncthreads();
    for (int i = t; i < 64 * 32 * 9; i += 256) {
        int oc = i / 288, rr = i % 288, ic = rr / 9, s = rr % 9;
        float h, l;
        split_tf32_f(pw1[i], h, l);
        w1h[s * 2176 + ic * 68 + oc] = h;
        w1l[s * 2112 + ic * 66 + oc] = l;
    }
    for (int i = t; i < 2048; i += 256) {
        int oc = i >> 6, ic = i & 63;
        float h, l;
        split_tf32_f(pw2[i], h, l);
        w2h[ic * 36 + oc] = h;
        w2l[ic * 36 + oc] = l;
    }
    for (int i = t; i < 2 * 1568; i += 256) {
        int img = i / 1568, j = i % 1568;
        int ch = j / 49, p = j % 49, py = p / 7, px = p % 7;
        float v = buf[(size_t)(b0 + img) * 1568 + j];
        xin[img * 2916 + ((py + 1) * 9 + (px + 1)) * 36 + ch] = fmaxf(v, 0.f);
    }
    __syncthreads();

    int lane = t & 31, wrp = t >> 5;
    int grp = lane >> 2, tig = lane & 3;
    int wm = wrp * 16;                   // 8 warps * 16 rows = 128 rows

    int rb[2];
    #pragma unroll
    for (int h = 0; h < 2; h++) {
        int r = wm + grp + h * 8;
        int img = r >> 6, p = r & 63;
        // fake rows (p>=49) read finite garbage at offset 0; discarded later
        rb[h] = (p < 49) ? img * 2916 + ((p / 7) * 9 + (p % 7)) * 36 : 0;
    }

    // ---- phase 1: conv3x3 (32->64), 3xTF32 ----
    float acc[8][4];
    #pragma unroll
    for (int ni = 0; ni < 8; ni++)
        #pragma unroll
        for (int c = 0; c < 4; c++) acc[ni][c] = 0.f;

    #pragma unroll
    for (int ky = 0; ky < 3; ky++) {
        #pragma unroll
        for (int kx = 0; kx < 3; kx++) {
            int soff = (ky * 9 + kx) * 36;
            const float* wbh = w1h + (ky * 3 + kx) * 2176;
            const float* wbl = w1l + (ky * 3 + kx) * 2112;
            #pragma unroll
            for (int kk = 0; kk < 4; kk++) {
                int kb = kk * 8;
                unsigned ah[4], al[4];
                split_tf32(xin[rb[0] + soff + kb + tig],     ah[0], al[0]);
                split_tf32(xin[rb[1] + soff + kb + tig],     ah[1], al[1]);
                split_tf32(xin[rb[0] + soff + kb + tig + 4], ah[2], al[2]);
                split_tf32(xin[rb[1] + soff + kb + tig + 4], ah[3], al[3]);
                #pragma unroll
                for (int ni = 0; ni < 8; ni++) {
                    unsigned bh0 = __float_as_uint(wbh[(kb + tig) * 68 + ni * 8 + grp]);
                    unsigned bh1 = __float_as_uint(wbh[(kb + tig + 4) * 68 + ni * 8 + grp]);
                    unsigned bl0 = __float_as_uint(wbl[(kb + tig) * 66 + ni * 8 + grp]);
                    unsigned bl1 = __float_as_uint(wbl[(kb + tig + 4) * 66 + ni * 8 + grp]);
                    mma3(acc[ni], ah, al, bh0, bh1, bl0, bl1);
                }
            }
        }
    }

    // relu -> rs (raw fp32, pitch 68); warp-private rows
    {
        int rlo = wm + grp, rhi = rlo + 8;
        #pragma unroll
        for (int ni = 0; ni < 8; ni++) {
            int c0 = ni * 8 + tig * 2;
            rs[rlo * 68 + c0]     = fmaxf(acc[ni][0], 0.f);
            rs[rlo * 68 + c0 + 1] = fmaxf(acc[ni][1], 0.f);
            rs[rhi * 68 + c0]     = fmaxf(acc[ni][2], 0.f);
            rs[rhi * 68 + c0 + 1] = fmaxf(acc[ni][3], 0.f);
        }
    }
    __syncwarp();

    // ---- phase 2: conv1x1 (64->32), 3xTF32 ----
    float acc2[4][4];
    #pragma unroll
    for (int ni = 0; ni < 4; ni++)
        #pragma unroll
        for (int c = 0; c < 4; c++) acc2[ni][c] = 0.f;

    #pragma unroll
    for (int kk = 0; kk < 8; kk++) {
        int kb = kk * 8;
        unsigned ah[4], al[4];
        int rlo = wm + grp;
        split_tf32(rs[rlo * 68 + kb + tig],           ah[0], al[0]);
        split_tf32(rs[(rlo + 8) * 68 + kb + tig],     ah[1], al[1]);
        split_tf32(rs[rlo * 68 + kb + tig + 4],       ah[2], al[2]);
        split_tf32(rs[(rlo + 8) * 68 + kb + tig + 4], ah[3], al[3]);
        #pragma unroll
        for (int ni = 0; ni < 4; ni++) {
            unsigned bh0 = __float_as_uint(w2h[(kb + tig) * 36 + ni * 8 + grp]);
            unsigned bh1 = __float_as_uint(w2h[(kb + tig + 4) * 36 + ni * 8 + grp]);
            unsigned bl0 = __float_as_uint(w2l[(kb + tig) * 36 + ni * 8 + grp]);
            unsigned bl1 = __float_as_uint(w2l[(kb + tig + 4) * 36 + ni * 8 + grp]);
            mma3(acc2[ni], ah, al, bh0, bh1, bl0, bl1);
        }
    }

    // epilogue: +residual (exact), relu, store
    #pragma unroll
    for (int ni = 0; ni < 4; ni++) {
        #pragma unroll
        for (int ci = 0; ci < 4; ci++) {
            int r = wm + grp + ((ci >= 2) ? 8 : 0);
            int img = r >> 6, p = r & 63;
            if (p < 49) {
                int ch = ni * 8 + tig * 2 + (ci & 1);
                size_t g = (size_t)(b0 + img) * 1568 + ch * 49 + p;
                float v = acc2[ni][ci] + __ldg(buf + g);
                buf[g] = fmaxf(v, 0.f);
            }
        }
    }
}

// ======================================================================
// res stack single-TF32 (decoder)  [round-3, proven]
// ======================================================================
#define RTC_IMSZ  2673
#define RTC_ZOFF  (4 * RTC_IMSZ)
#define RTC_XIN   (RTC_ZOFF + 704)
#define RTC_W1OFF RTC_XIN
#define RTC_W1SZ  (9 * 32 * 68)
#define RTC_W2OFF (RTC_W1OFF + RTC_W1SZ)
#define RTC_W2SZ  (64 * 33)
#define RTC_RSOFF (RTC_W2OFF + RTC_W2SZ)
#define RTC_RSSZ  (256 * 65)
#define RTC_SMEMB ((RTC_RSOFF + RTC_RSSZ) * 4)

__global__ void __launch_bounds__(256) res_tc_kernel(
        float* __restrict__ buf,
        const float* __restrict__ pw1,
        const float* __restrict__ pw2) {
    extern __shared__ float sm[];
    float* xin = sm;
    float* w1s = sm + RTC_W1OFF;
    float* w2s = sm + RTC_W2OFF;
    float* rs  = sm + RTC_RSOFF;
    int t = threadIdx.x;
    int b0 = blockIdx.x * 4;

    for (int i = t; i < RTC_XIN; i += 256) xin[i] = 0.f;
    for (int i = t; i < 64 * 32 * 9; i += 256) {
        int oc = i / 288, rr = i % 288, ic = rr / 9, s = rr % 9;
        w1s[s * 2176 + ic * 68 + oc] = to_tf32(pw1[i]);
    }
    for (int i = t; i < 2048; i += 256) {
        int oc = i >> 6, ic = i & 63;
        w2s[ic * 33 + oc] = to_tf32(pw2[i]);
    }
    __syncthreads();
    for (int i = t; i < 4 * 1568; i += 256) {
        int img = i / 1568, j = i % 1568;
        int ch = j / 49, p = j % 49, py = p / 7, px = p % 7;
        float v = buf[(size_t)(b0 + img) * 1568 + j];
        xin[img * RTC_IMSZ + ((py + 1) * 9 + (px + 1)) * 33 + ch] =
            to_tf32(fmaxf(v, 0.f));
    }
    __syncthreads();

    int lane = t & 31, w = t >> 5;
    int grp = lane >> 2, tig = lane & 3;
    int wm = w * 32;

    int rb[2][2];
    #pragma unroll
    for (int mi = 0; mi < 2; mi++)
        #pragma unroll
        for (int h = 0; h < 2; h++) {
            int r = wm + mi * 16 + grp + h * 8;
            int img = r >> 6, p = r & 63;
            rb[mi][h] = (p < 49)
                ? img * RTC_IMSZ + ((p / 7) * 9 + (p % 7)) * 33
                : RTC_ZOFF;
        }

    float acc[2][8][4];
    #pragma unroll
    for (int mi = 0; mi < 2; mi++)
        #pragma unroll
        for (int ni = 0; ni < 8; ni++)
            #pragma unroll
            for (int c = 0; c < 4; c++) acc[mi][ni][c] = 0.f;

    #pragma unroll
    for (int ky = 0; ky < 3; ky++) {
        #pragma unroll
        for (int kx = 0; kx < 3; kx++) {
            int soff = (ky * 9 + kx) * 33;
            const float* wb = w1s + (ky * 3 + kx) * 2176;
            #pragma unroll
            for (int kk = 0; kk < 4; kk++) {
                int kb = kk * 8;
                unsigned a[2][4];
                #pragma unroll
                for (int mi = 0; mi < 2; mi++) {
                    a[mi][0] = __float_as_uint(xin[rb[mi][0] + soff + kb + tig]);
                    a[mi][1] = __float_as_uint(xin[rb[mi][1] + soff + kb + tig]);
                    a[mi][2] = __float_as_uint(xin[rb[mi][0] + soff + kb + tig + 4]);
                    a[mi][3] = __float_as_uint(xin[rb[mi][1] + soff + kb + tig + 4]);
                }
                #pragma unroll
                for (int ni = 0; ni < 8; ni++) {
                    unsigned bb0 = __float_as_uint(wb[(kb + tig) * 68 + ni * 8 + grp]);
                    unsigned bb1 = __float_as_uint(wb[(kb + tig + 4) * 68 + ni * 8 + grp]);
                    mma_tf32(acc[0][ni], a[0], bb0, bb1);
                    mma_tf32(acc[1][ni], a[1], bb0, bb1);
                }
            }
        }
    }

    #pragma unroll
    for (int mi = 0; mi < 2; mi++) {
        int rlo = wm + mi * 16 + grp, rhi = rlo + 8;
        #pragma unroll
        for (int ni = 0; ni < 8; ni++) {
            int c0 = ni * 8 + tig * 2;
            rs[rlo * 65 + c0]     = to_tf32(fmaxf(acc[mi][ni][0], 0.f));
            rs[rlo * 65 + c0 + 1] = to_tf32(fmaxf(acc[mi][ni][1], 0.f));
            rs[rhi * 65 + c0]     = to_tf32(fmaxf(acc[mi][ni][2], 0.f));
            rs[rhi * 65 + c0 + 1] = to_tf32(fmaxf(acc[mi][ni][3], 0.f));
        }
    }
    __syncwarp();

    float acc2[2][4][4];
    #pragma unroll
    for (int mi = 0; mi < 2; mi++)
        #pragma unroll
        for (int ni = 0; ni < 4; ni++)
            #pragma unroll
            for (int c = 0; c < 4; c++) acc2[mi][ni][c] = 0.f;

    #pragma unroll
    for (int kk = 0; kk < 8; kk++) {
        int kb = kk * 8;
        unsigned a[2][4];
        #pragma unroll
        for (int mi = 0; mi < 2; mi++) {
            int rlo = wm + mi * 16 + grp;
            a[mi][0] = __float_as_uint(rs[rlo * 65 + kb + tig]);
            a[mi][1] = __float_as_uint(rs[(rlo + 8) * 65 + kb + tig]);
            a[mi][2] = __float_as_uint(rs[rlo * 65 + kb + tig + 4]);
            a[mi][3] = __float_as_uint(rs[(rlo + 8) * 65 + kb + tig + 4]);
        }
        #pragma unroll
        for (int ni = 0; ni < 4; ni++) {
            unsigned bb0 = __float_as_uint(w2s[(kb + tig) * 33 + ni * 8 + grp]);
            unsigned bb1 = __float_as_uint(w2s[(kb + tig + 4) * 33 + ni * 8 + grp]);
            mma_tf32(acc2[0][ni], a[0], bb0, bb1);
            mma_tf32(acc2[1][ni], a[1], bb0, bb1);
        }
    }

    #pragma unroll
    for (int mi = 0; mi < 2; mi++) {
        int rlo = wm + mi * 16 + grp;
        #pragma unroll
        for (int ni = 0; ni < 4; ni++) {
            #pragma unroll
            for (int ci = 0; ci < 4; ci++) {
                int r = rlo + ((ci >= 2) ? 8 : 0);
                int img = r >> 6, p = r & 63;
                if (p < 49) {
                    int ch = ni * 8 + tig * 2 + (ci & 1);
                    size_t g = (size_t)(b0 + img) * 1568 + ch * 49 + p;
                    float v = acc2[mi][ni][ci] + __ldg(buf + g);
                    buf[g] = fmaxf(v, 0.f);
                }
            }
        }
    }
}

// ======================================================================
// TF32 GEMM (single, decoder fc4): C = relu(A @ W^T + bias)
// BM=128 BN=64 BK=16, 256 thr                                 [round-3]
// ======================================================================
__global__ void __launch_bounds__(256) gemm_tc(
        const float* __restrict__ A,
        const float* __restrict__ W,
        const float* __restrict__ bias,
        float* __restrict__ C,
        int M, int N, int K) {
    __shared__ float As[128][17];
    __shared__ float Ws[64][17];
    int t = threadIdx.x, lane = t & 31, w = t >> 5;
    int grp = lane >> 2, tig = lane & 3;
    int m0 = blockIdx.x * 128, n0 = blockIdx.y * 64;
    int mw = (w & 3) * 32, nw = (w >> 2) * 32;
    float acc[2][4][4];
    #pragma unroll
    for (int mi = 0; mi < 2; mi++)
        #pragma unroll
        for (int ni = 0; ni < 4; ni++)
            #pragma unroll
            for (int c = 0; c < 4; c++) acc[mi][ni][c] = 0.f;

    for (int k0 = 0; k0 < K; k0 += 16) {
        int ar = t >> 1, ak = (t & 1) * 8;
        const float* ap = A + (size_t)(m0 + ar) * K + k0 + ak;
        float4 v0 = *(const float4*)ap;
        float4 v1 = *(const float4*)(ap + 4);
        As[ar][ak + 0] = to_tf32(v0.x); As[ar][ak + 1] = to_tf32(v0.y);
        As[ar][ak + 2] = to_tf32(v0.z); As[ar][ak + 3] = to_tf32(v0.w);
        As[ar][ak + 4] = to_tf32(v1.x); As[ar][ak + 5] = to_tf32(v1.y);
        As[ar][ak + 6] = to_tf32(v1.z); As[ar][ak + 7] = to_tf32(v1.w);
        int wr = t >> 2, wk = (t & 3) * 4;
        float4 wv = make_float4(0.f, 0.f, 0.f, 0.f);
        if (n0 + wr < N)
            wv = *(const float4*)(W + (size_t)(n0 + wr) * K + k0 + wk);
        Ws[wr][wk + 0] = to_tf32(wv.x); Ws[wr][wk + 1] = to_tf32(wv.y);
        Ws[wr][wk + 2] = to_tf32(wv.z); Ws[wr][wk + 3] = to_tf32(wv.w);
        __syncthreads();
        #pragma unroll
        for (int kk = 0; kk < 2; kk++) {
            int kb = kk * 8;
            unsigned a[2][4];
            #pragma unroll
            for (int mi = 0; mi < 2; mi++) {
                int r = mw + mi * 16 + grp;
                a[mi][0] = __float_as_uint(As[r][kb + tig]);
                a[mi][1] = __float_as_uint(As[r + 8][kb + tig]);
                a[mi][2] = __float_as_uint(As[r][kb + tig + 4]);
                a[mi][3] = __float_as_uint(As[r + 8][kb + tig + 4]);
            }
            #pragma unroll
            for (int ni = 0; ni < 4; ni++) {
                int n = nw + ni * 8 + grp;
                unsigned bb0 = __float_as_uint(Ws[n][kb + tig]);
                unsigned bb1 = __float_as_uint(Ws[n][kb + tig + 4]);
                mma_tf32(acc[0][ni], a[0], bb0, bb1);
                mma_tf32(acc[1][ni], a[1], bb0, bb1);
            }
        }
        __syncthreads();
    }
    #pragma unroll
    for (int mi = 0; mi < 2; mi++) {
        #pragma unroll
        for (int ni = 0; ni < 4; ni++) {
            #pragma unroll
            for (int ci = 0; ci < 4; ci++) {
                int r = m0 + mw + mi * 16 + grp + ((ci >= 2) ? 8 : 0);
                int n = n0 + nw + ni * 8 + tig * 2 + (ci & 1);
                if (n < N)
                    C[(size_t)r * N + n] = fmaxf(acc[mi][ni][ci] + bias[n], 0.f);
            }
        }
    }
}

// ======================================================================
// 3xTF32 GEMM (encoder fc1): PRE-SPLIT hi/lo planes in smem
// ======================================================================
__global__ void __launch_bounds__(256) gemm_tc3(
        const float* __restrict__ A,
        const float* __restrict__ W,
        const float* __restrict__ bias,
        float* __restrict__ C,
        int M, int N, int K) {
    __shared__ float Ah[128][17], Al[128][17];
    __shared__ float Wh[64][17],  Wl[64][17];
    int t = threadIdx.x, lane = t & 31, w = t >> 5;
    int grp = lane >> 2, tig = lane & 3;
    int m0 = blockIdx.x * 128, n0 = blockIdx.y * 64;
    int mw = (w & 3) * 32, nw = (w >> 2) * 32;
    float acc[2][4][4];
    #pragma unroll
    for (int mi = 0; mi < 2; mi++)
        #pragma unroll
        for (int ni = 0; ni < 4; ni++)
            #pragma unroll
            for (int c = 0; c < 4; c++) acc[mi][ni][c] = 0.f;

    for (int k0 = 0; k0 < K; k0 += 16) {
        int ar = t >> 1, ak = (t & 1) * 8;
        const float* ap = A + (size_t)(m0 + ar) * K + k0 + ak;
        float4 v0 = *(const float4*)ap;
        float4 v1 = *(const float4*)(ap + 4);
        float av[8] = {v0.x, v0.y, v0.z, v0.w, v1.x, v1.y, v1.z, v1.w};
        #pragma unroll
        for (int j = 0; j < 8; j++) {
            float h, l;
            split_tf32_f(av[j], h, l);
            Ah[ar][ak + j] = h;
            Al[ar][ak + j] = l;
        }
        int wr = t >> 2, wk = (t & 3) * 4;
        float4 wv = make_float4(0.f, 0.f, 0.f, 0.f);
        if (n0 + wr < N)
            wv = *(const float4*)(W + (size_t)(n0 + wr) * K + k0 + wk);
        float wvv[4] = {wv.x, wv.y, wv.z, wv.w};
        #pragma unroll
        for (int j = 0; j < 4; j++) {
            float h, l;
            split_tf32_f(wvv[j], h, l);
            Wh[wr][wk + j] = h;
            Wl[wr][wk + j] = l;
        }
        __syncthreads();
        #pragma unroll
        for (int kk = 0; kk < 2; kk++) {
            int kb = kk * 8;
            unsigned ah[2][4], al[2][4];
            #pragma unroll
            for (int mi = 0; mi < 2; mi++) {
                int r = mw + mi * 16 + grp;
                ah[mi][0] = __float_as_uint(Ah[r][kb + tig]);
                ah[mi][1] = __float_as_uint(Ah[r + 8][kb + tig]);
                ah[mi][2] = __float_as_uint(Ah[r][kb + tig + 4]);
                ah[mi][3] = __float_as_uint(Ah[r + 8][kb + tig + 4]);
                al[mi][0] = __float_as_uint(Al[r][kb + tig]);
                al[mi][1] = __float_as_uint(Al[r + 8][kb + tig]);
                al[mi][2] = __float_as_uint(Al[r][kb + tig + 4]);
                al[mi][3] = __float_as_uint(Al[r + 8][kb + tig + 4]);
            }
            #pragma unroll
            for (int ni = 0; ni < 4; ni++) {
                int n = nw + ni * 8 + grp;
                unsigned bh0 = __float_as_uint(Wh[n][kb + tig]);
                unsigned bh1 = __float_as_uint(Wh[n][kb + tig + 4]);
                unsigned bl0 = __float_as_uint(Wl[n][kb + tig]);
                unsigned bl1 = __float_as_uint(Wl[n][kb + tig + 4]);
                mma3(acc[0][ni], ah[0], al[0], bh0, bh1, bl0, bl1);
                mma3(acc[1][ni], ah[1], al[1], bh0, bh1, bl0, bl1);
            }
        }
        __syncthreads();
    }
    #pragma unroll
    for (int mi = 0; mi < 2; mi++) {
        #pragma unroll
        for (int ni = 0; ni < 4; ni++) {
            #pragma unroll
            for (int ci = 0; ci < 4; ci++) {
                int r = m0 + mw + mi * 16 + grp + ((ci >= 2) ? 8 : 0);
                int n = n0 + nw + ni * 8 + tig * 2 + (ci & 1);
                if (n < N)
                    C[(size_t)r * N + n] = fmaxf(acc[mi][ni][ci] + bias[n], 0.f);
            }
        }
    }
}

// ======================================================================
// convt1 single-TF32 (decoder)                                [round-4]
// ======================================================================
#define T1_IMSZ 2916
#define T1_ZB   6240
#define T1_XIN  6664
#define T1_WOFF T1_XIN
#define T1_WSZ  (16 * 32 * 24)
#define T1_SMEM ((T1_XIN + T1_WSZ) * 4)

__global__ void __launch_bounds__(256) convt1_tc(
        const float* __restrict__ in,
        const float* __restrict__ w,
        const float* __restrict__ bias,
        float* __restrict__ out) {
    extern __shared__ float sm[];
    float* xin = sm;
    float* wt  = sm + T1_WOFF;
    int t = threadIdx.x;
    int b0 = blockIdx.x * 2;

    for (int i = t; i < T1_XIN; i += 256) xin[i] = 0.f;
    __syncthreads();
    for (int i = t; i < 2 * 1568; i += 256) {
        int img = i / 1568, j = i % 1568;
        int ic = j / 49, p = j % 49, iy = p / 7, ix = p % 7;
        xin[img * T1_IMSZ + ((iy + 1) * 9 + (ix + 1)) * 36 + ic] =
            to_tf32(in[(size_t)(b0 + img) * 1568 + j]);
    }
    for (int i = t; i < 32 * 256; i += 256) {
        int ic = i / 256, r = i % 256, oc = r / 16, s = r % 16;
        wt[s * 768 + ic * 24 + oc] = to_tf32(w[i]);
    }
    __syncthreads();

    int lane = t & 31, wrp = t >> 5;
    int grp = lane >> 2, tig = lane & 3;
    int img = wrp >> 2, ph = wrp & 3;
    int a = ph >> 1, bp = ph & 1;
    int dyv[2], kyv[2], dxv[2], kxv[2];
    if (a == 0) { dyv[0] = 0; kyv[0] = 1; dyv[1] = -1; kyv[1] = 3; }
    else        { dyv[0] = 1; kyv[0] = 0; dyv[1] =  0; kyv[1] = 2; }
    if (bp == 0) { dxv[0] = 0; kxv[0] = 1; dxv[1] = -1; kxv[1] = 3; }
    else         { dxv[0] = 1; kxv[0] = 0; dxv[1] =  0; kxv[1] = 2; }

    int rb[4][2];
    #pragma unroll
    for (int mi = 0; mi < 4; mi++)
        #pragma unroll
        for (int h = 0; h < 2; h++) {
            int p = mi * 16 + grp + h * 8;
            rb[mi][h] = (p < 49)
                ? img * T1_IMSZ + ((p / 7 + 1) * 9 + (p % 7 + 1)) * 36
                : T1_ZB;
        }

    float acc[4][2][4];
    #pragma unroll
    for (int mi = 0; mi < 4; mi++)
        #pragma unroll
        for (int ni = 0; ni < 2; ni++)
            #pragma unroll
            for (int c = 0; c < 4; c++) acc[mi][ni][c] = 0.f;

    #pragma unroll
    for (int sy = 0; sy < 2; sy++) {
        #pragma unroll
        for (int sx = 0; sx < 2; sx++) {
            int soff = (dyv[sy] * 9 + dxv[sx]) * 36;
            const float* wsl = wt + (kyv[sy] * 4 + kxv[sx]) * 768;
            #pragma unroll
            for (int kk = 0; kk < 4; kk++) {
                int kb = kk * 8;
                unsigned afr[4][4];
                #pragma unroll
                for (int mi = 0; mi < 4; mi++) {
                    afr[mi][0] = __float_as_uint(xin[rb[mi][0] + soff + kb + tig]);
                    afr[mi][1] = __float_as_uint(xin[rb[mi][1] + soff + kb + tig]);
                    afr[mi][2] = __float_as_uint(xin[rb[mi][0] + soff + kb + tig + 4]);
                    afr[mi][3] = __float_as_uint(xin[rb[mi][1] + soff + kb + tig + 4]);
                }
                #pragma unroll
                for (int ni = 0; ni < 2; ni++) {
                    unsigned bb0 = __float_as_uint(wsl[(kb + tig) * 24 + ni * 8 + grp]);
                    unsigned bb1 = __float_as_uint(wsl[(kb + tig + 4) * 24 + ni * 8 + grp]);
                    #pragma unroll
                    for (int mi = 0; mi < 4; mi++)
                        mma_tf32(acc[mi][ni], afr[mi], bb0, bb1);
                }
            }
        }
    }

    #pragma unroll
    for (int mi = 0; mi < 4; mi++) {
        #pragma unroll
        for (int ni = 0; ni < 2; ni++) {
            #pragma unroll
            for (int ci = 0; ci < 4; ci++) {
                int p = mi * 16 + grp + ((ci >= 2) ? 8 : 0);
                if (p < 49) {
                    int m = p / 7, n = p % 7;
                    int oc = ni * 8 + tig * 2 + (ci & 1);
                    int oy = 2 * m + a, ox = 2 * n + bp;
                    float v = acc[mi][ni][ci] + __ldg(bias + oc);
                    out[(size_t)(b0 + img) * 3136 + oc * 196 + oy * 14 + ox] =
                        fmaxf(v, 0.f);
                }
            }
        }
    }
}

// ======================================================================
// fc2: z[B,32] = A[B,224] @ w^T + b  (fp32, feeds VQ)
// ======================================================================
__global__ void fc2_kernel(const float* __restrict__ A,
                           const float* __restrict__ w,
                           const float* __restrict__ bias,
                           float* __restrict__ out) {
    __shared__ float ws[32 * 224];
    int t = threadIdx.x;
    for (int i = t; i < 7168; i += 256) ws[i] = w[i];
    __syncthreads();
    int n = t & 31, r = t >> 5;
    int b = blockIdx.x * 8 + r;
    const float* ap = A + (size_t)b * 224;
    const float* wp = ws + n * 224;
    float acc = bias[n];
    #pragma unroll 8
    for (int k = 0; k < 224; k++) acc += ap[k] * wp[k];
    out[(size_t)b * 32 + n] = acc;
}

// ======================================================================
// VQ helpers (fp32 exact)
// ======================================================================
__global__ void enorm_kernel(const float* __restrict__ emb, float* __restrict__ enorm) {
    int e = blockIdx.x * blockDim.x + threadIdx.x;
    if (e < NE) {
        float s = 0.f;
        #pragma unroll
        for (int d = 0; d < ZD; d++) { float v = emb[e * ZD + d]; s += v * v; }
        enorm[e] = s;
    }
}

__global__ void zero_kernel(float* __restrict__ counts, float* __restrict__ sums,
                            float* __restrict__ loss) {
    int i = blockIdx.x * blockDim.x + threadIdx.x;
    if (i < NE) counts[i] = 0.f;
    if (i < NE * ZD) sums[i] = 0.f;
    if (i == 0) loss[0] = 0.f;
}

__global__ void vq_kernel(const float* __restrict__ z,
                          const float* __restrict__ emb,
                          const float* __restrict__ enorm,
                          int* __restrict__ idx,
                          float* __restrict__ counts,
                          float* __restrict__ sums,
                          float* __restrict__ loss) {
    int gw = (blockIdx.x * blockDim.x + threadIdx.x) >> 5;
    int lane = threadIdx.x & 31;
    int wl = threadIdx.x >> 5;
    __shared__ float zs[8][ZD];
    if (gw >= BATCH) return;
    zs[wl][lane] = z[(size_t)gw * ZD + lane];
    __syncwarp();
    float best = 3.4e38f; int bi = NE;
    for (int e = lane; e < NE; e += 32) {
        const float* ep = emb + e * ZD;
        float dot = 0.f;
        #pragma unroll
        for (int d = 0; d < ZD; d++) dot += zs[wl][d] * __ldg(ep + d);
        float s = enorm[e] - 2.f * dot;
        if (s < best) { best = s; bi = e; }
    }
    #pragma unroll
    for (int off = 16; off; off >>= 1) {
        float ob = __shfl_xor_sync(0xffffffffu, best, off);
        int   oi = __shfl_xor_sync(0xffffffffu, bi, off);
        if (ob < best || (ob == best && oi < bi)) { best = ob; bi = oi; }
    }
    float zl = zs[wl][lane];
    float diff = __ldg(emb + (size_t)bi * ZD + lane) - zl;
    float d2 = diff * diff;
    #pragma unroll
    for (int off = 16; off; off >>= 1) d2 += __shfl_xor_sync(0xffffffffu, d2, off);
    if (lane == 0) {
        idx[gw] = bi;
        atomicAdd(&counts[bi], 1.f);
        atomicAdd(loss, d2);
    }
    atomicAdd(&sums[bi * ZD + lane], zl);
}

__global__ void embnew_kernel(const float* __restrict__ m_mat,
                              const float* __restrict__ n_mat,
                              const float* __restrict__ sums,
                              const float* __restrict__ counts,
                              float* __restrict__ out) {
    int i = blockIdx.x * blockDim.x + threadIdx.x;
    if (i < NE * ZD) {
        int e = i >> 5;
        float m = m_mat[i] * GAMMA + sums[i] * ONE_M_GAMMA;
        float n = n_mat[e] * GAMMA + counts[e] * ONE_M_GAMMA;
        out[i] = m / n;
    }
}

__global__ void finalize_kernel(const float* __restrict__ counts,
                                const float* __restrict__ loss,
                                float* __restrict__ out_scalars) {
    __shared__ float red[NE];
    int t = threadIdx.x;
    float c = counts[t];
    float em = c * (1.f / (float)BATCH);
    red[t] = em * logf(em + 1e-10f);
    __syncthreads();
    for (int s = 256; s; s >>= 1) {
        if (t < s) red[t] += red[t + s];
        __syncthreads();
    }
    if (t == 0) {
        float q = loss[0] * (1.f / ((float)BATCH * (float)ZD));
        out_scalars[0] = q;
        out_scalars[1] = BETA * q;
        out_scalars[2] = expf(-red[0]);
    }
}

// ======================================================================
// fc3 (fp32)
// ======================================================================
__global__ void fc3_kernel(const float* __restrict__ emb,
                           const int* __restrict__ idx,
                           const float* __restrict__ w,
                           const float* __restrict__ bias,
                           float* __restrict__ out) {
    __shared__ float zq[ZD];
    int b = blockIdx.x, t = threadIdx.x;
    if (t < ZD) zq[t] = emb[(size_t)idx[b] * ZD + t];
    __syncthreads();
    const float* wp = w + t * ZD;
    float acc = bias[t];
    #pragma unroll
    for (int k = 0; k < ZD; k++) acc += zq[k] * __ldg(wp + k);
    out[(size_t)b * 224 + t] = fmaxf(acc, 0.f);
}

// ======================================================================
// convt2: in[B,16,14,14] -> out[B,1,28,28]  (fp32)
// ======================================================================
__global__ void convt2_kernel(const float* __restrict__ in,
                              const float* __restrict__ w,
                              const float* __restrict__ bias,
                              float* __restrict__ out) {
    __shared__ float img[3136];
    __shared__ float ws[256];
    int b = blockIdx.x, t = threadIdx.x;
    const float* ip = in + (size_t)b * 3136;
    for (int i = t; i < 3136; i += 256) img[i] = ip[i];
    if (t < 256) ws[t] = w[t];
    __syncthreads();
    float bv = bias[0];
    float* op = out + (size_t)b * 784;
    for (int o = t; o < 784; o += 256) {
        int oy = o / 28, ox = o % 28;
        float acc = bv;
        #pragma unroll
        for (int ky = 0; ky < 4; ky++) {
            int ty = oy + 1 - ky;
            if (ty < 0 || (ty & 1)) continue;
            int iy = ty >> 1;
            if (iy >= 14) continue;
            #pragma unroll
            for (int kx = 0; kx < 4; kx++) {
                int tx = ox + 1 - kx;
                if (tx < 0 || (tx & 1)) continue;
                int ix = tx >> 1;
                if (ix >= 14) continue;
                #pragma unroll
                for (int ic = 0; ic < 16; ic++)
                    acc += img[ic * 196 + iy * 14 + ix] * ws[ic * 16 + ky * 4 + kx];
            }
        }
        op[o] = acc;
    }
}

// ======================================================================
// launch
// ======================================================================
extern "C" void kernel_launch(void* const* d_in, const int* in_sizes, int n_in,
                              void* d_out, int out_size) {
    const float* x        = (const float*)d_in[0];
    const float* conv1_w  = (const float*)d_in[1];
    const float* conv1_b  = (const float*)d_in[2];
    const float* conv2_w  = (const float*)d_in[3];
    const float* conv2_b  = (const float*)d_in[4];
    const float* res1_w1  = (const float*)d_in[5];
    const float* res1_w2  = (const float*)d_in[6];
    const float* fc1_w    = (const float*)d_in[7];
    const float* fc1_b    = (const float*)d_in[8];
    const float* fc2_w    = (const float*)d_in[9];
    const float* fc2_b    = (const float*)d_in[10];
    const float* emb      = (const float*)d_in[11];
    const float* n_mat    = (const float*)d_in[12];
    const float* m_mat    = (const float*)d_in[13];
    const float* fc3_w    = (const float*)d_in[14];
    const float* fc3_b    = (const float*)d_in[15];
    const float* fc4_w    = (const float*)d_in[16];
    const float* fc4_b    = (const float*)d_in[17];
    const float* res2_w1  = (const float*)d_in[18];
    const float* res2_w2  = (const float*)d_in[19];
    const float* convt1_w = (const float*)d_in[20];
    const float* convt1_b = (const float*)d_in[21];
    const float* convt2_w = (const float*)d_in[22];
    const float* convt2_b = (const float*)d_in[23];
    float* out = (float*)d_out;

    float *h1, *h2, *a, *z, *enorm, *counts, *sums, *loss;
    int* idx;
    cudaGetSymbolAddress((void**)&h1,     g_h1);
    cudaGetSymbolAddress((void**)&h2,     g_h2);
    cudaGetSymbolAddress((void**)&a,      g_a);
    cudaGetSymbolAddress((void**)&z,      g_z);
    cudaGetSymbolAddress((void**)&idx,    g_idx);
    cudaGetSymbolAddress((void**)&enorm,  g_enorm);
    cudaGetSymbolAddress((void**)&counts, g_counts);
    cudaGetSymbolAddress((void**)&sums,   g_sums);
    cudaGetSymbolAddress((void**)&loss,   g_loss);

    cudaFuncSetAttribute(res_tc_kernel,
                         cudaFuncAttributeMaxDynamicSharedMemorySize, RTC_SMEMB);
    cudaFuncSetAttribute(res_tc3,
                         cudaFuncAttributeMaxDynamicSharedMemorySize, R3_SMEM);
    cudaFuncSetAttribute(conv2_tc3,
                         cudaFuncAttributeMaxDynamicSharedMemorySize, C2_SMEM);
    cudaFuncSetAttribute(convt1_tc,
                         cudaFuncAttributeMaxDynamicSharedMemorySize, T1_SMEM);

    // encoder (3xTF32 = fp32-class accuracy; VQ path preserved)
    conv1_kernel<<<BATCH, 256>>>(x, conv1_w, conv1_b, h1);
    conv2_tc3<<<BATCH / 4, 256, C2_SMEM>>>(h1, conv2_w, conv2_b, h2);
    res_tc3  <<<BATCH / 2, 256, R3_SMEM>>>(h2, res1_w1, res1_w2);
    gemm_tc3<<<dim3(BATCH / 128, 4), 256>>>(h2, fc1_w, fc1_b, a,
                                            BATCH, 224, 1568);
    fc2_kernel<<<BATCH / 8, 256>>>(a, fc2_w, fc2_b, z);

    // VQ
    zero_kernel <<<(NE * ZD + 255) / 256, 256>>>(counts, sums, loss);
    enorm_kernel<<<2, 256>>>(emb, enorm);
    vq_kernel   <<<BATCH / 8, 256>>>(z, emb, enorm, idx, counts, sums, loss);
    embnew_kernel  <<<(NE * ZD + 255) / 256, 256>>>(m_mat, n_mat, sums, counts,
                                                    out + OFF_SCAL + 3);
    finalize_kernel<<<1, NE>>>(counts, loss, out + OFF_SCAL);

    // decoder (single tf32)
    fc3_kernel<<<BATCH, 224>>>(emb, idx, fc3_w, fc3_b, a);
    gemm_tc<<<dim3(BATCH / 128, 25), 256>>>(a, fc4_w, fc4_b, h2,
                                            BATCH, 1568, 224);
    res_tc_kernel<<<BATCH / 4, 256, RTC_SMEMB>>>(h2, res2_w1, res2_w2);
    convt1_tc<<<BATCH / 2, 256, T1_SMEM>>>(h2, convt1_w, convt1_b, h1);
    convt2_kernel<<<BATCH, 256>>>(h1, convt2_w, convt2_b, out);
}

// round 6
// speedup vs baseline: 1.1964x; 1.1964x over previous
#include <cuda_runtime.h>
#include <cstdint>
#include <math.h>

// ---------------- problem constants ----------------
#define BATCH 16384
#define ZD 32
#define NE 512
#define GAMMA 0.99f
#define ONE_M_GAMMA 0.01f
#define BETA 1.0f

#define OFF_SCAL (BATCH * 784)   // x_rec size
// d_out layout: [x_rec (B*784)][quant][commit][perplexity][emb_new (512*32)]

// ---------------- scratch ----------------
__device__ float g_h1[BATCH * 16 * 14 * 14];
__device__ float g_h2[BATCH * 32 * 7 * 7];
__device__ float g_a [BATCH * 224];
__device__ float g_z [BATCH * ZD];
__device__ int   g_idx[BATCH];
__device__ float g_enorm[NE];
__device__ float g_counts[NE];
__device__ float g_sums[NE * ZD];
__device__ float g_loss[1];

// ---------------- tf32 mma helpers ----------------
__device__ __forceinline__ float to_tf32(float x) {
    float y;
    asm("cvt.rna.tf32.f32 %0, %1;" : "=f"(y) : "f"(x));
    return y;
}

__device__ __forceinline__ void split_tf32(float v, unsigned& hi, unsigned& lo) {
    float h;
    asm("cvt.rna.tf32.f32 %0, %1;" : "=f"(h) : "f"(v));
    float l = v - h;
    float l2;
    asm("cvt.rna.tf32.f32 %0, %1;" : "=f"(l2) : "f"(l));
    hi = __float_as_uint(h);
    lo = __float_as_uint(l2);
}

__device__ __forceinline__ void mma_tf32(float* d, const unsigned* a,
                                         unsigned b0, unsigned b1) {
    asm volatile(
        "mma.sync.aligned.m16n8k8.row.col.f32.tf32.tf32.f32 "
        "{%0,%1,%2,%3}, {%4,%5,%6,%7}, {%8,%9}, {%0,%1,%2,%3};\n"
        : "+f"(d[0]), "+f"(d[1]), "+f"(d[2]), "+f"(d[3])
        : "r"(a[0]), "r"(a[1]), "r"(a[2]), "r"(a[3]), "r"(b0), "r"(b1));
}

// 3-pass split mma: acc += a*b with ~fp32 accuracy
__device__ __forceinline__ void mma3(float* d, const unsigned* ah, const unsigned* al,
                                     unsigned bh0, unsigned bh1,
                                     unsigned bl0, unsigned bl1) {
    mma_tf32(d, ah, bl0, bl1);
    mma_tf32(d, al, bh0, bh1);
    mma_tf32(d, ah, bh0, bh1);
}

// ======================================================================
// conv1: x[B,1,28,28] -> relu -> h1[B,16,14,14]   (k4 s2 p1)  fp32
// ======================================================================
__global__ void conv1_kernel(const float* __restrict__ x,
                             const float* __restrict__ w,
                             const float* __restrict__ bias,
                             float* __restrict__ out) {
    __shared__ float img[784];
    __shared__ float ws[256];
    int b = blockIdx.x, t = threadIdx.x;
    const float* ip = x + (size_t)b * 784;
    for (int i = t; i < 784; i += 256) img[i] = ip[i];
    if (t < 256) ws[t] = w[t];
    __syncthreads();
    float* op = out + (size_t)b * 3136;
    for (int o = t; o < 3136; o += 256) {
        int oc = o / 196, s = o % 196, oy = s / 14, ox = s % 14;
        float acc = bias[oc];
        const float* wp = ws + oc * 16;
        #pragma unroll
        for (int ky = 0; ky < 4; ky++) {
            int iy = 2 * oy - 1 + ky;
            if ((unsigned)iy < 28u) {
                #pragma unroll
                for (int kx = 0; kx < 4; kx++) {
                    int ix = 2 * ox - 1 + kx;
                    if ((unsigned)ix < 28u)
                        acc += img[iy * 28 + ix] * wp[ky * 4 + kx];
                }
            }
        }
        op[o] = fmaxf(acc, 0.f);
    }
}

// ======================================================================
// conv2 3xTF32 shift-GEMM: h1[B,16,14,14] -> h2[B,32,7,7] (k4 s2 p1)
// 2 img/CTA, 256 thr, 92 KB smem -> 2 CTA/SM.
// warp = (img, m-half, n-half): mi=2 (32 rows), ni=2 (16 oc).
// Single-plane weights, inline splits (round-4 winning config).
// ======================================================================
#define C2B_ZOFF 9216                    // zero block (3rd image slot)
#define C2B_XIN  13824                   // 3 * 4608
#define C2B_W    C2B_XIN                 // wt [s][ic][36]: 16*16*36 = 9216
#define C2B_TOT  23040
#define C2B_SMEM (C2B_TOT * 4)           // 92160 B

__global__ void __launch_bounds__(256) conv2_tc3(
        const float* __restrict__ in,
        const float* __restrict__ w,
        const float* __restrict__ bias,
        float* __restrict__ out) {
    extern __shared__ float sm[];
    float* xin = sm;
    float* wt  = sm + C2B_W;
    int t = threadIdx.x;
    int b0 = blockIdx.x * 2;

    for (int i = t; i < C2B_XIN; i += 256) xin[i] = 0.f;
    __syncthreads();
    for (int i = t; i < 2 * 3136; i += 256) {
        int img = i / 3136, j = i % 3136;
        int ic = j / 196, p = j % 196, iy = p / 14, ix = p % 14;
        xin[img * 4608 + ((iy + 1) * 16 + (ix + 1)) * 18 + ic] =
            in[(size_t)(b0 + img) * 3136 + j];
    }
    for (int i = t; i < 8192; i += 256) {           // [oc][ic][s] -> [s][ic][oc]
        int oc = i / 256, r = i % 256, ic = r / 16, s = r % 16;
        wt[s * 576 + ic * 36 + oc] = w[i];
    }
    __syncthreads();

    int lane = t & 31, wrp = t >> 5;
    int grp = lane >> 2, tig = lane & 3;
    int img = wrp >> 2, mh = (wrp >> 1) & 1, nh = wrp & 1;

    int rb[2][2];
    #pragma unroll
    for (int mi = 0; mi < 2; mi++)
        #pragma unroll
        for (int h = 0; h < 2; h++) {
            int p = mh * 32 + mi * 16 + grp + h * 8;
            rb[mi][h] = (p < 49)
                ? img * 4608 + ((p / 7) * 32 + (p % 7) * 2) * 18
                : C2B_ZOFF;
        }

    float acc[2][2][4];
    #pragma unroll
    for (int mi = 0; mi < 2; mi++)
        #pragma unroll
        for (int ni = 0; ni < 2; ni++)
            #pragma unroll
            for (int c = 0; c < 4; c++) acc[mi][ni][c] = 0.f;

    #pragma unroll
    for (int ky = 0; ky < 4; ky++) {
        #pragma unroll
        for (int kx = 0; kx < 4; kx++) {
            int soff = (ky * 16 + kx) * 18;
            const float* wsp = wt + (ky * 4 + kx) * 576 + nh * 16;
            #pragma unroll
            for (int kk = 0; kk < 2; kk++) {
                int kb = kk * 8;
                unsigned ah[2][4], al[2][4];
                #pragma unroll
                for (int mi = 0; mi < 2; mi++) {
                    split_tf32(xin[rb[mi][0] + soff + kb + tig],     ah[mi][0], al[mi][0]);
                    split_tf32(xin[rb[mi][1] + soff + kb + tig],     ah[mi][1], al[mi][1]);
                    split_tf32(xin[rb[mi][0] + soff + kb + tig + 4], ah[mi][2], al[mi][2]);
                    split_tf32(xin[rb[mi][1] + soff + kb + tig + 4], ah[mi][3], al[mi][3]);
                }
                #pragma unroll
                for (int ni = 0; ni < 2; ni++) {
                    unsigned bh0, bl0, bh1, bl1;
                    split_tf32(wsp[(kb + tig) * 36 + ni * 8 + grp],     bh0, bl0);
                    split_tf32(wsp[(kb + tig + 4) * 36 + ni * 8 + grp], bh1, bl1);
                    mma3(acc[0][ni], ah[0], al[0], bh0, bh1, bl0, bl1);
                    mma3(acc[1][ni], ah[1], al[1], bh0, bh1, bl0, bl1);
                }
            }
        }
    }

    #pragma unroll
    for (int mi = 0; mi < 2; mi++) {
        #pragma unroll
        for (int ni = 0; ni < 2; ni++) {
            #pragma unroll
            for (int ci = 0; ci < 4; ci++) {
                int p = mh * 32 + mi * 16 + grp + ((ci >= 2) ? 8 : 0);
                if (p < 49) {
                    int oc = nh * 16 + ni * 8 + tig * 2 + (ci & 1);
                    out[(size_t)(b0 + img) * 1568 + oc * 49 + p] =
                        acc[mi][ni][ci] + __ldg(bias + oc);
                }
            }
        }
    }
}

// ======================================================================
// res stack 3xTF32 (encoder): 2 img/CTA, 111 KB -> 2 CTA/SM.
// warp = (img, m-half, n-half). Phase-2 rs buffer ALIASES the w1 region
// (w1 dead after phase 1; block syncs guard the transition).
// ======================================================================
#define E3_W1   5832                     // xin = 2 * 2916 (pitch 36)
#define E3_W2   25416                    // w1 [s][ic][68] = 19584
#define E3_TOT  27720                    // w2 [ic][36] = 2304
#define E3_RS   E3_W1                    // rs [128][68] = 8704 (alias)
#define E3_SMEM (E3_TOT * 4)             // 110880 B

__global__ void __launch_bounds__(256) res_tc3(
        float* __restrict__ buf,
        const float* __restrict__ pw1,
        const float* __restrict__ pw2) {
    extern __shared__ float sm[];
    float* xin = sm;
    float* w1s = sm + E3_W1;
    float* w2s = sm + E3_W2;
    float* rs  = sm + E3_RS;
    int t = threadIdx.x;
    int b0 = blockIdx.x * 2;

    for (int i = t; i < E3_W1; i += 256) xin[i] = 0.f;
    __syncthreads();
    for (int i = t; i < 18432; i += 256) {
        int oc = i / 288, rr = i % 288, ic = rr / 9, s = rr % 9;
        w1s[s * 2176 + ic * 68 + oc] = pw1[i];
    }
    for (int i = t; i < 2048; i += 256) {
        int oc = i >> 6, ic = i & 63;
        w2s[ic * 36 + oc] = pw2[i];
    }
    for (int i = t; i < 2 * 1568; i += 256) {
        int img = i / 1568, j = i % 1568;
        int ch = j / 49, p = j % 49;
        float v = buf[(size_t)(b0 + img) * 1568 + j];
        xin[img * 2916 + ((p / 7 + 1) * 9 + (p % 7 + 1)) * 36 + ch] = fmaxf(v, 0.f);
    }
    __syncthreads();

    int lane = t & 31, wrp = t >> 5;
    int grp = lane >> 2, tig = lane & 3;
    int img = wrp >> 2, mh = (wrp >> 1) & 1, nh = wrp & 1;
    int rbase = img * 64 + mh * 32;

    int rb[2][2];
    #pragma unroll
    for (int mi = 0; mi < 2; mi++)
        #pragma unroll
        for (int h = 0; h < 2; h++) {
            int p = mh * 32 + mi * 16 + grp + h * 8;
            // fake rows (p>=49) read img-0 halo zeros at base 0; discarded
            rb[mi][h] = (p < 49) ? img * 2916 + ((p / 7) * 9 + (p % 7)) * 36 : 0;
        }

    // ---- phase 1: conv3x3 (32 -> 64), 3xTF32, this warp's oc half ----
    float acc[2][4][4];
    #pragma unroll
    for (int mi = 0; mi < 2; mi++)
        #pragma unroll
        for (int ni = 0; ni < 4; ni++)
            #pragma unroll
            for (int c = 0; c < 4; c++) acc[mi][ni][c] = 0.f;

    #pragma unroll
    for (int ky = 0; ky < 3; ky++) {
        #pragma unroll
        for (int kx = 0; kx < 3; kx++) {
            int soff = (ky * 9 + kx) * 36;
            const float* wb = w1s + (ky * 3 + kx) * 2176 + nh * 32;
            #pragma unroll
            for (int kk = 0; kk < 4; kk++) {
                int kb = kk * 8;
                unsigned ah[2][4], al[2][4];
                #pragma unroll
                for (int mi = 0; mi < 2; mi++) {
                    split_tf32(xin[rb[mi][0] + soff + kb + tig],     ah[mi][0], al[mi][0]);
                    split_tf32(xin[rb[mi][1] + soff + kb + tig],     ah[mi][1], al[mi][1]);
                    split_tf32(xin[rb[mi][0] + soff + kb + tig + 4], ah[mi][2], al[mi][2]);
                    split_tf32(xin[rb[mi][1] + soff + kb + tig + 4], ah[mi][3], al[mi][3]);
                }
                #pragma unroll
                for (int ni = 0; ni < 4; ni++) {
                    unsigned bh0, bl0, bh1, bl1;
                    split_tf32(wb[(kb + tig) * 68 + ni * 8 + grp],     bh0, bl0);
                    split_tf32(wb[(kb + tig + 4) * 68 + ni * 8 + grp], bh1, bl1);
                    mma3(acc[0][ni], ah[0], al[0], bh0, bh1, bl0, bl1);
                    mma3(acc[1][ni], ah[1], al[1], bh0, bh1, bl0, bl1);
                }
            }
        }
    }

    __syncthreads();     // everyone done reading w1 -> safe to alias rs

    #pragma unroll
    for (int mi = 0; mi < 2; mi++) {
        int rlo = rbase + mi * 16 + grp, rhi = rlo + 8;
        #pragma unroll
        for (int ni = 0; ni < 4; ni++) {
            int c0 = nh * 32 + ni * 8 + tig * 2;
            rs[rlo * 68 + c0]     = fmaxf(acc[mi][ni][0], 0.f);
            rs[rlo * 68 + c0 + 1] = fmaxf(acc[mi][ni][1], 0.f);
            rs[rhi * 68 + c0]     = fmaxf(acc[mi][ni][2], 0.f);
            rs[rhi * 68 + c0 + 1] = fmaxf(acc[mi][ni][3], 0.f);
        }
    }
    __syncthreads();     // rs rows complete (written by both n-half warps)

    // ---- phase 2: conv1x1 (64 -> 32), 3xTF32, this warp's oc half ----
    float acc2[2][2][4];
    #pragma unroll
    for (int mi = 0; mi < 2; mi++)
        #pragma unroll
        for (int ni = 0; ni < 2; ni++)
            #pragma unroll
            for (int c = 0; c < 4; c++) acc2[mi][ni][c] = 0.f;

    #pragma unroll
    for (int kk = 0; kk < 8; kk++) {
        int kb = kk * 8;
        unsigned ah[2][4], al[2][4];
        #pragma unroll
        for (int mi = 0; mi < 2; mi++) {
            int rlo = rbase + mi * 16 + grp;
            split_tf32(rs[rlo * 68 + kb + tig],           ah[mi][0], al[mi][0]);
            split_tf32(rs[(rlo + 8) * 68 + kb + tig],     ah[mi][1], al[mi][1]);
            split_tf32(rs[rlo * 68 + kb + tig + 4],       ah[mi][2], al[mi][2]);
            split_tf32(rs[(rlo + 8) * 68 + kb + tig + 4], ah[mi][3], al[mi][3]);
        }
        #pragma unroll
        for (int ni = 0; ni < 2; ni++) {
            int c = nh * 16 + ni * 8 + grp;
            unsigned bh0, bl0, bh1, bl1;
            split_tf32(w2s[(kb + tig) * 36 + c],     bh0, bl0);
            split_tf32(w2s[(kb + tig + 4) * 36 + c], bh1, bl1);
            mma3(acc2[0][ni], ah[0], al[0], bh0, bh1, bl0, bl1);
            mma3(acc2[1][ni], ah[1], al[1], bh0, bh1, bl0, bl1);
        }
    }

    // epilogue: +residual (exact fp32 from gmem), relu, store
    #pragma unroll
    for (int mi = 0; mi < 2; mi++) {
        #pragma unroll
        for (int ni = 0; ni < 2; ni++) {
            #pragma unroll
            for (int ci = 0; ci < 4; ci++) {
                int p = mh * 32 + mi * 16 + grp + ((ci >= 2) ? 8 : 0);
                if (p < 49) {
                    int ch = nh * 16 + ni * 8 + tig * 2 + (ci & 1);
                    size_t g = (size_t)(b0 + img) * 1568 + ch * 49 + p;
                    float v = acc2[mi][ni][ci] + __ldg(buf + g);
                    buf[g] = fmaxf(v, 0.f);
                }
            }
        }
    }
}

// ======================================================================
// res stack single-TF32 (decoder): same 2-img/CTA + rs-alias structure.
// 109 KB -> 2 CTA/SM.
// ======================================================================
#define D3_W1   5346                     // xin = 2 * 2673 (pitch 33, tf32)
#define D3_W2   24930                    // w1 [s][ic][68] = 19584
#define D3_TOT  27234                    // w2 [ic][36] = 2304
#define D3_RS   D3_W1                    // rs [128][68] alias
#define D3_SMEM (D3_TOT * 4)             // 108936 B

__global__ void __launch_bounds__(256) res_tcd(
        float* __restrict__ buf,
        const float* __restrict__ pw1,
        const float* __restrict__ pw2) {
    extern __shared__ float sm[];
    float* xin = sm;
    float* w1s = sm + D3_W1;
    float* w2s = sm + D3_W2;
    float* rs  = sm + D3_RS;
    int t = threadIdx.x;
    int b0 = blockIdx.x * 2;

    for (int i = t; i < D3_W1; i += 256) xin[i] = 0.f;
    __syncthreads();
    for (int i = t; i < 18432; i += 256) {
        int oc = i / 288, rr = i % 288, ic = rr / 9, s = rr % 9;
        w1s[s * 2176 + ic * 68 + oc] = to_tf32(pw1[i]);
    }
    for (int i = t; i < 2048; i += 256) {
        int oc = i >> 6, ic = i & 63;
        w2s[ic * 36 + oc] = to_tf32(pw2[i]);
    }
    for (int i = t; i < 2 * 1568; i += 256) {
        int img = i / 1568, j = i % 1568;
        int ch = j / 49, p = j % 49;
        float v = buf[(size_t)(b0 + img) * 1568 + j];
        xin[img * 2673 + ((p / 7 + 1) * 9 + (p % 7 + 1)) * 33 + ch] =
            to_tf32(fmaxf(v, 0.f));
    }
    __syncthreads();

    int lane = t & 31, wrp = t >> 5;
    int grp = lane >> 2, tig = lane & 3;
    int img = wrp >> 2, mh = (wrp >> 1) & 1, nh = wrp & 1;
    int rbase = img * 64 + mh * 32;

    int rb[2][2];
    #pragma unroll
    for (int mi = 0; mi < 2; mi++)
        #pragma unroll
        for (int h = 0; h < 2; h++) {
            int p = mh * 32 + mi * 16 + grp + h * 8;
            rb[mi][h] = (p < 49) ? img * 2673 + ((p / 7) * 9 + (p % 7)) * 33 : 0;
        }

    // ---- phase 1 ----
    float acc[2][4][4];
    #pragma unroll
    for (int mi = 0; mi < 2; mi++)
        #pragma unroll
        for (int ni = 0; ni < 4; ni++)
            #pragma unroll
            for (int c = 0; c < 4; c++) acc[mi][ni][c] = 0.f;

    #pragma unroll
    for (int ky = 0; ky < 3; ky++) {
        #pragma unroll
        for (int kx = 0; kx < 3; kx++) {
            int soff = (ky * 9 + kx) * 33;
            const float* wb = w1s + (ky * 3 + kx) * 2176 + nh * 32;
            #pragma unroll
            for (int kk = 0; kk < 4; kk++) {
                int kb = kk * 8;
                unsigned a[2][4];
                #pragma unroll
                for (int mi = 0; mi < 2; mi++) {
                    a[mi][0] = __float_as_uint(xin[rb[mi][0] + soff + kb + tig]);
                    a[mi][1] = __float_as_uint(xin[rb[mi][1] + soff + kb + tig]);
                    a[mi][2] = __float_as_uint(xin[rb[mi][0] + soff + kb + tig + 4]);
                    a[mi][3] = __float_as_uint(xin[rb[mi][1] + soff + kb + tig + 4]);
                }
                #pragma unroll
                for (int ni = 0; ni < 4; ni++) {
                    unsigned bb0 = __float_as_uint(wb[(kb + tig) * 68 + ni * 8 + grp]);
                    unsigned bb1 = __float_as_uint(wb[(kb + tig + 4) * 68 + ni * 8 + grp]);
                    mma_tf32(acc[0][ni], a[0], bb0, bb1);
                    mma_tf32(acc[1][ni], a[1], bb0, bb1);
                }
            }
        }
    }

    __syncthreads();

    #pragma unroll
    for (int mi = 0; mi < 2; mi++) {
        int rlo = rbase + mi * 16 + grp, rhi = rlo + 8;
        #pragma unroll
        for (int ni = 0; ni < 4; ni++) {
            int c0 = nh * 32 + ni * 8 + tig * 2;
            rs[rlo * 68 + c0]     = to_tf32(fmaxf(acc[mi][ni][0], 0.f));
            rs[rlo * 68 + c0 + 1] = to_tf32(fmaxf(acc[mi][ni][1], 0.f));
            rs[rhi * 68 + c0]     = to_tf32(fmaxf(acc[mi][ni][2], 0.f));
            rs[rhi * 68 + c0 + 1] = to_tf32(fmaxf(acc[mi][ni][3], 0.f));
        }
    }
    __syncthreads();

    // ---- phase 2 ----
    float acc2[2][2][4];
    #pragma unroll
    for (int mi = 0; mi < 2; mi++)
        #pragma unroll
        for (int ni = 0; ni < 2; ni++)
            #pragma unroll
            for (int c = 0; c < 4; c++) acc2[mi][ni][c] = 0.f;

    #pragma unroll
    for (int kk = 0; kk < 8; kk++) {
        int kb = kk * 8;
        unsigned a[2][4];
        #pragma unroll
        for (int mi = 0; mi < 2; mi++) {
            int rlo = rbase + mi * 16 + grp;
            a[mi][0] = __float_as_uint(rs[rlo * 68 + kb + tig]);
            a[mi][1] = __float_as_uint(rs[(rlo + 8) * 68 + kb + tig]);
            a[mi][2] = __float_as_uint(rs[rlo * 68 + kb + tig + 4]);
            a[mi][3] = __float_as_uint(rs[(rlo + 8) * 68 + kb + tig + 4]);
        }
        #pragma unroll
        for (int ni = 0; ni < 2; ni++) {
            int c = nh * 16 + ni * 8 + grp;
            unsigned bb0 = __float_as_uint(w2s[(kb + tig) * 36 + c]);
            unsigned bb1 = __float_as_uint(w2s[(kb + tig + 4) * 36 + c]);
            mma_tf32(acc2[0][ni], a[0], bb0, bb1);
            mma_tf32(acc2[1][ni], a[1], bb0, bb1);
        }
    }

    #pragma unroll
    for (int mi = 0; mi < 2; mi++) {
        #pragma unroll
        for (int ni = 0; ni < 2; ni++) {
            #pragma unroll
            for (int ci = 0; ci < 4; ci++) {
                int p = mh * 32 + mi * 16 + grp + ((ci >= 2) ? 8 : 0);
                if (p < 49) {
                    int ch = nh * 16 + ni * 8 + tig * 2 + (ci & 1);
                    size_t g = (size_t)(b0 + img) * 1568 + ch * 49 + p;
                    float v = acc2[mi][ni][ci] + __ldg(buf + g);
                    buf[g] = fmaxf(v, 0.f);
                }
            }
        }
    }
}

// ======================================================================
// TF32 GEMM (single, decoder fc4): C = relu(A @ W^T + bias)   [round-3]
// ======================================================================
__global__ void __launch_bounds__(256) gemm_tc(
        const float* __restrict__ A,
        const float* __restrict__ W,
        const float* __restrict__ bias,
        float* __restrict__ C,
        int M, int N, int K) {
    __shared__ float As[128][17];
    __shared__ float Ws[64][17];
    int t = threadIdx.x, lane = t & 31, w = t >> 5;
    int grp = lane >> 2, tig = lane & 3;
    int m0 = blockIdx.x * 128, n0 = blockIdx.y * 64;
    int mw = (w & 3) * 32, nw = (w >> 2) * 32;
    float acc[2][4][4];
    #pragma unroll
    for (int mi = 0; mi < 2; mi++)
        #pragma unroll
        for (int ni = 0; ni < 4; ni++)
            #pragma unroll
            for (int c = 0; c < 4; c++) acc[mi][ni][c] = 0.f;

    for (int k0 = 0; k0 < K; k0 += 16) {
        int ar = t >> 1, ak = (t & 1) * 8;
        const float* ap = A + (size_t)(m0 + ar) * K + k0 + ak;
        float4 v0 = *(const float4*)ap;
        float4 v1 = *(const float4*)(ap + 4);
        As[ar][ak + 0] = to_tf32(v0.x); As[ar][ak + 1] = to_tf32(v0.y);
        As[ar][ak + 2] = to_tf32(v0.z); As[ar][ak + 3] = to_tf32(v0.w);
        As[ar][ak + 4] = to_tf32(v1.x); As[ar][ak + 5] = to_tf32(v1.y);
        As[ar][ak + 6] = to_tf32(v1.z); As[ar][ak + 7] = to_tf32(v1.w);
        int wr = t >> 2, wk = (t & 3) * 4;
        float4 wv = make_float4(0.f, 0.f, 0.f, 0.f);
        if (n0 + wr < N)
            wv = *(const float4*)(W + (size_t)(n0 + wr) * K + k0 + wk);
        Ws[wr][wk + 0] = to_tf32(wv.x); Ws[wr][wk + 1] = to_tf32(wv.y);
        Ws[wr][wk + 2] = to_tf32(wv.z); Ws[wr][wk + 3] = to_tf32(wv.w);
        __syncthreads();
        #pragma unroll
        for (int kk = 0; kk < 2; kk++) {
            int kb = kk * 8;
            unsigned a[2][4];
            #pragma unroll
            for (int mi = 0; mi < 2; mi++) {
                int r = mw + mi * 16 + grp;
                a[mi][0] = __float_as_uint(As[r][kb + tig]);
                a[mi][1] = __float_as_uint(As[r + 8][kb + tig]);
                a[mi][2] = __float_as_uint(As[r][kb + tig + 4]);
                a[mi][3] = __float_as_uint(As[r + 8][kb + tig + 4]);
            }
            #pragma unroll
            for (int ni = 0; ni < 4; ni++) {
                int n = nw + ni * 8 + grp;
                unsigned bb0 = __float_as_uint(Ws[n][kb + tig]);
                unsigned bb1 = __float_as_uint(Ws[n][kb + tig + 4]);
                mma_tf32(acc[0][ni], a[0], bb0, bb1);
                mma_tf32(acc[1][ni], a[1], bb0, bb1);
            }
        }
        __syncthreads();
    }
    #pragma unroll
    for (int mi = 0; mi < 2; mi++) {
        #pragma unroll
        for (int ni = 0; ni < 4; ni++) {
            #pragma unroll
            for (int ci = 0; ci < 4; ci++) {
                int r = m0 + mw + mi * 16 + grp + ((ci >= 2) ? 8 : 0);
                int n = n0 + nw + ni * 8 + tig * 2 + (ci & 1);
                if (n < N)
                    C[(size_t)r * N + n] = fmaxf(acc[mi][ni][ci] + bias[n], 0.f);
            }
        }
    }
}

// ======================================================================
// 3xTF32 GEMM (encoder fc1): inline splits (round-4 config)
// ======================================================================
__global__ void __launch_bounds__(256) gemm_tc3(
        const float* __restrict__ A,
        const float* __restrict__ W,
        const float* __restrict__ bias,
        float* __restrict__ C,
        int M, int N, int K) {
    __shared__ float As[128][17];
    __shared__ float Ws[64][17];
    int t = threadIdx.x, lane = t & 31, w = t >> 5;
    int grp = lane >> 2, tig = lane & 3;
    int m0 = blockIdx.x * 128, n0 = blockIdx.y * 64;
    int mw = (w & 3) * 32, nw = (w >> 2) * 32;
    float acc[2][4][4];
    #pragma unroll
    for (int mi = 0; mi < 2; mi++)
        #pragma unroll
        for (int ni = 0; ni < 4; ni++)
            #pragma unroll
            for (int c = 0; c < 4; c++) acc[mi][ni][c] = 0.f;

    for (int k0 = 0; k0 < K; k0 += 16) {
        int ar = t >> 1, ak = (t & 1) * 8;
        const float* ap = A + (size_t)(m0 + ar) * K + k0 + ak;
        float4 v0 = *(const float4*)ap;
        float4 v1 = *(const float4*)(ap + 4);
        As[ar][ak + 0] = v0.x; As[ar][ak + 1] = v0.y;
        As[ar][ak + 2] = v0.z; As[ar][ak + 3] = v0.w;
        As[ar][ak + 4] = v1.x; As[ar][ak + 5] = v1.y;
        As[ar][ak + 6] = v1.z; As[ar][ak + 7] = v1.w;
        int wr = t >> 2, wk = (t & 3) * 4;
        float4 wv = make_float4(0.f, 0.f, 0.f, 0.f);
        if (n0 + wr < N)
            wv = *(const float4*)(W + (size_t)(n0 + wr) * K + k0 + wk);
        Ws[wr][wk + 0] = wv.x; Ws[wr][wk + 1] = wv.y;
        Ws[wr][wk + 2] = wv.z; Ws[wr][wk + 3] = wv.w;
        __syncthreads();
        #pragma unroll
        for (int kk = 0; kk < 2; kk++) {
            int kb = kk * 8;
            unsigned ah[2][4], al[2][4];
            #pragma unroll
            for (int mi = 0; mi < 2; mi++) {
                int r = mw + mi * 16 + grp;
                split_tf32(As[r][kb + tig],         ah[mi][0], al[mi][0]);
                split_tf32(As[r + 8][kb + tig],     ah[mi][1], al[mi][1]);
                split_tf32(As[r][kb + tig + 4],     ah[mi][2], al[mi][2]);
                split_tf32(As[r + 8][kb + tig + 4], ah[mi][3], al[mi][3]);
            }
            #pragma unroll
            for (int ni = 0; ni < 4; ni++) {
                int n = nw + ni * 8 + grp;
                unsigned bh0, bl0, bh1, bl1;
                split_tf32(Ws[n][kb + tig],     bh0, bl0);
                split_tf32(Ws[n][kb + tig + 4], bh1, bl1);
                mma3(acc[0][ni], ah[0], al[0], bh0, bh1, bl0, bl1);
                mma3(acc[1][ni], ah[1], al[1], bh0, bh1, bl0, bl1);
            }
        }
        __syncthreads();
    }
    #pragma unroll
    for (int mi = 0; mi < 2; mi++) {
        #pragma unroll
        for (int ni = 0; ni < 4; ni++) {
            #pragma unroll
            for (int ci = 0; ci < 4; ci++) {
                int r = m0 + mw + mi * 16 + grp + ((ci >= 2) ? 8 : 0);
                int n = n0 + nw + ni * 8 + tig * 2 + (ci & 1);
                if (n < N)
                    C[(size_t)r * N + n] = fmaxf(acc[mi][ni][ci] + bias[n], 0.f);
            }
        }
    }
}

// ======================================================================
// convt1 single-TF32 (decoder)                                [round-4]
// ======================================================================
#define T1_IMSZ 2916
#define T1_ZB   6240
#define T1_XIN  6664
#define T1_WOFF T1_XIN
#define T1_WSZ  (16 * 32 * 24)
#define T1_SMEM ((T1_XIN + T1_WSZ) * 4)

__global__ void __launch_bounds__(256) convt1_tc(
        const float* __restrict__ in,
        const float* __restrict__ w,
        const float* __restrict__ bias,
        float* __restrict__ out) {
    extern __shared__ float sm[];
    float* xin = sm;
    float* wt  = sm + T1_WOFF;
    int t = threadIdx.x;
    int b0 = blockIdx.x * 2;

    for (int i = t; i < T1_XIN; i += 256) xin[i] = 0.f;
    __syncthreads();
    for (int i = t; i < 2 * 1568; i += 256) {
        int img = i / 1568, j = i % 1568;
        int ic = j / 49, p = j % 49, iy = p / 7, ix = p % 7;
        xin[img * T1_IMSZ + ((iy + 1) * 9 + (ix + 1)) * 36 + ic] =
            to_tf32(in[(size_t)(b0 + img) * 1568 + j]);
    }
    for (int i = t; i < 32 * 256; i += 256) {
        int ic = i / 256, r = i % 256, oc = r / 16, s = r % 16;
        wt[s * 768 + ic * 24 + oc] = to_tf32(w[i]);
    }
    __syncthreads();

    int lane = t & 31, wrp = t >> 5;
    int grp = lane >> 2, tig = lane & 3;
    int img = wrp >> 2, ph = wrp & 3;
    int a = ph >> 1, bp = ph & 1;
    int dyv[2], kyv[2], dxv[2], kxv[2];
    if (a == 0) { dyv[0] = 0; kyv[0] = 1; dyv[1] = -1; kyv[1] = 3; }
    else        { dyv[0] = 1; kyv[0] = 0; dyv[1] =  0; kyv[1] = 2; }
    if (bp == 0) { dxv[0] = 0; kxv[0] = 1; dxv[1] = -1; kxv[1] = 3; }
    else         { dxv[0] = 1; kxv[0] = 0; dxv[1] =  0; kxv[1] = 2; }

    int rb[4][2];
    #pragma unroll
    for (int mi = 0; mi < 4; mi++)
        #pragma unroll
        for (int h = 0; h < 2; h++) {
            int p = mi * 16 + grp + h * 8;
            rb[mi][h] = (p < 49)
                ? img * T1_IMSZ + ((p / 7 + 1) * 9 + (p % 7 + 1)) * 36
                : T1_ZB;
        }

    float acc[4][2][4];
    #pragma unroll
    for (int mi = 0; mi < 4; mi++)
        #pragma unroll
        for (int ni = 0; ni < 2; ni++)
            #pragma unroll
            for (int c = 0; c < 4; c++) acc[mi][ni][c] = 0.f;

    #pragma unroll
    for (int sy = 0; sy < 2; sy++) {
        #pragma unroll
        for (int sx = 0; sx < 2; sx++) {
            int soff = (dyv[sy] * 9 + dxv[sx]) * 36;
            const float* wsl = wt + (kyv[sy] * 4 + kxv[sx]) * 768;
            #pragma unroll
            for (int kk = 0; kk < 4; kk++) {
                int kb = kk * 8;
                unsigned afr[4][4];
                #pragma unroll
                for (int mi = 0; mi < 4; mi++) {
                    afr[mi][0] = __float_as_uint(xin[rb[mi][0] + soff + kb + tig]);
                    afr[mi][1] = __float_as_uint(xin[rb[mi][1] + soff + kb + tig]);
                    afr[mi][2] = __float_as_uint(xin[rb[mi][0] + soff + kb + tig + 4]);
                    afr[mi][3] = __float_as_uint(xin[rb[mi][1] + soff + kb + tig + 4]);
                }
                #pragma unroll
                for (int ni = 0; ni < 2; ni++) {
                    unsigned bb0 = __float_as_uint(wsl[(kb + tig) * 24 + ni * 8 + grp]);
                    unsigned bb1 = __float_as_uint(wsl[(kb + tig + 4) * 24 + ni * 8 + grp]);
                    #pragma unroll
                    for (int mi = 0; mi < 4; mi++)
                        mma_tf32(acc[mi][ni], afr[mi], bb0, bb1);
                }
            }
        }
    }

    #pragma unroll
    for (int mi = 0; mi < 4; mi++) {
        #pragma unroll
        for (int ni = 0; ni < 2; ni++) {
            #pragma unroll
            for (int ci = 0; ci < 4; ci++) {
                int p = mi * 16 + grp + ((ci >= 2) ? 8 : 0);
                if (p < 49) {
                    int m = p / 7, n = p % 7;
                    int oc = ni * 8 + tig * 2 + (ci & 1);
                    int oy = 2 * m + a, ox = 2 * n + bp;
                    float v = acc[mi][ni][ci] + __ldg(bias + oc);
                    out[(size_t)(b0 + img) * 3136 + oc * 196 + oy * 14 + ox] =
                        fmaxf(v, 0.f);
                }
            }
        }
    }
}

// ======================================================================
// fc2: z[B,32] = A[B,224] @ w^T + b  (fp32, feeds VQ)
// ======================================================================
__global__ void fc2_kernel(const float* __restrict__ A,
                           const float* __restrict__ w,
                           const float* __restrict__ bias,
                           float* __restrict__ out) {
    __shared__ float ws[32 * 224];
    int t = threadIdx.x;
    for (int i = t; i < 7168; i += 256) ws[i] = w[i];
    __syncthreads();
    int n = t & 31, r = t >> 5;
    int b = blockIdx.x * 8 + r;
    const float* ap = A + (size_t)b * 224;
    const float* wp = ws + n * 224;
    float acc = bias[n];
    #pragma unroll 8
    for (int k = 0; k < 224; k++) acc += ap[k] * wp[k];
    out[(size_t)b * 32 + n] = acc;
}

// ======================================================================
// VQ helpers (fp32 exact)
// ======================================================================
__global__ void enorm_kernel(const float* __restrict__ emb, float* __restrict__ enorm) {
    int e = blockIdx.x * blockDim.x + threadIdx.x;
    if (e < NE) {
        float s = 0.f;
        #pragma unroll
        for (int d = 0; d < ZD; d++) { float v = emb[e * ZD + d]; s += v * v; }
        enorm[e] = s;
    }
}

__global__ void zero_kernel(float* __restrict__ counts, float* __restrict__ sums,
                            float* __restrict__ loss) {
    int i = blockIdx.x * blockDim.x + threadIdx.x;
    if (i < NE) counts[i] = 0.f;
    if (i < NE * ZD) sums[i] = 0.f;
    if (i == 0) loss[0] = 0.f;
}

__global__ void vq_kernel(const float* __restrict__ z,
                          const float* __restrict__ emb,
                          const float* __restrict__ enorm,
                          int* __restrict__ idx,
                          float* __restrict__ counts,
                          float* __restrict__ sums,
                          float* __restrict__ loss) {
    int gw = (blockIdx.x * blockDim.x + threadIdx.x) >> 5;
    int lane = threadIdx.x & 31;
    int wl = threadIdx.x >> 5;
    __shared__ float zs[8][ZD];
    if (gw >= BATCH) return;
    zs[wl][lane] = z[(size_t)gw * ZD + lane];
    __syncwarp();
    float best = 3.4e38f; int bi = NE;
    for (int e = lane; e < NE; e += 32) {
        const float* ep = emb + e * ZD;
        float dot = 0.f;
        #pragma unroll
        for (int d = 0; d < ZD; d++) dot += zs[wl][d] * __ldg(ep + d);
        float s = enorm[e] - 2.f * dot;
        if (s < best) { best = s; bi = e; }
    }
    #pragma unroll
    for (int off = 16; off; off >>= 1) {
        float ob = __shfl_xor_sync(0xffffffffu, best, off);
        int   oi = __shfl_xor_sync(0xffffffffu, bi, off);
        if (ob < best || (ob == best && oi < bi)) { best = ob; bi = oi; }
    }
    float zl = zs[wl][lane];
    float diff = __ldg(emb + (size_t)bi * ZD + lane) - zl;
    float d2 = diff * diff;
    #pragma unroll
    for (int off = 16; off; off >>= 1) d2 += __shfl_xor_sync(0xffffffffu, d2, off);
    if (lane == 0) {
        idx[gw] = bi;
        atomicAdd(&counts[bi], 1.f);
        atomicAdd(loss, d2);
    }
    atomicAdd(&sums[bi * ZD + lane], zl);
}

__global__ void embnew_kernel(const float* __restrict__ m_mat,
                              const float* __restrict__ n_mat,
                              const float* __restrict__ sums,
                              const float* __restrict__ counts,
                              float* __restrict__ out) {
    int i = blockIdx.x * blockDim.x + threadIdx.x;
    if (i < NE * ZD) {
        int e = i >> 5;
        float m = m_mat[i] * GAMMA + sums[i] * ONE_M_GAMMA;
        float n = n_mat[e] * GAMMA + counts[e] * ONE_M_GAMMA;
        out[i] = m / n;
    }
}

__global__ void finalize_kernel(const float* __restrict__ counts,
                                const float* __restrict__ loss,
                                float* __restrict__ out_scalars) {
    __shared__ float red[NE];
    int t = threadIdx.x;
    float c = counts[t];
    float em = c * (1.f / (float)BATCH);
    red[t] = em * logf(em + 1e-10f);
    __syncthreads();
    for (int s = 256; s; s >>= 1) {
        if (t < s) red[t] += red[t + s];
        __syncthreads();
    }
    if (t == 0) {
        float q = loss[0] * (1.f / ((float)BATCH * (float)ZD));
        out_scalars[0] = q;
        out_scalars[1] = BETA * q;
        out_scalars[2] = expf(-red[0]);
    }
}

// ======================================================================
// fc3 (fp32)
// ======================================================================
__global__ void fc3_kernel(const float* __restrict__ emb,
                           const int* __restrict__ idx,
                           const float* __restrict__ w,
                           const float* __restrict__ bias,
                           float* __restrict__ out) {
    __shared__ float zq[ZD];
    int b = blockIdx.x, t = threadIdx.x;
    if (t < ZD) zq[t] = emb[(size_t)idx[b] * ZD + t];
    __syncthreads();
    const float* wp = w + t * ZD;
    float acc = bias[t];
    #pragma unroll
    for (int k = 0; k < ZD; k++) acc += zq[k] * __ldg(wp + k);
    out[(size_t)b * 224 + t] = fmaxf(acc, 0.f);
}

// ======================================================================
// convt2: in[B,16,14,14] -> out[B,1,28,28]  (fp32)
// ======================================================================
__global__ void convt2_kernel(const float* __restrict__ in,
                              const float* __restrict__ w,
                              const float* __restrict__ bias,
                              float* __restrict__ out) {
    __shared__ float img[3136];
    __shared__ float ws[256];
    int b = blockIdx.x, t = threadIdx.x;
    const float* ip = in + (size_t)b * 3136;
    for (int i = t; i < 3136; i += 256) img[i] = ip[i];
    if (t < 256) ws[t] = w[t];
    __syncthreads();
    float bv = bias[0];
    float* op = out + (size_t)b * 784;
    for (int o = t; o < 784; o += 256) {
        int oy = o / 28, ox = o % 28;
        float acc = bv;
        #pragma unroll
        for (int ky = 0; ky < 4; ky++) {
            int ty = oy + 1 - ky;
            if (ty < 0 || (ty & 1)) continue;
            int iy = ty >> 1;
            if (iy >= 14) continue;
            #pragma unroll
            for (int kx = 0; kx < 4; kx++) {
                int tx = ox + 1 - kx;
                if (tx < 0 || (tx & 1)) continue;
                int ix = tx >> 1;
                if (ix >= 14) continue;
                #pragma unroll
                for (int ic = 0; ic < 16; ic++)
                    acc += img[ic * 196 + iy * 14 + ix] * ws[ic * 16 + ky * 4 + kx];
            }
        }
        op[o] = acc;
    }
}

// ======================================================================
// launch
// ======================================================================
extern "C" void kernel_launch(void* const* d_in, const int* in_sizes, int n_in,
                              void* d_out, int out_size) {
    const float* x        = (const float*)d_in[0];
    const float* conv1_w  = (const float*)d_in[1];
    const float* conv1_b  = (const float*)d_in[2];
    const float* conv2_w  = (const float*)d_in[3];
    const float* conv2_b  = (const float*)d_in[4];
    const float* res1_w1  = (const float*)d_in[5];
    const float* res1_w2  = (const float*)d_in[6];
    const float* fc1_w    = (const float*)d_in[7];
    const float* fc1_b    = (const float*)d_in[8];
    const float* fc2_w    = (const float*)d_in[9];
    const float* fc2_b    = (const float*)d_in[10];
    const float* emb      = (const float*)d_in[11];
    const float* n_mat    = (const float*)d_in[12];
    const float* m_mat    = (const float*)d_in[13];
    const float* fc3_w    = (const float*)d_in[14];
    const float* fc3_b    = (const float*)d_in[15];
    const float* fc4_w    = (const float*)d_in[16];
    const float* fc4_b    = (const float*)d_in[17];
    const float* res2_w1  = (const float*)d_in[18];
    const float* res2_w2  = (const float*)d_in[19];
    const float* convt1_w = (const float*)d_in[20];
    const float* convt1_b = (const float*)d_in[21];
    const float* convt2_w = (const float*)d_in[22];
    const float* convt2_b = (const float*)d_in[23];
    float* out = (float*)d_out;

    float *h1, *h2, *a, *z, *enorm, *counts, *sums, *loss;
    int* idx;
    cudaGetSymbolAddress((void**)&h1,     g_h1);
    cudaGetSymbolAddress((void**)&h2,     g_h2);
    cudaGetSymbolAddress((void**)&a,      g_a);
    cudaGetSymbolAddress((void**)&z,      g_z);
    cudaGetSymbolAddress((void**)&idx,    g_idx);
    cudaGetSymbolAddress((void**)&enorm,  g_enorm);
    cudaGetSymbolAddress((void**)&counts, g_counts);
    cudaGetSymbolAddress((void**)&sums,   g_sums);
    cudaGetSymbolAddress((void**)&loss,   g_loss);

    cudaFuncSetAttribute(conv2_tc3,
                         cudaFuncAttributeMaxDynamicSharedMemorySize, C2B_SMEM);
    cudaFuncSetAttribute(res_tc3,
                         cudaFuncAttributeMaxDynamicSharedMemorySize, E3_SMEM);
    cudaFuncSetAttribute(res_tcd,
                         cudaFuncAttributeMaxDynamicSharedMemorySize, D3_SMEM);
    cudaFuncSetAttribute(convt1_tc,
                         cudaFuncAttributeMaxDynamicSharedMemorySize, T1_SMEM);

    // encoder (3xTF32 = fp32-class accuracy; VQ path preserved)
    conv1_kernel<<<BATCH, 256>>>(x, conv1_w, conv1_b, h1);
    conv2_tc3<<<BATCH / 2, 256, C2B_SMEM>>>(h1, conv2_w, conv2_b, h2);
    res_tc3  <<<BATCH / 2, 256, E3_SMEM>>>(h2, res1_w1, res1_w2);
    gemm_tc3<<<dim3(BATCH / 128, 4), 256>>>(h2, fc1_w, fc1_b, a,
                                            BATCH, 224, 1568);
    fc2_kernel<<<BATCH / 8, 256>>>(a, fc2_w, fc2_b, z);

    // VQ
    zero_kernel <<<(NE * ZD + 255) / 256, 256>>>(counts, sums, loss);
    enorm_kernel<<<2, 256>>>(emb, enorm);
    vq_kernel   <<<BATCH / 8, 256>>>(z, emb, enorm, idx, counts, sums, loss);
    embnew_kernel  <<<(NE * ZD + 255) / 256, 256>>>(m_mat, n_mat, sums, counts,
                                                    out + OFF_SCAL + 3);
    finalize_kernel<<<1, NE>>>(counts, loss, out + OFF_SCAL);

    // decoder (single tf32)
    fc3_kernel<<<BATCH, 224>>>(emb, idx, fc3_w, fc3_b, a);
    gemm_tc<<<dim3(BATCH / 128, 25), 256>>>(a, fc4_w, fc4_b, h2,
                                            BATCH, 1568, 224);
    res_tcd<<<BATCH / 2, 256, D3_SMEM>>>(h2, res2_w1, res2_w2);
    convt1_tc<<<BATCH / 2, 256, T1_SMEM>>>(h2, convt1_w, convt1_b, h1);
    convt2_kernel<<<BATCH, 256>>>(h1, convt2_w, convt2_b, out);
}

// round 7
// speedup vs baseline: 1.6024x; 1.3393x over previous
#include <cuda_runtime.h>
#include <cstdint>
#include <math.h>

// ---------------- problem constants ----------------
#define BATCH 16384
#define ZD 32
#define NE 512
#define GAMMA 0.99f
#define ONE_M_GAMMA 0.01f
#define BETA 1.0f

#define OFF_SCAL (BATCH * 784)   // x_rec size
// d_out layout: [x_rec (B*784)][quant][commit][perplexity][emb_new (512*32)]

// ---------------- scratch ----------------
__device__ float g_h1[BATCH * 16 * 14 * 14];
__device__ float g_h2[BATCH * 32 * 7 * 7];
__device__ float g_a [BATCH * 224];
__device__ float g_z [BATCH * ZD];
__device__ int   g_idx[BATCH];
__device__ float g_enorm[NE];
__device__ float g_counts[NE];
__device__ float g_sums[NE * ZD];
__device__ float g_loss[1];

// ---------------- tf32 mma helpers ----------------
__device__ __forceinline__ float to_tf32(float x) {
    float y;
    asm("cvt.rna.tf32.f32 %0, %1;" : "=f"(y) : "f"(x));
    return y;
}

__device__ __forceinline__ void split_tf32(float v, unsigned& hi, unsigned& lo) {
    float h;
    asm("cvt.rna.tf32.f32 %0, %1;" : "=f"(h) : "f"(v));
    float l = v - h;
    float l2;
    asm("cvt.rna.tf32.f32 %0, %1;" : "=f"(l2) : "f"(l));
    hi = __float_as_uint(h);
    lo = __float_as_uint(l2);
}

__device__ __forceinline__ void mma_tf32(float* d, const unsigned* a,
                                         unsigned b0, unsigned b1) {
    asm volatile(
        "mma.sync.aligned.m16n8k8.row.col.f32.tf32.tf32.f32 "
        "{%0,%1,%2,%3}, {%4,%5,%6,%7}, {%8,%9}, {%0,%1,%2,%3};\n"
        : "+f"(d[0]), "+f"(d[1]), "+f"(d[2]), "+f"(d[3])
        : "r"(a[0]), "r"(a[1]), "r"(a[2]), "r"(a[3]), "r"(b0), "r"(b1));
}

// 3-pass split mma: acc += a*b with ~fp32 accuracy
__device__ __forceinline__ void mma3(float* d, const unsigned* ah, const unsigned* al,
                                     unsigned bh0, unsigned bh1,
                                     unsigned bl0, unsigned bl1) {
    mma_tf32(d, ah, bl0, bl1);
    mma_tf32(d, al, bh0, bh1);
    mma_tf32(d, ah, bh0, bh1);
}

// ======================================================================
// conv1: x[B,1,28,28] -> relu -> h1[B,16,14,14]   (k4 s2 p1)  fp32
// 2 img/CTA, 224 thr = 2img x 8ocp x 14oy, padded smem [30][30]
// ======================================================================
__global__ void __launch_bounds__(224) conv1_kernel(
        const float* __restrict__ x,
        const float* __restrict__ w,
        const float* __restrict__ bias,
        float* __restrict__ out) {
    __shared__ float xp[2 * 900];   // [im][30][30], halo of 1
    int b0 = blockIdx.x * 2, t = threadIdx.x;
    for (int i = t; i < 1800; i += 224) xp[i] = 0.f;
    __syncthreads();
    for (int i = t; i < 1568; i += 224) {
        int im = i / 784, j = i % 784;
        int iy = j / 28, ix = j % 28;
        xp[im * 900 + (iy + 1) * 30 + (ix + 1)] = x[(size_t)(b0 + im) * 784 + j];
    }
    __syncthreads();
    int im = t / 112, r = t % 112;
    int ocp = r / 14, oy = r % 14;
    int oc0 = ocp * 2, oc1 = oc0 + 1;
    float acc0[14], acc1[14];
    float b0v = bias[oc0], b1v = bias[oc1];
    #pragma unroll
    for (int j = 0; j < 14; j++) { acc0[j] = b0v; acc1[j] = b1v; }
    const float* base = xp + im * 900;
    #pragma unroll
    for (int ky = 0; ky < 4; ky++) {
        int ry = 2 * oy + ky;          // = (2*oy-1+ky)+1 pad
        float row[30];
        #pragma unroll
        for (int j = 0; j < 30; j++) row[j] = base[ry * 30 + j];
        #pragma unroll
        for (int kx = 0; kx < 4; kx++) {
            float w0 = __ldg(w + oc0 * 16 + ky * 4 + kx);
            float w1 = __ldg(w + oc1 * 16 + ky * 4 + kx);
            #pragma unroll
            for (int ox = 0; ox < 14; ox++) {
                float v = row[2 * ox + kx];
                acc0[ox] += v * w0;
                acc1[ox] += v * w1;
            }
        }
    }
    float* op = out + (size_t)(b0 + im) * 3136 + oy * 14;
    #pragma unroll
    for (int ox = 0; ox < 14; ox++) {
        op[oc0 * 196 + ox] = fmaxf(acc0[ox], 0.f);
        op[oc1 * 196 + ox] = fmaxf(acc1[ox], 0.f);
    }
}

// ======================================================================
// conv2 3xTF32 shift-GEMM: h1[B,16,14,14] -> h2[B,32,7,7] (k4 s2 p1)
// 2 img/CTA, 256 thr, 92 KB smem -> 2 CTA/SM.     [round-6, proven]
// ======================================================================
#define C2B_ZOFF 9216
#define C2B_XIN  13824
#define C2B_W    C2B_XIN
#define C2B_TOT  23040
#define C2B_SMEM (C2B_TOT * 4)

__global__ void __launch_bounds__(256) conv2_tc3(
        const float* __restrict__ in,
        const float* __restrict__ w,
        const float* __restrict__ bias,
        float* __restrict__ out) {
    extern __shared__ float sm[];
    float* xin = sm;
    float* wt  = sm + C2B_W;
    int t = threadIdx.x;
    int b0 = blockIdx.x * 2;

    for (int i = t; i < C2B_XIN; i += 256) xin[i] = 0.f;
    __syncthreads();
    for (int i = t; i < 2 * 3136; i += 256) {
        int img = i / 3136, j = i % 3136;
        int ic = j / 196, p = j % 196, iy = p / 14, ix = p % 14;
        xin[img * 4608 + ((iy + 1) * 16 + (ix + 1)) * 18 + ic] =
            in[(size_t)(b0 + img) * 3136 + j];
    }
    for (int i = t; i < 8192; i += 256) {
        int oc = i / 256, r = i % 256, ic = r / 16, s = r % 16;
        wt[s * 576 + ic * 36 + oc] = w[i];
    }
    __syncthreads();

    int lane = t & 31, wrp = t >> 5;
    int grp = lane >> 2, tig = lane & 3;
    int img = wrp >> 2, mh = (wrp >> 1) & 1, nh = wrp & 1;

    int rb[2][2];
    #pragma unroll
    for (int mi = 0; mi < 2; mi++)
        #pragma unroll
        for (int h = 0; h < 2; h++) {
            int p = mh * 32 + mi * 16 + grp + h * 8;
            rb[mi][h] = (p < 49)
                ? img * 4608 + ((p / 7) * 32 + (p % 7) * 2) * 18
                : C2B_ZOFF;
        }

    float acc[2][2][4];
    #pragma unroll
    for (int mi = 0; mi < 2; mi++)
        #pragma unroll
        for (int ni = 0; ni < 2; ni++)
            #pragma unroll
            for (int c = 0; c < 4; c++) acc[mi][ni][c] = 0.f;

    #pragma unroll
    for (int ky = 0; ky < 4; ky++) {
        #pragma unroll
        for (int kx = 0; kx < 4; kx++) {
            int soff = (ky * 16 + kx) * 18;
            const float* wsp = wt + (ky * 4 + kx) * 576 + nh * 16;
            #pragma unroll
            for (int kk = 0; kk < 2; kk++) {
                int kb = kk * 8;
                unsigned ah[2][4], al[2][4];
                #pragma unroll
                for (int mi = 0; mi < 2; mi++) {
                    split_tf32(xin[rb[mi][0] + soff + kb + tig],     ah[mi][0], al[mi][0]);
                    split_tf32(xin[rb[mi][1] + soff + kb + tig],     ah[mi][1], al[mi][1]);
                    split_tf32(xin[rb[mi][0] + soff + kb + tig + 4], ah[mi][2], al[mi][2]);
                    split_tf32(xin[rb[mi][1] + soff + kb + tig + 4], ah[mi][3], al[mi][3]);
                }
                #pragma unroll
                for (int ni = 0; ni < 2; ni++) {
                    unsigned bh0, bl0, bh1, bl1;
                    split_tf32(wsp[(kb + tig) * 36 + ni * 8 + grp],     bh0, bl0);
                    split_tf32(wsp[(kb + tig + 4) * 36 + ni * 8 + grp], bh1, bl1);
                    mma3(acc[0][ni], ah[0], al[0], bh0, bh1, bl0, bl1);
                    mma3(acc[1][ni], ah[1], al[1], bh0, bh1, bl0, bl1);
                }
            }
        }
    }

    #pragma unroll
    for (int mi = 0; mi < 2; mi++) {
        #pragma unroll
        for (int ni = 0; ni < 2; ni++) {
            #pragma unroll
            for (int ci = 0; ci < 4; ci++) {
                int p = mh * 32 + mi * 16 + grp + ((ci >= 2) ? 8 : 0);
                if (p < 49) {
                    int oc = nh * 16 + ni * 8 + tig * 2 + (ci & 1);
                    out[(size_t)(b0 + img) * 1568 + oc * 49 + p] =
                        acc[mi][ni][ci] + __ldg(bias + oc);
                }
            }
        }
    }
}

// ======================================================================
// res stack 3xTF32 (encoder): 2 img/CTA, rs alias    [round-6, proven]
// ======================================================================
#define E3_W1   5832
#define E3_W2   25416
#define E3_TOT  27720
#define E3_RS   E3_W1
#define E3_SMEM (E3_TOT * 4)

__global__ void __launch_bounds__(256) res_tc3(
        float* __restrict__ buf,
        const float* __restrict__ pw1,
        const float* __restrict__ pw2) {
    extern __shared__ float sm[];
    float* xin = sm;
    float* w1s = sm + E3_W1;
    float* w2s = sm + E3_W2;
    float* rs  = sm + E3_RS;
    int t = threadIdx.x;
    int b0 = blockIdx.x * 2;

    for (int i = t; i < E3_W1; i += 256) xin[i] = 0.f;
    __syncthreads();
    for (int i = t; i < 18432; i += 256) {
        int oc = i / 288, rr = i % 288, ic = rr / 9, s = rr % 9;
        w1s[s * 2176 + ic * 68 + oc] = pw1[i];
    }
    for (int i = t; i < 2048; i += 256) {
        int oc = i >> 6, ic = i & 63;
        w2s[ic * 36 + oc] = pw2[i];
    }
    for (int i = t; i < 2 * 1568; i += 256) {
        int img = i / 1568, j = i % 1568;
        int ch = j / 49, p = j % 49;
        float v = buf[(size_t)(b0 + img) * 1568 + j];
        xin[img * 2916 + ((p / 7 + 1) * 9 + (p % 7 + 1)) * 36 + ch] = fmaxf(v, 0.f);
    }
    __syncthreads();

    int lane = t & 31, wrp = t >> 5;
    int grp = lane >> 2, tig = lane & 3;
    int img = wrp >> 2, mh = (wrp >> 1) & 1, nh = wrp & 1;
    int rbase = img * 64 + mh * 32;

    int rb[2][2];
    #pragma unroll
    for (int mi = 0; mi < 2; mi++)
        #pragma unroll
        for (int h = 0; h < 2; h++) {
            int p = mh * 32 + mi * 16 + grp + h * 8;
            rb[mi][h] = (p < 49) ? img * 2916 + ((p / 7) * 9 + (p % 7)) * 36 : 0;
        }

    float acc[2][4][4];
    #pragma unroll
    for (int mi = 0; mi < 2; mi++)
        #pragma unroll
        for (int ni = 0; ni < 4; ni++)
            #pragma unroll
            for (int c = 0; c < 4; c++) acc[mi][ni][c] = 0.f;

    #pragma unroll
    for (int ky = 0; ky < 3; ky++) {
        #pragma unroll
        for (int kx = 0; kx < 3; kx++) {
            int soff = (ky * 9 + kx) * 36;
            const float* wb = w1s + (ky * 3 + kx) * 2176 + nh * 32;
            #pragma unroll
            for (int kk = 0; kk < 4; kk++) {
                int kb = kk * 8;
                unsigned ah[2][4], al[2][4];
                #pragma unroll
                for (int mi = 0; mi < 2; mi++) {
                    split_tf32(xin[rb[mi][0] + soff + kb + tig],     ah[mi][0], al[mi][0]);
                    split_tf32(xin[rb[mi][1] + soff + kb + tig],     ah[mi][1], al[mi][1]);
                    split_tf32(xin[rb[mi][0] + soff + kb + tig + 4], ah[mi][2], al[mi][2]);
                    split_tf32(xin[rb[mi][1] + soff + kb + tig + 4], ah[mi][3], al[mi][3]);
                }
                #pragma unroll
                for (int ni = 0; ni < 4; ni++) {
                    unsigned bh0, bl0, bh1, bl1;
                    split_tf32(wb[(kb + tig) * 68 + ni * 8 + grp],     bh0, bl0);
                    split_tf32(wb[(kb + tig + 4) * 68 + ni * 8 + grp], bh1, bl1);
                    mma3(acc[0][ni], ah[0], al[0], bh0, bh1, bl0, bl1);
                    mma3(acc[1][ni], ah[1], al[1], bh0, bh1, bl0, bl1);
                }
            }
        }
    }

    __syncthreads();

    #pragma unroll
    for (int mi = 0; mi < 2; mi++) {
        int rlo = rbase + mi * 16 + grp, rhi = rlo + 8;
        #pragma unroll
        for (int ni = 0; ni < 4; ni++) {
            int c0 = nh * 32 + ni * 8 + tig * 2;
            rs[rlo * 68 + c0]     = fmaxf(acc[mi][ni][0], 0.f);
            rs[rlo * 68 + c0 + 1] = fmaxf(acc[mi][ni][1], 0.f);
            rs[rhi * 68 + c0]     = fmaxf(acc[mi][ni][2], 0.f);
            rs[rhi * 68 + c0 + 1] = fmaxf(acc[mi][ni][3], 0.f);
        }
    }
    __syncthreads();

    float acc2[2][2][4];
    #pragma unroll
    for (int mi = 0; mi < 2; mi++)
        #pragma unroll
        for (int ni = 0; ni < 2; ni++)
            #pragma unroll
            for (int c = 0; c < 4; c++) acc2[mi][ni][c] = 0.f;

    #pragma unroll
    for (int kk = 0; kk < 8; kk++) {
        int kb = kk * 8;
        unsigned ah[2][4], al[2][4];
        #pragma unroll
        for (int mi = 0; mi < 2; mi++) {
            int rlo = rbase + mi * 16 + grp;
            split_tf32(rs[rlo * 68 + kb + tig],           ah[mi][0], al[mi][0]);
            split_tf32(rs[(rlo + 8) * 68 + kb + tig],     ah[mi][1], al[mi][1]);
            split_tf32(rs[rlo * 68 + kb + tig + 4],       ah[mi][2], al[mi][2]);
            split_tf32(rs[(rlo + 8) * 68 + kb + tig + 4], ah[mi][3], al[mi][3]);
        }
        #pragma unroll
        for (int ni = 0; ni < 2; ni++) {
            int c = nh * 16 + ni * 8 + grp;
            unsigned bh0, bl0, bh1, bl1;
            split_tf32(w2s[(kb + tig) * 36 + c],     bh0, bl0);
            split_tf32(w2s[(kb + tig + 4) * 36 + c], bh1, bl1);
            mma3(acc2[0][ni], ah[0], al[0], bh0, bh1, bl0, bl1);
            mma3(acc2[1][ni], ah[1], al[1], bh0, bh1, bl0, bl1);
        }
    }

    #pragma unroll
    for (int mi = 0; mi < 2; mi++) {
        #pragma unroll
        for (int ni = 0; ni < 2; ni++) {
            #pragma unroll
            for (int ci = 0; ci < 4; ci++) {
                int p = mh * 32 + mi * 16 + grp + ((ci >= 2) ? 8 : 0);
                if (p < 49) {
                    int ch = nh * 16 + ni * 8 + tig * 2 + (ci & 1);
                    size_t g = (size_t)(b0 + img) * 1568 + ch * 49 + p;
                    float v = acc2[mi][ni][ci] + __ldg(buf + g);
                    buf[g] = fmaxf(v, 0.f);
                }
            }
        }
    }
}

// ======================================================================
// res stack single-TF32 (decoder)                    [round-6, proven]
// ======================================================================
#define D3_W1   5346
#define D3_W2   24930
#define D3_TOT  27234
#define D3_RS   D3_W1
#define D3_SMEM (D3_TOT * 4)

__global__ void __launch_bounds__(256) res_tcd(
        float* __restrict__ buf,
        const float* __restrict__ pw1,
        const float* __restrict__ pw2) {
    extern __shared__ float sm[];
    float* xin = sm;
    float* w1s = sm + D3_W1;
    float* w2s = sm + D3_W2;
    float* rs  = sm + D3_RS;
    int t = threadIdx.x;
    int b0 = blockIdx.x * 2;

    for (int i = t; i < D3_W1; i += 256) xin[i] = 0.f;
    __syncthreads();
    for (int i = t; i < 18432; i += 256) {
        int oc = i / 288, rr = i % 288, ic = rr / 9, s = rr % 9;
        w1s[s * 2176 + ic * 68 + oc] = to_tf32(pw1[i]);
    }
    for (int i = t; i < 2048; i += 256) {
        int oc = i >> 6, ic = i & 63;
        w2s[ic * 36 + oc] = to_tf32(pw2[i]);
    }
    for (int i = t; i < 2 * 1568; i += 256) {
        int img = i / 1568, j = i % 1568;
        int ch = j / 49, p = j % 49;
        float v = buf[(size_t)(b0 + img) * 1568 + j];
        xin[img * 2673 + ((p / 7 + 1) * 9 + (p % 7 + 1)) * 33 + ch] =
            to_tf32(fmaxf(v, 0.f));
    }
    __syncthreads();

    int lane = t & 31, wrp = t >> 5;
    int grp = lane >> 2, tig = lane & 3;
    int img = wrp >> 2, mh = (wrp >> 1) & 1, nh = wrp & 1;
    int rbase = img * 64 + mh * 32;

    int rb[2][2];
    #pragma unroll
    for (int mi = 0; mi < 2; mi++)
        #pragma unroll
        for (int h = 0; h < 2; h++) {
            int p = mh * 32 + mi * 16 + grp + h * 8;
            rb[mi][h] = (p < 49) ? img * 2673 + ((p / 7) * 9 + (p % 7)) * 33 : 0;
        }

    float acc[2][4][4];
    #pragma unroll
    for (int mi = 0; mi < 2; mi++)
        #pragma unroll
        for (int ni = 0; ni < 4; ni++)
            #pragma unroll
            for (int c = 0; c < 4; c++) acc[mi][ni][c] = 0.f;

    #pragma unroll
    for (int ky = 0; ky < 3; ky++) {
        #pragma unroll
        for (int kx = 0; kx < 3; kx++) {
            int soff = (ky * 9 + kx) * 33;
            const float* wb = w1s + (ky * 3 + kx) * 2176 + nh * 32;
            #pragma unroll
            for (int kk = 0; kk < 4; kk++) {
                int kb = kk * 8;
                unsigned a[2][4];
                #pragma unroll
                for (int mi = 0; mi < 2; mi++) {
                    a[mi][0] = __float_as_uint(xin[rb[mi][0] + soff + kb + tig]);
                    a[mi][1] = __float_as_uint(xin[rb[mi][1] + soff + kb + tig]);
                    a[mi][2] = __float_as_uint(xin[rb[mi][0] + soff + kb + tig + 4]);
                    a[mi][3] = __float_as_uint(xin[rb[mi][1] + soff + kb + tig + 4]);
                }
                #pragma unroll
                for (int ni = 0; ni < 4; ni++) {
                    unsigned bb0 = __float_as_uint(wb[(kb + tig) * 68 + ni * 8 + grp]);
                    unsigned bb1 = __float_as_uint(wb[(kb + tig + 4) * 68 + ni * 8 + grp]);
                    mma_tf32(acc[0][ni], a[0], bb0, bb1);
                    mma_tf32(acc[1][ni], a[1], bb0, bb1);
                }
            }
        }
    }

    __syncthreads();

    #pragma unroll
    for (int mi = 0; mi < 2; mi++) {
        int rlo = rbase + mi * 16 + grp, rhi = rlo + 8;
        #pragma unroll
        for (int ni = 0; ni < 4; ni++) {
            int c0 = nh * 32 + ni * 8 + tig * 2;
            rs[rlo * 68 + c0]     = to_tf32(fmaxf(acc[mi][ni][0], 0.f));
            rs[rlo * 68 + c0 + 1] = to_tf32(fmaxf(acc[mi][ni][1], 0.f));
            rs[rhi * 68 + c0]     = to_tf32(fmaxf(acc[mi][ni][2], 0.f));
            rs[rhi * 68 + c0 + 1] = to_tf32(fmaxf(acc[mi][ni][3], 0.f));
        }
    }
    __syncthreads();

    float acc2[2][2][4];
    #pragma unroll
    for (int mi = 0; mi < 2; mi++)
        #pragma unroll
        for (int ni = 0; ni < 2; ni++)
            #pragma unroll
            for (int c = 0; c < 4; c++) acc2[mi][ni][c] = 0.f;

    #pragma unroll
    for (int kk = 0; kk < 8; kk++) {
        int kb = kk * 8;
        unsigned a[2][4];
        #pragma unroll
        for (int mi = 0; mi < 2; mi++) {
            int rlo = rbase + mi * 16 + grp;
            a[mi][0] = __float_as_uint(rs[rlo * 68 + kb + tig]);
            a[mi][1] = __float_as_uint(rs[(rlo + 8) * 68 + kb + tig]);
            a[mi][2] = __float_as_uint(rs[rlo * 68 + kb + tig + 4]);
            a[mi][3] = __float_as_uint(rs[(rlo + 8) * 68 + kb + tig + 4]);
        }
        #pragma unroll
        for (int ni = 0; ni < 2; ni++) {
            int c = nh * 16 + ni * 8 + grp;
            unsigned bb0 = __float_as_uint(w2s[(kb + tig) * 36 + c]);
            unsigned bb1 = __float_as_uint(w2s[(kb + tig + 4) * 36 + c]);
            mma_tf32(acc2[0][ni], a[0], bb0, bb1);
            mma_tf32(acc2[1][ni], a[1], bb0, bb1);
        }
    }

    #pragma unroll
    for (int mi = 0; mi < 2; mi++) {
        #pragma unroll
        for (int ni = 0; ni < 2; ni++) {
            #pragma unroll
            for (int ci = 0; ci < 4; ci++) {
                int p = mh * 32 + mi * 16 + grp + ((ci >= 2) ? 8 : 0);
                if (p < 49) {
                    int ch = nh * 16 + ni * 8 + tig * 2 + (ci & 1);
                    size_t g = (size_t)(b0 + img) * 1568 + ch * 49 + p;
                    float v = acc2[mi][ni][ci] + __ldg(buf + g);
                    buf[g] = fmaxf(v, 0.f);
                }
            }
        }
    }
}

// ======================================================================
// TF32 GEMM (decoder fc4) with register-prefetch pipelining
// ======================================================================
__global__ void __launch_bounds__(256) gemm_tc(
        const float* __restrict__ A,
        const float* __restrict__ W,
        const float* __restrict__ bias,
        float* __restrict__ C,
        int M, int N, int K) {
    __shared__ float As[128][17];
    __shared__ float Ws[64][17];
    int t = threadIdx.x, lane = t & 31, w = t >> 5;
    int grp = lane >> 2, tig = lane & 3;
    int m0 = blockIdx.x * 128, n0 = blockIdx.y * 64;
    int mw = (w & 3) * 32, nw = (w >> 2) * 32;
    float acc[2][4][4];
    #pragma unroll
    for (int mi = 0; mi < 2; mi++)
        #pragma unroll
        for (int ni = 0; ni < 4; ni++)
            #pragma unroll
            for (int c = 0; c < 4; c++) acc[mi][ni][c] = 0.f;

    int ar = t >> 1, ak = (t & 1) * 8;
    int wr = t >> 2, wk = (t & 3) * 4;
    const float* apb = A + (size_t)(m0 + ar) * K + ak;
    bool wval = (n0 + wr < N);
    const float* wpb = W + (size_t)(n0 + wr) * K + wk;

    float4 v0 = *(const float4*)apb;
    float4 v1 = *(const float4*)(apb + 4);
    float4 wv = wval ? *(const float4*)wpb : make_float4(0.f, 0.f, 0.f, 0.f);

    for (int k0 = 0; k0 < K; k0 += 16) {
        As[ar][ak + 0] = to_tf32(v0.x); As[ar][ak + 1] = to_tf32(v0.y);
        As[ar][ak + 2] = to_tf32(v0.z); As[ar][ak + 3] = to_tf32(v0.w);
        As[ar][ak + 4] = to_tf32(v1.x); As[ar][ak + 5] = to_tf32(v1.y);
        As[ar][ak + 6] = to_tf32(v1.z); As[ar][ak + 7] = to_tf32(v1.w);
        Ws[wr][wk + 0] = to_tf32(wv.x); Ws[wr][wk + 1] = to_tf32(wv.y);
        Ws[wr][wk + 2] = to_tf32(wv.z); Ws[wr][wk + 3] = to_tf32(wv.w);
        __syncthreads();
        if (k0 + 16 < K) {
            v0 = *(const float4*)(apb + k0 + 16);
            v1 = *(const float4*)(apb + k0 + 20);
            wv = wval ? *(const float4*)(wpb + k0 + 16)
                      : make_float4(0.f, 0.f, 0.f, 0.f);
        }
        #pragma unroll
        for (int kk = 0; kk < 2; kk++) {
            int kb = kk * 8;
            unsigned a[2][4];
            #pragma unroll
            for (int mi = 0; mi < 2; mi++) {
                int r = mw + mi * 16 + grp;
                a[mi][0] = __float_as_uint(As[r][kb + tig]);
                a[mi][1] = __float_as_uint(As[r + 8][kb + tig]);
                a[mi][2] = __float_as_uint(As[r][kb + tig + 4]);
                a[mi][3] = __float_as_uint(As[r + 8][kb + tig + 4]);
            }
            #pragma unroll
            for (int ni = 0; ni < 4; ni++) {
                int n = nw + ni * 8 + grp;
                unsigned bb0 = __float_as_uint(Ws[n][kb + tig]);
                unsigned bb1 = __float_as_uint(Ws[n][kb + tig + 4]);
                mma_tf32(acc[0][ni], a[0], bb0, bb1);
                mma_tf32(acc[1][ni], a[1], bb0, bb1);
            }
        }
        __syncthreads();
    }
    #pragma unroll
    for (int mi = 0; mi < 2; mi++) {
        #pragma unroll
        for (int ni = 0; ni < 4; ni++) {
            #pragma unroll
            for (int ci = 0; ci < 4; ci++) {
                int r = m0 + mw + mi * 16 + grp + ((ci >= 2) ? 8 : 0);
                int n = n0 + nw + ni * 8 + tig * 2 + (ci & 1);
                if (n < N)
                    C[(size_t)r * N + n] = fmaxf(acc[mi][ni][ci] + bias[n], 0.f);
            }
        }
    }
}

// ======================================================================
// 3xTF32 GEMM (encoder fc1) with register-prefetch pipelining
// ======================================================================
__global__ void __launch_bounds__(256) gemm_tc3(
        const float* __restrict__ A,
        const float* __restrict__ W,
        const float* __restrict__ bias,
        float* __restrict__ C,
        int M, int N, int K) {
    __shared__ float As[128][17];
    __shared__ float Ws[64][17];
    int t = threadIdx.x, lane = t & 31, w = t >> 5;
    int grp = lane >> 2, tig = lane & 3;
    int m0 = blockIdx.x * 128, n0 = blockIdx.y * 64;
    int mw = (w & 3) * 32, nw = (w >> 2) * 32;
    float acc[2][4][4];
    #pragma unroll
    for (int mi = 0; mi < 2; mi++)
        #pragma unroll
        for (int ni = 0; ni < 4; ni++)
            #pragma unroll
            for (int c = 0; c < 4; c++) acc[mi][ni][c] = 0.f;

    int ar = t >> 1, ak = (t & 1) * 8;
    int wr = t >> 2, wk = (t & 3) * 4;
    const float* apb = A + (size_t)(m0 + ar) * K + ak;
    bool wval = (n0 + wr < N);
    const float* wpb = W + (size_t)(n0 + wr) * K + wk;

    float4 v0 = *(const float4*)apb;
    float4 v1 = *(const float4*)(apb + 4);
    float4 wv = wval ? *(const float4*)wpb : make_float4(0.f, 0.f, 0.f, 0.f);

    for (int k0 = 0; k0 < K; k0 += 16) {
        As[ar][ak + 0] = v0.x; As[ar][ak + 1] = v0.y;
        As[ar][ak + 2] = v0.z; As[ar][ak + 3] = v0.w;
        As[ar][ak + 4] = v1.x; As[ar][ak + 5] = v1.y;
        As[ar][ak + 6] = v1.z; As[ar][ak + 7] = v1.w;
        Ws[wr][wk + 0] = wv.x; Ws[wr][wk + 1] = wv.y;
        Ws[wr][wk + 2] = wv.z; Ws[wr][wk + 3] = wv.w;
        __syncthreads();
        if (k0 + 16 < K) {
            v0 = *(const float4*)(apb + k0 + 16);
            v1 = *(const float4*)(apb + k0 + 20);
            wv = wval ? *(const float4*)(wpb + k0 + 16)
                      : make_float4(0.f, 0.f, 0.f, 0.f);
        }
        #pragma unroll
        for (int kk = 0; kk < 2; kk++) {
            int kb = kk * 8;
            unsigned ah[2][4], al[2][4];
            #pragma unroll
            for (int mi = 0; mi < 2; mi++) {
                int r = mw + mi * 16 + grp;
                split_tf32(As[r][kb + tig],         ah[mi][0], al[mi][0]);
                split_tf32(As[r + 8][kb + tig],     ah[mi][1], al[mi][1]);
                split_tf32(As[r][kb + tig + 4],     ah[mi][2], al[mi][2]);
                split_tf32(As[r + 8][kb + tig + 4], ah[mi][3], al[mi][3]);
            }
            #pragma unroll
            for (int ni = 0; ni < 4; ni++) {
                int n = nw + ni * 8 + grp;
                unsigned bh0, bl0, bh1, bl1;
                split_tf32(Ws[n][kb + tig],     bh0, bl0);
                split_tf32(Ws[n][kb + tig + 4], bh1, bl1);
                mma3(acc[0][ni], ah[0], al[0], bh0, bh1, bl0, bl1);
                mma3(acc[1][ni], ah[1], al[1], bh0, bh1, bl0, bl1);
            }
        }
        __syncthreads();
    }
    #pragma unroll
    for (int mi = 0; mi < 2; mi++) {
        #pragma unroll
        for (int ni = 0; ni < 4; ni++) {
            #pragma unroll
            for (int ci = 0; ci < 4; ci++) {
                int r = m0 + mw + mi * 16 + grp + ((ci >= 2) ? 8 : 0);
                int n = n0 + nw + ni * 8 + tig * 2 + (ci & 1);
                if (n < N)
                    C[(size_t)r * N + n] = fmaxf(acc[mi][ni][ci] + bias[n], 0.f);
            }
        }
    }
}

// ======================================================================
// convt1 single-TF32 (decoder)                                [round-4]
// ======================================================================
#define T1_IMSZ 2916
#define T1_ZB   6240
#define T1_XIN  6664
#define T1_WOFF T1_XIN
#define T1_WSZ  (16 * 32 * 24)
#define T1_SMEM ((T1_XIN + T1_WSZ) * 4)

__global__ void __launch_bounds__(256) convt1_tc(
        const float* __restrict__ in,
        const float* __restrict__ w,
        const float* __restrict__ bias,
        float* __restrict__ out) {
    extern __shared__ float sm[];
    float* xin = sm;
    float* wt  = sm + T1_WOFF;
    int t = threadIdx.x;
    int b0 = blockIdx.x * 2;

    for (int i = t; i < T1_XIN; i += 256) xin[i] = 0.f;
    __syncthreads();
    for (int i = t; i < 2 * 1568; i += 256) {
        int img = i / 1568, j = i % 1568;
        int ic = j / 49, p = j % 49, iy = p / 7, ix = p % 7;
        xin[img * T1_IMSZ + ((iy + 1) * 9 + (ix + 1)) * 36 + ic] =
            to_tf32(in[(size_t)(b0 + img) * 1568 + j]);
    }
    for (int i = t; i < 32 * 256; i += 256) {
        int ic = i / 256, r = i % 256, oc = r / 16, s = r % 16;
        wt[s * 768 + ic * 24 + oc] = to_tf32(w[i]);
    }
    __syncthreads();

    int lane = t & 31, wrp = t >> 5;
    int grp = lane >> 2, tig = lane & 3;
    int img = wrp >> 2, ph = wrp & 3;
    int a = ph >> 1, bp = ph & 1;
    int dyv[2], kyv[2], dxv[2], kxv[2];
    if (a == 0) { dyv[0] = 0; kyv[0] = 1; dyv[1] = -1; kyv[1] = 3; }
    else        { dyv[0] = 1; kyv[0] = 0; dyv[1] =  0; kyv[1] = 2; }
    if (bp == 0) { dxv[0] = 0; kxv[0] = 1; dxv[1] = -1; kxv[1] = 3; }
    else         { dxv[0] = 1; kxv[0] = 0; dxv[1] =  0; kxv[1] = 2; }

    int rb[4][2];
    #pragma unroll
    for (int mi = 0; mi < 4; mi++)
        #pragma unroll
        for (int h = 0; h < 2; h++) {
            int p = mi * 16 + grp + h * 8;
            rb[mi][h] = (p < 49)
                ? img * T1_IMSZ + ((p / 7 + 1) * 9 + (p % 7 + 1)) * 36
                : T1_ZB;
        }

    float acc[4][2][4];
    #pragma unroll
    for (int mi = 0; mi < 4; mi++)
        #pragma unroll
        for (int ni = 0; ni < 2; ni++)
            #pragma unroll
            for (int c = 0; c < 4; c++) acc[mi][ni][c] = 0.f;

    #pragma unroll
    for (int sy = 0; sy < 2; sy++) {
        #pragma unroll
        for (int sx = 0; sx < 2; sx++) {
            int soff = (dyv[sy] * 9 + dxv[sx]) * 36;
            const float* wsl = wt + (kyv[sy] * 4 + kxv[sx]) * 768;
            #pragma unroll
            for (int kk = 0; kk < 4; kk++) {
                int kb = kk * 8;
                unsigned afr[4][4];
                #pragma unroll
                for (int mi = 0; mi < 4; mi++) {
                    afr[mi][0] = __float_as_uint(xin[rb[mi][0] + soff + kb + tig]);
                    afr[mi][1] = __float_as_uint(xin[rb[mi][1] + soff + kb + tig]);
                    afr[mi][2] = __float_as_uint(xin[rb[mi][0] + soff + kb + tig + 4]);
                    afr[mi][3] = __float_as_uint(xin[rb[mi][1] + soff + kb + tig + 4]);
                }
                #pragma unroll
                for (int ni = 0; ni < 2; ni++) {
                    unsigned bb0 = __float_as_uint(wsl[(kb + tig) * 24 + ni * 8 + grp]);
                    unsigned bb1 = __float_as_uint(wsl[(kb + tig + 4) * 24 + ni * 8 + grp]);
                    #pragma unroll
                    for (int mi = 0; mi < 4; mi++)
                        mma_tf32(acc[mi][ni], afr[mi], bb0, bb1);
                }
            }
        }
    }

    #pragma unroll
    for (int mi = 0; mi < 4; mi++) {
        #pragma unroll
        for (int ni = 0; ni < 2; ni++) {
            #pragma unroll
            for (int ci = 0; ci < 4; ci++) {
                int p = mi * 16 + grp + ((ci >= 2) ? 8 : 0);
                if (p < 49) {
                    int m = p / 7, n = p % 7;
                    int oc = ni * 8 + tig * 2 + (ci & 1);
                    int oy = 2 * m + a, ox = 2 * n + bp;
                    float v = acc[mi][ni][ci] + __ldg(bias + oc);
                    out[(size_t)(b0 + img) * 3136 + oc * 196 + oy * 14 + ox] =
                        fmaxf(v, 0.f);
                }
            }
        }
    }
}

// ======================================================================
// fc2: z[B,32] = A[B,224] @ w^T + b  (fp32, feeds VQ)
// ======================================================================
__global__ void fc2_kernel(const float* __restrict__ A,
                           const float* __restrict__ w,
                           const float* __restrict__ bias,
                           float* __restrict__ out) {
    __shared__ float ws[32 * 224];
    int t = threadIdx.x;
    for (int i = t; i < 7168; i += 256) ws[i] = w[i];
    __syncthreads();
    int n = t & 31, r = t >> 5;
    int b = blockIdx.x * 8 + r;
    const float* ap = A + (size_t)b * 224;
    const float* wp = ws + n * 224;
    float acc = bias[n];
    #pragma unroll 8
    for (int k = 0; k < 224; k++) acc += ap[k] * wp[k];
    out[(size_t)b * 32 + n] = acc;
}

// ======================================================================
// VQ helpers (fp32 exact)
// ======================================================================
__global__ void enorm_kernel(const float* __restrict__ emb, float* __restrict__ enorm) {
    int e = blockIdx.x * blockDim.x + threadIdx.x;
    if (e < NE) {
        float s = 0.f;
        #pragma unroll
        for (int d = 0; d < ZD; d++) { float v = emb[e * ZD + d]; s += v * v; }
        enorm[e] = s;
    }
}

__global__ void zero_kernel(float* __restrict__ counts, float* __restrict__ sums,
                            float* __restrict__ loss) {
    int i = blockIdx.x * blockDim.x + threadIdx.x;
    if (i < NE) counts[i] = 0.f;
    if (i < NE * ZD) sums[i] = 0.f;
    if (i == 0) loss[0] = 0.f;
}

// 64 rows/CTA; emb staged in smem (pitch 36 -> conflict-free float4)
#define VQ_SMEM (NE * 36 * 4)

__global__ void __launch_bounds__(256) vq_kernel(
        const float* __restrict__ z,
        const float* __restrict__ emb,
        const float* __restrict__ enorm,
        int* __restrict__ idx,
        float* __restrict__ counts,
        float* __restrict__ sums,
        float* __restrict__ loss) {
    extern __shared__ float es[];          // [512][36]
    __shared__ float en[NE];
    __shared__ float zs[8][ZD];
    int t = threadIdx.x, lane = t & 31, wl = t >> 5;
    for (int i = t; i < NE * ZD; i += 256) {
        int e = i >> 5, d = i & 31;
        es[e * 36 + d] = emb[i];
    }
    for (int i = t; i < NE; i += 256) en[i] = enorm[i];
    __syncthreads();

    for (int rr = 0; rr < 8; rr++) {
        int row = blockIdx.x * 64 + wl * 8 + rr;
        zs[wl][lane] = z[(size_t)row * ZD + lane];
        __syncwarp();
        float best = 3.4e38f; int bi = NE;
        for (int e = lane; e < NE; e += 32) {
            const float* ep = es + e * 36;
            float dot = 0.f;
            #pragma unroll
            for (int d = 0; d < ZD; d += 4) {
                float4 v = *(const float4*)(ep + d);
                dot += zs[wl][d + 0] * v.x;
                dot += zs[wl][d + 1] * v.y;
                dot += zs[wl][d + 2] * v.z;
                dot += zs[wl][d + 3] * v.w;
            }
            float s = en[e] - 2.f * dot;
            if (s < best) { best = s; bi = e; }
        }
        #pragma unroll
        for (int off = 16; off; off >>= 1) {
            float ob = __shfl_xor_sync(0xffffffffu, best, off);
            int   oi = __shfl_xor_sync(0xffffffffu, bi, off);
            if (ob < best || (ob == best && oi < bi)) { best = ob; bi = oi; }
        }
        float zl = zs[wl][lane];
        float diff = es[bi * 36 + lane] - zl;
        float d2 = diff * diff;
        #pragma unroll
        for (int off = 16; off; off >>= 1)
            d2 += __shfl_xor_sync(0xffffffffu, d2, off);
        if (lane == 0) {
            idx[row] = bi;
            atomicAdd(&counts[bi], 1.f);
            atomicAdd(loss, d2);
        }
        atomicAdd(&sums[bi * ZD + lane], zl);
        __syncwarp();
    }
}

__global__ void embnew_kernel(const float* __restrict__ m_mat,
                              const float* __restrict__ n_mat,
                              const float* __restrict__ sums,
                              const float* __restrict__ counts,
                              float* __restrict__ out) {
    int i = blockIdx.x * blockDim.x + threadIdx.x;
    if (i < NE * ZD) {
        int e = i >> 5;
        float m = m_mat[i] * GAMMA + sums[i] * ONE_M_GAMMA;
        float n = n_mat[e] * GAMMA + counts[e] * ONE_M_GAMMA;
        out[i] = m / n;
    }
}

__global__ void finalize_kernel(const float* __restrict__ counts,
                                const float* __restrict__ loss,
                                float* __restrict__ out_scalars) {
    __shared__ float red[NE];
    int t = threadIdx.x;
    float c = counts[t];
    float em = c * (1.f / (float)BATCH);
    red[t] = em * logf(em + 1e-10f);
    __syncthreads();
    for (int s = 256; s; s >>= 1) {
        if (t < s) red[t] += red[t + s];
        __syncthreads();
    }
    if (t == 0) {
        float q = loss[0] * (1.f / ((float)BATCH * (float)ZD));
        out_scalars[0] = q;
        out_scalars[1] = BETA * q;
        out_scalars[2] = expf(-red[0]);
    }
}

// ======================================================================
// fc3 (fp32)
// ======================================================================
__global__ void fc3_kernel(const float* __restrict__ emb,
                           const int* __restrict__ idx,
                           const float* __restrict__ w,
                           const float* __restrict__ bias,
                           float* __restrict__ out) {
    __shared__ float zq[ZD];
    int b = blockIdx.x, t = threadIdx.x;
    if (t < ZD) zq[t] = emb[(size_t)idx[b] * ZD + t];
    __syncthreads();
    const float* wp = w + t * ZD;
    float acc = bias[t];
    #pragma unroll
    for (int k = 0; k < ZD; k++) acc += zq[k] * __ldg(wp + k);
    out[(size_t)b * 224 + t] = fmaxf(acc, 0.f);
}

// ======================================================================
// convt2 phase-decomposed fp32: in[B,16,14,14] -> out[B,1,28,28]
// 4 img/CTA, 256 thr: ph = t>>6 (uniform per warp), s = t&63 (56 active):
// img = s/14, m = s%14. Compile-time tap tables per phase branch.
// ======================================================================
#define CT2_SMEM (4 * 4096 * 4)   // 65536 B

template<int DY0, int KY0, int DY1, int KY1,
         int DX0, int KX0, int DX1, int KX1>
__device__ __forceinline__ void ct2_body(
        const float* __restrict__ base, const float* __restrict__ w,
        float bv, float* __restrict__ outp, int m) {
    float acc[14];
    #pragma unroll
    for (int j = 0; j < 14; j++) acc[j] = bv;
    for (int ic = 0; ic < 16; ic++) {
        const float* xc = base + ic * 256;
        #pragma unroll
        for (int sy = 0; sy < 2; sy++) {
            int iy = m + (sy ? DY1 : DY0);
            float row[16];
            #pragma unroll
            for (int j = 0; j < 16; j++) row[j] = xc[(iy + 1) * 16 + j];
            {
                float wv = __ldg(w + ic * 16 + (sy ? KY1 : KY0) * 4 + KX0);
                #pragma unroll
                for (int n = 0; n < 14; n++) acc[n] += row[n + DX0 + 1] * wv;
            }
            {
                float wv = __ldg(w + ic * 16 + (sy ? KY1 : KY0) * 4 + KX1);
                #pragma unroll
                for (int n = 0; n < 14; n++) acc[n] += row[n + DX1 + 1] * wv;
            }
        }
    }
    #pragma unroll
    for (int n = 0; n < 14; n++) outp[2 * n] = acc[n];
}

__global__ void __launch_bounds__(256) convt2_tc(
        const float* __restrict__ in,
        const float* __restrict__ w,
        const float* __restrict__ bias,
        float* __restrict__ out) {
    extern __shared__ float xp[];   // [4 img][16 ic][16][16], halo 1
    int t = threadIdx.x;
    int b0 = blockIdx.x * 4;

    for (int i = t; i < 16384; i += 256) xp[i] = 0.f;
    __syncthreads();
    for (int i = t; i < 4 * 3136; i += 256) {
        int img = i / 3136, j = i % 3136;
        int ic = j / 196, p = j % 196, iy = p / 14, ix = p % 14;
        xp[img * 4096 + ic * 256 + (iy + 1) * 16 + (ix + 1)] =
            in[(size_t)(b0 + img) * 3136 + j];
    }
    __syncthreads();

    int ph = t >> 6, s = t & 63;
    if (s >= 56) return;
    int img = s / 14, m = s % 14;
    int a = ph >> 1, b = ph & 1;
    const float* base = xp + img * 4096;
    float bv = bias[0];
    float* outp = out + (size_t)(b0 + img) * 784 + (2 * m + a) * 28 + b;

    if (ph == 0)      ct2_body<0, 1, -1, 3,  0, 1, -1, 3>(base, w, bv, outp, m);
    else if (ph == 1) ct2_body<0, 1, -1, 3,  1, 0,  0, 2>(base, w, bv, outp, m);
    else if (ph == 2) ct2_body<1, 0,  0, 2,  0, 1, -1, 3>(base, w, bv, outp, m);
    else              ct2_body<1, 0,  0, 2,  1, 0,  0, 2>(base, w, bv, outp, m);
}

// ======================================================================
// launch
// ======================================================================
extern "C" void kernel_launch(void* const* d_in, const int* in_sizes, int n_in,
                              void* d_out, int out_size) {
    const float* x        = (const float*)d_in[0];
    const float* conv1_w  = (const float*)d_in[1];
    const float* conv1_b  = (const float*)d_in[2];
    const float* conv2_w  = (const float*)d_in[3];
    const float* conv2_b  = (const float*)d_in[4];
    const float* res1_w1  = (const float*)d_in[5];
    const float* res1_w2  = (const float*)d_in[6];
    const float* fc1_w    = (const float*)d_in[7];
    const float* fc1_b    = (const float*)d_in[8];
    const float* fc2_w    = (const float*)d_in[9];
    const float* fc2_b    = (const float*)d_in[10];
    const float* emb      = (const float*)d_in[11];
    const float* n_mat    = (const float*)d_in[12];
    const float* m_mat    = (const float*)d_in[13];
    const float* fc3_w    = (const float*)d_in[14];
    const float* fc3_b    = (const float*)d_in[15];
    const float* fc4_w    = (const float*)d_in[16];
    const float* fc4_b    = (const float*)d_in[17];
    const float* res2_w1  = (const float*)d_in[18];
    const float* res2_w2  = (const float*)d_in[19];
    const float* convt1_w = (const float*)d_in[20];
    const float* convt1_b = (const float*)d_in[21];
    const float* convt2_w = (const float*)d_in[22];
    const float* convt2_b = (const float*)d_in[23];
    float* out = (float*)d_out;

    float *h1, *h2, *a, *z, *enorm, *counts, *sums, *loss;
    int* idx;
    cudaGetSymbolAddress((void**)&h1,     g_h1);
    cudaGetSymbolAddress((void**)&h2,     g_h2);
    cudaGetSymbolAddress((void**)&a,      g_a);
    cudaGetSymbolAddress((void**)&z,      g_z);
    cudaGetSymbolAddress((void**)&idx,    g_idx);
    cudaGetSymbolAddress((void**)&enorm,  g_enorm);
    cudaGetSymbolAddress((void**)&counts, g_counts);
    cudaGetSymbolAddress((void**)&sums,   g_sums);
    cudaGetSymbolAddress((void**)&loss,   g_loss);

    cudaFuncSetAttribute(conv2_tc3,
                         cudaFuncAttributeMaxDynamicSharedMemorySize, C2B_SMEM);
    cudaFuncSetAttribute(res_tc3,
                         cudaFuncAttributeMaxDynamicSharedMemorySize, E3_SMEM);
    cudaFuncSetAttribute(res_tcd,
                         cudaFuncAttributeMaxDynamicSharedMemorySize, D3_SMEM);
    cudaFuncSetAttribute(convt1_tc,
                         cudaFuncAttributeMaxDynamicSharedMemorySize, T1_SMEM);
    cudaFuncSetAttribute(convt2_tc,
                         cudaFuncAttributeMaxDynamicSharedMemorySize, CT2_SMEM);
    cudaFuncSetAttribute(vq_kernel,
                         cudaFuncAttributeMaxDynamicSharedMemorySize, VQ_SMEM);

    // encoder (3xTF32 = fp32-class accuracy; VQ path preserved)
    conv1_kernel<<<BATCH / 2, 224>>>(x, conv1_w, conv1_b, h1);
    conv2_tc3<<<BATCH / 2, 256, C2B_SMEM>>>(h1, conv2_w, conv2_b, h2);
    res_tc3  <<<BATCH / 2, 256, E3_SMEM>>>(h2, res1_w1, res1_w2);
    gemm_tc3<<<dim3(BATCH / 128, 4), 256>>>(h2, fc1_w, fc1_b, a,
                                            BATCH, 224, 1568);
    fc2_kernel<<<BATCH / 8, 256>>>(a, fc2_w, fc2_b, z);

    // VQ
    zero_kernel <<<(NE * ZD + 255) / 256, 256>>>(counts, sums, loss);
    enorm_kernel<<<2, 256>>>(emb, enorm);
    vq_kernel   <<<BATCH / 64, 256, VQ_SMEM>>>(z, emb, enorm, idx, counts,
                                               sums, loss);
    embnew_kernel  <<<(NE * ZD + 255) / 256, 256>>>(m_mat, n_mat, sums, counts,
                                                    out + OFF_SCAL + 3);
    finalize_kernel<<<1, NE>>>(counts, loss, out + OFF_SCAL);

    // decoder (single tf32)
    fc3_kernel<<<BATCH, 224>>>(emb, idx, fc3_w, fc3_b, a);
    gemm_tc<<<dim3(BATCH / 128, 25), 256>>>(a, fc4_w, fc4_b, h2,
                                            BATCH, 1568, 224);
    res_tcd<<<BATCH / 2, 256, D3_SMEM>>>(h2, res2_w1, res2_w2);
    convt1_tc<<<BATCH / 2, 256, T1_SMEM>>>(h2, convt1_w, convt1_b, h1);
    convt2_tc<<<BATCH / 4, 256, CT2_SMEM>>>(h1, convt2_w, convt2_b, out);
}

// round 8
// speedup vs baseline: 1.9207x; 1.1986x over previous
#include <cuda_runtime.h>
#include <cstdint>
#include <math.h>

// ---------------- problem constants ----------------
#define BATCH 16384
#define ZD 32
#define NE 512
#define GAMMA 0.99f
#define ONE_M_GAMMA 0.01f
#define BETA 1.0f

#define OFF_SCAL (BATCH * 784)   // x_rec size
// d_out layout: [x_rec (B*784)][quant][commit][perplexity][emb_new (512*32)]

// ---------------- scratch ----------------
__device__ float g_h1[BATCH * 16 * 14 * 14];
__device__ float g_h2[BATCH * 32 * 7 * 7];
__device__ float g_a [BATCH * 224];
__device__ float g_z [BATCH * ZD];
__device__ int   g_idx[BATCH];
__device__ float g_enorm[NE];
__device__ float g_counts[NE];
__device__ float g_sums[NE * ZD];
__device__ float g_loss[1];

// ---------------- tf32 mma helpers ----------------
__device__ __forceinline__ float to_tf32(float x) {
    float y;
    asm("cvt.rna.tf32.f32 %0, %1;" : "=f"(y) : "f"(x));
    return y;
}

// Bitwise hi/lo split: hi = RZ-truncated tf32 (LOP3), lo = v - hi (exact FADD).
// hi + lo == v exactly; replaces two half-rate cvt.rna.tf32 ops with fast ALU.
__device__ __forceinline__ void split_tf32(float v, unsigned& hi, unsigned& lo) {
    unsigned h = __float_as_uint(v) & 0xffffe000u;
    hi = h;
    lo = __float_as_uint(v - __uint_as_float(h));
}

__device__ __forceinline__ void mma_tf32(float* d, const unsigned* a,
                                         unsigned b0, unsigned b1) {
    asm volatile(
        "mma.sync.aligned.m16n8k8.row.col.f32.tf32.tf32.f32 "
        "{%0,%1,%2,%3}, {%4,%5,%6,%7}, {%8,%9}, {%0,%1,%2,%3};\n"
        : "+f"(d[0]), "+f"(d[1]), "+f"(d[2]), "+f"(d[3])
        : "r"(a[0]), "r"(a[1]), "r"(a[2]), "r"(a[3]), "r"(b0), "r"(b1));
}

// 3-pass split mma: acc += a*b with ~fp32 accuracy
__device__ __forceinline__ void mma3(float* d, const unsigned* ah, const unsigned* al,
                                     unsigned bh0, unsigned bh1,
                                     unsigned bl0, unsigned bl1) {
    mma_tf32(d, ah, bl0, bl1);
    mma_tf32(d, al, bh0, bh1);
    mma_tf32(d, ah, bh0, bh1);
}

// ======================================================================
// conv1: x[B,1,28,28] -> relu -> h1[B,16,14,14]   (k4 s2 p1)  fp32
// ======================================================================
__global__ void __launch_bounds__(224) conv1_kernel(
        const float* __restrict__ x,
        const float* __restrict__ w,
        const float* __restrict__ bias,
        float* __restrict__ out) {
    __shared__ float xp[2 * 900];   // [im][30][30], halo of 1
    int b0 = blockIdx.x * 2, t = threadIdx.x;
    for (int i = t; i < 1800; i += 224) xp[i] = 0.f;
    __syncthreads();
    for (int i = t; i < 1568; i += 224) {
        int im = i / 784, j = i % 784;
        int iy = j / 28, ix = j % 28;
        xp[im * 900 + (iy + 1) * 30 + (ix + 1)] = x[(size_t)(b0 + im) * 784 + j];
    }
    __syncthreads();
    int im = t / 112, r = t % 112;
    int ocp = r / 14, oy = r % 14;
    int oc0 = ocp * 2, oc1 = oc0 + 1;
    float acc0[14], acc1[14];
    float b0v = bias[oc0], b1v = bias[oc1];
    #pragma unroll
    for (int j = 0; j < 14; j++) { acc0[j] = b0v; acc1[j] = b1v; }
    const float* base = xp + im * 900;
    #pragma unroll
    for (int ky = 0; ky < 4; ky++) {
        int ry = 2 * oy + ky;
        float row[30];
        #pragma unroll
        for (int j = 0; j < 30; j++) row[j] = base[ry * 30 + j];
        #pragma unroll
        for (int kx = 0; kx < 4; kx++) {
            float w0 = __ldg(w + oc0 * 16 + ky * 4 + kx);
            float w1 = __ldg(w + oc1 * 16 + ky * 4 + kx);
            #pragma unroll
            for (int ox = 0; ox < 14; ox++) {
                float v = row[2 * ox + kx];
                acc0[ox] += v * w0;
                acc1[ox] += v * w1;
            }
        }
    }
    float* op = out + (size_t)(b0 + im) * 3136 + oy * 14;
    #pragma unroll
    for (int ox = 0; ox < 14; ox++) {
        op[oc0 * 196 + ox] = fmaxf(acc0[ox], 0.f);
        op[oc1 * 196 + ox] = fmaxf(acc1[ox], 0.f);
    }
}

// ======================================================================
// conv2 3xTF32 shift-GEMM: h1[B,16,14,14] -> h2[B,32,7,7] (k4 s2 p1)
// 2 img/CTA, 256 thr, 92 KB smem -> 2 CTA/SM.     [round-6, proven]
// ======================================================================
#define C2B_ZOFF 9216
#define C2B_XIN  13824
#define C2B_W    C2B_XIN
#define C2B_TOT  23040
#define C2B_SMEM (C2B_TOT * 4)

__global__ void __launch_bounds__(256) conv2_tc3(
        const float* __restrict__ in,
        const float* __restrict__ w,
        const float* __restrict__ bias,
        float* __restrict__ out) {
    extern __shared__ float sm[];
    float* xin = sm;
    float* wt  = sm + C2B_W;
    int t = threadIdx.x;
    int b0 = blockIdx.x * 2;

    for (int i = t; i < C2B_XIN; i += 256) xin[i] = 0.f;
    __syncthreads();
    for (int i = t; i < 2 * 3136; i += 256) {
        int img = i / 3136, j = i % 3136;
        int ic = j / 196, p = j % 196, iy = p / 14, ix = p % 14;
        xin[img * 4608 + ((iy + 1) * 16 + (ix + 1)) * 18 + ic] =
            in[(size_t)(b0 + img) * 3136 + j];
    }
    for (int i = t; i < 8192; i += 256) {
        int oc = i / 256, r = i % 256, ic = r / 16, s = r % 16;
        wt[s * 576 + ic * 36 + oc] = w[i];
    }
    __syncthreads();

    int lane = t & 31, wrp = t >> 5;
    int grp = lane >> 2, tig = lane & 3;
    int img = wrp >> 2, mh = (wrp >> 1) & 1, nh = wrp & 1;

    int rb[2][2];
    #pragma unroll
    for (int mi = 0; mi < 2; mi++)
        #pragma unroll
        for (int h = 0; h < 2; h++) {
            int p = mh * 32 + mi * 16 + grp + h * 8;
            rb[mi][h] = (p < 49)
                ? img * 4608 + ((p / 7) * 32 + (p % 7) * 2) * 18
                : C2B_ZOFF;
        }

    float acc[2][2][4];
    #pragma unroll
    for (int mi = 0; mi < 2; mi++)
        #pragma unroll
        for (int ni = 0; ni < 2; ni++)
            #pragma unroll
            for (int c = 0; c < 4; c++) acc[mi][ni][c] = 0.f;

    #pragma unroll
    for (int ky = 0; ky < 4; ky++) {
        #pragma unroll
        for (int kx = 0; kx < 4; kx++) {
            int soff = (ky * 16 + kx) * 18;
            const float* wsp = wt + (ky * 4 + kx) * 576 + nh * 16;
            #pragma unroll
            for (int kk = 0; kk < 2; kk++) {
                int kb = kk * 8;
                unsigned ah[2][4], al[2][4];
                #pragma unroll
                for (int mi = 0; mi < 2; mi++) {
                    split_tf32(xin[rb[mi][0] + soff + kb + tig],     ah[mi][0], al[mi][0]);
                    split_tf32(xin[rb[mi][1] + soff + kb + tig],     ah[mi][1], al[mi][1]);
                    split_tf32(xin[rb[mi][0] + soff + kb + tig + 4], ah[mi][2], al[mi][2]);
                    split_tf32(xin[rb[mi][1] + soff + kb + tig + 4], ah[mi][3], al[mi][3]);
                }
                #pragma unroll
                for (int ni = 0; ni < 2; ni++) {
                    unsigned bh0, bl0, bh1, bl1;
                    split_tf32(wsp[(kb + tig) * 36 + ni * 8 + grp],     bh0, bl0);
                    split_tf32(wsp[(kb + tig + 4) * 36 + ni * 8 + grp], bh1, bl1);
                    mma3(acc[0][ni], ah[0], al[0], bh0, bh1, bl0, bl1);
                    mma3(acc[1][ni], ah[1], al[1], bh0, bh1, bl0, bl1);
                }
            }
        }
    }

    #pragma unroll
    for (int mi = 0; mi < 2; mi++) {
        #pragma unroll
        for (int ni = 0; ni < 2; ni++) {
            #pragma unroll
            for (int ci = 0; ci < 4; ci++) {
                int p = mh * 32 + mi * 16 + grp + ((ci >= 2) ? 8 : 0);
                if (p < 49) {
                    int oc = nh * 16 + ni * 8 + tig * 2 + (ci & 1);
                    out[(size_t)(b0 + img) * 1568 + oc * 49 + p] =
                        acc[mi][ni][ci] + __ldg(bias + oc);
                }
            }
        }
    }
}

// ======================================================================
// res stack 3xTF32 (encoder): 2 img/CTA, rs alias    [round-6, proven]
// ======================================================================
#define E3_W1   5832
#define E3_W2   25416
#define E3_TOT  27720
#define E3_RS   E3_W1
#define E3_SMEM (E3_TOT * 4)

__global__ void __launch_bounds__(256) res_tc3(
        float* __restrict__ buf,
        const float* __restrict__ pw1,
        const float* __restrict__ pw2) {
    extern __shared__ float sm[];
    float* xin = sm;
    float* w1s = sm + E3_W1;
    float* w2s = sm + E3_W2;
    float* rs  = sm + E3_RS;
    int t = threadIdx.x;
    int b0 = blockIdx.x * 2;

    for (int i = t; i < E3_W1; i += 256) xin[i] = 0.f;
    __syncthreads();
    for (int i = t; i < 18432; i += 256) {
        int oc = i / 288, rr = i % 288, ic = rr / 9, s = rr % 9;
        w1s[s * 2176 + ic * 68 + oc] = pw1[i];
    }
    for (int i = t; i < 2048; i += 256) {
        int oc = i >> 6, ic = i & 63;
        w2s[ic * 36 + oc] = pw2[i];
    }
    for (int i = t; i < 2 * 1568; i += 256) {
        int img = i / 1568, j = i % 1568;
        int ch = j / 49, p = j % 49;
        float v = buf[(size_t)(b0 + img) * 1568 + j];
        xin[img * 2916 + ((p / 7 + 1) * 9 + (p % 7 + 1)) * 36 + ch] = fmaxf(v, 0.f);
    }
    __syncthreads();

    int lane = t & 31, wrp = t >> 5;
    int grp = lane >> 2, tig = lane & 3;
    int img = wrp >> 2, mh = (wrp >> 1) & 1, nh = wrp & 1;
    int rbase = img * 64 + mh * 32;

    int rb[2][2];
    #pragma unroll
    for (int mi = 0; mi < 2; mi++)
        #pragma unroll
        for (int h = 0; h < 2; h++) {
            int p = mh * 32 + mi * 16 + grp + h * 8;
            rb[mi][h] = (p < 49) ? img * 2916 + ((p / 7) * 9 + (p % 7)) * 36 : 0;
        }

    float acc[2][4][4];
    #pragma unroll
    for (int mi = 0; mi < 2; mi++)
        #pragma unroll
        for (int ni = 0; ni < 4; ni++)
            #pragma unroll
            for (int c = 0; c < 4; c++) acc[mi][ni][c] = 0.f;

    #pragma unroll
    for (int ky = 0; ky < 3; ky++) {
        #pragma unroll
        for (int kx = 0; kx < 3; kx++) {
            int soff = (ky * 9 + kx) * 36;
            const float* wb = w1s + (ky * 3 + kx) * 2176 + nh * 32;
            #pragma unroll
            for (int kk = 0; kk < 4; kk++) {
                int kb = kk * 8;
                unsigned ah[2][4], al[2][4];
                #pragma unroll
                for (int mi = 0; mi < 2; mi++) {
                    split_tf32(xin[rb[mi][0] + soff + kb + tig],     ah[mi][0], al[mi][0]);
                    split_tf32(xin[rb[mi][1] + soff + kb + tig],     ah[mi][1], al[mi][1]);
                    split_tf32(xin[rb[mi][0] + soff + kb + tig + 4], ah[mi][2], al[mi][2]);
                    split_tf32(xin[rb[mi][1] + soff + kb + tig + 4], ah[mi][3], al[mi][3]);
                }
                #pragma unroll
                for (int ni = 0; ni < 4; ni++) {
                    unsigned bh0, bl0, bh1, bl1;
                    split_tf32(wb[(kb + tig) * 68 + ni * 8 + grp],     bh0, bl0);
                    split_tf32(wb[(kb + tig + 4) * 68 + ni * 8 + grp], bh1, bl1);
                    mma3(acc[0][ni], ah[0], al[0], bh0, bh1, bl0, bl1);
                    mma3(acc[1][ni], ah[1], al[1], bh0, bh1, bl0, bl1);
                }
            }
        }
    }

    __syncthreads();

    #pragma unroll
    for (int mi = 0; mi < 2; mi++) {
        int rlo = rbase + mi * 16 + grp, rhi = rlo + 8;
        #pragma unroll
        for (int ni = 0; ni < 4; ni++) {
            int c0 = nh * 32 + ni * 8 + tig * 2;
            rs[rlo * 68 + c0]     = fmaxf(acc[mi][ni][0], 0.f);
            rs[rlo * 68 + c0 + 1] = fmaxf(acc[mi][ni][1], 0.f);
            rs[rhi * 68 + c0]     = fmaxf(acc[mi][ni][2], 0.f);
            rs[rhi * 68 + c0 + 1] = fmaxf(acc[mi][ni][3], 0.f);
        }
    }
    __syncthreads();

    float acc2[2][2][4];
    #pragma unroll
    for (int mi = 0; mi < 2; mi++)
        #pragma unroll
        for (int ni = 0; ni < 2; ni++)
            #pragma unroll
            for (int c = 0; c < 4; c++) acc2[mi][ni][c] = 0.f;

    #pragma unroll
    for (int kk = 0; kk < 8; kk++) {
        int kb = kk * 8;
        unsigned ah[2][4], al[2][4];
        #pragma unroll
        for (int mi = 0; mi < 2; mi++) {
            int rlo = rbase + mi * 16 + grp;
            split_tf32(rs[rlo * 68 + kb + tig],           ah[mi][0], al[mi][0]);
            split_tf32(rs[(rlo + 8) * 68 + kb + tig],     ah[mi][1], al[mi][1]);
            split_tf32(rs[rlo * 68 + kb + tig + 4],       ah[mi][2], al[mi][2]);
            split_tf32(rs[(rlo + 8) * 68 + kb + tig + 4], ah[mi][3], al[mi][3]);
        }
        #pragma unroll
        for (int ni = 0; ni < 2; ni++) {
            int c = nh * 16 + ni * 8 + grp;
            unsigned bh0, bl0, bh1, bl1;
            split_tf32(w2s[(kb + tig) * 36 + c],     bh0, bl0);
            split_tf32(w2s[(kb + tig + 4) * 36 + c], bh1, bl1);
            mma3(acc2[0][ni], ah[0], al[0], bh0, bh1, bl0, bl1);
            mma3(acc2[1][ni], ah[1], al[1], bh0, bh1, bl0, bl1);
        }
    }

    #pragma unroll
    for (int mi = 0; mi < 2; mi++) {
        #pragma unroll
        for (int ni = 0; ni < 2; ni++) {
            #pragma unroll
            for (int ci = 0; ci < 4; ci++) {
                int p = mh * 32 + mi * 16 + grp + ((ci >= 2) ? 8 : 0);
                if (p < 49) {
                    int ch = nh * 16 + ni * 8 + tig * 2 + (ci & 1);
                    size_t g = (size_t)(b0 + img) * 1568 + ch * 49 + p;
                    float v = acc2[mi][ni][ci] + __ldg(buf + g);
                    buf[g] = fmaxf(v, 0.f);
                }
            }
        }
    }
}

// ======================================================================
// res stack single-TF32 (decoder)                    [round-6, proven]
// ======================================================================
#define D3_W1   5346
#define D3_W2   24930
#define D3_TOT  27234
#define D3_RS   D3_W1
#define D3_SMEM (D3_TOT * 4)

__global__ void __launch_bounds__(256) res_tcd(
        float* __restrict__ buf,
        const float* __restrict__ pw1,
        const float* __restrict__ pw2) {
    extern __shared__ float sm[];
    float* xin = sm;
    float* w1s = sm + D3_W1;
    float* w2s = sm + D3_W2;
    float* rs  = sm + D3_RS;
    int t = threadIdx.x;
    int b0 = blockIdx.x * 2;

    for (int i = t; i < D3_W1; i += 256) xin[i] = 0.f;
    __syncthreads();
    for (int i = t; i < 18432; i += 256) {
        int oc = i / 288, rr = i % 288, ic = rr / 9, s = rr % 9;
        w1s[s * 2176 + ic * 68 + oc] = to_tf32(pw1[i]);
    }
    for (int i = t; i < 2048; i += 256) {
        int oc = i >> 6, ic = i & 63;
        w2s[ic * 36 + oc] = to_tf32(pw2[i]);
    }
    for (int i = t; i < 2 * 1568; i += 256) {
        int img = i / 1568, j = i % 1568;
        int ch = j / 49, p = j % 49;
        float v = buf[(size_t)(b0 + img) * 1568 + j];
        xin[img * 2673 + ((p / 7 + 1) * 9 + (p % 7 + 1)) * 33 + ch] =
            to_tf32(fmaxf(v, 0.f));
    }
    __syncthreads();

    int lane = t & 31, wrp = t >> 5;
    int grp = lane >> 2, tig = lane & 3;
    int img = wrp >> 2, mh = (wrp >> 1) & 1, nh = wrp & 1;
    int rbase = img * 64 + mh * 32;

    int rb[2][2];
    #pragma unroll
    for (int mi = 0; mi < 2; mi++)
        #pragma unroll
        for (int h = 0; h < 2; h++) {
            int p = mh * 32 + mi * 16 + grp + h * 8;
            rb[mi][h] = (p < 49) ? img * 2673 + ((p / 7) * 9 + (p % 7)) * 33 : 0;
        }

    float acc[2][4][4];
    #pragma unroll
    for (int mi = 0; mi < 2; mi++)
        #pragma unroll
        for (int ni = 0; ni < 4; ni++)
            #pragma unroll
            for (int c = 0; c < 4; c++) acc[mi][ni][c] = 0.f;

    #pragma unroll
    for (int ky = 0; ky < 3; ky++) {
        #pragma unroll
        for (int kx = 0; kx < 3; kx++) {
            int soff = (ky * 9 + kx) * 33;
            const float* wb = w1s + (ky * 3 + kx) * 2176 + nh * 32;
            #pragma unroll
            for (int kk = 0; kk < 4; kk++) {
                int kb = kk * 8;
                unsigned a[2][4];
                #pragma unroll
                for (int mi = 0; mi < 2; mi++) {
                    a[mi][0] = __float_as_uint(xin[rb[mi][0] + soff + kb + tig]);
                    a[mi][1] = __float_as_uint(xin[rb[mi][1] + soff + kb + tig]);
                    a[mi][2] = __float_as_uint(xin[rb[mi][0] + soff + kb + tig + 4]);
                    a[mi][3] = __float_as_uint(xin[rb[mi][1] + soff + kb + tig + 4]);
                }
                #pragma unroll
                for (int ni = 0; ni < 4; ni++) {
                    unsigned bb0 = __float_as_uint(wb[(kb + tig) * 68 + ni * 8 + grp]);
                    unsigned bb1 = __float_as_uint(wb[(kb + tig + 4) * 68 + ni * 8 + grp]);
                    mma_tf32(acc[0][ni], a[0], bb0, bb1);
                    mma_tf32(acc[1][ni], a[1], bb0, bb1);
                }
            }
        }
    }

    __syncthreads();

    #pragma unroll
    for (int mi = 0; mi < 2; mi++) {
        int rlo = rbase + mi * 16 + grp, rhi = rlo + 8;
        #pragma unroll
        for (int ni = 0; ni < 4; ni++) {
            int c0 = nh * 32 + ni * 8 + tig * 2;
            rs[rlo * 68 + c0]     = to_tf32(fmaxf(acc[mi][ni][0], 0.f));
            rs[rlo * 68 + c0 + 1] = to_tf32(fmaxf(acc[mi][ni][1], 0.f));
            rs[rhi * 68 + c0]     = to_tf32(fmaxf(acc[mi][ni][2], 0.f));
            rs[rhi * 68 + c0 + 1] = to_tf32(fmaxf(acc[mi][ni][3], 0.f));
        }
    }
    __syncthreads();

    float acc2[2][2][4];
    #pragma unroll
    for (int mi = 0; mi < 2; mi++)
        #pragma unroll
        for (int ni = 0; ni < 2; ni++)
            #pragma unroll
            for (int c = 0; c < 4; c++) acc2[mi][ni][c] = 0.f;

    #pragma unroll
    for (int kk = 0; kk < 8; kk++) {
        int kb = kk * 8;
        unsigned a[2][4];
        #pragma unroll
        for (int mi = 0; mi < 2; mi++) {
            int rlo = rbase + mi * 16 + grp;
            a[mi][0] = __float_as_uint(rs[rlo * 68 + kb + tig]);
            a[mi][1] = __float_as_uint(rs[(rlo + 8) * 68 + kb + tig]);
            a[mi][2] = __float_as_uint(rs[rlo * 68 + kb + tig + 4]);
            a[mi][3] = __float_as_uint(rs[(rlo + 8) * 68 + kb + tig + 4]);
        }
        #pragma unroll
        for (int ni = 0; ni < 2; ni++) {
            int c = nh * 16 + ni * 8 + grp;
            unsigned bb0 = __float_as_uint(w2s[(kb + tig) * 36 + c]);
            unsigned bb1 = __float_as_uint(w2s[(kb + tig + 4) * 36 + c]);
            mma_tf32(acc2[0][ni], a[0], bb0, bb1);
            mma_tf32(acc2[1][ni], a[1], bb0, bb1);
        }
    }

    #pragma unroll
    for (int mi = 0; mi < 2; mi++) {
        #pragma unroll
        for (int ni = 0; ni < 2; ni++) {
            #pragma unroll
            for (int ci = 0; ci < 4; ci++) {
                int p = mh * 32 + mi * 16 + grp + ((ci >= 2) ? 8 : 0);
                if (p < 49) {
                    int ch = nh * 16 + ni * 8 + tig * 2 + (ci & 1);
                    size_t g = (size_t)(b0 + img) * 1568 + ch * 49 + p;
                    float v = acc2[mi][ni][ci] + __ldg(buf + g);
                    buf[g] = fmaxf(v, 0.f);
                }
            }
        }
    }
}

// ======================================================================
// TF32 GEMM (decoder fc4) with register-prefetch pipelining  [round-7]
// ======================================================================
__global__ void __launch_bounds__(256) gemm_tc(
        const float* __restrict__ A,
        const float* __restrict__ W,
        const float* __restrict__ bias,
        float* __restrict__ C,
        int M, int N, int K) {
    __shared__ float As[128][17];
    __shared__ float Ws[64][17];
    int t = threadIdx.x, lane = t & 31, w = t >> 5;
    int grp = lane >> 2, tig = lane & 3;
    int m0 = blockIdx.x * 128, n0 = blockIdx.y * 64;
    int mw = (w & 3) * 32, nw = (w >> 2) * 32;
    float acc[2][4][4];
    #pragma unroll
    for (int mi = 0; mi < 2; mi++)
        #pragma unroll
        for (int ni = 0; ni < 4; ni++)
            #pragma unroll
            for (int c = 0; c < 4; c++) acc[mi][ni][c] = 0.f;

    int ar = t >> 1, ak = (t & 1) * 8;
    int wr = t >> 2, wk = (t & 3) * 4;
    const float* apb = A + (size_t)(m0 + ar) * K + ak;
    bool wval = (n0 + wr < N);
    const float* wpb = W + (size_t)(n0 + wr) * K + wk;

    float4 v0 = *(const float4*)apb;
    float4 v1 = *(const float4*)(apb + 4);
    float4 wv = wval ? *(const float4*)wpb : make_float4(0.f, 0.f, 0.f, 0.f);

    for (int k0 = 0; k0 < K; k0 += 16) {
        As[ar][ak + 0] = to_tf32(v0.x); As[ar][ak + 1] = to_tf32(v0.y);
        As[ar][ak + 2] = to_tf32(v0.z); As[ar][ak + 3] = to_tf32(v0.w);
        As[ar][ak + 4] = to_tf32(v1.x); As[ar][ak + 5] = to_tf32(v1.y);
        As[ar][ak + 6] = to_tf32(v1.z); As[ar][ak + 7] = to_tf32(v1.w);
        Ws[wr][wk + 0] = to_tf32(wv.x); Ws[wr][wk + 1] = to_tf32(wv.y);
        Ws[wr][wk + 2] = to_tf32(wv.z); Ws[wr][wk + 3] = to_tf32(wv.w);
        __syncthreads();
        if (k0 + 16 < K) {
            v0 = *(const float4*)(apb + k0 + 16);
            v1 = *(const float4*)(apb + k0 + 20);
            wv = wval ? *(const float4*)(wpb + k0 + 16)
                      : make_float4(0.f, 0.f, 0.f, 0.f);
        }
        #pragma unroll
        for (int kk = 0; kk < 2; kk++) {
            int kb = kk * 8;
            unsigned a[2][4];
            #pragma unroll
            for (int mi = 0; mi < 2; mi++) {
                int r = mw + mi * 16 + grp;
                a[mi][0] = __float_as_uint(As[r][kb + tig]);
                a[mi][1] = __float_as_uint(As[r + 8][kb + tig]);
                a[mi][2] = __float_as_uint(As[r][kb + tig + 4]);
                a[mi][3] = __float_as_uint(As[r + 8][kb + tig + 4]);
            }
            #pragma unroll
            for (int ni = 0; ni < 4; ni++) {
                int n = nw + ni * 8 + grp;
                unsigned bb0 = __float_as_uint(Ws[n][kb + tig]);
                unsigned bb1 = __float_as_uint(Ws[n][kb + tig + 4]);
                mma_tf32(acc[0][ni], a[0], bb0, bb1);
                mma_tf32(acc[1][ni], a[1], bb0, bb1);
            }
        }
        __syncthreads();
    }
    #pragma unroll
    for (int mi = 0; mi < 2; mi++) {
        #pragma unroll
        for (int ni = 0; ni < 4; ni++) {
            #pragma unroll
            for (int ci = 0; ci < 4; ci++) {
                int r = m0 + mw + mi * 16 + grp + ((ci >= 2) ? 8 : 0);
                int n = n0 + nw + ni * 8 + tig * 2 + (ci & 1);
                if (n < N)
                    C[(size_t)r * N + n] = fmaxf(acc[mi][ni][ci] + bias[n], 0.f);
            }
        }
    }
}

// ======================================================================
// 3xTF32 GEMM (encoder fc1) with register-prefetch pipelining [round-7]
// ======================================================================
__global__ void __launch_bounds__(256) gemm_tc3(
        const float* __restrict__ A,
        const float* __restrict__ W,
        const float* __restrict__ bias,
        float* __restrict__ C,
        int M, int N, int K) {
    __shared__ float As[128][17];
    __shared__ float Ws[64][17];
    int t = threadIdx.x, lane = t & 31, w = t >> 5;
    int grp = lane >> 2, tig = lane & 3;
    int m0 = blockIdx.x * 128, n0 = blockIdx.y * 64;
    int mw = (w & 3) * 32, nw = (w >> 2) * 32;
    float acc[2][4][4];
    #pragma unroll
    for (int mi = 0; mi < 2; mi++)
        #pragma unroll
        for (int ni = 0; ni < 4; ni++)
            #pragma unroll
            for (int c = 0; c < 4; c++) acc[mi][ni][c] = 0.f;

    int ar = t >> 1, ak = (t & 1) * 8;
    int wr = t >> 2, wk = (t & 3) * 4;
    const float* apb = A + (size_t)(m0 + ar) * K + ak;
    bool wval = (n0 + wr < N);
    const float* wpb = W + (size_t)(n0 + wr) * K + wk;

    float4 v0 = *(const float4*)apb;
    float4 v1 = *(const float4*)(apb + 4);
    float4 wv = wval ? *(const float4*)wpb : make_float4(0.f, 0.f, 0.f, 0.f);

    for (int k0 = 0; k0 < K; k0 += 16) {
        As[ar][ak + 0] = v0.x; As[ar][ak + 1] = v0.y;
        As[ar][ak + 2] = v0.z; As[ar][ak + 3] = v0.w;
        As[ar][ak + 4] = v1.x; As[ar][ak + 5] = v1.y;
        As[ar][ak + 6] = v1.z; As[ar][ak + 7] = v1.w;
        Ws[wr][wk + 0] = wv.x; Ws[wr][wk + 1] = wv.y;
        Ws[wr][wk + 2] = wv.z; Ws[wr][wk + 3] = wv.w;
        __syncthreads();
        if (k0 + 16 < K) {
            v0 = *(const float4*)(apb + k0 + 16);
            v1 = *(const float4*)(apb + k0 + 20);
            wv = wval ? *(const float4*)(wpb + k0 + 16)
                      : make_float4(0.f, 0.f, 0.f, 0.f);
        }
        #pragma unroll
        for (int kk = 0; kk < 2; kk++) {
            int kb = kk * 8;
            unsigned ah[2][4], al[2][4];
            #pragma unroll
            for (int mi = 0; mi < 2; mi++) {
                int r = mw + mi * 16 + grp;
                split_tf32(As[r][kb + tig],         ah[mi][0], al[mi][0]);
                split_tf32(As[r + 8][kb + tig],     ah[mi][1], al[mi][1]);
                split_tf32(As[r][kb + tig + 4],     ah[mi][2], al[mi][2]);
                split_tf32(As[r + 8][kb + tig + 4], ah[mi][3], al[mi][3]);
            }
            #pragma unroll
            for (int ni = 0; ni < 4; ni++) {
                int n = nw + ni * 8 + grp;
                unsigned bh0, bl0, bh1, bl1;
                split_tf32(Ws[n][kb + tig],     bh0, bl0);
                split_tf32(Ws[n][kb + tig + 4], bh1, bl1);
                mma3(acc[0][ni], ah[0], al[0], bh0, bh1, bl0, bl1);
                mma3(acc[1][ni], ah[1], al[1], bh0, bh1, bl0, bl1);
            }
        }
        __syncthreads();
    }
    #pragma unroll
    for (int mi = 0; mi < 2; mi++) {
        #pragma unroll
        for (int ni = 0; ni < 4; ni++) {
            #pragma unroll
            for (int ci = 0; ci < 4; ci++) {
                int r = m0 + mw + mi * 16 + grp + ((ci >= 2) ? 8 : 0);
                int n = n0 + nw + ni * 8 + tig * 2 + (ci & 1);
                if (n < N)
                    C[(size_t)r * N + n] = fmaxf(acc[mi][ni][ci] + bias[n], 0.f);
            }
        }
    }
}

// ======================================================================
// convt1 single-TF32 (decoder)                                [round-4]
// ======================================================================
#define T1_IMSZ 2916
#define T1_ZB   6240
#define T1_XIN  6664
#define T1_WOFF T1_XIN
#define T1_WSZ  (16 * 32 * 24)
#define T1_SMEM ((T1_XIN + T1_WSZ) * 4)

__global__ void __launch_bounds__(256) convt1_tc(
        const float* __restrict__ in,
        const float* __restrict__ w,
        const float* __restrict__ bias,
        float* __restrict__ out) {
    extern __shared__ float sm[];
    float* xin = sm;
    float* wt  = sm + T1_WOFF;
    int t = threadIdx.x;
    int b0 = blockIdx.x * 2;

    for (int i = t; i < T1_XIN; i += 256) xin[i] = 0.f;
    __syncthreads();
    for (int i = t; i < 2 * 1568; i += 256) {
        int img = i / 1568, j = i % 1568;
        int ic = j / 49, p = j % 49, iy = p / 7, ix = p % 7;
        xin[img * T1_IMSZ + ((iy + 1) * 9 + (ix + 1)) * 36 + ic] =
            to_tf32(in[(size_t)(b0 + img) * 1568 + j]);
    }
    for (int i = t; i < 32 * 256; i += 256) {
        int ic = i / 256, r = i % 256, oc = r / 16, s = r % 16;
        wt[s * 768 + ic * 24 + oc] = to_tf32(w[i]);
    }
    __syncthreads();

    int lane = t & 31, wrp = t >> 5;
    int grp = lane >> 2, tig = lane & 3;
    int img = wrp >> 2, ph = wrp & 3;
    int a = ph >> 1, bp = ph & 1;
    int dyv[2], kyv[2], dxv[2], kxv[2];
    if (a == 0) { dyv[0] = 0; kyv[0] = 1; dyv[1] = -1; kyv[1] = 3; }
    else        { dyv[0] = 1; kyv[0] = 0; dyv[1] =  0; kyv[1] = 2; }
    if (bp == 0) { dxv[0] = 0; kxv[0] = 1; dxv[1] = -1; kxv[1] = 3; }
    else         { dxv[0] = 1; kxv[0] = 0; dxv[1] =  0; kxv[1] = 2; }

    int rb[4][2];
    #pragma unroll
    for (int mi = 0; mi < 4; mi++)
        #pragma unroll
        for (int h = 0; h < 2; h++) {
            int p = mi * 16 + grp + h * 8;
            rb[mi][h] = (p < 49)
                ? img * T1_IMSZ + ((p / 7 + 1) * 9 + (p % 7 + 1)) * 36
                : T1_ZB;
        }

    float acc[4][2][4];
    #pragma unroll
    for (int mi = 0; mi < 4; mi++)
        #pragma unroll
        for (int ni = 0; ni < 2; ni++)
            #pragma unroll
            for (int c = 0; c < 4; c++) acc[mi][ni][c] = 0.f;

    #pragma unroll
    for (int sy = 0; sy < 2; sy++) {
        #pragma unroll
        for (int sx = 0; sx < 2; sx++) {
            int soff = (dyv[sy] * 9 + dxv[sx]) * 36;
            const float* wsl = wt + (kyv[sy] * 4 + kxv[sx]) * 768;
            #pragma unroll
            for (int kk = 0; kk < 4; kk++) {
                int kb = kk * 8;
                unsigned afr[4][4];
                #pragma unroll
                for (int mi = 0; mi < 4; mi++) {
                    afr[mi][0] = __float_as_uint(xin[rb[mi][0] + soff + kb + tig]);
                    afr[mi][1] = __float_as_uint(xin[rb[mi][1] + soff + kb + tig]);
                    afr[mi][2] = __float_as_uint(xin[rb[mi][0] + soff + kb + tig + 4]);
                    afr[mi][3] = __float_as_uint(xin[rb[mi][1] + soff + kb + tig + 4]);
                }
                #pragma unroll
                for (int ni = 0; ni < 2; ni++) {
                    unsigned bb0 = __float_as_uint(wsl[(kb + tig) * 24 + ni * 8 + grp]);
                    unsigned bb1 = __float_as_uint(wsl[(kb + tig + 4) * 24 + ni * 8 + grp]);
                    #pragma unroll
                    for (int mi = 0; mi < 4; mi++)
                        mma_tf32(acc[mi][ni], afr[mi], bb0, bb1);
                }
            }
        }
    }

    #pragma unroll
    for (int mi = 0; mi < 4; mi++) {
        #pragma unroll
        for (int ni = 0; ni < 2; ni++) {
            #pragma unroll
            for (int ci = 0; ci < 4; ci++) {
                int p = mi * 16 + grp + ((ci >= 2) ? 8 : 0);
                if (p < 49) {
                    int m = p / 7, n = p % 7;
                    int oc = ni * 8 + tig * 2 + (ci & 1);
                    int oy = 2 * m + a, ox = 2 * n + bp;
                    float v = acc[mi][ni][ci] + __ldg(bias + oc);
                    out[(size_t)(b0 + img) * 3136 + oc * 196 + oy * 14 + ox] =
                        fmaxf(v, 0.f);
                }
            }
        }
    }
}

// ======================================================================
// fc2: z[B,32] = A[B,224] @ w^T + b  (fp32, feeds VQ)
// 32 rows/CTA (4x fewer weight reloads); identical accumulation order.
// ======================================================================
__global__ void __launch_bounds__(256) fc2_kernel(
        const float* __restrict__ A,
        const float* __restrict__ w,
        const float* __restrict__ bias,
        float* __restrict__ out) {
    __shared__ float ws[32 * 224];
    int t = threadIdx.x;
    for (int i = t; i < 7168; i += 256) ws[i] = w[i];
    __syncthreads();
    int n = t & 31, r = t >> 5;
    float bv = bias[n];
    const float* wp = ws + n * 224;
    #pragma unroll
    for (int rr = 0; rr < 4; rr++) {
        int b = blockIdx.x * 32 + rr * 8 + r;
        const float* ap = A + (size_t)b * 224;
        float acc = bv;
        #pragma unroll 8
        for (int k = 0; k < 224; k++) acc += ap[k] * wp[k];
        out[(size_t)b * 32 + n] = acc;
    }
}

// ======================================================================
// VQ helpers (fp32 exact)
// ======================================================================
__global__ void enorm_kernel(const float* __restrict__ emb, float* __restrict__ enorm) {
    int e = blockIdx.x * blockDim.x + threadIdx.x;
    if (e < NE) {
        float s = 0.f;
        #pragma unroll
        for (int d = 0; d < ZD; d++) { float v = emb[e * ZD + d]; s += v * v; }
        enorm[e] = s;
    }
}

__global__ void zero_kernel(float* __restrict__ counts, float* __restrict__ sums,
                            float* __restrict__ loss) {
    int i = blockIdx.x * blockDim.x + threadIdx.x;
    if (i < NE) counts[i] = 0.f;
    if (i < NE * ZD) sums[i] = 0.f;
    if (i == 0) loss[0] = 0.f;
}

// 64 rows/CTA; emb staged in smem (pitch 36)          [round-7, proven]
#define VQ_SMEM (NE * 36 * 4)

__global__ void __launch_bounds__(256) vq_kernel(
        const float* __restrict__ z,
        const float* __restrict__ emb,
        const float* __restrict__ enorm,
        int* __restrict__ idx,
        float* __restrict__ counts,
        float* __restrict__ sums,
        float* __restrict__ loss) {
    extern __shared__ float es[];          // [512][36]
    __shared__ float en[NE];
    __shared__ float zs[8][ZD];
    int t = threadIdx.x, lane = t & 31, wl = t >> 5;
    for (int i = t; i < NE * ZD; i += 256) {
        int e = i >> 5, d = i & 31;
        es[e * 36 + d] = emb[i];
    }
    for (int i = t; i < NE; i += 256) en[i] = enorm[i];
    __syncthreads();

    for (int rr = 0; rr < 8; rr++) {
        int row = blockIdx.x * 64 + wl * 8 + rr;
        zs[wl][lane] = z[(size_t)row * ZD + lane];
        __syncwarp();
        float best = 3.4e38f; int bi = NE;
        for (int e = lane; e < NE; e += 32) {
            const float* ep = es + e * 36;
            float dot = 0.f;
            #pragma unroll
            for (int d = 0; d < ZD; d += 4) {
                float4 v = *(const float4*)(ep + d);
                dot += zs[wl][d + 0] * v.x;
                dot += zs[wl][d + 1] * v.y;
                dot += zs[wl][d + 2] * v.z;
                dot += zs[wl][d + 3] * v.w;
            }
            float s = en[e] - 2.f * dot;
            if (s < best) { best = s; bi = e; }
        }
        #pragma unroll
        for (int off = 16; off; off >>= 1) {
            float ob = __shfl_xor_sync(0xffffffffu, best, off);
            int   oi = __shfl_xor_sync(0xffffffffu, bi, off);
            if (ob < best || (ob == best && oi < bi)) { best = ob; bi = oi; }
        }
        float zl = zs[wl][lane];
        float diff = es[bi * 36 + lane] - zl;
        float d2 = diff * diff;
        #pragma unroll
        for (int off = 16; off; off >>= 1)
            d2 += __shfl_xor_sync(0xffffffffu, d2, off);
        if (lane == 0) {
            idx[row] = bi;
            atomicAdd(&counts[bi], 1.f);
            atomicAdd(loss, d2);
        }
        atomicAdd(&sums[bi * ZD + lane], zl);
        __syncwarp();
    }
}

__global__ void embnew_kernel(const float* __restrict__ m_mat,
                              const float* __restrict__ n_mat,
                              const float* __restrict__ sums,
                              const float* __restrict__ counts,
                              float* __restrict__ out) {
    int i = blockIdx.x * blockDim.x + threadIdx.x;
    if (i < NE * ZD) {
        int e = i >> 5;
        float m = m_mat[i] * GAMMA + sums[i] * ONE_M_GAMMA;
        float n = n_mat[e] * GAMMA + counts[e] * ONE_M_GAMMA;
        out[i] = m / n;
    }
}

__global__ void finalize_kernel(const float* __restrict__ counts,
                                const float* __restrict__ loss,
                                float* __restrict__ out_scalars) {
    __shared__ float red[NE];
    int t = threadIdx.x;
    float c = counts[t];
    float em = c * (1.f / (float)BATCH);
    red[t] = em * logf(em + 1e-10f);
    __syncthreads();
    for (int s = 256; s; s >>= 1) {
        if (t < s) red[t] += red[t + s];
        __syncthreads();
    }
    if (t == 0) {
        float q = loss[0] * (1.f / ((float)BATCH * (float)ZD));
        out_scalars[0] = q;
        out_scalars[1] = BETA * q;
        out_scalars[2] = expf(-red[0]);
    }
}

// ======================================================================
// fc3 (fp32): 16 images/CTA, weights staged once, w row in registers
// ======================================================================
__global__ void __launch_bounds__(224) fc3_kernel(
        const float* __restrict__ emb,
        const int* __restrict__ idx,
        const float* __restrict__ w,
        const float* __restrict__ bias,
        float* __restrict__ out) {
    __shared__ float ws[224 * ZD];
    __shared__ float zq[16][ZD + 1];
    int b0 = blockIdx.x * 16, t = threadIdx.x;
    for (int i = t; i < 224 * ZD; i += 224) ws[i] = w[i];
    for (int i = t; i < 16 * ZD; i += 224) {
        int im = i >> 5, d = i & 31;
        zq[im][d] = emb[(size_t)idx[b0 + im] * ZD + d];
    }
    __syncthreads();
    float bv = bias[t];
    float wreg[ZD];
    const float* wp = ws + t * ZD;
    #pragma unroll
    for (int k = 0; k < ZD; k++) wreg[k] = wp[k];
    #pragma unroll 4
    for (int im = 0; im < 16; im++) {
        float acc = bv;
        #pragma unroll
        for (int k = 0; k < ZD; k++) acc += zq[im][k] * wreg[k];
        out[(size_t)(b0 + im) * 224 + t] = fmaxf(acc, 0.f);
    }
}

// ======================================================================
// convt2 phase-decomposed fp32                        [round-7, proven]
// ======================================================================
#define CT2_SMEM (4 * 4096 * 4)   // 65536 B

template<int DY0, int KY0, int DY1, int KY1,
         int DX0, int KX0, int DX1, int KX1>
__device__ __forceinline__ void ct2_body(
        const float* __restrict__ base, const float* __restrict__ w,
        float bv, float* __restrict__ outp, int m) {
    float acc[14];
    #pragma unroll
    for (int j = 0; j < 14; j++) acc[j] = bv;
    for (int ic = 0; ic < 16; ic++) {
        const float* xc = base + ic * 256;
        #pragma unroll
        for (int sy = 0; sy < 2; sy++) {
            int iy = m + (sy ? DY1 : DY0);
            float row[16];
            #pragma unroll
            for (int j = 0; j < 16; j++) row[j] = xc[(iy + 1) * 16 + j];
            {
                float wv = __ldg(w + ic * 16 + (sy ? KY1 : KY0) * 4 + KX0);
                #pragma unroll
                for (int n = 0; n < 14; n++) acc[n] += row[n + DX0 + 1] * wv;
            }
            {
                float wv = __ldg(w + ic * 16 + (sy ? KY1 : KY0) * 4 + KX1);
                #pragma unroll
                for (int n = 0; n < 14; n++) acc[n] += row[n + DX1 + 1] * wv;
            }
        }
    }
    #pragma unroll
    for (int n = 0; n < 14; n++) outp[2 * n] = acc[n];
}

__global__ void __launch_bounds__(256) convt2_tc(
        const float* __restrict__ in,
        const float* __restrict__ w,
        const float* __restrict__ bias,
        float* __restrict__ out) {
    extern __shared__ float xp[];   // [4 img][16 ic][16][16], halo 1
    int t = threadIdx.x;
    int b0 = blockIdx.x * 4;

    for (int i = t; i < 16384; i += 256) xp[i] = 0.f;
    __syncthreads();
    for (int i = t; i < 4 * 3136; i += 256) {
        int img = i / 3136, j = i % 3136;
        int ic = j / 196, p = j % 196, iy = p / 14, ix = p % 14;
        xp[img * 4096 + ic * 256 + (iy + 1) * 16 + (ix + 1)] =
            in[(size_t)(b0 + img) * 3136 + j];
    }
    __syncthreads();

    int ph = t >> 6, s = t & 63;
    if (s >= 56) return;
    int img = s / 14, m = s % 14;
    int a = ph >> 1, b = ph & 1;
    const float* base = xp + img * 4096;
    float bv = bias[0];
    float* outp = out + (size_t)(b0 + img) * 784 + (2 * m + a) * 28 + b;

    if (ph == 0)      ct2_body<0, 1, -1, 3,  0, 1, -1, 3>(base, w, bv, outp, m);
    else if (ph == 1) ct2_body<0, 1, -1, 3,  1, 0,  0, 2>(base, w, bv, outp, m);
    else if (ph == 2) ct2_body<1, 0,  0, 2,  0, 1, -1, 3>(base, w, bv, outp, m);
    else              ct2_body<1, 0,  0, 2,  1, 0,  0, 2>(base, w, bv, outp, m);
}

// ======================================================================
// launch
// ======================================================================
extern "C" void kernel_launch(void* const* d_in, const int* in_sizes, int n_in,
                              void* d_out, int out_size) {
    const float* x        = (const float*)d_in[0];
    const float* conv1_w  = (const float*)d_in[1];
    const float* conv1_b  = (const float*)d_in[2];
    const float* conv2_w  = (const float*)d_in[3];
    const float* conv2_b  = (const float*)d_in[4];
    const float* res1_w1  = (const float*)d_in[5];
    const float* res1_w2  = (const float*)d_in[6];
    const float* fc1_w    = (const float*)d_in[7];
    const float* fc1_b    = (const float*)d_in[8];
    const float* fc2_w    = (const float*)d_in[9];
    const float* fc2_b    = (const float*)d_in[10];
    const float* emb      = (const float*)d_in[11];
    const float* n_mat    = (const float*)d_in[12];
    const float* m_mat    = (const float*)d_in[13];
    const float* fc3_w    = (const float*)d_in[14];
    const float* fc3_b    = (const float*)d_in[15];
    const float* fc4_w    = (const float*)d_in[16];
    const float* fc4_b    = (const float*)d_in[17];
    const float* res2_w1  = (const float*)d_in[18];
    const float* res2_w2  = (const float*)d_in[19];
    const float* convt1_w = (const float*)d_in[20];
    const float* convt1_b = (const float*)d_in[21];
    const float* convt2_w = (const float*)d_in[22];
    const float* convt2_b = (const float*)d_in[23];
    float* out = (float*)d_out;

    float *h1, *h2, *a, *z, *enorm, *counts, *sums, *loss;
    int* idx;
    cudaGetSymbolAddress((void**)&h1,     g_h1);
    cudaGetSymbolAddress((void**)&h2,     g_h2);
    cudaGetSymbolAddress((void**)&a,      g_a);
    cudaGetSymbolAddress((void**)&z,      g_z);
    cudaGetSymbolAddress((void**)&idx,    g_idx);
    cudaGetSymbolAddress((void**)&enorm,  g_enorm);
    cudaGetSymbolAddress((void**)&counts, g_counts);
    cudaGetSymbolAddress((void**)&sums,   g_sums);
    cudaGetSymbolAddress((void**)&loss,   g_loss);

    cudaFuncSetAttribute(conv2_tc3,
                         cudaFuncAttributeMaxDynamicSharedMemorySize, C2B_SMEM);
    cudaFuncSetAttribute(res_tc3,
                         cudaFuncAttributeMaxDynamicSharedMemorySize, E3_SMEM);
    cudaFuncSetAttribute(res_tcd,
                         cudaFuncAttributeMaxDynamicSharedMemorySize, D3_SMEM);
    cudaFuncSetAttribute(convt1_tc,
                         cudaFuncAttributeMaxDynamicSharedMemorySize, T1_SMEM);
    cudaFuncSetAttribute(convt2_tc,
                         cudaFuncAttributeMaxDynamicSharedMemorySize, CT2_SMEM);
    cudaFuncSetAttribute(vq_kernel,
                         cudaFuncAttributeMaxDynamicSharedMemorySize, VQ_SMEM);

    // encoder (3xTF32 = fp32-class accuracy; VQ path preserved)
    conv1_kernel<<<BATCH / 2, 224>>>(x, conv1_w, conv1_b, h1);
    conv2_tc3<<<BATCH / 2, 256, C2B_SMEM>>>(h1, conv2_w, conv2_b, h2);
    res_tc3  <<<BATCH / 2, 256, E3_SMEM>>>(h2, res1_w1, res1_w2);
    gemm_tc3<<<dim3(BATCH / 128, 4), 256>>>(h2, fc1_w, fc1_b, a,
                                            BATCH, 224, 1568);
    fc2_kernel<<<BATCH / 32, 256>>>(a, fc2_w, fc2_b, z);

    // VQ
    zero_kernel <<<(NE * ZD + 255) / 256, 256>>>(counts, sums, loss);
    enorm_kernel<<<2, 256>>>(emb, enorm);
    vq_kernel   <<<BATCH / 64, 256, VQ_SMEM>>>(z, emb, enorm, idx, counts,
                                               sums, loss);
    embnew_kernel  <<<(NE * ZD + 255) / 256, 256>>>(m_mat, n_mat, sums, counts,
                                                    out + OFF_SCAL + 3);
    finalize_kernel<<<1, NE>>>(counts, loss, out + OFF_SCAL);

    // decoder (single tf32)
    fc3_kernel<<<BATCH / 16, 224>>>(emb, idx, fc3_w, fc3_b, a);
    gemm_tc<<<dim3(BATCH / 128, 25), 256>>>(a, fc4_w, fc4_b, h2,
                                            BATCH, 1568, 224);
    res_tcd<<<BATCH / 2, 256, D3_SMEM>>>(h2, res2_w1, res2_w2);
    convt1_tc<<<BATCH / 2, 256, T1_SMEM>>>(h2, convt1_w, convt1_b, h1);
    convt2_tc<<<BATCH / 4, 256, CT2_SMEM>>>(h1, convt2_w, convt2_b, out);
}

// round 10
// speedup vs baseline: 2.2872x; 1.1908x over previous
#include <cuda_runtime.h>
#include <cstdint>
#include <math.h>

// ---------------- problem constants ----------------
#define BATCH 16384
#define ZD 32
#define NE 512
#define GAMMA 0.99f
#define ONE_M_GAMMA 0.01f
#define BETA 1.0f

#define OFF_SCAL (BATCH * 784)   // x_rec size
// d_out layout: [x_rec (B*784)][quant][commit][perplexity][emb_new (512*32)]

// ---------------- scratch ----------------
__device__ float g_h1[BATCH * 16 * 14 * 14];
__device__ float g_h2[BATCH * 32 * 7 * 7];
__device__ float g_a [BATCH * 224];
__device__ float g_z [BATCH * ZD];
__device__ int   g_idx[BATCH];
__device__ float g_enorm[NE];
__device__ float g_counts[NE];
__device__ float g_sums[NE * ZD];
__device__ float g_loss[1];
// fragment-order weight textures: [s][kk][oct][lane] -> (b0,b1)
__device__ float2 g_wf_r1[9216];   // res1 w1 (raw fp32)
__device__ float2 g_wf_r2[9216];   // res2 w1 (tf32)
__device__ float2 g_wf_c2[4096];   // conv2 w  (raw fp32)

// ---------------- tf32 mma helpers ----------------
__device__ __forceinline__ float to_tf32(float x) {
    float y;
    asm("cvt.rna.tf32.f32 %0, %1;" : "=f"(y) : "f"(x));
    return y;
}

// Bitwise hi/lo split: hi = RZ-truncated tf32 (LOP3), lo = v - hi (exact FADD).
__device__ __forceinline__ void split_tf32(float v, unsigned& hi, unsigned& lo) {
    unsigned h = __float_as_uint(v) & 0xffffe000u;
    hi = h;
    lo = __float_as_uint(v - __uint_as_float(h));
}

__device__ __forceinline__ void mma_tf32(float* d, const unsigned* a,
                                         unsigned b0, unsigned b1) {
    asm volatile(
        "mma.sync.aligned.m16n8k8.row.col.f32.tf32.tf32.f32 "
        "{%0,%1,%2,%3}, {%4,%5,%6,%7}, {%8,%9}, {%0,%1,%2,%3};\n"
        : "+f"(d[0]), "+f"(d[1]), "+f"(d[2]), "+f"(d[3])
        : "r"(a[0]), "r"(a[1]), "r"(a[2]), "r"(a[3]), "r"(b0), "r"(b1));
}

// 3-pass split mma: acc += a*b with ~fp32 accuracy
__device__ __forceinline__ void mma3(float* d, const unsigned* ah, const unsigned* al,
                                     unsigned bh0, unsigned bh1,
                                     unsigned bl0, unsigned bl1) {
    mma_tf32(d, ah, bl0, bl1);
    mma_tf32(d, al, bh0, bh1);
    mma_tf32(d, ah, bh0, bh1);
}

// ======================================================================
// weight repack kernels (run once per launch; tiny)
// res w1[64oc][32ic][9s] -> [s][kk<4][oct<8][lane]: (b0=w[oc][kk*8+tig], b1=+4)
// ======================================================================
__global__ void repack_res(const float* __restrict__ w1,
                           float2* __restrict__ out, int cvt) {
    int i = blockIdx.x * 256 + threadIdx.x;
    if (i >= 9216) return;
    int lane = i & 31, oct = (i >> 5) & 7, kk = (i >> 8) & 3, s = i >> 10;
    int grp = lane >> 2, tig = lane & 3;
    int oc = oct * 8 + grp, ic = kk * 8 + tig;
    float b0 = w1[oc * 288 + ic * 9 + s];
    float b1 = w1[oc * 288 + (ic + 4) * 9 + s];
    if (cvt) { b0 = to_tf32(b0); b1 = to_tf32(b1); }
    out[i] = make_float2(b0, b1);
}

// conv2 w[32oc][16ic][16s] -> [s][kk<2][oct<4][lane]
__global__ void repack_c2(const float* __restrict__ w,
                          float2* __restrict__ out) {
    int i = blockIdx.x * 256 + threadIdx.x;
    if (i >= 4096) return;
    int lane = i & 31, oct = (i >> 5) & 3, kk = (i >> 7) & 1, s = i >> 8;
    int grp = lane >> 2, tig = lane & 3;
    int oc = oct * 8 + grp, ic = kk * 8 + tig;
    out[i] = make_float2(w[oc * 256 + ic * 16 + s],
                         w[oc * 256 + (ic + 4) * 16 + s]);
}

// ======================================================================
// conv1: x[B,1,28,28] -> relu -> h1[B,16,14,14]   (k4 s2 p1)  fp32
// ======================================================================
__global__ void __launch_bounds__(224) conv1_kernel(
        const float* __restrict__ x,
        const float* __restrict__ w,
        const float* __restrict__ bias,
        float* __restrict__ out) {
    __shared__ float xp[2 * 900];
    int b0 = blockIdx.x * 2, t = threadIdx.x;
    for (int i = t; i < 1800; i += 224) xp[i] = 0.f;
    __syncthreads();
    for (int i = t; i < 1568; i += 224) {
        int im = i / 784, j = i % 784;
        int iy = j / 28, ix = j % 28;
        xp[im * 900 + (iy + 1) * 30 + (ix + 1)] = x[(size_t)(b0 + im) * 784 + j];
    }
    __syncthreads();
    int im = t / 112, r = t % 112;
    int ocp = r / 14, oy = r % 14;
    int oc0 = ocp * 2, oc1 = oc0 + 1;
    float acc0[14], acc1[14];
    float b0v = bias[oc0], b1v = bias[oc1];
    #pragma unroll
    for (int j = 0; j < 14; j++) { acc0[j] = b0v; acc1[j] = b1v; }
    const float* base = xp + im * 900;
    #pragma unroll
    for (int ky = 0; ky < 4; ky++) {
        int ry = 2 * oy + ky;
        float row[30];
        #pragma unroll
        for (int j = 0; j < 30; j++) row[j] = base[ry * 30 + j];
        #pragma unroll
        for (int kx = 0; kx < 4; kx++) {
            float w0 = __ldg(w + oc0 * 16 + ky * 4 + kx);
            float w1 = __ldg(w + oc1 * 16 + ky * 4 + kx);
            #pragma unroll
            for (int ox = 0; ox < 14; ox++) {
                float v = row[2 * ox + kx];
                acc0[ox] += v * w0;
                acc1[ox] += v * w1;
            }
        }
    }
    float* op = out + (size_t)(b0 + im) * 3136 + oy * 14;
    #pragma unroll
    for (int ox = 0; ox < 14; ox++) {
        op[oc0 * 196 + ox] = fmaxf(acc0[ox], 0.f);
        op[oc1 * 196 + ox] = fmaxf(acc1[ox], 0.f);
    }
}

// ======================================================================
// conv2 3xTF32 shift-GEMM: weights via fragment-texture LDG
// 2 img/CTA, 256 thr, smem = xin only (55 KB) -> 3-4 CTA/SM
// ======================================================================
#define C2B_ZOFF 9216
#define C2B_XIN  13824
#define C2B_SMEM (C2B_XIN * 4)   // 55296 B

__global__ void __launch_bounds__(256) conv2_tc3(
        const float* __restrict__ in,
        const float2* __restrict__ wf,
        const float* __restrict__ bias,
        float* __restrict__ out) {
    extern __shared__ float sm[];
    float* xin = sm;
    int t = threadIdx.x;
    int b0 = blockIdx.x * 2;

    for (int i = t; i < C2B_XIN; i += 256) xin[i] = 0.f;
    __syncthreads();
    for (int i = t; i < 2 * 3136; i += 256) {
        int img = i / 3136, j = i % 3136;
        int ic = j / 196, p = j % 196, iy = p / 14, ix = p % 14;
        xin[img * 4608 + ((iy + 1) * 16 + (ix + 1)) * 18 + ic] =
            in[(size_t)(b0 + img) * 3136 + j];
    }
    __syncthreads();

    int lane = t & 31, wrp = t >> 5;
    int grp = lane >> 2, tig = lane & 3;
    int img = wrp >> 2, mh = (wrp >> 1) & 1, nh = wrp & 1;

    int rb[2][2];
    #pragma unroll
    for (int mi = 0; mi < 2; mi++)
        #pragma unroll
        for (int h = 0; h < 2; h++) {
            int p = mh * 32 + mi * 16 + grp + h * 8;
            rb[mi][h] = (p < 49)
                ? img * 4608 + ((p / 7) * 32 + (p % 7) * 2) * 18
                : C2B_ZOFF;
        }

    float acc[2][2][4];
    #pragma unroll
    for (int mi = 0; mi < 2; mi++)
        #pragma unroll
        for (int ni = 0; ni < 2; ni++)
            #pragma unroll
            for (int c = 0; c < 4; c++) acc[mi][ni][c] = 0.f;

    #pragma unroll
    for (int ky = 0; ky < 4; ky++) {
        #pragma unroll
        for (int kx = 0; kx < 4; kx++) {
            int s = ky * 4 + kx;               // weight-texture index
            int soff = (ky * 16 + kx) * 18;    // spatial shift in padded image
            #pragma unroll
            for (int kk = 0; kk < 2; kk++) {
                int kb = kk * 8;
                unsigned ah[2][4], al[2][4];
                #pragma unroll
                for (int mi = 0; mi < 2; mi++) {
                    split_tf32(xin[rb[mi][0] + soff + kb + tig],     ah[mi][0], al[mi][0]);
                    split_tf32(xin[rb[mi][1] + soff + kb + tig],     ah[mi][1], al[mi][1]);
                    split_tf32(xin[rb[mi][0] + soff + kb + tig + 4], ah[mi][2], al[mi][2]);
                    split_tf32(xin[rb[mi][1] + soff + kb + tig + 4], ah[mi][3], al[mi][3]);
                }
                #pragma unroll
                for (int ni = 0; ni < 2; ni++) {
                    int oct = nh * 2 + ni;
                    float2 bw = __ldg(wf + (size_t)s * 256 + kk * 128 + oct * 32 + lane);
                    unsigned bh0, bl0, bh1, bl1;
                    split_tf32(bw.x, bh0, bl0);
                    split_tf32(bw.y, bh1, bl1);
                    mma3(acc[0][ni], ah[0], al[0], bh0, bh1, bl0, bl1);
                    mma3(acc[1][ni], ah[1], al[1], bh0, bh1, bl0, bl1);
                }
            }
        }
    }

    #pragma unroll
    for (int mi = 0; mi < 2; mi++) {
        #pragma unroll
        for (int ni = 0; ni < 2; ni++) {
            #pragma unroll
            for (int ci = 0; ci < 4; ci++) {
                int p = mh * 32 + mi * 16 + grp + ((ci >= 2) ? 8 : 0);
                if (p < 49) {
                    int oc = nh * 16 + ni * 8 + tig * 2 + (ci & 1);
                    out[(size_t)(b0 + img) * 1568 + oc * 49 + p] =
                        acc[mi][ni][ci] + __ldg(bias + oc);
                }
            }
        }
    }
}

// ======================================================================
// res stack 3xTF32 (encoder): weights via fragment-texture LDG
// 2 img/CTA, smem = xin + rs + w2 = 67 KB -> 3 CTA/SM
// ======================================================================
#define E3_RS   5832
#define E3_W2   14536
#define E3_TOT  16840
#define E3_SMEM (E3_TOT * 4)     // 67360 B

__global__ void __launch_bounds__(256) res_tc3(
        float* __restrict__ buf,
        const float2* __restrict__ wf,
        const float* __restrict__ pw2) {
    extern __shared__ float sm[];
    float* xin = sm;
    float* rs  = sm + E3_RS;
    float* w2s = sm + E3_W2;
    int t = threadIdx.x;
    int b0 = blockIdx.x * 2;

    for (int i = t; i < E3_RS; i += 256) xin[i] = 0.f;
    __syncthreads();
    for (int i = t; i < 2048; i += 256) {
        int oc = i >> 6, ic = i & 63;
        w2s[ic * 36 + oc] = pw2[i];
    }
    for (int i = t; i < 2 * 1568; i += 256) {
        int img = i / 1568, j = i % 1568;
        int ch = j / 49, p = j % 49;
        float v = buf[(size_t)(b0 + img) * 1568 + j];
        xin[img * 2916 + ((p / 7 + 1) * 9 + (p % 7 + 1)) * 36 + ch] = fmaxf(v, 0.f);
    }
    __syncthreads();

    int lane = t & 31, wrp = t >> 5;
    int grp = lane >> 2, tig = lane & 3;
    int img = wrp >> 2, mh = (wrp >> 1) & 1, nh = wrp & 1;
    int rbase = img * 64 + mh * 32;

    int rb[2][2];
    #pragma unroll
    for (int mi = 0; mi < 2; mi++)
        #pragma unroll
        for (int h = 0; h < 2; h++) {
            int p = mh * 32 + mi * 16 + grp + h * 8;
            rb[mi][h] = (p < 49) ? img * 2916 + ((p / 7) * 9 + (p % 7)) * 36 : 0;
        }

    float acc[2][4][4];
    #pragma unroll
    for (int mi = 0; mi < 2; mi++)
        #pragma unroll
        for (int ni = 0; ni < 4; ni++)
            #pragma unroll
            for (int c = 0; c < 4; c++) acc[mi][ni][c] = 0.f;

    #pragma unroll
    for (int ky = 0; ky < 3; ky++) {
        #pragma unroll
        for (int kx = 0; kx < 3; kx++) {
            int s = ky * 3 + kx;               // weight-texture index
            int soff = (ky * 9 + kx) * 36;     // spatial shift (9-col pitch)
            #pragma unroll
            for (int kk = 0; kk < 4; kk++) {
                int kb = kk * 8;
                unsigned ah[2][4], al[2][4];
                #pragma unroll
                for (int mi = 0; mi < 2; mi++) {
                    split_tf32(xin[rb[mi][0] + soff + kb + tig],     ah[mi][0], al[mi][0]);
                    split_tf32(xin[rb[mi][1] + soff + kb + tig],     ah[mi][1], al[mi][1]);
                    split_tf32(xin[rb[mi][0] + soff + kb + tig + 4], ah[mi][2], al[mi][2]);
                    split_tf32(xin[rb[mi][1] + soff + kb + tig + 4], ah[mi][3], al[mi][3]);
                }
                #pragma unroll
                for (int ni = 0; ni < 4; ni++) {
                    int oct = nh * 4 + ni;
                    float2 bw = __ldg(wf + (size_t)s * 1024 + kk * 256 + oct * 32 + lane);
                    unsigned bh0, bl0, bh1, bl1;
                    split_tf32(bw.x, bh0, bl0);
                    split_tf32(bw.y, bh1, bl1);
                    mma3(acc[0][ni], ah[0], al[0], bh0, bh1, bl0, bl1);
                    mma3(acc[1][ni], ah[1], al[1], bh0, bh1, bl0, bl1);
                }
            }
        }
    }

    #pragma unroll
    for (int mi = 0; mi < 2; mi++) {
        int rlo = rbase + mi * 16 + grp, rhi = rlo + 8;
        #pragma unroll
        for (int ni = 0; ni < 4; ni++) {
            int c0 = nh * 32 + ni * 8 + tig * 2;
            rs[rlo * 68 + c0]     = fmaxf(acc[mi][ni][0], 0.f);
            rs[rlo * 68 + c0 + 1] = fmaxf(acc[mi][ni][1], 0.f);
            rs[rhi * 68 + c0]     = fmaxf(acc[mi][ni][2], 0.f);
            rs[rhi * 68 + c0 + 1] = fmaxf(acc[mi][ni][3], 0.f);
        }
    }
    __syncthreads();

    float acc2[2][2][4];
    #pragma unroll
    for (int mi = 0; mi < 2; mi++)
        #pragma unroll
        for (int ni = 0; ni < 2; ni++)
            #pragma unroll
            for (int c = 0; c < 4; c++) acc2[mi][ni][c] = 0.f;

    #pragma unroll
    for (int kk = 0; kk < 8; kk++) {
        int kb = kk * 8;
        unsigned ah[2][4], al[2][4];
        #pragma unroll
        for (int mi = 0; mi < 2; mi++) {
            int rlo = rbase + mi * 16 + grp;
            split_tf32(rs[rlo * 68 + kb + tig],           ah[mi][0], al[mi][0]);
            split_tf32(rs[(rlo + 8) * 68 + kb + tig],     ah[mi][1], al[mi][1]);
            split_tf32(rs[rlo * 68 + kb + tig + 4],       ah[mi][2], al[mi][2]);
            split_tf32(rs[(rlo + 8) * 68 + kb + tig + 4], ah[mi][3], al[mi][3]);
        }
        #pragma unroll
        for (int ni = 0; ni < 2; ni++) {
            int c = nh * 16 + ni * 8 + grp;
            unsigned bh0, bl0, bh1, bl1;
            split_tf32(w2s[(kb + tig) * 36 + c],     bh0, bl0);
            split_tf32(w2s[(kb + tig + 4) * 36 + c], bh1, bl1);
            mma3(acc2[0][ni], ah[0], al[0], bh0, bh1, bl0, bl1);
            mma3(acc2[1][ni], ah[1], al[1], bh0, bh1, bl0, bl1);
        }
    }

    #pragma unroll
    for (int mi = 0; mi < 2; mi++) {
        #pragma unroll
        for (int ni = 0; ni < 2; ni++) {
            #pragma unroll
            for (int ci = 0; ci < 4; ci++) {
                int p = mh * 32 + mi * 16 + grp + ((ci >= 2) ? 8 : 0);
                if (p < 49) {
                    int ch = nh * 16 + ni * 8 + tig * 2 + (ci & 1);
                    size_t g = (size_t)(b0 + img) * 1568 + ch * 49 + p;
                    float v = acc2[mi][ni][ci] + __ldg(buf + g);
                    buf[g] = fmaxf(v, 0.f);
                }
            }
        }
    }
}

// ======================================================================
// res stack single-TF32 (decoder): weights via fragment-texture LDG
// smem = xin + rs + w2 = 65 KB -> 3 CTA/SM
// ======================================================================
#define D3_RS   5346
#define D3_W2   14050
#define D3_TOT  16354
#define D3_SMEM (D3_TOT * 4)     // 65416 B

__global__ void __launch_bounds__(256) res_tcd(
        float* __restrict__ buf,
        const float2* __restrict__ wf,
        const float* __restrict__ pw2) {
    extern __shared__ float sm[];
    float* xin = sm;
    float* rs  = sm + D3_RS;
    float* w2s = sm + D3_W2;
    int t = threadIdx.x;
    int b0 = blockIdx.x * 2;

    for (int i = t; i < D3_RS; i += 256) xin[i] = 0.f;
    __syncthreads();
    for (int i = t; i < 2048; i += 256) {
        int oc = i >> 6, ic = i & 63;
        w2s[ic * 36 + oc] = to_tf32(pw2[i]);
    }
    for (int i = t; i < 2 * 1568; i += 256) {
        int img = i / 1568, j = i % 1568;
        int ch = j / 49, p = j % 49;
        float v = buf[(size_t)(b0 + img) * 1568 + j];
        xin[img * 2673 + ((p / 7 + 1) * 9 + (p % 7 + 1)) * 33 + ch] =
            to_tf32(fmaxf(v, 0.f));
    }
    __syncthreads();

    int lane = t & 31, wrp = t >> 5;
    int grp = lane >> 2, tig = lane & 3;
    int img = wrp >> 2, mh = (wrp >> 1) & 1, nh = wrp & 1;
    int rbase = img * 64 + mh * 32;

    int rb[2][2];
    #pragma unroll
    for (int mi = 0; mi < 2; mi++)
        #pragma unroll
        for (int h = 0; h < 2; h++) {
            int p = mh * 32 + mi * 16 + grp + h * 8;
            rb[mi][h] = (p < 49) ? img * 2673 + ((p / 7) * 9 + (p % 7)) * 33 : 0;
        }

    float acc[2][4][4];
    #pragma unroll
    for (int mi = 0; mi < 2; mi++)
        #pragma unroll
        for (int ni = 0; ni < 4; ni++)
            #pragma unroll
            for (int c = 0; c < 4; c++) acc[mi][ni][c] = 0.f;

    #pragma unroll
    for (int ky = 0; ky < 3; ky++) {
        #pragma unroll
        for (int kx = 0; kx < 3; kx++) {
            int s = ky * 3 + kx;               // weight-texture index
            int soff = (ky * 9 + kx) * 33;     // spatial shift (9-col pitch)
            #pragma unroll
            for (int kk = 0; kk < 4; kk++) {
                int kb = kk * 8;
                unsigned a[2][4];
                #pragma unroll
                for (int mi = 0; mi < 2; mi++) {
                    a[mi][0] = __float_as_uint(xin[rb[mi][0] + soff + kb + tig]);
                    a[mi][1] = __float_as_uint(xin[rb[mi][1] + soff + kb + tig]);
                    a[mi][2] = __float_as_uint(xin[rb[mi][0] + soff + kb + tig + 4]);
                    a[mi][3] = __float_as_uint(xin[rb[mi][1] + soff + kb + tig + 4]);
                }
                #pragma unroll
                for (int ni = 0; ni < 4; ni++) {
                    int oct = nh * 4 + ni;
                    float2 bw = __ldg(wf + (size_t)s * 1024 + kk * 256 + oct * 32 + lane);
                    unsigned bb0 = __float_as_uint(bw.x);
                    unsigned bb1 = __float_as_uint(bw.y);
                    mma_tf32(acc[0][ni], a[0], bb0, bb1);
                    mma_tf32(acc[1][ni], a[1], bb0, bb1);
                }
            }
        }
    }

    #pragma unroll
    for (int mi = 0; mi < 2; mi++) {
        int rlo = rbase + mi * 16 + grp, rhi = rlo + 8;
        #pragma unroll
        for (int ni = 0; ni < 4; ni++) {
            int c0 = nh * 32 + ni * 8 + tig * 2;
            rs[rlo * 68 + c0]     = to_tf32(fmaxf(acc[mi][ni][0], 0.f));
            rs[rlo * 68 + c0 + 1] = to_tf32(fmaxf(acc[mi][ni][1], 0.f));
            rs[rhi * 68 + c0]     = to_tf32(fmaxf(acc[mi][ni][2], 0.f));
            rs[rhi * 68 + c0 + 1] = to_tf32(fmaxf(acc[mi][ni][3], 0.f));
        }
    }
    __syncthreads();

    float acc2[2][2][4];
    #pragma unroll
    for (int mi = 0; mi < 2; mi++)
        #pragma unroll
        for (int ni = 0; ni < 2; ni++)
            #pragma unroll
            for (int c = 0; c < 4; c++) acc2[mi][ni][c] = 0.f;

    #pragma unroll
    for (int kk = 0; kk < 8; kk++) {
        int kb = kk * 8;
        unsigned a[2][4];
        #pragma unroll
        for (int mi = 0; mi < 2; mi++) {
            int rlo = rbase + mi * 16 + grp;
            a[mi][0] = __float_as_uint(rs[rlo * 68 + kb + tig]);
            a[mi][1] = __float_as_uint(rs[(rlo + 8) * 68 + kb + tig]);
            a[mi][2] = __float_as_uint(rs[rlo * 68 + kb + tig + 4]);
            a[mi][3] = __float_as_uint(rs[(rlo + 8) * 68 + kb + tig + 4]);
        }
        #pragma unroll
        for (int ni = 0; ni < 2; ni++) {
            int c = nh * 16 + ni * 8 + grp;
            unsigned bb0 = __float_as_uint(w2s[(kb + tig) * 36 + c]);
            unsigned bb1 = __float_as_uint(w2s[(kb + tig + 4) * 36 + c]);
            mma_tf32(acc2[0][ni], a[0], bb0, bb1);
            mma_tf32(acc2[1][ni], a[1], bb0, bb1);
        }
    }

    #pragma unroll
    for (int mi = 0; mi < 2; mi++) {
        #pragma unroll
        for (int ni = 0; ni < 2; ni++) {
            #pragma unroll
            for (int ci = 0; ci < 4; ci++) {
                int p = mh * 32 + mi * 16 + grp + ((ci >= 2) ? 8 : 0);
                if (p < 49) {
                    int ch = nh * 16 + ni * 8 + tig * 2 + (ci & 1);
                    size_t g = (size_t)(b0 + img) * 1568 + ch * 49 + p;
                    float v = acc2[mi][ni][ci] + __ldg(buf + g);
                    buf[g] = fmaxf(v, 0.f);
                }
            }
        }
    }
}

// ======================================================================
// TF32 GEMM (decoder fc4) with register-prefetch pipelining  [round-7]
// ======================================================================
__global__ void __launch_bounds__(256) gemm_tc(
        const float* __restrict__ A,
        const float* __restrict__ W,
        const float* __restrict__ bias,
        float* __restrict__ C,
        int M, int N, int K) {
    __shared__ float As[128][17];
    __shared__ float Ws[64][17];
    int t = threadIdx.x, lane = t & 31, w = t >> 5;
    int grp = lane >> 2, tig = lane & 3;
    int m0 = blockIdx.x * 128, n0 = blockIdx.y * 64;
    int mw = (w & 3) * 32, nw = (w >> 2) * 32;
    float acc[2][4][4];
    #pragma unroll
    for (int mi = 0; mi < 2; mi++)
        #pragma unroll
        for (int ni = 0; ni < 4; ni++)
            #pragma unroll
            for (int c = 0; c < 4; c++) acc[mi][ni][c] = 0.f;

    int ar = t >> 1, ak = (t & 1) * 8;
    int wr = t >> 2, wk = (t & 3) * 4;
    const float* apb = A + (size_t)(m0 + ar) * K + ak;
    bool wval = (n0 + wr < N);
    const float* wpb = W + (size_t)(n0 + wr) * K + wk;

    float4 v0 = *(const float4*)apb;
    float4 v1 = *(const float4*)(apb + 4);
    float4 wv = wval ? *(const float4*)wpb : make_float4(0.f, 0.f, 0.f, 0.f);

    for (int k0 = 0; k0 < K; k0 += 16) {
        As[ar][ak + 0] = to_tf32(v0.x); As[ar][ak + 1] = to_tf32(v0.y);
        As[ar][ak + 2] = to_tf32(v0.z); As[ar][ak + 3] = to_tf32(v0.w);
        As[ar][ak + 4] = to_tf32(v1.x); As[ar][ak + 5] = to_tf32(v1.y);
        As[ar][ak + 6] = to_tf32(v1.z); As[ar][ak + 7] = to_tf32(v1.w);
        Ws[wr][wk + 0] = to_tf32(wv.x); Ws[wr][wk + 1] = to_tf32(wv.y);
        Ws[wr][wk + 2] = to_tf32(wv.z); Ws[wr][wk + 3] = to_tf32(wv.w);
        __syncthreads();
        if (k0 + 16 < K) {
            v0 = *(const float4*)(apb + k0 + 16);
            v1 = *(const float4*)(apb + k0 + 20);
            wv = wval ? *(const float4*)(wpb + k0 + 16)
                      : make_float4(0.f, 0.f, 0.f, 0.f);
        }
        #pragma unroll
        for (int kk = 0; kk < 2; kk++) {
            int kb = kk * 8;
            unsigned a[2][4];
            #pragma unroll
            for (int mi = 0; mi < 2; mi++) {
                int r = mw + mi * 16 + grp;
                a[mi][0] = __float_as_uint(As[r][kb + tig]);
                a[mi][1] = __float_as_uint(As[r + 8][kb + tig]);
                a[mi][2] = __float_as_uint(As[r][kb + tig + 4]);
                a[mi][3] = __float_as_uint(As[r + 8][kb + tig + 4]);
            }
            #pragma unroll
            for (int ni = 0; ni < 4; ni++) {
                int n = nw + ni * 8 + grp;
                unsigned bb0 = __float_as_uint(Ws[n][kb + tig]);
                unsigned bb1 = __float_as_uint(Ws[n][kb + tig + 4]);
                mma_tf32(acc[0][ni], a[0], bb0, bb1);
                mma_tf32(acc[1][ni], a[1], bb0, bb1);
            }
        }
        __syncthreads();
    }
    #pragma unroll
    for (int mi = 0; mi < 2; mi++) {
        #pragma unroll
        for (int ni = 0; ni < 4; ni++) {
            #pragma unroll
            for (int ci = 0; ci < 4; ci++) {
                int r = m0 + mw + mi * 16 + grp + ((ci >= 2) ? 8 : 0);
                int n = n0 + nw + ni * 8 + tig * 2 + (ci & 1);
                if (n < N)
                    C[(size_t)r * N + n] = fmaxf(acc[mi][ni][ci] + bias[n], 0.f);
            }
        }
    }
}

// ======================================================================
// 3xTF32 GEMM (encoder fc1) with register-prefetch pipelining [round-8]
// ======================================================================
__global__ void __launch_bounds__(256) gemm_tc3(
        const float* __restrict__ A,
        const float* __restrict__ W,
        const float* __restrict__ bias,
        float* __restrict__ C,
        int M, int N, int K) {
    __shared__ float As[128][17];
    __shared__ float Ws[64][17];
    int t = threadIdx.x, lane = t & 31, w = t >> 5;
    int grp = lane >> 2, tig = lane & 3;
    int m0 = blockIdx.x * 128, n0 = blockIdx.y * 64;
    int mw = (w & 3) * 32, nw = (w >> 2) * 32;
    float acc[2][4][4];
    #pragma unroll
    for (int mi = 0; mi < 2; mi++)
        #pragma unroll
        for (int ni = 0; ni < 4; ni++)
            #pragma unroll
            for (int c = 0; c < 4; c++) acc[mi][ni][c] = 0.f;

    int ar = t >> 1, ak = (t & 1) * 8;
    int wr = t >> 2, wk = (t & 3) * 4;
    const float* apb = A + (size_t)(m0 + ar) * K + ak;
    bool wval = (n0 + wr < N);
    const float* wpb = W + (size_t)(n0 + wr) * K + wk;

    float4 v0 = *(const float4*)apb;
    float4 v1 = *(const float4*)(apb + 4);
    float4 wv = wval ? *(const float4*)wpb : make_float4(0.f, 0.f, 0.f, 0.f);

    for (int k0 = 0; k0 < K; k0 += 16) {
        As[ar][ak + 0] = v0.x; As[ar][ak + 1] = v0.y;
        As[ar][ak + 2] = v0.z; As[ar][ak + 3] = v0.w;
        As[ar][ak + 4] = v1.x; As[ar][ak + 5] = v1.y;
        As[ar][ak + 6] = v1.z; As[ar][ak + 7] = v1.w;
        Ws[wr][wk + 0] = wv.x; Ws[wr][wk + 1] = wv.y;
        Ws[wr][wk + 2] = wv.z; Ws[wr][wk + 3] = wv.w;
        __syncthreads();
        if (k0 + 16 < K) {
            v0 = *(const float4*)(apb + k0 + 16);
            v1 = *(const float4*)(apb + k0 + 20);
            wv = wval ? *(const float4*)(wpb + k0 + 16)
                      : make_float4(0.f, 0.f, 0.f, 0.f);
        }
        #pragma unroll
        for (int kk = 0; kk < 2; kk++) {
            int kb = kk * 8;
            unsigned ah[2][4], al[2][4];
            #pragma unroll
            for (int mi = 0; mi < 2; mi++) {
                int r = mw + mi * 16 + grp;
                split_tf32(As[r][kb + tig],         ah[mi][0], al[mi][0]);
                split_tf32(As[r + 8][kb + tig],     ah[mi][1], al[mi][1]);
                split_tf32(As[r][kb + tig + 4],     ah[mi][2], al[mi][2]);
                split_tf32(As[r + 8][kb + tig + 4], ah[mi][3], al[mi][3]);
            }
            #pragma unroll
            for (int ni = 0; ni < 4; ni++) {
                int n = nw + ni * 8 + grp;
                unsigned bh0, bl0, bh1, bl1;
                split_tf32(Ws[n][kb + tig],     bh0, bl0);
                split_tf32(Ws[n][kb + tig + 4], bh1, bl1);
                mma3(acc[0][ni], ah[0], al[0], bh0, bh1, bl0, bl1);
                mma3(acc[1][ni], ah[1], al[1], bh0, bh1, bl0, bl1);
            }
        }
        __syncthreads();
    }
    #pragma unroll
    for (int mi = 0; mi < 2; mi++) {
        #pragma unroll
        for (int ni = 0; ni < 4; ni++) {
            #pragma unroll
            for (int ci = 0; ci < 4; ci++) {
                int r = m0 + mw + mi * 16 + grp + ((ci >= 2) ? 8 : 0);
                int n = n0 + nw + ni * 8 + tig * 2 + (ci & 1);
                if (n < N)
                    C[(size_t)r * N + n] = fmaxf(acc[mi][ni][ci] + bias[n], 0.f);
            }
        }
    }
}

// ======================================================================
// convt1 single-TF32 (decoder)                                [round-4]
// ======================================================================
#define T1_IMSZ 2916
#define T1_ZB   6240
#define T1_XIN  6664
#define T1_WOFF T1_XIN
#define T1_WSZ  (16 * 32 * 24)
#define T1_SMEM ((T1_XIN + T1_WSZ) * 4)

__global__ void __launch_bounds__(256) convt1_tc(
        const float* __restrict__ in,
        const float* __restrict__ w,
        const float* __restrict__ bias,
        float* __restrict__ out) {
    extern __shared__ float sm[];
    float* xin = sm;
    float* wt  = sm + T1_WOFF;
    int t = threadIdx.x;
    int b0 = blockIdx.x * 2;

    for (int i = t; i < T1_XIN; i += 256) xin[i] = 0.f;
    __syncthreads();
    for (int i = t; i < 2 * 1568; i += 256) {
        int img = i / 1568, j = i % 1568;
        int ic = j / 49, p = j % 49, iy = p / 7, ix = p % 7;
        xin[img * T1_IMSZ + ((iy + 1) * 9 + (ix + 1)) * 36 + ic] =
            to_tf32(in[(size_t)(b0 + img) * 1568 + j]);
    }
    for (int i = t; i < 32 * 256; i += 256) {
        int ic = i / 256, r = i % 256, oc = r / 16, s = r % 16;
        wt[s * 768 + ic * 24 + oc] = to_tf32(w[i]);
    }
    __syncthreads();

    int lane = t & 31, wrp = t >> 5;
    int grp = lane >> 2, tig = lane & 3;
    int img = wrp >> 2, ph = wrp & 3;
    int a = ph >> 1, bp = ph & 1;
    int dyv[2], kyv[2], dxv[2], kxv[2];
    if (a == 0) { dyv[0] = 0; kyv[0] = 1; dyv[1] = -1; kyv[1] = 3; }
    else        { dyv[0] = 1; kyv[0] = 0; dyv[1] =  0; kyv[1] = 2; }
    if (bp == 0) { dxv[0] = 0; kxv[0] = 1; dxv[1] = -1; kxv[1] = 3; }
    else         { dxv[0] = 1; kxv[0] = 0; dxv[1] =  0; kxv[1] = 2; }

    int rb[4][2];
    #pragma unroll
    for (int mi = 0; mi < 4; mi++)
        #pragma unroll
        for (int h = 0; h < 2; h++) {
            int p = mi * 16 + grp + h * 8;
            rb[mi][h] = (p < 49)
                ? img * T1_IMSZ + ((p / 7 + 1) * 9 + (p % 7 + 1)) * 36
                : T1_ZB;
        }

    float acc[4][2][4];
    #pragma unroll
    for (int mi = 0; mi < 4; mi++)
        #pragma unroll
        for (int ni = 0; ni < 2; ni++)
            #pragma unroll
            for (int c = 0; c < 4; c++) acc[mi][ni][c] = 0.f;

    #pragma unroll
    for (int sy = 0; sy < 2; sy++) {
        #pragma unroll
        for (int sx = 0; sx < 2; sx++) {
            int soff = (dyv[sy] * 9 + dxv[sx]) * 36;
            const float* wsl = wt + (kyv[sy] * 4 + kxv[sx]) * 768;
            #pragma unroll
            for (int kk = 0; kk < 4; kk++) {
                int kb = kk * 8;
                unsigned afr[4][4];
                #pragma unroll
                for (int mi = 0; mi < 4; mi++) {
                    afr[mi][0] = __float_as_uint(xin[rb[mi][0] + soff + kb + tig]);
                    afr[mi][1] = __float_as_uint(xin[rb[mi][1] + soff + kb + tig]);
                    afr[mi][2] = __float_as_uint(xin[rb[mi][0] + soff + kb + tig + 4]);
                    afr[mi][3] = __float_as_uint(xin[rb[mi][1] + soff + kb + tig + 4]);
                }
                #pragma unroll
                for (int ni = 0; ni < 2; ni++) {
                    unsigned bb0 = __float_as_uint(wsl[(kb + tig) * 24 + ni * 8 + grp]);
                    unsigned bb1 = __float_as_uint(wsl[(kb + tig + 4) * 24 + ni * 8 + grp]);
                    #pragma unroll
                    for (int mi = 0; mi < 4; mi++)
                        mma_tf32(acc[mi][ni], afr[mi], bb0, bb1);
                }
            }
        }
    }

    #pragma unroll
    for (int mi = 0; mi < 4; mi++) {
        #pragma unroll
        for (int ni = 0; ni < 2; ni++) {
            #pragma unroll
            for (int ci = 0; ci < 4; ci++) {
                int p = mi * 16 + grp + ((ci >= 2) ? 8 : 0);
                if (p < 49) {
                    int m = p / 7, n = p % 7;
                    int oc = ni * 8 + tig * 2 + (ci & 1);
                    int oy = 2 * m + a, ox = 2 * n + bp;
                    float v = acc[mi][ni][ci] + __ldg(bias + oc);
                    out[(size_t)(b0 + img) * 3136 + oc * 196 + oy * 14 + ox] =
                        fmaxf(v, 0.f);
                }
            }
        }
    }
}

// ======================================================================
// fc2: z[B,32] = A[B,224] @ w^T + b  (fp32, feeds VQ)   [round-8]
// ======================================================================
__global__ void __launch_bounds__(256) fc2_kernel(
        const float* __restrict__ A,
        const float* __restrict__ w,
        const float* __restrict__ bias,
        float* __restrict__ out) {
    __shared__ float ws[32 * 224];
    int t = threadIdx.x;
    for (int i = t; i < 7168; i += 256) ws[i] = w[i];
    __syncthreads();
    int n = t & 31, r = t >> 5;
    float bv = bias[n];
    const float* wp = ws + n * 224;
    #pragma unroll
    for (int rr = 0; rr < 4; rr++) {
        int b = blockIdx.x * 32 + rr * 8 + r;
        const float* ap = A + (size_t)b * 224;
        float acc = bv;
        #pragma unroll 8
        for (int k = 0; k < 224; k++) acc += ap[k] * wp[k];
        out[(size_t)b * 32 + n] = acc;
    }
}

// ======================================================================
// VQ helpers (fp32 exact)
// ======================================================================
__global__ void enorm_kernel(const float* __restrict__ emb, float* __restrict__ enorm) {
    int e = blockIdx.x * blockDim.x + threadIdx.x;
    if (e < NE) {
        float s = 0.f;
        #pragma unroll
        for (int d = 0; d < ZD; d++) { float v = emb[e * ZD + d]; s += v * v; }
        enorm[e] = s;
    }
}

__global__ void zero_kernel(float* __restrict__ counts, float* __restrict__ sums,
                            float* __restrict__ loss) {
    int i = blockIdx.x * blockDim.x + threadIdx.x;
    if (i < NE) counts[i] = 0.f;
    if (i < NE * ZD) sums[i] = 0.f;
    if (i == 0) loss[0] = 0.f;
}

#define VQ_SMEM (NE * 36 * 4)

__global__ void __launch_bounds__(256) vq_kernel(
        const float* __restrict__ z,
        const float* __restrict__ emb,
        const float* __restrict__ enorm,
        int* __restrict__ idx,
        float* __restrict__ counts,
        float* __restrict__ sums,
        float* __restrict__ loss) {
    extern __shared__ float es[];          // [512][36]
    __shared__ float en[NE];
    __shared__ float zs[8][ZD];
    int t = threadIdx.x, lane = t & 31, wl = t >> 5;
    for (int i = t; i < NE * ZD; i += 256) {
        int e = i >> 5, d = i & 31;
        es[e * 36 + d] = emb[i];
    }
    for (int i = t; i < NE; i += 256) en[i] = enorm[i];
    __syncthreads();

    for (int rr = 0; rr < 8; rr++) {
        int row = blockIdx.x * 64 + wl * 8 + rr;
        zs[wl][lane] = z[(size_t)row * ZD + lane];
        __syncwarp();
        float best = 3.4e38f; int bi = NE;
        for (int e = lane; e < NE; e += 32) {
            const float* ep = es + e * 36;
            float dot = 0.f;
            #pragma unroll
            for (int d = 0; d < ZD; d += 4) {
                float4 v = *(const float4*)(ep + d);
                dot += zs[wl][d + 0] * v.x;
                dot += zs[wl][d + 1] * v.y;
                dot += zs[wl][d + 2] * v.z;
                dot += zs[wl][d + 3] * v.w;
            }
            float s = en[e] - 2.f * dot;
            if (s < best) { best = s; bi = e; }
        }
        #pragma unroll
        for (int off = 16; off; off >>= 1) {
            float ob = __shfl_xor_sync(0xffffffffu, best, off);
            int   oi = __shfl_xor_sync(0xffffffffu, bi, off);
            if (ob < best || (ob == best && oi < bi)) { best = ob; bi = oi; }
        }
        float zl = zs[wl][lane];
        float diff = es[bi * 36 + lane] - zl;
        float d2 = diff * diff;
        #pragma unroll
        for (int off = 16; off; off >>= 1)
            d2 += __shfl_xor_sync(0xffffffffu, d2, off);
        if (lane == 0) {
            idx[row] = bi;
            atomicAdd(&counts[bi], 1.f);
            atomicAdd(loss, d2);
        }
        atomicAdd(&sums[bi * ZD + lane], zl);
        __syncwarp();
    }
}

__global__ void embnew_kernel(const float* __restrict__ m_mat,
                              const float* __restrict__ n_mat,
                              const float* __restrict__ sums,
                              const float* __restrict__ counts,
                              float* __restrict__ out) {
    int i = blockIdx.x * blockDim.x + threadIdx.x;
    if (i < NE * ZD) {
        int e = i >> 5;
        float m = m_mat[i] * GAMMA + sums[i] * ONE_M_GAMMA;
        float n = n_mat[e] * GAMMA + counts[e] * ONE_M_GAMMA;
        out[i] = m / n;
    }
}

__global__ void finalize_kernel(const float* __restrict__ counts,
                                const float* __restrict__ loss,
                                float* __restrict__ out_scalars) {
    __shared__ float red[NE];
    int t = threadIdx.x;
    float c = counts[t];
    float em = c * (1.f / (float)BATCH);
    red[t] = em * logf(em + 1e-10f);
    __syncthreads();
    for (int s = 256; s; s >>= 1) {
        if (t < s) red[t] += red[t + s];
        __syncthreads();
    }
    if (t == 0) {
        float q = loss[0] * (1.f / ((float)BATCH * (float)ZD));
        out_scalars[0] = q;
        out_scalars[1] = BETA * q;
        out_scalars[2] = expf(-red[0]);
    }
}

// ======================================================================
// fc3 (fp32): 16 images/CTA                           [round-8, proven]
// ======================================================================
__global__ void __launch_bounds__(224) fc3_kernel(
        const float* __restrict__ emb,
        const int* __restrict__ idx,
        const float* __restrict__ w,
        const float* __restrict__ bias,
        float* __restrict__ out) {
    __shared__ float ws[224 * ZD];
    __shared__ float zq[16][ZD + 1];
    int b0 = blockIdx.x * 16, t = threadIdx.x;
    for (int i = t; i < 224 * ZD; i += 224) ws[i] = w[i];
    for (int i = t; i < 16 * ZD; i += 224) {
        int im = i >> 5, d = i & 31;
        zq[im][d] = emb[(size_t)idx[b0 + im] * ZD + d];
    }
    __syncthreads();
    float bv = bias[t];
    float wreg[ZD];
    const float* wp = ws + t * ZD;
    #pragma unroll
    for (int k = 0; k < ZD; k++) wreg[k] = wp[k];
    #pragma unroll 4
    for (int im = 0; im < 16; im++) {
        float acc = bv;
        #pragma unroll
        for (int k = 0; k < ZD; k++) acc += zq[im][k] * wreg[k];
        out[(size_t)(b0 + im) * 224 + t] = fmaxf(acc, 0.f);
    }
}

// ======================================================================
// convt2 phase-decomposed fp32                        [round-7, proven]
// ======================================================================
#define CT2_SMEM (4 * 4096 * 4)   // 65536 B

template<int DY0, int KY0, int DY1, int KY1,
         int DX0, int KX0, int DX1, int KX1>
__device__ __forceinline__ void ct2_body(
        const float* __restrict__ base, const float* __restrict__ w,
        float bv, float* __restrict__ outp, int m) {
    float acc[14];
    #pragma unroll
    for (int j = 0; j < 14; j++) acc[j] = bv;
    for (int ic = 0; ic < 16; ic++) {
        const float* xc = base + ic * 256;
        #pragma unroll
        for (int sy = 0; sy < 2; sy++) {
            int iy = m + (sy ? DY1 : DY0);
            float row[16];
            #pragma unroll
            for (int j = 0; j < 16; j++) row[j] = xc[(iy + 1) * 16 + j];
            {
                float wv = __ldg(w + ic * 16 + (sy ? KY1 : KY0) * 4 + KX0);
                #pragma unroll
                for (int n = 0; n < 14; n++) acc[n] += row[n + DX0 + 1] * wv;
            }
            {
                float wv = __ldg(w + ic * 16 + (sy ? KY1 : KY0) * 4 + KX1);
                #pragma unroll
                for (int n = 0; n < 14; n++) acc[n] += row[n + DX1 + 1] * wv;
            }
        }
    }
    #pragma unroll
    for (int n = 0; n < 14; n++) outp[2 * n] = acc[n];
}

__global__ void __launch_bounds__(256) convt2_tc(
        const float* __restrict__ in,
        const float* __restrict__ w,
        const float* __restrict__ bias,
        float* __restrict__ out) {
    extern __shared__ float xp[];
    int t = threadIdx.x;
    int b0 = blockIdx.x * 4;

    for (int i = t; i < 16384; i += 256) xp[i] = 0.f;
    __syncthreads();
    for (int i = t; i < 4 * 3136; i += 256) {
        int img = i / 3136, j = i % 3136;
        int ic = j / 196, p = j % 196, iy = p / 14, ix = p % 14;
        xp[img * 4096 + ic * 256 + (iy + 1) * 16 + (ix + 1)] =
            in[(size_t)(b0 + img) * 3136 + j];
    }
    __syncthreads();

    int ph = t >> 6, s = t & 63;
    if (s >= 56) return;
    int img = s / 14, m = s % 14;
    int a = ph >> 1, b = ph & 1;
    const float* base = xp + img * 4096;
    float bv = bias[0];
    float* outp = out + (size_t)(b0 + img) * 784 + (2 * m + a) * 28 + b;

    if (ph == 0)      ct2_body<0, 1, -1, 3,  0, 1, -1, 3>(base, w, bv, outp, m);
    else if (ph == 1) ct2_body<0, 1, -1, 3,  1, 0,  0, 2>(base, w, bv, outp, m);
    else if (ph == 2) ct2_body<1, 0,  0, 2,  0, 1, -1, 3>(base, w, bv, outp, m);
    else              ct2_body<1, 0,  0, 2,  1, 0,  0, 2>(base, w, bv, outp, m);
}

// ======================================================================
// launch
// ======================================================================
extern "C" void kernel_launch(void* const* d_in, const int* in_sizes, int n_in,
                              void* d_out, int out_size) {
    const float* x        = (const float*)d_in[0];
    const float* conv1_w  = (const float*)d_in[1];
    const float* conv1_b  = (const float*)d_in[2];
    const float* conv2_w  = (const float*)d_in[3];
    const float* conv2_b  = (const float*)d_in[4];
    const float* res1_w1  = (const float*)d_in[5];
    const float* res1_w2  = (const float*)d_in[6];
    const float* fc1_w    = (const float*)d_in[7];
    const float* fc1_b    = (const float*)d_in[8];
    const float* fc2_w    = (const float*)d_in[9];
    const float* fc2_b    = (const float*)d_in[10];
    const float* emb      = (const float*)d_in[11];
    const float* n_mat    = (const float*)d_in[12];
    const float* m_mat    = (const float*)d_in[13];
    const float* fc3_w    = (const float*)d_in[14];
    const float* fc3_b    = (const float*)d_in[15];
    const float* fc4_w    = (const float*)d_in[16];
    const float* fc4_b    = (const float*)d_in[17];
    const float* res2_w1  = (const float*)d_in[18];
    const float* res2_w2  = (const float*)d_in[19];
    const float* convt1_w = (const float*)d_in[20];
    const float* convt1_b = (const float*)d_in[21];
    const float* convt2_w = (const float*)d_in[22];
    const float* convt2_b = (const float*)d_in[23];
    float* out = (float*)d_out;

    float *h1, *h2, *a, *z, *enorm, *counts, *sums, *loss;
    int* idx;
    float2 *wf_r1, *wf_r2, *wf_c2;
    cudaGetSymbolAddress((void**)&h1,     g_h1);
    cudaGetSymbolAddress((void**)&h2,     g_h2);
    cudaGetSymbolAddress((void**)&a,      g_a);
    cudaGetSymbolAddress((void**)&z,      g_z);
    cudaGetSymbolAddress((void**)&idx,    g_idx);
    cudaGetSymbolAddress((void**)&enorm,  g_enorm);
    cudaGetSymbolAddress((void**)&counts, g_counts);
    cudaGetSymbolAddress((void**)&sums,   g_sums);
    cudaGetSymbolAddress((void**)&loss,   g_loss);
    cudaGetSymbolAddress((void**)&wf_r1,  g_wf_r1);
    cudaGetSymbolAddress((void**)&wf_r2,  g_wf_r2);
    cudaGetSymbolAddress((void**)&wf_c2,  g_wf_c2);

    cudaFuncSetAttribute(conv2_tc3,
                         cudaFuncAttributeMaxDynamicSharedMemorySize, C2B_SMEM);
    cudaFuncSetAttribute(res_tc3,
                         cudaFuncAttributeMaxDynamicSharedMemorySize, E3_SMEM);
    cudaFuncSetAttribute(res_tcd,
                         cudaFuncAttributeMaxDynamicSharedMemorySize, D3_SMEM);
    cudaFuncSetAttribute(convt1_tc,
                         cudaFuncAttributeMaxDynamicSharedMemorySize, T1_SMEM);
    cudaFuncSetAttribute(convt2_tc,
                         cudaFuncAttributeMaxDynamicSharedMemorySize, CT2_SMEM);
    cudaFuncSetAttribute(vq_kernel,
                         cudaFuncAttributeMaxDynamicSharedMemorySize, VQ_SMEM);

    // weight repack (fragment-order textures)
    repack_res<<<36, 256>>>(res1_w1, wf_r1, 0);
    repack_res<<<36, 256>>>(res2_w1, wf_r2, 1);
    repack_c2 <<<16, 256>>>(conv2_w, wf_c2);

    // encoder (3xTF32 = fp32-class accuracy; VQ path preserved)
    conv1_kernel<<<BATCH / 2, 224>>>(x, conv1_w, conv1_b, h1);
    conv2_tc3<<<BATCH / 2, 256, C2B_SMEM>>>(h1, wf_c2, conv2_b, h2);
    res_tc3  <<<BATCH / 2, 256, E3_SMEM>>>(h2, wf_r1, res1_w2);
    gemm_tc3<<<dim3(BATCH / 128, 4), 256>>>(h2, fc1_w, fc1_b, a,
                                            BATCH, 224, 1568);
    fc2_kernel<<<BATCH / 32, 256>>>(a, fc2_w, fc2_b, z);

    // VQ
    zero_kernel <<<(NE * ZD + 255) / 256, 256>>>(counts, sums, loss);
    enorm_kernel<<<2, 256>>>(emb, enorm);
    vq_kernel   <<<BATCH / 64, 256, VQ_SMEM>>>(z, emb, enorm, idx, counts,
                                               sums, loss);
    embnew_kernel  <<<(NE * ZD + 255) / 256, 256>>>(m_mat, n_mat, sums, counts,
                                                    out + OFF_SCAL + 3);
    finalize_kernel<<<1, NE>>>(counts, loss, out + OFF_SCAL);

    // decoder (single tf32)
    fc3_kernel<<<BATCH / 16, 224>>>(emb, idx, fc3_w, fc3_b, a);
    gemm_tc<<<dim3(BATCH / 128, 25), 256>>>(a, fc4_w, fc4_b, h2,
                                            BATCH, 1568, 224);
    res_tcd<<<BATCH / 2, 256, D3_SMEM>>>(h2, wf_r2, res2_w2);
    convt1_tc<<<BATCH / 2, 256, T1_SMEM>>>(h2, convt1_w, convt1_b, h1);
    convt2_tc<<<BATCH / 4, 256, CT2_SMEM>>>(h1, convt2_w, convt2_b, out);
}

// round 11
// speedup vs baseline: 2.3073x; 1.0088x over previous
#include <cuda_runtime.h>
#include <cstdint>
#include <math.h>

// ---------------- problem constants ----------------
#define BATCH 16384
#define ZD 32
#define NE 512
#define GAMMA 0.99f
#define ONE_M_GAMMA 0.01f
#define BETA 1.0f

#define OFF_SCAL (BATCH * 784)   // x_rec size
// d_out layout: [x_rec (B*784)][quant][commit][perplexity][emb_new (512*32)]

// ---------------- scratch ----------------
__device__ float g_h1[BATCH * 16 * 14 * 14];
__device__ float g_h2[BATCH * 32 * 7 * 7];
__device__ float g_a [BATCH * 224];
__device__ float g_z [BATCH * ZD];
__device__ int   g_idx[BATCH];
__device__ float g_enorm[NE];
__device__ float g_counts[NE];
__device__ float g_sums[NE * ZD];
__device__ float g_loss[1];
// fragment-order weight textures: [s][kk][oct][lane] -> (b0,b1)
__device__ float2 g_wf_r1[9216];   // res1 w1 (raw fp32)
__device__ float2 g_wf_r2[9216];   // res2 w1 (tf32)
__device__ float2 g_wf_c2[4096];   // conv2 w  (raw fp32)

// ---------------- tf32 mma helpers ----------------
__device__ __forceinline__ float to_tf32(float x) {
    float y;
    asm("cvt.rna.tf32.f32 %0, %1;" : "=f"(y) : "f"(x));
    return y;
}

// Bitwise hi/lo split: hi = RZ-truncated tf32 (LOP3), lo = v - hi (exact FADD).
__device__ __forceinline__ void split_tf32(float v, unsigned& hi, unsigned& lo) {
    unsigned h = __float_as_uint(v) & 0xffffe000u;
    hi = h;
    lo = __float_as_uint(v - __uint_as_float(h));
}

__device__ __forceinline__ void mma_tf32(float* d, const unsigned* a,
                                         unsigned b0, unsigned b1) {
    asm volatile(
        "mma.sync.aligned.m16n8k8.row.col.f32.tf32.tf32.f32 "
        "{%0,%1,%2,%3}, {%4,%5,%6,%7}, {%8,%9}, {%0,%1,%2,%3};\n"
        : "+f"(d[0]), "+f"(d[1]), "+f"(d[2]), "+f"(d[3])
        : "r"(a[0]), "r"(a[1]), "r"(a[2]), "r"(a[3]), "r"(b0), "r"(b1));
}

// 3-pass split mma: acc += a*b with ~fp32 accuracy
__device__ __forceinline__ void mma3(float* d, const unsigned* ah, const unsigned* al,
                                     unsigned bh0, unsigned bh1,
                                     unsigned bl0, unsigned bl1) {
    mma_tf32(d, ah, bl0, bl1);
    mma_tf32(d, al, bh0, bh1);
    mma_tf32(d, ah, bh0, bh1);
}

// ======================================================================
// weight repack kernels (run once per launch; tiny)
// ======================================================================
__global__ void repack_res(const float* __restrict__ w1,
                           float2* __restrict__ out, int cvt) {
    int i = blockIdx.x * 256 + threadIdx.x;
    if (i >= 9216) return;
    int lane = i & 31, oct = (i >> 5) & 7, kk = (i >> 8) & 3, s = i >> 10;
    int grp = lane >> 2, tig = lane & 3;
    int oc = oct * 8 + grp, ic = kk * 8 + tig;
    float b0 = w1[oc * 288 + ic * 9 + s];
    float b1 = w1[oc * 288 + (ic + 4) * 9 + s];
    if (cvt) { b0 = to_tf32(b0); b1 = to_tf32(b1); }
    out[i] = make_float2(b0, b1);
}

__global__ void repack_c2(const float* __restrict__ w,
                          float2* __restrict__ out) {
    int i = blockIdx.x * 256 + threadIdx.x;
    if (i >= 4096) return;
    int lane = i & 31, oct = (i >> 5) & 3, kk = (i >> 7) & 1, s = i >> 8;
    int grp = lane >> 2, tig = lane & 3;
    int oc = oct * 8 + grp, ic = kk * 8 + tig;
    out[i] = make_float2(w[oc * 256 + ic * 16 + s],
                         w[oc * 256 + (ic + 4) * 16 + s]);
}

// ======================================================================
// conv1: x[B,1,28,28] -> relu -> h1[B,16,14,14]   (k4 s2 p1)  fp32
// NEW: thread = (img, pixel), computes ALL 16 oc. Patch shared across oc:
// 16 LDS feed 256 FMAs. 2 img/CTA, 448 thr, ~40 regs -> high occupancy.
// Tap order (ky,kx) ascending == old kernel -> bit-identical output.
// ======================================================================
__global__ void __launch_bounds__(448) conv1_kernel(
        const float* __restrict__ x,
        const float* __restrict__ w,
        const float* __restrict__ bias,
        float* __restrict__ out) {
    __shared__ float xp[2 * 900];   // [im][30][30], halo of 1
    __shared__ float ws[256];
    __shared__ float bs[16];
    int b0 = blockIdx.x * 2, t = threadIdx.x;
    for (int i = t; i < 1800; i += 448) xp[i] = 0.f;
    if (t < 256) ws[t] = w[t];
    if (t < 16)  bs[t] = bias[t];
    __syncthreads();
    for (int i = t; i < 1568; i += 448) {
        int im = i / 784, j = i % 784;
        int iy = j / 28, ix = j % 28;
        xp[im * 900 + (iy + 1) * 30 + (ix + 1)] = x[(size_t)(b0 + im) * 784 + j];
    }
    __syncthreads();
    if (t >= 392) return;
    int im = t / 196, pix = t % 196;
    int oy = pix / 14, ox = pix % 14;
    // padded top-left: row = 2*oy (since iy=2*oy-1+ky -> padded 2*oy+ky), col = 2*ox
    const float* base = xp + im * 900 + (2 * oy) * 30 + 2 * ox;
    float patch[16];
    #pragma unroll
    for (int ky = 0; ky < 4; ky++)
        #pragma unroll
        for (int kx = 0; kx < 4; kx++)
            patch[ky * 4 + kx] = base[ky * 30 + kx];
    float acc[16];
    #pragma unroll
    for (int oc = 0; oc < 16; oc++) acc[oc] = bs[oc];
    #pragma unroll
    for (int tap = 0; tap < 16; tap++) {
        float v = patch[tap];
        #pragma unroll
        for (int oc = 0; oc < 16; oc++)
            acc[oc] += v * ws[oc * 16 + tap];
    }
    float* op = out + (size_t)(b0 + im) * 3136 + pix;
    #pragma unroll
    for (int oc = 0; oc < 16; oc++)
        op[oc * 196] = fmaxf(acc[oc], 0.f);
}

// ======================================================================
// conv2 3xTF32 shift-GEMM: weights via fragment-texture LDG  [round-10]
// ======================================================================
#define C2B_ZOFF 9216
#define C2B_XIN  13824
#define C2B_SMEM (C2B_XIN * 4)   // 55296 B

__global__ void __launch_bounds__(256) conv2_tc3(
        const float* __restrict__ in,
        const float2* __restrict__ wf,
        const float* __restrict__ bias,
        float* __restrict__ out) {
    extern __shared__ float sm[];
    float* xin = sm;
    int t = threadIdx.x;
    int b0 = blockIdx.x * 2;

    for (int i = t; i < C2B_XIN; i += 256) xin[i] = 0.f;
    __syncthreads();
    for (int i = t; i < 2 * 3136; i += 256) {
        int img = i / 3136, j = i % 3136;
        int ic = j / 196, p = j % 196, iy = p / 14, ix = p % 14;
        xin[img * 4608 + ((iy + 1) * 16 + (ix + 1)) * 18 + ic] =
            in[(size_t)(b0 + img) * 3136 + j];
    }
    __syncthreads();

    int lane = t & 31, wrp = t >> 5;
    int grp = lane >> 2, tig = lane & 3;
    int img = wrp >> 2, mh = (wrp >> 1) & 1, nh = wrp & 1;

    int rb[2][2];
    #pragma unroll
    for (int mi = 0; mi < 2; mi++)
        #pragma unroll
        for (int h = 0; h < 2; h++) {
            int p = mh * 32 + mi * 16 + grp + h * 8;
            rb[mi][h] = (p < 49)
                ? img * 4608 + ((p / 7) * 32 + (p % 7) * 2) * 18
                : C2B_ZOFF;
        }

    float acc[2][2][4];
    #pragma unroll
    for (int mi = 0; mi < 2; mi++)
        #pragma unroll
        for (int ni = 0; ni < 2; ni++)
            #pragma unroll
            for (int c = 0; c < 4; c++) acc[mi][ni][c] = 0.f;

    #pragma unroll
    for (int ky = 0; ky < 4; ky++) {
        #pragma unroll
        for (int kx = 0; kx < 4; kx++) {
            int s = ky * 4 + kx;
            int soff = (ky * 16 + kx) * 18;
            #pragma unroll
            for (int kk = 0; kk < 2; kk++) {
                int kb = kk * 8;
                unsigned ah[2][4], al[2][4];
                #pragma unroll
                for (int mi = 0; mi < 2; mi++) {
                    split_tf32(xin[rb[mi][0] + soff + kb + tig],     ah[mi][0], al[mi][0]);
                    split_tf32(xin[rb[mi][1] + soff + kb + tig],     ah[mi][1], al[mi][1]);
                    split_tf32(xin[rb[mi][0] + soff + kb + tig + 4], ah[mi][2], al[mi][2]);
                    split_tf32(xin[rb[mi][1] + soff + kb + tig + 4], ah[mi][3], al[mi][3]);
                }
                #pragma unroll
                for (int ni = 0; ni < 2; ni++) {
                    int oct = nh * 2 + ni;
                    float2 bw = __ldg(wf + (size_t)s * 256 + kk * 128 + oct * 32 + lane);
                    unsigned bh0, bl0, bh1, bl1;
                    split_tf32(bw.x, bh0, bl0);
                    split_tf32(bw.y, bh1, bl1);
                    mma3(acc[0][ni], ah[0], al[0], bh0, bh1, bl0, bl1);
                    mma3(acc[1][ni], ah[1], al[1], bh0, bh1, bl0, bl1);
                }
            }
        }
    }

    #pragma unroll
    for (int mi = 0; mi < 2; mi++) {
        #pragma unroll
        for (int ni = 0; ni < 2; ni++) {
            #pragma unroll
            for (int ci = 0; ci < 4; ci++) {
                int p = mh * 32 + mi * 16 + grp + ((ci >= 2) ? 8 : 0);
                if (p < 49) {
                    int oc = nh * 16 + ni * 8 + tig * 2 + (ci & 1);
                    out[(size_t)(b0 + img) * 1568 + oc * 49 + p] =
                        acc[mi][ni][ci] + __ldg(bias + oc);
                }
            }
        }
    }
}

// ======================================================================
// res stack 3xTF32 (encoder): weights via fragment-texture  [round-10]
// ======================================================================
#define E3_RS   5832
#define E3_W2   14536
#define E3_TOT  16840
#define E3_SMEM (E3_TOT * 4)     // 67360 B

__global__ void __launch_bounds__(256) res_tc3(
        float* __restrict__ buf,
        const float2* __restrict__ wf,
        const float* __restrict__ pw2) {
    extern __shared__ float sm[];
    float* xin = sm;
    float* rs  = sm + E3_RS;
    float* w2s = sm + E3_W2;
    int t = threadIdx.x;
    int b0 = blockIdx.x * 2;

    for (int i = t; i < E3_RS; i += 256) xin[i] = 0.f;
    __syncthreads();
    for (int i = t; i < 2048; i += 256) {
        int oc = i >> 6, ic = i & 63;
        w2s[ic * 36 + oc] = pw2[i];
    }
    for (int i = t; i < 2 * 1568; i += 256) {
        int img = i / 1568, j = i % 1568;
        int ch = j / 49, p = j % 49;
        float v = buf[(size_t)(b0 + img) * 1568 + j];
        xin[img * 2916 + ((p / 7 + 1) * 9 + (p % 7 + 1)) * 36 + ch] = fmaxf(v, 0.f);
    }
    __syncthreads();

    int lane = t & 31, wrp = t >> 5;
    int grp = lane >> 2, tig = lane & 3;
    int img = wrp >> 2, mh = (wrp >> 1) & 1, nh = wrp & 1;
    int rbase = img * 64 + mh * 32;

    int rb[2][2];
    #pragma unroll
    for (int mi = 0; mi < 2; mi++)
        #pragma unroll
        for (int h = 0; h < 2; h++) {
            int p = mh * 32 + mi * 16 + grp + h * 8;
            rb[mi][h] = (p < 49) ? img * 2916 + ((p / 7) * 9 + (p % 7)) * 36 : 0;
        }

    float acc[2][4][4];
    #pragma unroll
    for (int mi = 0; mi < 2; mi++)
        #pragma unroll
        for (int ni = 0; ni < 4; ni++)
            #pragma unroll
            for (int c = 0; c < 4; c++) acc[mi][ni][c] = 0.f;

    #pragma unroll
    for (int ky = 0; ky < 3; ky++) {
        #pragma unroll
        for (int kx = 0; kx < 3; kx++) {
            int s = ky * 3 + kx;
            int soff = (ky * 9 + kx) * 36;
            #pragma unroll
            for (int kk = 0; kk < 4; kk++) {
                int kb = kk * 8;
                unsigned ah[2][4], al[2][4];
                #pragma unroll
                for (int mi = 0; mi < 2; mi++) {
                    split_tf32(xin[rb[mi][0] + soff + kb + tig],     ah[mi][0], al[mi][0]);
                    split_tf32(xin[rb[mi][1] + soff + kb + tig],     ah[mi][1], al[mi][1]);
                    split_tf32(xin[rb[mi][0] + soff + kb + tig + 4], ah[mi][2], al[mi][2]);
                    split_tf32(xin[rb[mi][1] + soff + kb + tig + 4], ah[mi][3], al[mi][3]);
                }
                #pragma unroll
                for (int ni = 0; ni < 4; ni++) {
                    int oct = nh * 4 + ni;
                    float2 bw = __ldg(wf + (size_t)s * 1024 + kk * 256 + oct * 32 + lane);
                    unsigned bh0, bl0, bh1, bl1;
                    split_tf32(bw.x, bh0, bl0);
                    split_tf32(bw.y, bh1, bl1);
                    mma3(acc[0][ni], ah[0], al[0], bh0, bh1, bl0, bl1);
                    mma3(acc[1][ni], ah[1], al[1], bh0, bh1, bl0, bl1);
                }
            }
        }
    }

    #pragma unroll
    for (int mi = 0; mi < 2; mi++) {
        int rlo = rbase + mi * 16 + grp, rhi = rlo + 8;
        #pragma unroll
        for (int ni = 0; ni < 4; ni++) {
            int c0 = nh * 32 + ni * 8 + tig * 2;
            rs[rlo * 68 + c0]     = fmaxf(acc[mi][ni][0], 0.f);
            rs[rlo * 68 + c0 + 1] = fmaxf(acc[mi][ni][1], 0.f);
            rs[rhi * 68 + c0]     = fmaxf(acc[mi][ni][2], 0.f);
            rs[rhi * 68 + c0 + 1] = fmaxf(acc[mi][ni][3], 0.f);
        }
    }
    __syncthreads();

    float acc2[2][2][4];
    #pragma unroll
    for (int mi = 0; mi < 2; mi++)
        #pragma unroll
        for (int ni = 0; ni < 2; ni++)
            #pragma unroll
            for (int c = 0; c < 4; c++) acc2[mi][ni][c] = 0.f;

    #pragma unroll
    for (int kk = 0; kk < 8; kk++) {
        int kb = kk * 8;
        unsigned ah[2][4], al[2][4];
        #pragma unroll
        for (int mi = 0; mi < 2; mi++) {
            int rlo = rbase + mi * 16 + grp;
            split_tf32(rs[rlo * 68 + kb + tig],           ah[mi][0], al[mi][0]);
            split_tf32(rs[(rlo + 8) * 68 + kb + tig],     ah[mi][1], al[mi][1]);
            split_tf32(rs[rlo * 68 + kb + tig + 4],       ah[mi][2], al[mi][2]);
            split_tf32(rs[(rlo + 8) * 68 + kb + tig + 4], ah[mi][3], al[mi][3]);
        }
        #pragma unroll
        for (int ni = 0; ni < 2; ni++) {
            int c = nh * 16 + ni * 8 + grp;
            unsigned bh0, bl0, bh1, bl1;
            split_tf32(w2s[(kb + tig) * 36 + c],     bh0, bl0);
            split_tf32(w2s[(kb + tig + 4) * 36 + c], bh1, bl1);
            mma3(acc2[0][ni], ah[0], al[0], bh0, bh1, bl0, bl1);
            mma3(acc2[1][ni], ah[1], al[1], bh0, bh1, bl0, bl1);
        }
    }

    #pragma unroll
    for (int mi = 0; mi < 2; mi++) {
        #pragma unroll
        for (int ni = 0; ni < 2; ni++) {
            #pragma unroll
            for (int ci = 0; ci < 4; ci++) {
                int p = mh * 32 + mi * 16 + grp + ((ci >= 2) ? 8 : 0);
                if (p < 49) {
                    int ch = nh * 16 + ni * 8 + tig * 2 + (ci & 1);
                    size_t g = (size_t)(b0 + img) * 1568 + ch * 49 + p;
                    float v = acc2[mi][ni][ci] + __ldg(buf + g);
                    buf[g] = fmaxf(v, 0.f);
                }
            }
        }
    }
}

// ======================================================================
// res stack single-TF32 (decoder): fragment-texture weights [round-10]
// ======================================================================
#define D3_RS   5346
#define D3_W2   14050
#define D3_TOT  16354
#define D3_SMEM (D3_TOT * 4)     // 65416 B

__global__ void __launch_bounds__(256) res_tcd(
        float* __restrict__ buf,
        const float2* __restrict__ wf,
        const float* __restrict__ pw2) {
    extern __shared__ float sm[];
    float* xin = sm;
    float* rs  = sm + D3_RS;
    float* w2s = sm + D3_W2;
    int t = threadIdx.x;
    int b0 = blockIdx.x * 2;

    for (int i = t; i < D3_RS; i += 256) xin[i] = 0.f;
    __syncthreads();
    for (int i = t; i < 2048; i += 256) {
        int oc = i >> 6, ic = i & 63;
        w2s[ic * 36 + oc] = to_tf32(pw2[i]);
    }
    for (int i = t; i < 2 * 1568; i += 256) {
        int img = i / 1568, j = i % 1568;
        int ch = j / 49, p = j % 49;
        float v = buf[(size_t)(b0 + img) * 1568 + j];
        xin[img * 2673 + ((p / 7 + 1) * 9 + (p % 7 + 1)) * 33 + ch] =
            to_tf32(fmaxf(v, 0.f));
    }
    __syncthreads();

    int lane = t & 31, wrp = t >> 5;
    int grp = lane >> 2, tig = lane & 3;
    int img = wrp >> 2, mh = (wrp >> 1) & 1, nh = wrp & 1;
    int rbase = img * 64 + mh * 32;

    int rb[2][2];
    #pragma unroll
    for (int mi = 0; mi < 2; mi++)
        #pragma unroll
        for (int h = 0; h < 2; h++) {
            int p = mh * 32 + mi * 16 + grp + h * 8;
            rb[mi][h] = (p < 49) ? img * 2673 + ((p / 7) * 9 + (p % 7)) * 33 : 0;
        }

    float acc[2][4][4];
    #pragma unroll
    for (int mi = 0; mi < 2; mi++)
        #pragma unroll
        for (int ni = 0; ni < 4; ni++)
            #pragma unroll
            for (int c = 0; c < 4; c++) acc[mi][ni][c] = 0.f;

    #pragma unroll
    for (int ky = 0; ky < 3; ky++) {
        #pragma unroll
        for (int kx = 0; kx < 3; kx++) {
            int s = ky * 3 + kx;
            int soff = (ky * 9 + kx) * 33;
            #pragma unroll
            for (int kk = 0; kk < 4; kk++) {
                int kb = kk * 8;
                unsigned a[2][4];
                #pragma unroll
                for (int mi = 0; mi < 2; mi++) {
                    a[mi][0] = __float_as_uint(xin[rb[mi][0] + soff + kb + tig]);
                    a[mi][1] = __float_as_uint(xin[rb[mi][1] + soff + kb + tig]);
                    a[mi][2] = __float_as_uint(xin[rb[mi][0] + soff + kb + tig + 4]);
                    a[mi][3] = __float_as_uint(xin[rb[mi][1] + soff + kb + tig + 4]);
                }
                #pragma unroll
                for (int ni = 0; ni < 4; ni++) {
                    int oct = nh * 4 + ni;
                    float2 bw = __ldg(wf + (size_t)s * 1024 + kk * 256 + oct * 32 + lane);
                    unsigned bb0 = __float_as_uint(bw.x);
                    unsigned bb1 = __float_as_uint(bw.y);
                    mma_tf32(acc[0][ni], a[0], bb0, bb1);
                    mma_tf32(acc[1][ni], a[1], bb0, bb1);
                }
            }
        }
    }

    #pragma unroll
    for (int mi = 0; mi < 2; mi++) {
        int rlo = rbase + mi * 16 + grp, rhi = rlo + 8;
        #pragma unroll
        for (int ni = 0; ni < 4; ni++) {
            int c0 = nh * 32 + ni * 8 + tig * 2;
            rs[rlo * 68 + c0]     = to_tf32(fmaxf(acc[mi][ni][0], 0.f));
            rs[rlo * 68 + c0 + 1] = to_tf32(fmaxf(acc[mi][ni][1], 0.f));
            rs[rhi * 68 + c0]     = to_tf32(fmaxf(acc[mi][ni][2], 0.f));
            rs[rhi * 68 + c0 + 1] = to_tf32(fmaxf(acc[mi][ni][3], 0.f));
        }
    }
    __syncthreads();

    float acc2[2][2][4];
    #pragma unroll
    for (int mi = 0; mi < 2; mi++)
        #pragma unroll
        for (int ni = 0; ni < 2; ni++)
            #pragma unroll
            for (int c = 0; c < 4; c++) acc2[mi][ni][c] = 0.f;

    #pragma unroll
    for (int kk = 0; kk < 8; kk++) {
        int kb = kk * 8;
        unsigned a[2][4];
        #pragma unroll
        for (int mi = 0; mi < 2; mi++) {
            int rlo = rbase + mi * 16 + grp;
            a[mi][0] = __float_as_uint(rs[rlo * 68 + kb + tig]);
            a[mi][1] = __float_as_uint(rs[(rlo + 8) * 68 + kb + tig]);
            a[mi][2] = __float_as_uint(rs[rlo * 68 + kb + tig + 4]);
            a[mi][3] = __float_as_uint(rs[(rlo + 8) * 68 + kb + tig + 4]);
        }
        #pragma unroll
        for (int ni = 0; ni < 2; ni++) {
            int c = nh * 16 + ni * 8 + grp;
            unsigned bb0 = __float_as_uint(w2s[(kb + tig) * 36 + c]);
            unsigned bb1 = __float_as_uint(w2s[(kb + tig + 4) * 36 + c]);
            mma_tf32(acc2[0][ni], a[0], bb0, bb1);
            mma_tf32(acc2[1][ni], a[1], bb0, bb1);
        }
    }

    #pragma unroll
    for (int mi = 0; mi < 2; mi++) {
        #pragma unroll
        for (int ni = 0; ni < 2; ni++) {
            #pragma unroll
            for (int ci = 0; ci < 4; ci++) {
                int p = mh * 32 + mi * 16 + grp + ((ci >= 2) ? 8 : 0);
                if (p < 49) {
                    int ch = nh * 16 + ni * 8 + tig * 2 + (ci & 1);
                    size_t g = (size_t)(b0 + img) * 1568 + ch * 49 + p;
                    float v = acc2[mi][ni][ci] + __ldg(buf + g);
                    buf[g] = fmaxf(v, 0.f);
                }
            }
        }
    }
}

// ======================================================================
// TF32 GEMM (decoder fc4) with register-prefetch pipelining  [round-7]
// ======================================================================
__global__ void __launch_bounds__(256) gemm_tc(
        const float* __restrict__ A,
        const float* __restrict__ W,
        const float* __restrict__ bias,
        float* __restrict__ C,
        int M, int N, int K) {
    __shared__ float As[128][17];
    __shared__ float Ws[64][17];
    int t = threadIdx.x, lane = t & 31, w = t >> 5;
    int grp = lane >> 2, tig = lane & 3;
    int m0 = blockIdx.x * 128, n0 = blockIdx.y * 64;
    int mw = (w & 3) * 32, nw = (w >> 2) * 32;
    float acc[2][4][4];
    #pragma unroll
    for (int mi = 0; mi < 2; mi++)
        #pragma unroll
        for (int ni = 0; ni < 4; ni++)
            #pragma unroll
            for (int c = 0; c < 4; c++) acc[mi][ni][c] = 0.f;

    int ar = t >> 1, ak = (t & 1) * 8;
    int wr = t >> 2, wk = (t & 3) * 4;
    const float* apb = A + (size_t)(m0 + ar) * K + ak;
    bool wval = (n0 + wr < N);
    const float* wpb = W + (size_t)(n0 + wr) * K + wk;

    float4 v0 = *(const float4*)apb;
    float4 v1 = *(const float4*)(apb + 4);
    float4 wv = wval ? *(const float4*)wpb : make_float4(0.f, 0.f, 0.f, 0.f);

    for (int k0 = 0; k0 < K; k0 += 16) {
        As[ar][ak + 0] = to_tf32(v0.x); As[ar][ak + 1] = to_tf32(v0.y);
        As[ar][ak + 2] = to_tf32(v0.z); As[ar][ak + 3] = to_tf32(v0.w);
        As[ar][ak + 4] = to_tf32(v1.x); As[ar][ak + 5] = to_tf32(v1.y);
        As[ar][ak + 6] = to_tf32(v1.z); As[ar][ak + 7] = to_tf32(v1.w);
        Ws[wr][wk + 0] = to_tf32(wv.x); Ws[wr][wk + 1] = to_tf32(wv.y);
        Ws[wr][wk + 2] = to_tf32(wv.z); Ws[wr][wk + 3] = to_tf32(wv.w);
        __syncthreads();
        if (k0 + 16 < K) {
            v0 = *(const float4*)(apb + k0 + 16);
            v1 = *(const float4*)(apb + k0 + 20);
            wv = wval ? *(const float4*)(wpb + k0 + 16)
                      : make_float4(0.f, 0.f, 0.f, 0.f);
        }
        #pragma unroll
        for (int kk = 0; kk < 2; kk++) {
            int kb = kk * 8;
            unsigned a[2][4];
            #pragma unroll
            for (int mi = 0; mi < 2; mi++) {
                int r = mw + mi * 16 + grp;
                a[mi][0] = __float_as_uint(As[r][kb + tig]);
                a[mi][1] = __float_as_uint(As[r + 8][kb + tig]);
                a[mi][2] = __float_as_uint(As[r][kb + tig + 4]);
                a[mi][3] = __float_as_uint(As[r + 8][kb + tig + 4]);
            }
            #pragma unroll
            for (int ni = 0; ni < 4; ni++) {
                int n = nw + ni * 8 + grp;
                unsigned bb0 = __float_as_uint(Ws[n][kb + tig]);
                unsigned bb1 = __float_as_uint(Ws[n][kb + tig + 4]);
                mma_tf32(acc[0][ni], a[0], bb0, bb1);
                mma_tf32(acc[1][ni], a[1], bb0, bb1);
            }
        }
        __syncthreads();
    }
    #pragma unroll
    for (int mi = 0; mi < 2; mi++) {
        #pragma unroll
        for (int ni = 0; ni < 4; ni++) {
            #pragma unroll
            for (int ci = 0; ci < 4; ci++) {
                int r = m0 + mw + mi * 16 + grp + ((ci >= 2) ? 8 : 0);
                int n = n0 + nw + ni * 8 + tig * 2 + (ci & 1);
                if (n < N)
                    C[(size_t)r * N + n] = fmaxf(acc[mi][ni][ci] + bias[n], 0.f);
            }
        }
    }
}

// ======================================================================
// 3xTF32 GEMM (encoder fc1) with register-prefetch pipelining [round-8]
// ======================================================================
__global__ void __launch_bounds__(256) gemm_tc3(
        const float* __restrict__ A,
        const float* __restrict__ W,
        const float* __restrict__ bias,
        float* __restrict__ C,
        int M, int N, int K) {
    __shared__ float As[128][17];
    __shared__ float Ws[64][17];
    int t = threadIdx.x, lane = t & 31, w = t >> 5;
    int grp = lane >> 2, tig = lane & 3;
    int m0 = blockIdx.x * 128, n0 = blockIdx.y * 64;
    int mw = (w & 3) * 32, nw = (w >> 2) * 32;
    float acc[2][4][4];
    #pragma unroll
    for (int mi = 0; mi < 2; mi++)
        #pragma unroll
        for (int ni = 0; ni < 4; ni++)
            #pragma unroll
            for (int c = 0; c < 4; c++) acc[mi][ni][c] = 0.f;

    int ar = t >> 1, ak = (t & 1) * 8;
    int wr = t >> 2, wk = (t & 3) * 4;
    const float* apb = A + (size_t)(m0 + ar) * K + ak;
    bool wval = (n0 + wr < N);
    const float* wpb = W + (size_t)(n0 + wr) * K + wk;

    float4 v0 = *(const float4*)apb;
    float4 v1 = *(const float4*)(apb + 4);
    float4 wv = wval ? *(const float4*)wpb : make_float4(0.f, 0.f, 0.f, 0.f);

    for (int k0 = 0; k0 < K; k0 += 16) {
        As[ar][ak + 0] = v0.x; As[ar][ak + 1] = v0.y;
        As[ar][ak + 2] = v0.z; As[ar][ak + 3] = v0.w;
        As[ar][ak + 4] = v1.x; As[ar][ak + 5] = v1.y;
        As[ar][ak + 6] = v1.z; As[ar][ak + 7] = v1.w;
        Ws[wr][wk + 0] = wv.x; Ws[wr][wk + 1] = wv.y;
        Ws[wr][wk + 2] = wv.z; Ws[wr][wk + 3] = wv.w;
        __syncthreads();
        if (k0 + 16 < K) {
            v0 = *(const float4*)(apb + k0 + 16);
            v1 = *(const float4*)(apb + k0 + 20);
            wv = wval ? *(const float4*)(wpb + k0 + 16)
                      : make_float4(0.f, 0.f, 0.f, 0.f);
        }
        #pragma unroll
        for (int kk = 0; kk < 2; kk++) {
            int kb = kk * 8;
            unsigned ah[2][4], al[2][4];
            #pragma unroll
            for (int mi = 0; mi < 2; mi++) {
                int r = mw + mi * 16 + grp;
                split_tf32(As[r][kb + tig],         ah[mi][0], al[mi][0]);
                split_tf32(As[r + 8][kb + tig],     ah[mi][1], al[mi][1]);
                split_tf32(As[r][kb + tig + 4],     ah[mi][2], al[mi][2]);
                split_tf32(As[r + 8][kb + tig + 4], ah[mi][3], al[mi][3]);
            }
            #pragma unroll
            for (int ni = 0; ni < 4; ni++) {
                int n = nw + ni * 8 + grp;
                unsigned bh0, bl0, bh1, bl1;
                split_tf32(Ws[n][kb + tig],     bh0, bl0);
                split_tf32(Ws[n][kb + tig + 4], bh1, bl1);
                mma3(acc[0][ni], ah[0], al[0], bh0, bh1, bl0, bl1);
                mma3(acc[1][ni], ah[1], al[1], bh0, bh1, bl0, bl1);
            }
        }
        __syncthreads();
    }
    #pragma unroll
    for (int mi = 0; mi < 2; mi++) {
        #pragma unroll
        for (int ni = 0; ni < 4; ni++) {
            #pragma unroll
            for (int ci = 0; ci < 4; ci++) {
                int r = m0 + mw + mi * 16 + grp + ((ci >= 2) ? 8 : 0);
                int n = n0 + nw + ni * 8 + tig * 2 + (ci & 1);
                if (n < N)
                    C[(size_t)r * N + n] = fmaxf(acc[mi][ni][ci] + bias[n], 0.f);
            }
        }
    }
}

// ======================================================================
// convt1 single-TF32 (decoder)                                [round-4]
// ======================================================================
#define T1_IMSZ 2916
#define T1_ZB   6240
#define T1_XIN  6664
#define T1_WOFF T1_XIN
#define T1_WSZ  (16 * 32 * 24)
#define T1_SMEM ((T1_XIN + T1_WSZ) * 4)

__global__ void __launch_bounds__(256) convt1_tc(
        const float* __restrict__ in,
        const float* __restrict__ w,
        const float* __restrict__ bias,
        float* __restrict__ out) {
    extern __shared__ float sm[];
    float* xin = sm;
    float* wt  = sm + T1_WOFF;
    int t = threadIdx.x;
    int b0 = blockIdx.x * 2;

    for (int i = t; i < T1_XIN; i += 256) xin[i] = 0.f;
    __syncthreads();
    for (int i = t; i < 2 * 1568; i += 256) {
        int img = i / 1568, j = i % 1568;
        int ic = j / 49, p = j % 49, iy = p / 7, ix = p % 7;
        xin[img * T1_IMSZ + ((iy + 1) * 9 + (ix + 1)) * 36 + ic] =
            to_tf32(in[(size_t)(b0 + img) * 1568 + j]);
    }
    for (int i = t; i < 32 * 256; i += 256) {
        int ic = i / 256, r = i % 256, oc = r / 16, s = r % 16;
        wt[s * 768 + ic * 24 + oc] = to_tf32(w[i]);
    }
    __syncthreads();

    int lane = t & 31, wrp = t >> 5;
    int grp = lane >> 2, tig = lane & 3;
    int img = wrp >> 2, ph = wrp & 3;
    int a = ph >> 1, bp = ph & 1;
    int dyv[2], kyv[2], dxv[2], kxv[2];
    if (a == 0) { dyv[0] = 0; kyv[0] = 1; dyv[1] = -1; kyv[1] = 3; }
    else        { dyv[0] = 1; kyv[0] = 0; dyv[1] =  0; kyv[1] = 2; }
    if (bp == 0) { dxv[0] = 0; kxv[0] = 1; dxv[1] = -1; kxv[1] = 3; }
    else         { dxv[0] = 1; kxv[0] = 0; dxv[1] =  0; kxv[1] = 2; }

    int rb[4][2];
    #pragma unroll
    for (int mi = 0; mi < 4; mi++)
        #pragma unroll
        for (int h = 0; h < 2; h++) {
            int p = mi * 16 + grp + h * 8;
            rb[mi][h] = (p < 49)
                ? img * T1_IMSZ + ((p / 7 + 1) * 9 + (p % 7 + 1)) * 36
                : T1_ZB;
        }

    float acc[4][2][4];
    #pragma unroll
    for (int mi = 0; mi < 4; mi++)
        #pragma unroll
        for (int ni = 0; ni < 2; ni++)
            #pragma unroll
            for (int c = 0; c < 4; c++) acc[mi][ni][c] = 0.f;

    #pragma unroll
    for (int sy = 0; sy < 2; sy++) {
        #pragma unroll
        for (int sx = 0; sx < 2; sx++) {
            int soff = (dyv[sy] * 9 + dxv[sx]) * 36;
            const float* wsl = wt + (kyv[sy] * 4 + kxv[sx]) * 768;
            #pragma unroll
            for (int kk = 0; kk < 4; kk++) {
                int kb = kk * 8;
                unsigned afr[4][4];
                #pragma unroll
                for (int mi = 0; mi < 4; mi++) {
                    afr[mi][0] = __float_as_uint(xin[rb[mi][0] + soff + kb + tig]);
                    afr[mi][1] = __float_as_uint(xin[rb[mi][1] + soff + kb + tig]);
                    afr[mi][2] = __float_as_uint(xin[rb[mi][0] + soff + kb + tig + 4]);
                    afr[mi][3] = __float_as_uint(xin[rb[mi][1] + soff + kb + tig + 4]);
                }
                #pragma unroll
                for (int ni = 0; ni < 2; ni++) {
                    unsigned bb0 = __float_as_uint(wsl[(kb + tig) * 24 + ni * 8 + grp]);
                    unsigned bb1 = __float_as_uint(wsl[(kb + tig + 4) * 24 + ni * 8 + grp]);
                    #pragma unroll
                    for (int mi = 0; mi < 4; mi++)
                        mma_tf32(acc[mi][ni], afr[mi], bb0, bb1);
                }
            }
        }
    }

    #pragma unroll
    for (int mi = 0; mi < 4; mi++) {
        #pragma unroll
        for (int ni = 0; ni < 2; ni++) {
            #pragma unroll
            for (int ci = 0; ci < 4; ci++) {
                int p = mi * 16 + grp + ((ci >= 2) ? 8 : 0);
                if (p < 49) {
                    int m = p / 7, n = p % 7;
                    int oc = ni * 8 + tig * 2 + (ci & 1);
                    int oy = 2 * m + a, ox = 2 * n + bp;
                    float v = acc[mi][ni][ci] + __ldg(bias + oc);
                    out[(size_t)(b0 + img) * 3136 + oc * 196 + oy * 14 + ox] =
                        fmaxf(v, 0.f);
                }
            }
        }
    }
}

// ======================================================================
// fc2: z[B,32] = A[B,224] @ w^T + b  (fp32, feeds VQ)   [round-8]
// ======================================================================
__global__ void __launch_bounds__(256) fc2_kernel(
        const float* __restrict__ A,
        const float* __restrict__ w,
        const float* __restrict__ bias,
        float* __restrict__ out) {
    __shared__ float ws[32 * 224];
    int t = threadIdx.x;
    for (int i = t; i < 7168; i += 256) ws[i] = w[i];
    __syncthreads();
    int n = t & 31, r = t >> 5;
    float bv = bias[n];
    const float* wp = ws + n * 224;
    #pragma unroll
    for (int rr = 0; rr < 4; rr++) {
        int b = blockIdx.x * 32 + rr * 8 + r;
        const float* ap = A + (size_t)b * 224;
        float acc = bv;
        #pragma unroll 8
        for (int k = 0; k < 224; k++) acc += ap[k] * wp[k];
        out[(size_t)b * 32 + n] = acc;
    }
}

// ======================================================================
// VQ helpers (fp32 exact)
// ======================================================================
__global__ void enorm_kernel(const float* __restrict__ emb, float* __restrict__ enorm) {
    int e = blockIdx.x * blockDim.x + threadIdx.x;
    if (e < NE) {
        float s = 0.f;
        #pragma unroll
        for (int d = 0; d < ZD; d++) { float v = emb[e * ZD + d]; s += v * v; }
        enorm[e] = s;
    }
}

__global__ void zero_kernel(float* __restrict__ counts, float* __restrict__ sums,
                            float* __restrict__ loss) {
    int i = blockIdx.x * blockDim.x + threadIdx.x;
    if (i < NE) counts[i] = 0.f;
    if (i < NE * ZD) sums[i] = 0.f;
    if (i == 0) loss[0] = 0.f;
}

#define VQ_SMEM (NE * 36 * 4)

__global__ void __launch_bounds__(256) vq_kernel(
        const float* __restrict__ z,
        const float* __restrict__ emb,
        const float* __restrict__ enorm,
        int* __restrict__ idx,
        float* __restrict__ counts,
        float* __restrict__ sums,
        float* __restrict__ loss) {
    extern __shared__ float es[];          // [512][36]
    __shared__ float en[NE];
    __shared__ float zs[8][ZD];
    int t = threadIdx.x, lane = t & 31, wl = t >> 5;
    for (int i = t; i < NE * ZD; i += 256) {
        int e = i >> 5, d = i & 31;
        es[e * 36 + d] = emb[i];
    }
    for (int i = t; i < NE; i += 256) en[i] = enorm[i];
    __syncthreads();

    for (int rr = 0; rr < 8; rr++) {
        int row = blockIdx.x * 64 + wl * 8 + rr;
        zs[wl][lane] = z[(size_t)row * ZD + lane];
        __syncwarp();
        float best = 3.4e38f; int bi = NE;
        for (int e = lane; e < NE; e += 32) {
            const float* ep = es + e * 36;
            float dot = 0.f;
            #pragma unroll
            for (int d = 0; d < ZD; d += 4) {
                float4 v = *(const float4*)(ep + d);
                dot += zs[wl][d + 0] * v.x;
                dot += zs[wl][d + 1] * v.y;
                dot += zs[wl][d + 2] * v.z;
                dot += zs[wl][d + 3] * v.w;
            }
            float s = en[e] - 2.f * dot;
            if (s < best) { best = s; bi = e; }
        }
        #pragma unroll
        for (int off = 16; off; off >>= 1) {
            float ob = __shfl_xor_sync(0xffffffffu, best, off);
            int   oi = __shfl_xor_sync(0xffffffffu, bi, off);
            if (ob < best || (ob == best && oi < bi)) { best = ob; bi = oi; }
        }
        float zl = zs[wl][lane];
        float diff = es[bi * 36 + lane] - zl;
        float d2 = diff * diff;
        #pragma unroll
        for (int off = 16; off; off >>= 1)
            d2 += __shfl_xor_sync(0xffffffffu, d2, off);
        if (lane == 0) {
            idx[row] = bi;
            atomicAdd(&counts[bi], 1.f);
            atomicAdd(loss, d2);
        }
        atomicAdd(&sums[bi * ZD + lane], zl);
        __syncwarp();
    }
}

__global__ void embnew_kernel(const float* __restrict__ m_mat,
                              const float* __restrict__ n_mat,
                              const float* __restrict__ sums,
                              const float* __restrict__ counts,
                              float* __restrict__ out) {
    int i = blockIdx.x * blockDim.x + threadIdx.x;
    if (i < NE * ZD) {
        int e = i >> 5;
        float m = m_mat[i] * GAMMA + sums[i] * ONE_M_GAMMA;
        float n = n_mat[e] * GAMMA + counts[e] * ONE_M_GAMMA;
        out[i] = m / n;
    }
}

__global__ void finalize_kernel(const float* __restrict__ counts,
                                const float* __restrict__ loss,
                                float* __restrict__ out_scalars) {
    __shared__ float red[NE];
    int t = threadIdx.x;
    float c = counts[t];
    float em = c * (1.f / (float)BATCH);
    red[t] = em * logf(em + 1e-10f);
    __syncthreads();
    for (int s = 256; s; s >>= 1) {
        if (t < s) red[t] += red[t + s];
        __syncthreads();
    }
    if (t == 0) {
        float q = loss[0] * (1.f / ((float)BATCH * (float)ZD));
        out_scalars[0] = q;
        out_scalars[1] = BETA * q;
        out_scalars[2] = expf(-red[0]);
    }
}

// ======================================================================
// fc3 (fp32): 16 images/CTA                           [round-8, proven]
// ======================================================================
__global__ void __launch_bounds__(224) fc3_kernel(
        const float* __restrict__ emb,
        const int* __restrict__ idx,
        const float* __restrict__ w,
        const float* __restrict__ bias,
        float* __restrict__ out) {
    __shared__ float ws[224 * ZD];
    __shared__ float zq[16][ZD + 1];
    int b0 = blockIdx.x * 16, t = threadIdx.x;
    for (int i = t; i < 224 * ZD; i += 224) ws[i] = w[i];
    for (int i = t; i < 16 * ZD; i += 224) {
        int im = i >> 5, d = i & 31;
        zq[im][d] = emb[(size_t)idx[b0 + im] * ZD + d];
    }
    __syncthreads();
    float bv = bias[t];
    float wreg[ZD];
    const float* wp = ws + t * ZD;
    #pragma unroll
    for (int k = 0; k < ZD; k++) wreg[k] = wp[k];
    #pragma unroll 4
    for (int im = 0; im < 16; im++) {
        float acc = bv;
        #pragma unroll
        for (int k = 0; k < ZD; k++) acc += zq[im][k] * wreg[k];
        out[(size_t)(b0 + im) * 224 + t] = fmaxf(acc, 0.f);
    }
}

// ======================================================================
// convt2 phase-decomposed fp32                        [round-7, proven]
// ======================================================================
#define CT2_SMEM (4 * 4096 * 4)   // 65536 B

template<int DY0, int KY0, int DY1, int KY1,
         int DX0, int KX0, int DX1, int KX1>
__device__ __forceinline__ void ct2_body(
        const float* __restrict__ base, const float* __restrict__ w,
        float bv, float* __restrict__ outp, int m) {
    float acc[14];
    #pragma unroll
    for (int j = 0; j < 14; j++) acc[j] = bv;
    for (int ic = 0; ic < 16; ic++) {
        const float* xc = base + ic * 256;
        #pragma unroll
        for (int sy = 0; sy < 2; sy++) {
            int iy = m + (sy ? DY1 : DY0);
            float row[16];
            #pragma unroll
            for (int j = 0; j < 16; j++) row[j] = xc[(iy + 1) * 16 + j];
            {
                float wv = __ldg(w + ic * 16 + (sy ? KY1 : KY0) * 4 + KX0);
                #pragma unroll
                for (int n = 0; n < 14; n++) acc[n] += row[n + DX0 + 1] * wv;
            }
            {
                float wv = __ldg(w + ic * 16 + (sy ? KY1 : KY0) * 4 + KX1);
                #pragma unroll
                for (int n = 0; n < 14; n++) acc[n] += row[n + DX1 + 1] * wv;
            }
        }
    }
    #pragma unroll
    for (int n = 0; n < 14; n++) outp[2 * n] = acc[n];
}

__global__ void __launch_bounds__(256) convt2_tc(
        const float* __restrict__ in,
        const float* __restrict__ w,
        const float* __restrict__ bias,
        float* __restrict__ out) {
    extern __shared__ float xp[];
    int t = threadIdx.x;
    int b0 = blockIdx.x * 4;

    for (int i = t; i < 16384; i += 256) xp[i] = 0.f;
    __syncthreads();
    for (int i = t; i < 4 * 3136; i += 256) {
        int img = i / 3136, j = i % 3136;
        int ic = j / 196, p = j % 196, iy = p / 14, ix = p % 14;
        xp[img * 4096 + ic * 256 + (iy + 1) * 16 + (ix + 1)] =
            in[(size_t)(b0 + img) * 3136 + j];
    }
    __syncthreads();

    int ph = t >> 6, s = t & 63;
    if (s >= 56) return;
    int img = s / 14, m = s % 14;
    int a = ph >> 1, b = ph & 1;
    const float* base = xp + img * 4096;
    float bv = bias[0];
    float* outp = out + (size_t)(b0 + img) * 784 + (2 * m + a) * 28 + b;

    if (ph == 0)      ct2_body<0, 1, -1, 3,  0, 1, -1, 3>(base, w, bv, outp, m);
    else if (ph == 1) ct2_body<0, 1, -1, 3,  1, 0,  0, 2>(base, w, bv, outp, m);
    else if (ph == 2) ct2_body<1, 0,  0, 2,  0, 1, -1, 3>(base, w, bv, outp, m);
    else              ct2_body<1, 0,  0, 2,  1, 0,  0, 2>(base, w, bv, outp, m);
}

// ======================================================================
// launch
// ======================================================================
extern "C" void kernel_launch(void* const* d_in, const int* in_sizes, int n_in,
                              void* d_out, int out_size) {
    const float* x        = (const float*)d_in[0];
    const float* conv1_w  = (const float*)d_in[1];
    const float* conv1_b  = (const float*)d_in[2];
    const float* conv2_w  = (const float*)d_in[3];
    const float* conv2_b  = (const float*)d_in[4];
    const float* res1_w1  = (const float*)d_in[5];
    const float* res1_w2  = (const float*)d_in[6];
    const float* fc1_w    = (const float*)d_in[7];
    const float* fc1_b    = (const float*)d_in[8];
    const float* fc2_w    = (const float*)d_in[9];
    const float* fc2_b    = (const float*)d_in[10];
    const float* emb      = (const float*)d_in[11];
    const float* n_mat    = (const float*)d_in[12];
    const float* m_mat    = (const float*)d_in[13];
    const float* fc3_w    = (const float*)d_in[14];
    const float* fc3_b    = (const float*)d_in[15];
    const float* fc4_w    = (const float*)d_in[16];
    const float* fc4_b    = (const float*)d_in[17];
    const float* res2_w1  = (const float*)d_in[18];
    const float* res2_w2  = (const float*)d_in[19];
    const float* convt1_w = (const float*)d_in[20];
    const float* convt1_b = (const float*)d_in[21];
    const float* convt2_w = (const float*)d_in[22];
    const float* convt2_b = (const float*)d_in[23];
    float* out = (float*)d_out;

    float *h1, *h2, *a, *z, *enorm, *counts, *sums, *loss;
    int* idx;
    float2 *wf_r1, *wf_r2, *wf_c2;
    cudaGetSymbolAddress((void**)&h1,     g_h1);
    cudaGetSymbolAddress((void**)&h2,     g_h2);
    cudaGetSymbolAddress((void**)&a,      g_a);
    cudaGetSymbolAddress((void**)&z,      g_z);
    cudaGetSymbolAddress((void**)&idx,    g_idx);
    cudaGetSymbolAddress((void**)&enorm,  g_enorm);
    cudaGetSymbolAddress((void**)&counts, g_counts);
    cudaGetSymbolAddress((void**)&sums,   g_sums);
    cudaGetSymbolAddress((void**)&loss,   g_loss);
    cudaGetSymbolAddress((void**)&wf_r1,  g_wf_r1);
    cudaGetSymbolAddress((void**)&wf_r2,  g_wf_r2);
    cudaGetSymbolAddress((void**)&wf_c2,  g_wf_c2);

    cudaFuncSetAttribute(conv2_tc3,
                         cudaFuncAttributeMaxDynamicSharedMemorySize, C2B_SMEM);
    cudaFuncSetAttribute(res_tc3,
                         cudaFuncAttributeMaxDynamicSharedMemorySize, E3_SMEM);
    cudaFuncSetAttribute(res_tcd,
                         cudaFuncAttributeMaxDynamicSharedMemorySize, D3_SMEM);
    cudaFuncSetAttribute(convt1_tc,
                         cudaFuncAttributeMaxDynamicSharedMemorySize, T1_SMEM);
    cudaFuncSetAttribute(convt2_tc,
                         cudaFuncAttributeMaxDynamicSharedMemorySize, CT2_SMEM);
    cudaFuncSetAttribute(vq_kernel,
                         cudaFuncAttributeMaxDynamicSharedMemorySize, VQ_SMEM);

    // weight repack (fragment-order textures)
    repack_res<<<36, 256>>>(res1_w1, wf_r1, 0);
    repack_res<<<36, 256>>>(res2_w1, wf_r2, 1);
    repack_c2 <<<16, 256>>>(conv2_w, wf_c2);

    // encoder (3xTF32 = fp32-class accuracy; VQ path preserved)
    conv1_kernel<<<BATCH / 2, 448>>>(x, conv1_w, conv1_b, h1);
    conv2_tc3<<<BATCH / 2, 256, C2B_SMEM>>>(h1, wf_c2, conv2_b, h2);
    res_tc3  <<<BATCH / 2, 256, E3_SMEM>>>(h2, wf_r1, res1_w2);
    gemm_tc3<<<dim3(BATCH / 128, 4), 256>>>(h2, fc1_w, fc1_b, a,
                                            BATCH, 224, 1568);
    fc2_kernel<<<BATCH / 32, 256>>>(a, fc2_w, fc2_b, z);

    // VQ
    zero_kernel <<<(NE * ZD + 255) / 256, 256>>>(counts, sums, loss);
    enorm_kernel<<<2, 256>>>(emb, enorm);
    vq_kernel   <<<BATCH / 64, 256, VQ_SMEM>>>(z, emb, enorm, idx, counts,
                                               sums, loss);
    embnew_kernel  <<<(NE * ZD + 255) / 256, 256>>>(m_mat, n_mat, sums, counts,
                                                    out + OFF_SCAL + 3);
    finalize_kernel<<<1, NE>>>(counts, loss, out + OFF_SCAL);

    // decoder (single tf32)
    fc3_kernel<<<BATCH / 16, 224>>>(emb, idx, fc3_w, fc3_b, a);
    gemm_tc<<<dim3(BATCH / 128, 25), 256>>>(a, fc4_w, fc4_b, h2,
                                            BATCH, 1568, 224);
    res_tcd<<<BATCH / 2, 256, D3_SMEM>>>(h2, wf_r2, res2_w2);
    convt1_tc<<<BATCH / 2, 256, T1_SMEM>>>(h2, convt1_w, convt1_b, h1);
    convt2_tc<<<BATCH / 4, 256, CT2_SMEM>>>(h1, convt2_w, convt2_b, out);
}

// round 12
// speedup vs baseline: 2.4710x; 1.0709x over previous
#include <cuda_runtime.h>
#include <cstdint>
#include <math.h>

// ---------------- problem constants ----------------
#define BATCH 16384
#define ZD 32
#define NE 512
#define GAMMA 0.99f
#define ONE_M_GAMMA 0.01f
#define BETA 1.0f

#define OFF_SCAL (BATCH * 784)   // x_rec size
// d_out layout: [x_rec (B*784)][quant][commit][perplexity][emb_new (512*32)]

// ---------------- scratch ----------------
__device__ float g_h2[BATCH * 32 * 7 * 7];
__device__ float g_a [BATCH * 224];
__device__ float g_z [BATCH * ZD];
__device__ int   g_idx[BATCH];
__device__ float g_enorm[NE];
__device__ float g_counts[NE];
__device__ float g_sums[NE * ZD];
__device__ float g_loss[1];
// fragment-order weight textures: [s][kk][oct][lane] -> (b0,b1)
__device__ float2 g_wf_r1[9216];   // res1 w1 (raw fp32)
__device__ float2 g_wf_r2[9216];   // res2 w1 (tf32)
__device__ float2 g_wf_c2[4096];   // conv2 w  (raw fp32)

// ---------------- tf32 mma helpers ----------------
__device__ __forceinline__ float to_tf32(float x) {
    float y;
    asm("cvt.rna.tf32.f32 %0, %1;" : "=f"(y) : "f"(x));
    return y;
}

// Bitwise hi/lo split: hi = RZ-truncated tf32 (LOP3), lo = v - hi (exact FADD).
__device__ __forceinline__ void split_tf32(float v, unsigned& hi, unsigned& lo) {
    unsigned h = __float_as_uint(v) & 0xffffe000u;
    hi = h;
    lo = __float_as_uint(v - __uint_as_float(h));
}

__device__ __forceinline__ void mma_tf32(float* d, const unsigned* a,
                                         unsigned b0, unsigned b1) {
    asm volatile(
        "mma.sync.aligned.m16n8k8.row.col.f32.tf32.tf32.f32 "
        "{%0,%1,%2,%3}, {%4,%5,%6,%7}, {%8,%9}, {%0,%1,%2,%3};\n"
        : "+f"(d[0]), "+f"(d[1]), "+f"(d[2]), "+f"(d[3])
        : "r"(a[0]), "r"(a[1]), "r"(a[2]), "r"(a[3]), "r"(b0), "r"(b1));
}

// 3-pass split mma: acc += a*b with ~fp32 accuracy
__device__ __forceinline__ void mma3(float* d, const unsigned* ah, const unsigned* al,
                                     unsigned bh0, unsigned bh1,
                                     unsigned bl0, unsigned bl1) {
    mma_tf32(d, ah, bl0, bl1);
    mma_tf32(d, al, bh0, bh1);
    mma_tf32(d, ah, bh0, bh1);
}

// ======================================================================
// weight repack kernels (run once per launch; tiny)
// ======================================================================
__global__ void repack_res(const float* __restrict__ w1,
                           float2* __restrict__ out, int cvt) {
    int i = blockIdx.x * 256 + threadIdx.x;
    if (i >= 9216) return;
    int lane = i & 31, oct = (i >> 5) & 7, kk = (i >> 8) & 3, s = i >> 10;
    int grp = lane >> 2, tig = lane & 3;
    int oc = oct * 8 + grp, ic = kk * 8 + tig;
    float b0 = w1[oc * 288 + ic * 9 + s];
    float b1 = w1[oc * 288 + (ic + 4) * 9 + s];
    if (cvt) { b0 = to_tf32(b0); b1 = to_tf32(b1); }
    out[i] = make_float2(b0, b1);
}

__global__ void repack_c2(const float* __restrict__ w,
                          float2* __restrict__ out) {
    int i = blockIdx.x * 256 + threadIdx.x;
    if (i >= 4096) return;
    int lane = i & 31, oct = (i >> 5) & 3, kk = (i >> 7) & 1, s = i >> 8;
    int grp = lane >> 2, tig = lane & 3;
    int oc = oct * 8 + grp, ic = kk * 8 + tig;
    out[i] = make_float2(w[oc * 256 + ic * 16 + s],
                         w[oc * 256 + (ic + 4) * 16 + s]);
}

// ======================================================================
// FUSED conv1+conv2 (encoder): x[B,1,28,28] -> h2[B,32,7,7]
// conv1 computed in-CTA (bit-identical tap order) directly into conv2's
// padded xin; conv2 mma phase unchanged [round-10 proven].
// 2 img/CTA, 256 thr.
// ======================================================================
#define C12_ZOFF 9216
#define C12_XIN  13824                  // [img][256 pos][18 pitch] + zero blk
#define C12_XP   13824                  // x padded: 2 * 900
#define C12_W1   (C12_XP + 1800)        // 15624
#define C12_B1   (C12_W1 + 256)         // 15880
#define C12_TOT  15896
#define C12_SMEM (C12_TOT * 4)          // 63584 B

__global__ void __launch_bounds__(256) conv12_tc3(
        const float* __restrict__ x,
        const float* __restrict__ c1wg,
        const float* __restrict__ c1bg,
        const float2* __restrict__ wf,
        const float* __restrict__ bias,
        float* __restrict__ out) {
    extern __shared__ float sm[];
    float* xin = sm;
    float* xp  = sm + C12_XP;
    float* c1w = sm + C12_W1;
    float* c1b = sm + C12_B1;
    int t = threadIdx.x;
    int b0 = blockIdx.x * 2;

    for (int i = t; i < C12_XIN; i += 256) xin[i] = 0.f;
    for (int i = t; i < 1800; i += 256) xp[i] = 0.f;
    if (t < 256) c1w[t] = c1wg[t];
    if (t < 16)  c1b[t] = c1bg[t];
    __syncthreads();
    for (int i = t; i < 1568; i += 256) {
        int im = i / 784, j = i % 784;
        int iy = j / 28, ix = j % 28;
        xp[im * 900 + (iy + 1) * 30 + (ix + 1)] = x[(size_t)(b0 + im) * 784 + j];
    }
    __syncthreads();

    // conv1 phase: 392 pixel-tasks (2 img x 196), each computes all 16 oc
    for (int pi = t; pi < 392; pi += 256) {
        int im = pi / 196, pix = pi % 196;
        int oy = pix / 14, ox = pix % 14;
        const float* basep = xp + im * 900 + (2 * oy) * 30 + 2 * ox;
        float patch[16];
        #pragma unroll
        for (int ky = 0; ky < 4; ky++)
            #pragma unroll
            for (int kx = 0; kx < 4; kx++)
                patch[ky * 4 + kx] = basep[ky * 30 + kx];
        float* dst = xin + im * 4608 + ((oy + 1) * 16 + (ox + 1)) * 18;
        #pragma unroll
        for (int oc = 0; oc < 16; oc++) {
            float acc = c1b[oc];
            #pragma unroll
            for (int tap = 0; tap < 16; tap++)
                acc += patch[tap] * c1w[oc * 16 + tap];
            dst[oc] = fmaxf(acc, 0.f);
        }
    }
    __syncthreads();

    // conv2 mma phase [round-10, unchanged]
    int lane = t & 31, wrp = t >> 5;
    int grp = lane >> 2, tig = lane & 3;
    int img = wrp >> 2, mh = (wrp >> 1) & 1, nh = wrp & 1;

    int rb[2][2];
    #pragma unroll
    for (int mi = 0; mi < 2; mi++)
        #pragma unroll
        for (int h = 0; h < 2; h++) {
            int p = mh * 32 + mi * 16 + grp + h * 8;
            rb[mi][h] = (p < 49)
                ? img * 4608 + ((p / 7) * 32 + (p % 7) * 2) * 18
                : C12_ZOFF;
        }

    float acc[2][2][4];
    #pragma unroll
    for (int mi = 0; mi < 2; mi++)
        #pragma unroll
        for (int ni = 0; ni < 2; ni++)
            #pragma unroll
            for (int c = 0; c < 4; c++) acc[mi][ni][c] = 0.f;

    #pragma unroll
    for (int ky = 0; ky < 4; ky++) {
        #pragma unroll
        for (int kx = 0; kx < 4; kx++) {
            int s = ky * 4 + kx;
            int soff = (ky * 16 + kx) * 18;
            #pragma unroll
            for (int kk = 0; kk < 2; kk++) {
                int kb = kk * 8;
                unsigned ah[2][4], al[2][4];
                #pragma unroll
                for (int mi = 0; mi < 2; mi++) {
                    split_tf32(xin[rb[mi][0] + soff + kb + tig],     ah[mi][0], al[mi][0]);
                    split_tf32(xin[rb[mi][1] + soff + kb + tig],     ah[mi][1], al[mi][1]);
                    split_tf32(xin[rb[mi][0] + soff + kb + tig + 4], ah[mi][2], al[mi][2]);
                    split_tf32(xin[rb[mi][1] + soff + kb + tig + 4], ah[mi][3], al[mi][3]);
                }
                #pragma unroll
                for (int ni = 0; ni < 2; ni++) {
                    int oct = nh * 2 + ni;
                    float2 bw = __ldg(wf + (size_t)s * 256 + kk * 128 + oct * 32 + lane);
                    unsigned bh0, bl0, bh1, bl1;
                    split_tf32(bw.x, bh0, bl0);
                    split_tf32(bw.y, bh1, bl1);
                    mma3(acc[0][ni], ah[0], al[0], bh0, bh1, bl0, bl1);
                    mma3(acc[1][ni], ah[1], al[1], bh0, bh1, bl0, bl1);
                }
            }
        }
    }

    #pragma unroll
    for (int mi = 0; mi < 2; mi++) {
        #pragma unroll
        for (int ni = 0; ni < 2; ni++) {
            #pragma unroll
            for (int ci = 0; ci < 4; ci++) {
                int p = mh * 32 + mi * 16 + grp + ((ci >= 2) ? 8 : 0);
                if (p < 49) {
                    int oc = nh * 16 + ni * 8 + tig * 2 + (ci & 1);
                    out[(size_t)(b0 + img) * 1568 + oc * 49 + p] =
                        acc[mi][ni][ci] + __ldg(bias + oc);
                }
            }
        }
    }
}

// ======================================================================
// res stack 3xTF32 (encoder): fragment-texture weights [round-10 proven]
// ======================================================================
#define E3_RS   5832
#define E3_W2   14536
#define E3_TOT  16840
#define E3_SMEM (E3_TOT * 4)     // 67360 B

__global__ void __launch_bounds__(256) res_tc3(
        float* __restrict__ buf,
        const float2* __restrict__ wf,
        const float* __restrict__ pw2) {
    extern __shared__ float sm[];
    float* xin = sm;
    float* rs  = sm + E3_RS;
    float* w2s = sm + E3_W2;
    int t = threadIdx.x;
    int b0 = blockIdx.x * 2;

    for (int i = t; i < E3_RS; i += 256) xin[i] = 0.f;
    __syncthreads();
    for (int i = t; i < 2048; i += 256) {
        int oc = i >> 6, ic = i & 63;
        w2s[ic * 36 + oc] = pw2[i];
    }
    for (int i = t; i < 2 * 1568; i += 256) {
        int img = i / 1568, j = i % 1568;
        int ch = j / 49, p = j % 49;
        float v = buf[(size_t)(b0 + img) * 1568 + j];
        xin[img * 2916 + ((p / 7 + 1) * 9 + (p % 7 + 1)) * 36 + ch] = fmaxf(v, 0.f);
    }
    __syncthreads();

    int lane = t & 31, wrp = t >> 5;
    int grp = lane >> 2, tig = lane & 3;
    int img = wrp >> 2, mh = (wrp >> 1) & 1, nh = wrp & 1;
    int rbase = img * 64 + mh * 32;

    int rb[2][2];
    #pragma unroll
    for (int mi = 0; mi < 2; mi++)
        #pragma unroll
        for (int h = 0; h < 2; h++) {
            int p = mh * 32 + mi * 16 + grp + h * 8;
            rb[mi][h] = (p < 49) ? img * 2916 + ((p / 7) * 9 + (p % 7)) * 36 : 0;
        }

    float acc[2][4][4];
    #pragma unroll
    for (int mi = 0; mi < 2; mi++)
        #pragma unroll
        for (int ni = 0; ni < 4; ni++)
            #pragma unroll
            for (int c = 0; c < 4; c++) acc[mi][ni][c] = 0.f;

    #pragma unroll
    for (int ky = 0; ky < 3; ky++) {
        #pragma unroll
        for (int kx = 0; kx < 3; kx++) {
            int s = ky * 3 + kx;
            int soff = (ky * 9 + kx) * 36;
            #pragma unroll
            for (int kk = 0; kk < 4; kk++) {
                int kb = kk * 8;
                unsigned ah[2][4], al[2][4];
                #pragma unroll
                for (int mi = 0; mi < 2; mi++) {
                    split_tf32(xin[rb[mi][0] + soff + kb + tig],     ah[mi][0], al[mi][0]);
                    split_tf32(xin[rb[mi][1] + soff + kb + tig],     ah[mi][1], al[mi][1]);
                    split_tf32(xin[rb[mi][0] + soff + kb + tig + 4], ah[mi][2], al[mi][2]);
                    split_tf32(xin[rb[mi][1] + soff + kb + tig + 4], ah[mi][3], al[mi][3]);
                }
                #pragma unroll
                for (int ni = 0; ni < 4; ni++) {
                    int oct = nh * 4 + ni;
                    float2 bw = __ldg(wf + (size_t)s * 1024 + kk * 256 + oct * 32 + lane);
                    unsigned bh0, bl0, bh1, bl1;
                    split_tf32(bw.x, bh0, bl0);
                    split_tf32(bw.y, bh1, bl1);
                    mma3(acc[0][ni], ah[0], al[0], bh0, bh1, bl0, bl1);
                    mma3(acc[1][ni], ah[1], al[1], bh0, bh1, bl0, bl1);
                }
            }
        }
    }

    #pragma unroll
    for (int mi = 0; mi < 2; mi++) {
        int rlo = rbase + mi * 16 + grp, rhi = rlo + 8;
        #pragma unroll
        for (int ni = 0; ni < 4; ni++) {
            int c0 = nh * 32 + ni * 8 + tig * 2;
            rs[rlo * 68 + c0]     = fmaxf(acc[mi][ni][0], 0.f);
            rs[rlo * 68 + c0 + 1] = fmaxf(acc[mi][ni][1], 0.f);
            rs[rhi * 68 + c0]     = fmaxf(acc[mi][ni][2], 0.f);
            rs[rhi * 68 + c0 + 1] = fmaxf(acc[mi][ni][3], 0.f);
        }
    }
    __syncthreads();

    float acc2[2][2][4];
    #pragma unroll
    for (int mi = 0; mi < 2; mi++)
        #pragma unroll
        for (int ni = 0; ni < 2; ni++)
            #pragma unroll
            for (int c = 0; c < 4; c++) acc2[mi][ni][c] = 0.f;

    #pragma unroll
    for (int kk = 0; kk < 8; kk++) {
        int kb = kk * 8;
        unsigned ah[2][4], al[2][4];
        #pragma unroll
        for (int mi = 0; mi < 2; mi++) {
            int rlo = rbase + mi * 16 + grp;
            split_tf32(rs[rlo * 68 + kb + tig],           ah[mi][0], al[mi][0]);
            split_tf32(rs[(rlo + 8) * 68 + kb + tig],     ah[mi][1], al[mi][1]);
            split_tf32(rs[rlo * 68 + kb + tig + 4],       ah[mi][2], al[mi][2]);
            split_tf32(rs[(rlo + 8) * 68 + kb + tig + 4], ah[mi][3], al[mi][3]);
        }
        #pragma unroll
        for (int ni = 0; ni < 2; ni++) {
            int c = nh * 16 + ni * 8 + grp;
            unsigned bh0, bl0, bh1, bl1;
            split_tf32(w2s[(kb + tig) * 36 + c],     bh0, bl0);
            split_tf32(w2s[(kb + tig + 4) * 36 + c], bh1, bl1);
            mma3(acc2[0][ni], ah[0], al[0], bh0, bh1, bl0, bl1);
            mma3(acc2[1][ni], ah[1], al[1], bh0, bh1, bl0, bl1);
        }
    }

    #pragma unroll
    for (int mi = 0; mi < 2; mi++) {
        #pragma unroll
        for (int ni = 0; ni < 2; ni++) {
            #pragma unroll
            for (int ci = 0; ci < 4; ci++) {
                int p = mh * 32 + mi * 16 + grp + ((ci >= 2) ? 8 : 0);
                if (p < 49) {
                    int ch = nh * 16 + ni * 8 + tig * 2 + (ci & 1);
                    size_t g = (size_t)(b0 + img) * 1568 + ch * 49 + p;
                    float v = acc2[mi][ni][ci] + __ldg(buf + g);
                    buf[g] = fmaxf(v, 0.f);
                }
            }
        }
    }
}

// ======================================================================
// res stack single-TF32 (decoder): fragment-texture weights [round-10]
// ======================================================================
#define D3_RS   5346
#define D3_W2   14050
#define D3_TOT  16354
#define D3_SMEM (D3_TOT * 4)     // 65416 B

__global__ void __launch_bounds__(256) res_tcd(
        float* __restrict__ buf,
        const float2* __restrict__ wf,
        const float* __restrict__ pw2) {
    extern __shared__ float sm[];
    float* xin = sm;
    float* rs  = sm + D3_RS;
    float* w2s = sm + D3_W2;
    int t = threadIdx.x;
    int b0 = blockIdx.x * 2;

    for (int i = t; i < D3_RS; i += 256) xin[i] = 0.f;
    __syncthreads();
    for (int i = t; i < 2048; i += 256) {
        int oc = i >> 6, ic = i & 63;
        w2s[ic * 36 + oc] = to_tf32(pw2[i]);
    }
    for (int i = t; i < 2 * 1568; i += 256) {
        int img = i / 1568, j = i % 1568;
        int ch = j / 49, p = j % 49;
        float v = buf[(size_t)(b0 + img) * 1568 + j];
        xin[img * 2673 + ((p / 7 + 1) * 9 + (p % 7 + 1)) * 33 + ch] =
            to_tf32(fmaxf(v, 0.f));
    }
    __syncthreads();

    int lane = t & 31, wrp = t >> 5;
    int grp = lane >> 2, tig = lane & 3;
    int img = wrp >> 2, mh = (wrp >> 1) & 1, nh = wrp & 1;
    int rbase = img * 64 + mh * 32;

    int rb[2][2];
    #pragma unroll
    for (int mi = 0; mi < 2; mi++)
        #pragma unroll
        for (int h = 0; h < 2; h++) {
            int p = mh * 32 + mi * 16 + grp + h * 8;
            rb[mi][h] = (p < 49) ? img * 2673 + ((p / 7) * 9 + (p % 7)) * 33 : 0;
        }

    float acc[2][4][4];
    #pragma unroll
    for (int mi = 0; mi < 2; mi++)
        #pragma unroll
        for (int ni = 0; ni < 4; ni++)
            #pragma unroll
            for (int c = 0; c < 4; c++) acc[mi][ni][c] = 0.f;

    #pragma unroll
    for (int ky = 0; ky < 3; ky++) {
        #pragma unroll
        for (int kx = 0; kx < 3; kx++) {
            int s = ky * 3 + kx;
            int soff = (ky * 9 + kx) * 33;
            #pragma unroll
            for (int kk = 0; kk < 4; kk++) {
                int kb = kk * 8;
                unsigned a[2][4];
                #pragma unroll
                for (int mi = 0; mi < 2; mi++) {
                    a[mi][0] = __float_as_uint(xin[rb[mi][0] + soff + kb + tig]);
                    a[mi][1] = __float_as_uint(xin[rb[mi][1] + soff + kb + tig]);
                    a[mi][2] = __float_as_uint(xin[rb[mi][0] + soff + kb + tig + 4]);
                    a[mi][3] = __float_as_uint(xin[rb[mi][1] + soff + kb + tig + 4]);
                }
                #pragma unroll
                for (int ni = 0; ni < 4; ni++) {
                    int oct = nh * 4 + ni;
                    float2 bw = __ldg(wf + (size_t)s * 1024 + kk * 256 + oct * 32 + lane);
                    unsigned bb0 = __float_as_uint(bw.x);
                    unsigned bb1 = __float_as_uint(bw.y);
                    mma_tf32(acc[0][ni], a[0], bb0, bb1);
                    mma_tf32(acc[1][ni], a[1], bb0, bb1);
                }
            }
        }
    }

    #pragma unroll
    for (int mi = 0; mi < 2; mi++) {
        int rlo = rbase + mi * 16 + grp, rhi = rlo + 8;
        #pragma unroll
        for (int ni = 0; ni < 4; ni++) {
            int c0 = nh * 32 + ni * 8 + tig * 2;
            rs[rlo * 68 + c0]     = to_tf32(fmaxf(acc[mi][ni][0], 0.f));
            rs[rlo * 68 + c0 + 1] = to_tf32(fmaxf(acc[mi][ni][1], 0.f));
            rs[rhi * 68 + c0]     = to_tf32(fmaxf(acc[mi][ni][2], 0.f));
            rs[rhi * 68 + c0 + 1] = to_tf32(fmaxf(acc[mi][ni][3], 0.f));
        }
    }
    __syncthreads();

    float acc2[2][2][4];
    #pragma unroll
    for (int mi = 0; mi < 2; mi++)
        #pragma unroll
        for (int ni = 0; ni < 2; ni++)
            #pragma unroll
            for (int c = 0; c < 4; c++) acc2[mi][ni][c] = 0.f;

    #pragma unroll
    for (int kk = 0; kk < 8; kk++) {
        int kb = kk * 8;
        unsigned a[2][4];
        #pragma unroll
        for (int mi = 0; mi < 2; mi++) {
            int rlo = rbase + mi * 16 + grp;
            a[mi][0] = __float_as_uint(rs[rlo * 68 + kb + tig]);
            a[mi][1] = __float_as_uint(rs[(rlo + 8) * 68 + kb + tig]);
            a[mi][2] = __float_as_uint(rs[rlo * 68 + kb + tig + 4]);
            a[mi][3] = __float_as_uint(rs[(rlo + 8) * 68 + kb + tig + 4]);
        }
        #pragma unroll
        for (int ni = 0; ni < 2; ni++) {
            int c = nh * 16 + ni * 8 + grp;
            unsigned bb0 = __float_as_uint(w2s[(kb + tig) * 36 + c]);
            unsigned bb1 = __float_as_uint(w2s[(kb + tig + 4) * 36 + c]);
            mma_tf32(acc2[0][ni], a[0], bb0, bb1);
            mma_tf32(acc2[1][ni], a[1], bb0, bb1);
        }
    }

    #pragma unroll
    for (int mi = 0; mi < 2; mi++) {
        #pragma unroll
        for (int ni = 0; ni < 2; ni++) {
            #pragma unroll
            for (int ci = 0; ci < 4; ci++) {
                int p = mh * 32 + mi * 16 + grp + ((ci >= 2) ? 8 : 0);
                if (p < 49) {
                    int ch = nh * 16 + ni * 8 + tig * 2 + (ci & 1);
                    size_t g = (size_t)(b0 + img) * 1568 + ch * 49 + p;
                    float v = acc2[mi][ni][ci] + __ldg(buf + g);
                    buf[g] = fmaxf(v, 0.f);
                }
            }
        }
    }
}

// ======================================================================
// TF32 GEMM (decoder fc4) with register-prefetch pipelining  [round-7]
// ======================================================================
__global__ void __launch_bounds__(256) gemm_tc(
        const float* __restrict__ A,
        const float* __restrict__ W,
        const float* __restrict__ bias,
        float* __restrict__ C,
        int M, int N, int K) {
    __shared__ float As[128][17];
    __shared__ float Ws[64][17];
    int t = threadIdx.x, lane = t & 31, w = t >> 5;
    int grp = lane >> 2, tig = lane & 3;
    int m0 = blockIdx.x * 128, n0 = blockIdx.y * 64;
    int mw = (w & 3) * 32, nw = (w >> 2) * 32;
    float acc[2][4][4];
    #pragma unroll
    for (int mi = 0; mi < 2; mi++)
        #pragma unroll
        for (int ni = 0; ni < 4; ni++)
            #pragma unroll
            for (int c = 0; c < 4; c++) acc[mi][ni][c] = 0.f;

    int ar = t >> 1, ak = (t & 1) * 8;
    int wr = t >> 2, wk = (t & 3) * 4;
    const float* apb = A + (size_t)(m0 + ar) * K + ak;
    bool wval = (n0 + wr < N);
    const float* wpb = W + (size_t)(n0 + wr) * K + wk;

    float4 v0 = *(const float4*)apb;
    float4 v1 = *(const float4*)(apb + 4);
    float4 wv = wval ? *(const float4*)wpb : make_float4(0.f, 0.f, 0.f, 0.f);

    for (int k0 = 0; k0 < K; k0 += 16) {
        As[ar][ak + 0] = to_tf32(v0.x); As[ar][ak + 1] = to_tf32(v0.y);
        As[ar][ak + 2] = to_tf32(v0.z); As[ar][ak + 3] = to_tf32(v0.w);
        As[ar][ak + 4] = to_tf32(v1.x); As[ar][ak + 5] = to_tf32(v1.y);
        As[ar][ak + 6] = to_tf32(v1.z); As[ar][ak + 7] = to_tf32(v1.w);
        Ws[wr][wk + 0] = to_tf32(wv.x); Ws[wr][wk + 1] = to_tf32(wv.y);
        Ws[wr][wk + 2] = to_tf32(wv.z); Ws[wr][wk + 3] = to_tf32(wv.w);
        __syncthreads();
        if (k0 + 16 < K) {
            v0 = *(const float4*)(apb + k0 + 16);
            v1 = *(const float4*)(apb + k0 + 20);
            wv = wval ? *(const float4*)(wpb + k0 + 16)
                      : make_float4(0.f, 0.f, 0.f, 0.f);
        }
        #pragma unroll
        for (int kk = 0; kk < 2; kk++) {
            int kb = kk * 8;
            unsigned a[2][4];
            #pragma unroll
            for (int mi = 0; mi < 2; mi++) {
                int r = mw + mi * 16 + grp;
                a[mi][0] = __float_as_uint(As[r][kb + tig]);
                a[mi][1] = __float_as_uint(As[r + 8][kb + tig]);
                a[mi][2] = __float_as_uint(As[r][kb + tig + 4]);
                a[mi][3] = __float_as_uint(As[r + 8][kb + tig + 4]);
            }
            #pragma unroll
            for (int ni = 0; ni < 4; ni++) {
                int n = nw + ni * 8 + grp;
                unsigned bb0 = __float_as_uint(Ws[n][kb + tig]);
                unsigned bb1 = __float_as_uint(Ws[n][kb + tig + 4]);
                mma_tf32(acc[0][ni], a[0], bb0, bb1);
                mma_tf32(acc[1][ni], a[1], bb0, bb1);
            }
        }
        __syncthreads();
    }
    #pragma unroll
    for (int mi = 0; mi < 2; mi++) {
        #pragma unroll
        for (int ni = 0; ni < 4; ni++) {
            #pragma unroll
            for (int ci = 0; ci < 4; ci++) {
                int r = m0 + mw + mi * 16 + grp + ((ci >= 2) ? 8 : 0);
                int n = n0 + nw + ni * 8 + tig * 2 + (ci & 1);
                if (n < N)
                    C[(size_t)r * N + n] = fmaxf(acc[mi][ni][ci] + bias[n], 0.f);
            }
        }
    }
}

// ======================================================================
// 3xTF32 GEMM (encoder fc1) with register-prefetch pipelining [round-8]
// ======================================================================
__global__ void __launch_bounds__(256) gemm_tc3(
        const float* __restrict__ A,
        const float* __restrict__ W,
        const float* __restrict__ bias,
        float* __restrict__ C,
        int M, int N, int K) {
    __shared__ float As[128][17];
    __shared__ float Ws[64][17];
    int t = threadIdx.x, lane = t & 31, w = t >> 5;
    int grp = lane >> 2, tig = lane & 3;
    int m0 = blockIdx.x * 128, n0 = blockIdx.y * 64;
    int mw = (w & 3) * 32, nw = (w >> 2) * 32;
    float acc[2][4][4];
    #pragma unroll
    for (int mi = 0; mi < 2; mi++)
        #pragma unroll
        for (int ni = 0; ni < 4; ni++)
            #pragma unroll
            for (int c = 0; c < 4; c++) acc[mi][ni][c] = 0.f;

    int ar = t >> 1, ak = (t & 1) * 8;
    int wr = t >> 2, wk = (t & 3) * 4;
    const float* apb = A + (size_t)(m0 + ar) * K + ak;
    bool wval = (n0 + wr < N);
    const float* wpb = W + (size_t)(n0 + wr) * K + wk;

    float4 v0 = *(const float4*)apb;
    float4 v1 = *(const float4*)(apb + 4);
    float4 wv = wval ? *(const float4*)wpb : make_float4(0.f, 0.f, 0.f, 0.f);

    for (int k0 = 0; k0 < K; k0 += 16) {
        As[ar][ak + 0] = v0.x; As[ar][ak + 1] = v0.y;
        As[ar][ak + 2] = v0.z; As[ar][ak + 3] = v0.w;
        As[ar][ak + 4] = v1.x; As[ar][ak + 5] = v1.y;
        As[ar][ak + 6] = v1.z; As[ar][ak + 7] = v1.w;
        Ws[wr][wk + 0] = wv.x; Ws[wr][wk + 1] = wv.y;
        Ws[wr][wk + 2] = wv.z; Ws[wr][wk + 3] = wv.w;
        __syncthreads();
        if (k0 + 16 < K) {
            v0 = *(const float4*)(apb + k0 + 16);
            v1 = *(const float4*)(apb + k0 + 20);
            wv = wval ? *(const float4*)(wpb + k0 + 16)
                      : make_float4(0.f, 0.f, 0.f, 0.f);
        }
        #pragma unroll
        for (int kk = 0; kk < 2; kk++) {
            int kb = kk * 8;
            unsigned ah[2][4], al[2][4];
            #pragma unroll
            for (int mi = 0; mi < 2; mi++) {
                int r = mw + mi * 16 + grp;
                split_tf32(As[r][kb + tig],         ah[mi][0], al[mi][0]);
                split_tf32(As[r + 8][kb + tig],     ah[mi][1], al[mi][1]);
                split_tf32(As[r][kb + tig + 4],     ah[mi][2], al[mi][2]);
                split_tf32(As[r + 8][kb + tig + 4], ah[mi][3], al[mi][3]);
            }
            #pragma unroll
            for (int ni = 0; ni < 4; ni++) {
                int n = nw + ni * 8 + grp;
                unsigned bh0, bl0, bh1, bl1;
                split_tf32(Ws[n][kb + tig],     bh0, bl0);
                split_tf32(Ws[n][kb + tig + 4], bh1, bl1);
                mma3(acc[0][ni], ah[0], al[0], bh0, bh1, bl0, bl1);
                mma3(acc[1][ni], ah[1], al[1], bh0, bh1, bl0, bl1);
            }
        }
        __syncthreads();
    }
    #pragma unroll
    for (int mi = 0; mi < 2; mi++) {
        #pragma unroll
        for (int ni = 0; ni < 4; ni++) {
            #pragma unroll
            for (int ci = 0; ci < 4; ci++) {
                int r = m0 + mw + mi * 16 + grp + ((ci >= 2) ? 8 : 0);
                int n = n0 + nw + ni * 8 + tig * 2 + (ci & 1);
                if (n < N)
                    C[(size_t)r * N + n] = fmaxf(acc[mi][ni][ci] + bias[n], 0.f);
            }
        }
    }
}

// ======================================================================
// convt2 inner body (compile-time tap tables)          [round-7 proven]
// ======================================================================
template<int DY0, int KY0, int DY1, int KY1,
         int DX0, int KX0, int DX1, int KX1>
__device__ __forceinline__ void ct2_body(
        const float* __restrict__ base, const float* __restrict__ w,
        float bv, float* __restrict__ outp, int m) {
    float acc[14];
    #pragma unroll
    for (int j = 0; j < 14; j++) acc[j] = bv;
    for (int ic = 0; ic < 16; ic++) {
        const float* xc = base + ic * 256;
        #pragma unroll
        for (int sy = 0; sy < 2; sy++) {
            int iy = m + (sy ? DY1 : DY0);
            float row[16];
            #pragma unroll
            for (int j = 0; j < 16; j++) row[j] = xc[(iy + 1) * 16 + j];
            {
                float wv = __ldg(w + ic * 16 + (sy ? KY1 : KY0) * 4 + KX0);
                #pragma unroll
                for (int n = 0; n < 14; n++) acc[n] += row[n + DX0 + 1] * wv;
            }
            {
                float wv = __ldg(w + ic * 16 + (sy ? KY1 : KY0) * 4 + KX1);
                #pragma unroll
                for (int n = 0; n < 14; n++) acc[n] += row[n + DX1 + 1] * wv;
            }
        }
    }
    #pragma unroll
    for (int n = 0; n < 14; n++) outp[2 * n] = acc[n];
}

// ======================================================================
// FUSED convt1+convt2 (decoder): h2[B,32,7,7] -> x_rec[B,1,28,28]
// convt1 mma epilogue writes relu'd h1 into padded smem hp; convt2
// (phase-decomposed, ct2_body) runs from hp. 2 img/CTA, 256 thr.
// ======================================================================
#define T12_IMSZ 2916
#define T12_ZB   6240
#define T12_XIN  6664
#define T12_W    T12_XIN
#define T12_HP   (T12_W + 16 * 32 * 24)   // 18952
#define T12_TOT  (T12_HP + 2 * 4096)      // 27144
#define T12_SMEM (T12_TOT * 4)            // 108576 B

__global__ void __launch_bounds__(256) convt12_tc(
        const float* __restrict__ in,
        const float* __restrict__ w,
        const float* __restrict__ bias,
        const float* __restrict__ c2w,
        const float* __restrict__ c2b,
        float* __restrict__ out) {
    extern __shared__ float sm[];
    float* xin = sm;
    float* wt  = sm + T12_W;
    float* hp  = sm + T12_HP;
    int t = threadIdx.x;
    int b0 = blockIdx.x * 2;

    for (int i = t; i < T12_XIN; i += 256) xin[i] = 0.f;
    for (int i = t; i < 8192; i += 256) hp[i] = 0.f;
    __syncthreads();
    for (int i = t; i < 2 * 1568; i += 256) {
        int img = i / 1568, j = i % 1568;
        int ic = j / 49, p = j % 49, iy = p / 7, ix = p % 7;
        xin[img * T12_IMSZ + ((iy + 1) * 9 + (ix + 1)) * 36 + ic] =
            to_tf32(in[(size_t)(b0 + img) * 1568 + j]);
    }
    for (int i = t; i < 32 * 256; i += 256) {
        int ic = i / 256, r = i % 256, oc = r / 16, s = r % 16;
        wt[s * 768 + ic * 24 + oc] = to_tf32(w[i]);
    }
    __syncthreads();

    // ---- convt1 mma phase [round-4 proven] ----
    int lane = t & 31, wrp = t >> 5;
    int grp = lane >> 2, tig = lane & 3;
    int img = wrp >> 2, ph = wrp & 3;
    int a = ph >> 1, bp = ph & 1;
    int dyv[2], kyv[2], dxv[2], kxv[2];
    if (a == 0) { dyv[0] = 0; kyv[0] = 1; dyv[1] = -1; kyv[1] = 3; }
    else        { dyv[0] = 1; kyv[0] = 0; dyv[1] =  0; kyv[1] = 2; }
    if (bp == 0) { dxv[0] = 0; kxv[0] = 1; dxv[1] = -1; kxv[1] = 3; }
    else         { dxv[0] = 1; kxv[0] = 0; dxv[1] =  0; kxv[1] = 2; }

    int rb[4][2];
    #pragma unroll
    for (int mi = 0; mi < 4; mi++)
        #pragma unroll
        for (int h = 0; h < 2; h++) {
            int p = mi * 16 + grp + h * 8;
            rb[mi][h] = (p < 49)
                ? img * T12_IMSZ + ((p / 7 + 1) * 9 + (p % 7 + 1)) * 36
                : T12_ZB;
        }

    float acc[4][2][4];
    #pragma unroll
    for (int mi = 0; mi < 4; mi++)
        #pragma unroll
        for (int ni = 0; ni < 2; ni++)
            #pragma unroll
            for (int c = 0; c < 4; c++) acc[mi][ni][c] = 0.f;

    #pragma unroll
    for (int sy = 0; sy < 2; sy++) {
        #pragma unroll
        for (int sx = 0; sx < 2; sx++) {
            int soff = (dyv[sy] * 9 + dxv[sx]) * 36;
            const float* wsl = wt + (kyv[sy] * 4 + kxv[sx]) * 768;
            #pragma unroll
            for (int kk = 0; kk < 4; kk++) {
                int kb = kk * 8;
                unsigned afr[4][4];
                #pragma unroll
                for (int mi = 0; mi < 4; mi++) {
                    afr[mi][0] = __float_as_uint(xin[rb[mi][0] + soff + kb + tig]);
                    afr[mi][1] = __float_as_uint(xin[rb[mi][1] + soff + kb + tig]);
                    afr[mi][2] = __float_as_uint(xin[rb[mi][0] + soff + kb + tig + 4]);
                    afr[mi][3] = __float_as_uint(xin[rb[mi][1] + soff + kb + tig + 4]);
                }
                #pragma unroll
                for (int ni = 0; ni < 2; ni++) {
                    unsigned bb0 = __float_as_uint(wsl[(kb + tig) * 24 + ni * 8 + grp]);
                    unsigned bb1 = __float_as_uint(wsl[(kb + tig + 4) * 24 + ni * 8 + grp]);
                    #pragma unroll
                    for (int mi = 0; mi < 4; mi++)
                        mma_tf32(acc[mi][ni], afr[mi], bb0, bb1);
                }
            }
        }
    }

    // epilogue -> padded smem hp [img][oc][16][16] (halo 1), relu
    #pragma unroll
    for (int mi = 0; mi < 4; mi++) {
        #pragma unroll
        for (int ni = 0; ni < 2; ni++) {
            #pragma unroll
            for (int ci = 0; ci < 4; ci++) {
                int p = mi * 16 + grp + ((ci >= 2) ? 8 : 0);
                if (p < 49) {
                    int m = p / 7, n = p % 7;
                    int oc = ni * 8 + tig * 2 + (ci & 1);
                    int oy = 2 * m + a, ox = 2 * n + bp;
                    float v = acc[mi][ni][ci] + __ldg(bias + oc);
                    hp[img * 4096 + oc * 256 + (oy + 1) * 16 + (ox + 1)] =
                        fmaxf(v, 0.f);
                }
            }
        }
    }
    __syncthreads();

    // ---- convt2 phase (ct2_body, from hp) ----
    if (t < 112) {
        int ph2 = t / 28, r2 = t % 28;
        int img2 = r2 / 14, m2 = r2 % 14;
        int a2 = ph2 >> 1, b2 = ph2 & 1;
        const float* base2 = hp + img2 * 4096;
        float bv2 = c2b[0];
        float* outp = out + (size_t)(b0 + img2) * 784 + (2 * m2 + a2) * 28 + b2;
        if (ph2 == 0)      ct2_body<0, 1, -1, 3,  0, 1, -1, 3>(base2, c2w, bv2, outp, m2);
        else if (ph2 == 1) ct2_body<0, 1, -1, 3,  1, 0,  0, 2>(base2, c2w, bv2, outp, m2);
        else if (ph2 == 2) ct2_body<1, 0,  0, 2,  0, 1, -1, 3>(base2, c2w, bv2, outp, m2);
        else               ct2_body<1, 0,  0, 2,  1, 0,  0, 2>(base2, c2w, bv2, outp, m2);
    }
}

// ======================================================================
// fc2: z[B,32] = A[B,224] @ w^T + b  (fp32, feeds VQ)   [round-8]
// ======================================================================
__global__ void __launch_bounds__(256) fc2_kernel(
        const float* __restrict__ A,
        const float* __restrict__ w,
        const float* __restrict__ bias,
        float* __restrict__ out) {
    __shared__ float ws[32 * 224];
    int t = threadIdx.x;
    for (int i = t; i < 7168; i += 256) ws[i] = w[i];
    __syncthreads();
    int n = t & 31, r = t >> 5;
    float bv = bias[n];
    const float* wp = ws + n * 224;
    #pragma unroll
    for (int rr = 0; rr < 4; rr++) {
        int b = blockIdx.x * 32 + rr * 8 + r;
        const float* ap = A + (size_t)b * 224;
        float acc = bv;
        #pragma unroll 8
        for (int k = 0; k < 224; k++) acc += ap[k] * wp[k];
        out[(size_t)b * 32 + n] = acc;
    }
}

// ======================================================================
// VQ helpers (fp32 exact)
// ======================================================================
__global__ void enorm_kernel(const float* __restrict__ emb, float* __restrict__ enorm) {
    int e = blockIdx.x * blockDim.x + threadIdx.x;
    if (e < NE) {
        float s = 0.f;
        #pragma unroll
        for (int d = 0; d < ZD; d++) { float v = emb[e * ZD + d]; s += v * v; }
        enorm[e] = s;
    }
}

__global__ void zero_kernel(float* __restrict__ counts, float* __restrict__ sums,
                            float* __restrict__ loss) {
    int i = blockIdx.x * blockDim.x + threadIdx.x;
    if (i < NE) counts[i] = 0.f;
    if (i < NE * ZD) sums[i] = 0.f;
    if (i == 0) loss[0] = 0.f;
}

#define VQ_SMEM (NE * 36 * 4)

__global__ void __launch_bounds__(256) vq_kernel(
        const float* __restrict__ z,
        const float* __restrict__ emb,
        const float* __restrict__ enorm,
        int* __restrict__ idx,
        float* __restrict__ counts,
        float* __restrict__ sums,
        float* __restrict__ loss) {
    extern __shared__ float es[];          // [512][36]
    __shared__ float en[NE];
    __shared__ float zs[8][ZD];
    int t = threadIdx.x, lane = t & 31, wl = t >> 5;
    for (int i = t; i < NE * ZD; i += 256) {
        int e = i >> 5, d = i & 31;
        es[e * 36 + d] = emb[i];
    }
    for (int i = t; i < NE; i += 256) en[i] = enorm[i];
    __syncthreads();

    for (int rr = 0; rr < 8; rr++) {
        int row = blockIdx.x * 64 + wl * 8 + rr;
        zs[wl][lane] = z[(size_t)row * ZD + lane];
        __syncwarp();
        float best = 3.4e38f; int bi = NE;
        for (int e = lane; e < NE; e += 32) {
            const float* ep = es + e * 36;
            float dot = 0.f;
            #pragma unroll
            for (int d = 0; d < ZD; d += 4) {
                float4 v = *(const float4*)(ep + d);
                dot += zs[wl][d + 0] * v.x;
                dot += zs[wl][d + 1] * v.y;
                dot += zs[wl][d + 2] * v.z;
                dot += zs[wl][d + 3] * v.w;
            }
            float s = en[e] - 2.f * dot;
            if (s < best) { best = s; bi = e; }
        }
        #pragma unroll
        for (int off = 16; off; off >>= 1) {
            float ob = __shfl_xor_sync(0xffffffffu, best, off);
            int   oi = __shfl_xor_sync(0xffffffffu, bi, off);
            if (ob < best || (ob == best && oi < bi)) { best = ob; bi = oi; }
        }
        float zl = zs[wl][lane];
        float diff = es[bi * 36 + lane] - zl;
        float d2 = diff * diff;
        #pragma unroll
        for (int off = 16; off; off >>= 1)
            d2 += __shfl_xor_sync(0xffffffffu, d2, off);
        if (lane == 0) {
            idx[row] = bi;
            atomicAdd(&counts[bi], 1.f);
            atomicAdd(loss, d2);
        }
        atomicAdd(&sums[bi * ZD + lane], zl);
        __syncwarp();
    }
}

__global__ void embnew_kernel(const float* __restrict__ m_mat,
                              const float* __restrict__ n_mat,
                              const float* __restrict__ sums,
                              const float* __restrict__ counts,
                              float* __restrict__ out) {
    int i = blockIdx.x * blockDim.x + threadIdx.x;
    if (i < NE * ZD) {
        int e = i >> 5;
        float m = m_mat[i] * GAMMA + sums[i] * ONE_M_GAMMA;
        float n = n_mat[e] * GAMMA + counts[e] * ONE_M_GAMMA;
        out[i] = m / n;
    }
}

__global__ void finalize_kernel(const float* __restrict__ counts,
                                const float* __restrict__ loss,
                                float* __restrict__ out_scalars) {
    __shared__ float red[NE];
    int t = threadIdx.x;
    float c = counts[t];
    float em = c * (1.f / (float)BATCH);
    red[t] = em * logf(em + 1e-10f);
    __syncthreads();
    for (int s = 256; s; s >>= 1) {
        if (t < s) red[t] += red[t + s];
        __syncthreads();
    }
    if (t == 0) {
        float q = loss[0] * (1.f / ((float)BATCH * (float)ZD));
        out_scalars[0] = q;
        out_scalars[1] = BETA * q;
        out_scalars[2] = expf(-red[0]);
    }
}

// ======================================================================
// fc3 (fp32): 16 images/CTA                           [round-8, proven]
// ======================================================================
__global__ void __launch_bounds__(224) fc3_kernel(
        const float* __restrict__ emb,
        const int* __restrict__ idx,
        const float* __restrict__ w,
        const float* __restrict__ bias,
        float* __restrict__ out) {
    __shared__ float ws[224 * ZD];
    __shared__ float zq[16][ZD + 1];
    int b0 = blockIdx.x * 16, t = threadIdx.x;
    for (int i = t; i < 224 * ZD; i += 224) ws[i] = w[i];
    for (int i = t; i < 16 * ZD; i += 224) {
        int im = i >> 5, d = i & 31;
        zq[im][d] = emb[(size_t)idx[b0 + im] * ZD + d];
    }
    __syncthreads();
    float bv = bias[t];
    float wreg[ZD];
    const float* wp = ws + t * ZD;
    #pragma unroll
    for (int k = 0; k < ZD; k++) wreg[k] = wp[k];
    #pragma unroll 4
    for (int im = 0; im < 16; im++) {
        float acc = bv;
        #pragma unroll
        for (int k = 0; k < ZD; k++) acc += zq[im][k] * wreg[k];
        out[(size_t)(b0 + im) * 224 + t] = fmaxf(acc, 0.f);
    }
}

// ======================================================================
// launch
// ======================================================================
extern "C" void kernel_launch(void* const* d_in, const int* in_sizes, int n_in,
                              void* d_out, int out_size) {
    const float* x        = (const float*)d_in[0];
    const float* conv1_w  = (const float*)d_in[1];
    const float* conv1_b  = (const float*)d_in[2];
    const float* conv2_w  = (const float*)d_in[3];
    const float* conv2_b  = (const float*)d_in[4];
    const float* res1_w1  = (const float*)d_in[5];
    const float* res1_w2  = (const float*)d_in[6];
    const float* fc1_w    = (const float*)d_in[7];
    const float* fc1_b    = (const float*)d_in[8];
    const float* fc2_w    = (const float*)d_in[9];
    const float* fc2_b    = (const float*)d_in[10];
    const float* emb      = (const float*)d_in[11];
    const float* n_mat    = (const float*)d_in[12];
    const float* m_mat    = (const float*)d_in[13];
    const float* fc3_w    = (const float*)d_in[14];
    const float* fc3_b    = (const float*)d_in[15];
    const float* fc4_w    = (const float*)d_in[16];
    const float* fc4_b    = (const float*)d_in[17];
    const float* res2_w1  = (const float*)d_in[18];
    const float* res2_w2  = (const float*)d_in[19];
    const float* convt1_w = (const float*)d_in[20];
    const float* convt1_b = (const float*)d_in[21];
    const float* convt2_w = (const float*)d_in[22];
    const float* convt2_b = (const float*)d_in[23];
    float* out = (float*)d_out;

    float *h2, *a, *z, *enorm, *counts, *sums, *loss;
    int* idx;
    float2 *wf_r1, *wf_r2, *wf_c2;
    cudaGetSymbolAddress((void**)&h2,     g_h2);
    cudaGetSymbolAddress((void**)&a,      g_a);
    cudaGetSymbolAddress((void**)&z,      g_z);
    cudaGetSymbolAddress((void**)&idx,    g_idx);
    cudaGetSymbolAddress((void**)&enorm,  g_enorm);
    cudaGetSymbolAddress((void**)&counts, g_counts);
    cudaGetSymbolAddress((void**)&sums,   g_sums);
    cudaGetSymbolAddress((void**)&loss,   g_loss);
    cudaGetSymbolAddress((void**)&wf_r1,  g_wf_r1);
    cudaGetSymbolAddress((void**)&wf_r2,  g_wf_r2);
    cudaGetSymbolAddress((void**)&wf_c2,  g_wf_c2);

    cudaFuncSetAttribute(conv12_tc3,
                         cudaFuncAttributeMaxDynamicSharedMemorySize, C12_SMEM);
    cudaFuncSetAttribute(res_tc3,
                         cudaFuncAttributeMaxDynamicSharedMemorySize, E3_SMEM);
    cudaFuncSetAttribute(res_tcd,
                         cudaFuncAttributeMaxDynamicSharedMemorySize, D3_SMEM);
    cudaFuncSetAttribute(convt12_tc,
                         cudaFuncAttributeMaxDynamicSharedMemorySize, T12_SMEM);
    cudaFuncSetAttribute(vq_kernel,
                         cudaFuncAttributeMaxDynamicSharedMemorySize, VQ_SMEM);

    // weight repack (fragment-order textures)
    repack_res<<<36, 256>>>(res1_w1, wf_r1, 0);
    repack_res<<<36, 256>>>(res2_w1, wf_r2, 1);
    repack_c2 <<<16, 256>>>(conv2_w, wf_c2);

    // encoder (3xTF32 = fp32-class accuracy; VQ path preserved)
    conv12_tc3<<<BATCH / 2, 256, C12_SMEM>>>(x, conv1_w, conv1_b, wf_c2,
                                             conv2_b, h2);
    res_tc3  <<<BATCH / 2, 256, E3_SMEM>>>(h2, wf_r1, res1_w2);
    gemm_tc3<<<dim3(BATCH / 128, 4), 256>>>(h2, fc1_w, fc1_b, a,
                                            BATCH, 224, 1568);
    fc2_kernel<<<BATCH / 32, 256>>>(a, fc2_w, fc2_b, z);

    // VQ
    zero_kernel <<<(NE * ZD + 255) / 256, 256>>>(counts, sums, loss);
    enorm_kernel<<<2, 256>>>(emb, enorm);
    vq_kernel   <<<BATCH / 64, 256, VQ_SMEM>>>(z, emb, enorm, idx, counts,
                                               sums, loss);
    embnew_kernel  <<<(NE * ZD + 255) / 256, 256>>>(m_mat, n_mat, sums, counts,
                                                    out + OFF_SCAL + 3);
    finalize_kernel<<<1, NE>>>(counts, loss, out + OFF_SCAL);

    // decoder (single tf32)
    fc3_kernel<<<BATCH / 16, 224>>>(emb, idx, fc3_w, fc3_b, a);
    gemm_tc<<<dim3(BATCH / 128, 25), 256>>>(a, fc4_w, fc4_b, h2,
                                            BATCH, 1568, 224);
    res_tcd<<<BATCH / 2, 256, D3_SMEM>>>(h2, wf_r2, res2_w2);
    convt12_tc<<<BATCH / 2, 256, T12_SMEM>>>(h2, convt1_w, convt1_b,
                                             convt2_w, convt2_b, out);
}

// round 13
// speedup vs baseline: 2.4853x; 1.0058x over previous
#include <cuda_runtime.h>
#include <cstdint>
#include <math.h>

// ---------------- problem constants ----------------
#define BATCH 16384
#define ZD 32
#define NE 512
#define GAMMA 0.99f
#define ONE_M_GAMMA 0.01f
#define BETA 1.0f

#define OFF_SCAL (BATCH * 784)   // x_rec size
// d_out layout: [x_rec (B*784)][quant][commit][perplexity][emb_new (512*32)]

// ---------------- scratch ----------------
__device__ float g_h2[BATCH * 32 * 7 * 7];
__device__ float g_a [BATCH * 224];
__device__ float g_z [BATCH * ZD];
__device__ int   g_idx[BATCH];
__device__ float g_enorm[NE];
__device__ float g_counts[NE];
__device__ float g_sums[NE * ZD];
__device__ float g_loss[1];
// fragment-order weight textures: [s][kk][oct][lane] -> (b0,b1)
__device__ float2 g_wf_r1[9216];   // res1 w1 (raw fp32)
__device__ float2 g_wf_r2[9216];   // res2 w1 (tf32)
__device__ float2 g_wf_c2[4096];   // conv2 w  (raw fp32)

// ---------------- tf32 mma helpers ----------------
__device__ __forceinline__ float to_tf32(float x) {
    float y;
    asm("cvt.rna.tf32.f32 %0, %1;" : "=f"(y) : "f"(x));
    return y;
}

// Bitwise hi/lo split: hi = RZ-truncated tf32 (LOP3), lo = v - hi (exact FADD).
__device__ __forceinline__ void split_tf32(float v, unsigned& hi, unsigned& lo) {
    unsigned h = __float_as_uint(v) & 0xffffe000u;
    hi = h;
    lo = __float_as_uint(v - __uint_as_float(h));
}

__device__ __forceinline__ void mma_tf32(float* d, const unsigned* a,
                                         unsigned b0, unsigned b1) {
    asm volatile(
        "mma.sync.aligned.m16n8k8.row.col.f32.tf32.tf32.f32 "
        "{%0,%1,%2,%3}, {%4,%5,%6,%7}, {%8,%9}, {%0,%1,%2,%3};\n"
        : "+f"(d[0]), "+f"(d[1]), "+f"(d[2]), "+f"(d[3])
        : "r"(a[0]), "r"(a[1]), "r"(a[2]), "r"(a[3]), "r"(b0), "r"(b1));
}

// 3-pass split mma: acc += a*b with ~fp32 accuracy
__device__ __forceinline__ void mma3(float* d, const unsigned* ah, const unsigned* al,
                                     unsigned bh0, unsigned bh1,
                                     unsigned bl0, unsigned bl1) {
    mma_tf32(d, ah, bl0, bl1);
    mma_tf32(d, al, bh0, bh1);
    mma_tf32(d, ah, bh0, bh1);
}

// ======================================================================
// weight repack kernels (run once per launch; tiny)
// ======================================================================
__global__ void repack_res(const float* __restrict__ w1,
                           float2* __restrict__ out, int cvt) {
    int i = blockIdx.x * 256 + threadIdx.x;
    if (i >= 9216) return;
    int lane = i & 31, oct = (i >> 5) & 7, kk = (i >> 8) & 3, s = i >> 10;
    int grp = lane >> 2, tig = lane & 3;
    int oc = oct * 8 + grp, ic = kk * 8 + tig;
    float b0 = w1[oc * 288 + ic * 9 + s];
    float b1 = w1[oc * 288 + (ic + 4) * 9 + s];
    if (cvt) { b0 = to_tf32(b0); b1 = to_tf32(b1); }
    out[i] = make_float2(b0, b1);
}

__global__ void repack_c2(const float* __restrict__ w,
                          float2* __restrict__ out) {
    int i = blockIdx.x * 256 + threadIdx.x;
    if (i >= 4096) return;
    int lane = i & 31, oct = (i >> 5) & 3, kk = (i >> 7) & 1, s = i >> 8;
    int grp = lane >> 2, tig = lane & 3;
    int oc = oct * 8 + grp, ic = kk * 8 + tig;
    out[i] = make_float2(w[oc * 256 + ic * 16 + s],
                         w[oc * 256 + (ic + 4) * 16 + s]);
}

// ======================================================================
// FUSED conv1+conv2 (encoder)                           [round-12 proven]
// ======================================================================
#define C12_ZOFF 9216
#define C12_XIN  13824
#define C12_XP   13824
#define C12_W1   (C12_XP + 1800)
#define C12_B1   (C12_W1 + 256)
#define C12_TOT  15896
#define C12_SMEM (C12_TOT * 4)

__global__ void __launch_bounds__(256) conv12_tc3(
        const float* __restrict__ x,
        const float* __restrict__ c1wg,
        const float* __restrict__ c1bg,
        const float2* __restrict__ wf,
        const float* __restrict__ bias,
        float* __restrict__ out) {
    extern __shared__ float sm[];
    float* xin = sm;
    float* xp  = sm + C12_XP;
    float* c1w = sm + C12_W1;
    float* c1b = sm + C12_B1;
    int t = threadIdx.x;
    int b0 = blockIdx.x * 2;

    for (int i = t; i < C12_XIN; i += 256) xin[i] = 0.f;
    for (int i = t; i < 1800; i += 256) xp[i] = 0.f;
    if (t < 256) c1w[t] = c1wg[t];
    if (t < 16)  c1b[t] = c1bg[t];
    __syncthreads();
    for (int i = t; i < 1568; i += 256) {
        int im = i / 784, j = i % 784;
        int iy = j / 28, ix = j % 28;
        xp[im * 900 + (iy + 1) * 30 + (ix + 1)] = x[(size_t)(b0 + im) * 784 + j];
    }
    __syncthreads();

    for (int pi = t; pi < 392; pi += 256) {
        int im = pi / 196, pix = pi % 196;
        int oy = pix / 14, ox = pix % 14;
        const float* basep = xp + im * 900 + (2 * oy) * 30 + 2 * ox;
        float patch[16];
        #pragma unroll
        for (int ky = 0; ky < 4; ky++)
            #pragma unroll
            for (int kx = 0; kx < 4; kx++)
                patch[ky * 4 + kx] = basep[ky * 30 + kx];
        float* dst = xin + im * 4608 + ((oy + 1) * 16 + (ox + 1)) * 18;
        #pragma unroll
        for (int oc = 0; oc < 16; oc++) {
            float acc = c1b[oc];
            #pragma unroll
            for (int tap = 0; tap < 16; tap++)
                acc += patch[tap] * c1w[oc * 16 + tap];
            dst[oc] = fmaxf(acc, 0.f);
        }
    }
    __syncthreads();

    int lane = t & 31, wrp = t >> 5;
    int grp = lane >> 2, tig = lane & 3;
    int img = wrp >> 2, mh = (wrp >> 1) & 1, nh = wrp & 1;

    int rb[2][2];
    #pragma unroll
    for (int mi = 0; mi < 2; mi++)
        #pragma unroll
        for (int h = 0; h < 2; h++) {
            int p = mh * 32 + mi * 16 + grp + h * 8;
            rb[mi][h] = (p < 49)
                ? img * 4608 + ((p / 7) * 32 + (p % 7) * 2) * 18
                : C12_ZOFF;
        }

    float acc[2][2][4];
    #pragma unroll
    for (int mi = 0; mi < 2; mi++)
        #pragma unroll
        for (int ni = 0; ni < 2; ni++)
            #pragma unroll
            for (int c = 0; c < 4; c++) acc[mi][ni][c] = 0.f;

    #pragma unroll
    for (int ky = 0; ky < 4; ky++) {
        #pragma unroll
        for (int kx = 0; kx < 4; kx++) {
            int s = ky * 4 + kx;
            int soff = (ky * 16 + kx) * 18;
            #pragma unroll
            for (int kk = 0; kk < 2; kk++) {
                int kb = kk * 8;
                unsigned ah[2][4], al[2][4];
                #pragma unroll
                for (int mi = 0; mi < 2; mi++) {
                    split_tf32(xin[rb[mi][0] + soff + kb + tig],     ah[mi][0], al[mi][0]);
                    split_tf32(xin[rb[mi][1] + soff + kb + tig],     ah[mi][1], al[mi][1]);
                    split_tf32(xin[rb[mi][0] + soff + kb + tig + 4], ah[mi][2], al[mi][2]);
                    split_tf32(xin[rb[mi][1] + soff + kb + tig + 4], ah[mi][3], al[mi][3]);
                }
                #pragma unroll
                for (int ni = 0; ni < 2; ni++) {
                    int oct = nh * 2 + ni;
                    float2 bw = __ldg(wf + (size_t)s * 256 + kk * 128 + oct * 32 + lane);
                    unsigned bh0, bl0, bh1, bl1;
                    split_tf32(bw.x, bh0, bl0);
                    split_tf32(bw.y, bh1, bl1);
                    mma3(acc[0][ni], ah[0], al[0], bh0, bh1, bl0, bl1);
                    mma3(acc[1][ni], ah[1], al[1], bh0, bh1, bl0, bl1);
                }
            }
        }
    }

    #pragma unroll
    for (int mi = 0; mi < 2; mi++) {
        #pragma unroll
        for (int ni = 0; ni < 2; ni++) {
            #pragma unroll
            for (int ci = 0; ci < 4; ci++) {
                int p = mh * 32 + mi * 16 + grp + ((ci >= 2) ? 8 : 0);
                if (p < 49) {
                    int oc = nh * 16 + ni * 8 + tig * 2 + (ci & 1);
                    out[(size_t)(b0 + img) * 1568 + oc * 49 + p] =
                        acc[mi][ni][ci] + __ldg(bias + oc);
                }
            }
        }
    }
}

// ======================================================================
// res stack 3xTF32 (encoder)                           [round-10 proven]
// ======================================================================
#define E3_RS   5832
#define E3_W2   14536
#define E3_TOT  16840
#define E3_SMEM (E3_TOT * 4)

__global__ void __launch_bounds__(256) res_tc3(
        float* __restrict__ buf,
        const float2* __restrict__ wf,
        const float* __restrict__ pw2) {
    extern __shared__ float sm[];
    float* xin = sm;
    float* rs  = sm + E3_RS;
    float* w2s = sm + E3_W2;
    int t = threadIdx.x;
    int b0 = blockIdx.x * 2;

    for (int i = t; i < E3_RS; i += 256) xin[i] = 0.f;
    __syncthreads();
    for (int i = t; i < 2048; i += 256) {
        int oc = i >> 6, ic = i & 63;
        w2s[ic * 36 + oc] = pw2[i];
    }
    for (int i = t; i < 2 * 1568; i += 256) {
        int img = i / 1568, j = i % 1568;
        int ch = j / 49, p = j % 49;
        float v = buf[(size_t)(b0 + img) * 1568 + j];
        xin[img * 2916 + ((p / 7 + 1) * 9 + (p % 7 + 1)) * 36 + ch] = fmaxf(v, 0.f);
    }
    __syncthreads();

    int lane = t & 31, wrp = t >> 5;
    int grp = lane >> 2, tig = lane & 3;
    int img = wrp >> 2, mh = (wrp >> 1) & 1, nh = wrp & 1;
    int rbase = img * 64 + mh * 32;

    int rb[2][2];
    #pragma unroll
    for (int mi = 0; mi < 2; mi++)
        #pragma unroll
        for (int h = 0; h < 2; h++) {
            int p = mh * 32 + mi * 16 + grp + h * 8;
            rb[mi][h] = (p < 49) ? img * 2916 + ((p / 7) * 9 + (p % 7)) * 36 : 0;
        }

    float acc[2][4][4];
    #pragma unroll
    for (int mi = 0; mi < 2; mi++)
        #pragma unroll
        for (int ni = 0; ni < 4; ni++)
            #pragma unroll
            for (int c = 0; c < 4; c++) acc[mi][ni][c] = 0.f;

    #pragma unroll
    for (int ky = 0; ky < 3; ky++) {
        #pragma unroll
        for (int kx = 0; kx < 3; kx++) {
            int s = ky * 3 + kx;
            int soff = (ky * 9 + kx) * 36;
            #pragma unroll
            for (int kk = 0; kk < 4; kk++) {
                int kb = kk * 8;
                unsigned ah[2][4], al[2][4];
                #pragma unroll
                for (int mi = 0; mi < 2; mi++) {
                    split_tf32(xin[rb[mi][0] + soff + kb + tig],     ah[mi][0], al[mi][0]);
                    split_tf32(xin[rb[mi][1] + soff + kb + tig],     ah[mi][1], al[mi][1]);
                    split_tf32(xin[rb[mi][0] + soff + kb + tig + 4], ah[mi][2], al[mi][2]);
                    split_tf32(xin[rb[mi][1] + soff + kb + tig + 4], ah[mi][3], al[mi][3]);
                }
                #pragma unroll
                for (int ni = 0; ni < 4; ni++) {
                    int oct = nh * 4 + ni;
                    float2 bw = __ldg(wf + (size_t)s * 1024 + kk * 256 + oct * 32 + lane);
                    unsigned bh0, bl0, bh1, bl1;
                    split_tf32(bw.x, bh0, bl0);
                    split_tf32(bw.y, bh1, bl1);
                    mma3(acc[0][ni], ah[0], al[0], bh0, bh1, bl0, bl1);
                    mma3(acc[1][ni], ah[1], al[1], bh0, bh1, bl0, bl1);
                }
            }
        }
    }

    #pragma unroll
    for (int mi = 0; mi < 2; mi++) {
        int rlo = rbase + mi * 16 + grp, rhi = rlo + 8;
        #pragma unroll
        for (int ni = 0; ni < 4; ni++) {
            int c0 = nh * 32 + ni * 8 + tig * 2;
            rs[rlo * 68 + c0]     = fmaxf(acc[mi][ni][0], 0.f);
            rs[rlo * 68 + c0 + 1] = fmaxf(acc[mi][ni][1], 0.f);
            rs[rhi * 68 + c0]     = fmaxf(acc[mi][ni][2], 0.f);
            rs[rhi * 68 + c0 + 1] = fmaxf(acc[mi][ni][3], 0.f);
        }
    }
    __syncthreads();

    float acc2[2][2][4];
    #pragma unroll
    for (int mi = 0; mi < 2; mi++)
        #pragma unroll
        for (int ni = 0; ni < 2; ni++)
            #pragma unroll
            for (int c = 0; c < 4; c++) acc2[mi][ni][c] = 0.f;

    #pragma unroll
    for (int kk = 0; kk < 8; kk++) {
        int kb = kk * 8;
        unsigned ah[2][4], al[2][4];
        #pragma unroll
        for (int mi = 0; mi < 2; mi++) {
            int rlo = rbase + mi * 16 + grp;
            split_tf32(rs[rlo * 68 + kb + tig],           ah[mi][0], al[mi][0]);
            split_tf32(rs[(rlo + 8) * 68 + kb + tig],     ah[mi][1], al[mi][1]);
            split_tf32(rs[rlo * 68 + kb + tig + 4],       ah[mi][2], al[mi][2]);
            split_tf32(rs[(rlo + 8) * 68 + kb + tig + 4], ah[mi][3], al[mi][3]);
        }
        #pragma unroll
        for (int ni = 0; ni < 2; ni++) {
            int c = nh * 16 + ni * 8 + grp;
            unsigned bh0, bl0, bh1, bl1;
            split_tf32(w2s[(kb + tig) * 36 + c],     bh0, bl0);
            split_tf32(w2s[(kb + tig + 4) * 36 + c], bh1, bl1);
            mma3(acc2[0][ni], ah[0], al[0], bh0, bh1, bl0, bl1);
            mma3(acc2[1][ni], ah[1], al[1], bh0, bh1, bl0, bl1);
        }
    }

    #pragma unroll
    for (int mi = 0; mi < 2; mi++) {
        #pragma unroll
        for (int ni = 0; ni < 2; ni++) {
            #pragma unroll
            for (int ci = 0; ci < 4; ci++) {
                int p = mh * 32 + mi * 16 + grp + ((ci >= 2) ? 8 : 0);
                if (p < 49) {
                    int ch = nh * 16 + ni * 8 + tig * 2 + (ci & 1);
                    size_t g = (size_t)(b0 + img) * 1568 + ch * 49 + p;
                    float v = acc2[mi][ni][ci] + __ldg(buf + g);
                    buf[g] = fmaxf(v, 0.f);
                }
            }
        }
    }
}

// ======================================================================
// res stack single-TF32 (decoder)                      [round-10 proven]
// ======================================================================
#define D3_RS   5346
#define D3_W2   14050
#define D3_TOT  16354
#define D3_SMEM (D3_TOT * 4)

__global__ void __launch_bounds__(256) res_tcd(
        float* __restrict__ buf,
        const float2* __restrict__ wf,
        const float* __restrict__ pw2) {
    extern __shared__ float sm[];
    float* xin = sm;
    float* rs  = sm + D3_RS;
    float* w2s = sm + D3_W2;
    int t = threadIdx.x;
    int b0 = blockIdx.x * 2;

    for (int i = t; i < D3_RS; i += 256) xin[i] = 0.f;
    __syncthreads();
    for (int i = t; i < 2048; i += 256) {
        int oc = i >> 6, ic = i & 63;
        w2s[ic * 36 + oc] = to_tf32(pw2[i]);
    }
    for (int i = t; i < 2 * 1568; i += 256) {
        int img = i / 1568, j = i % 1568;
        int ch = j / 49, p = j % 49;
        float v = buf[(size_t)(b0 + img) * 1568 + j];
        xin[img * 2673 + ((p / 7 + 1) * 9 + (p % 7 + 1)) * 33 + ch] =
            to_tf32(fmaxf(v, 0.f));
    }
    __syncthreads();

    int lane = t & 31, wrp = t >> 5;
    int grp = lane >> 2, tig = lane & 3;
    int img = wrp >> 2, mh = (wrp >> 1) & 1, nh = wrp & 1;
    int rbase = img * 64 + mh * 32;

    int rb[2][2];
    #pragma unroll
    for (int mi = 0; mi < 2; mi++)
        #pragma unroll
        for (int h = 0; h < 2; h++) {
            int p = mh * 32 + mi * 16 + grp + h * 8;
            rb[mi][h] = (p < 49) ? img * 2673 + ((p / 7) * 9 + (p % 7)) * 33 : 0;
        }

    float acc[2][4][4];
    #pragma unroll
    for (int mi = 0; mi < 2; mi++)
        #pragma unroll
        for (int ni = 0; ni < 4; ni++)
            #pragma unroll
            for (int c = 0; c < 4; c++) acc[mi][ni][c] = 0.f;

    #pragma unroll
    for (int ky = 0; ky < 3; ky++) {
        #pragma unroll
        for (int kx = 0; kx < 3; kx++) {
            int s = ky * 3 + kx;
            int soff = (ky * 9 + kx) * 33;
            #pragma unroll
            for (int kk = 0; kk < 4; kk++) {
                int kb = kk * 8;
                unsigned a[2][4];
                #pragma unroll
                for (int mi = 0; mi < 2; mi++) {
                    a[mi][0] = __float_as_uint(xin[rb[mi][0] + soff + kb + tig]);
                    a[mi][1] = __float_as_uint(xin[rb[mi][1] + soff + kb + tig]);
                    a[mi][2] = __float_as_uint(xin[rb[mi][0] + soff + kb + tig + 4]);
                    a[mi][3] = __float_as_uint(xin[rb[mi][1] + soff + kb + tig + 4]);
                }
                #pragma unroll
                for (int ni = 0; ni < 4; ni++) {
                    int oct = nh * 4 + ni;
                    float2 bw = __ldg(wf + (size_t)s * 1024 + kk * 256 + oct * 32 + lane);
                    unsigned bb0 = __float_as_uint(bw.x);
                    unsigned bb1 = __float_as_uint(bw.y);
                    mma_tf32(acc[0][ni], a[0], bb0, bb1);
                    mma_tf32(acc[1][ni], a[1], bb0, bb1);
                }
            }
        }
    }

    #pragma unroll
    for (int mi = 0; mi < 2; mi++) {
        int rlo = rbase + mi * 16 + grp, rhi = rlo + 8;
        #pragma unroll
        for (int ni = 0; ni < 4; ni++) {
            int c0 = nh * 32 + ni * 8 + tig * 2;
            rs[rlo * 68 + c0]     = to_tf32(fmaxf(acc[mi][ni][0], 0.f));
            rs[rlo * 68 + c0 + 1] = to_tf32(fmaxf(acc[mi][ni][1], 0.f));
            rs[rhi * 68 + c0]     = to_tf32(fmaxf(acc[mi][ni][2], 0.f));
            rs[rhi * 68 + c0 + 1] = to_tf32(fmaxf(acc[mi][ni][3], 0.f));
        }
    }
    __syncthreads();

    float acc2[2][2][4];
    #pragma unroll
    for (int mi = 0; mi < 2; mi++)
        #pragma unroll
        for (int ni = 0; ni < 2; ni++)
            #pragma unroll
            for (int c = 0; c < 4; c++) acc2[mi][ni][c] = 0.f;

    #pragma unroll
    for (int kk = 0; kk < 8; kk++) {
        int kb = kk * 8;
        unsigned a[2][4];
        #pragma unroll
        for (int mi = 0; mi < 2; mi++) {
            int rlo = rbase + mi * 16 + grp;
            a[mi][0] = __float_as_uint(rs[rlo * 68 + kb + tig]);
            a[mi][1] = __float_as_uint(rs[(rlo + 8) * 68 + kb + tig]);
            a[mi][2] = __float_as_uint(rs[rlo * 68 + kb + tig + 4]);
            a[mi][3] = __float_as_uint(rs[(rlo + 8) * 68 + kb + tig + 4]);
        }
        #pragma unroll
        for (int ni = 0; ni < 2; ni++) {
            int c = nh * 16 + ni * 8 + grp;
            unsigned bb0 = __float_as_uint(w2s[(kb + tig) * 36 + c]);
            unsigned bb1 = __float_as_uint(w2s[(kb + tig + 4) * 36 + c]);
            mma_tf32(acc2[0][ni], a[0], bb0, bb1);
            mma_tf32(acc2[1][ni], a[1], bb0, bb1);
        }
    }

    #pragma unroll
    for (int mi = 0; mi < 2; mi++) {
        #pragma unroll
        for (int ni = 0; ni < 2; ni++) {
            #pragma unroll
            for (int ci = 0; ci < 4; ci++) {
                int p = mh * 32 + mi * 16 + grp + ((ci >= 2) ? 8 : 0);
                if (p < 49) {
                    int ch = nh * 16 + ni * 8 + tig * 2 + (ci & 1);
                    size_t g = (size_t)(b0 + img) * 1568 + ch * 49 + p;
                    float v = acc2[mi][ni][ci] + __ldg(buf + g);
                    buf[g] = fmaxf(v, 0.f);
                }
            }
        }
    }
}

// ======================================================================
// TF32 GEMM (decoder fc4): double-buffered smem, ONE sync per k-tile
// ======================================================================
__global__ void __launch_bounds__(256) gemm_tc(
        const float* __restrict__ A,
        const float* __restrict__ W,
        const float* __restrict__ bias,
        float* __restrict__ C,
        int M, int N, int K) {
    __shared__ float As[2][128][17];
    __shared__ float Ws[2][64][17];
    int t = threadIdx.x, lane = t & 31, w = t >> 5;
    int grp = lane >> 2, tig = lane & 3;
    int m0 = blockIdx.x * 128, n0 = blockIdx.y * 64;
    int mw = (w & 3) * 32, nw = (w >> 2) * 32;
    float acc[2][4][4];
    #pragma unroll
    for (int mi = 0; mi < 2; mi++)
        #pragma unroll
        for (int ni = 0; ni < 4; ni++)
            #pragma unroll
            for (int c = 0; c < 4; c++) acc[mi][ni][c] = 0.f;

    int ar = t >> 1, ak = (t & 1) * 8;
    int wr = t >> 2, wk = (t & 3) * 4;
    const float* apb = A + (size_t)(m0 + ar) * K + ak;
    bool wval = (n0 + wr < N);
    const float* wpb = W + (size_t)(n0 + wr) * K + wk;

    float4 v0 = *(const float4*)apb;
    float4 v1 = *(const float4*)(apb + 4);
    float4 wv = wval ? *(const float4*)wpb : make_float4(0.f, 0.f, 0.f, 0.f);
    int s = 0;
    As[0][ar][ak + 0] = to_tf32(v0.x); As[0][ar][ak + 1] = to_tf32(v0.y);
    As[0][ar][ak + 2] = to_tf32(v0.z); As[0][ar][ak + 3] = to_tf32(v0.w);
    As[0][ar][ak + 4] = to_tf32(v1.x); As[0][ar][ak + 5] = to_tf32(v1.y);
    As[0][ar][ak + 6] = to_tf32(v1.z); As[0][ar][ak + 7] = to_tf32(v1.w);
    Ws[0][wr][wk + 0] = to_tf32(wv.x); Ws[0][wr][wk + 1] = to_tf32(wv.y);
    Ws[0][wr][wk + 2] = to_tf32(wv.z); Ws[0][wr][wk + 3] = to_tf32(wv.w);
    __syncthreads();

    for (int k0 = 0; k0 < K; k0 += 16) {
        bool more = (k0 + 16 < K);
        if (more) {
            v0 = *(const float4*)(apb + k0 + 16);
            v1 = *(const float4*)(apb + k0 + 20);
            wv = wval ? *(const float4*)(wpb + k0 + 16)
                      : make_float4(0.f, 0.f, 0.f, 0.f);
        }
        #pragma unroll
        for (int kk = 0; kk < 2; kk++) {
            int kb = kk * 8;
            unsigned a[2][4];
            #pragma unroll
            for (int mi = 0; mi < 2; mi++) {
                int r = mw + mi * 16 + grp;
                a[mi][0] = __float_as_uint(As[s][r][kb + tig]);
                a[mi][1] = __float_as_uint(As[s][r + 8][kb + tig]);
                a[mi][2] = __float_as_uint(As[s][r][kb + tig + 4]);
                a[mi][3] = __float_as_uint(As[s][r + 8][kb + tig + 4]);
            }
            #pragma unroll
            for (int ni = 0; ni < 4; ni++) {
                int n = nw + ni * 8 + grp;
                unsigned bb0 = __float_as_uint(Ws[s][n][kb + tig]);
                unsigned bb1 = __float_as_uint(Ws[s][n][kb + tig + 4]);
                mma_tf32(acc[0][ni], a[0], bb0, bb1);
                mma_tf32(acc[1][ni], a[1], bb0, bb1);
            }
        }
        if (more) {
            int d = s ^ 1;
            As[d][ar][ak + 0] = to_tf32(v0.x); As[d][ar][ak + 1] = to_tf32(v0.y);
            As[d][ar][ak + 2] = to_tf32(v0.z); As[d][ar][ak + 3] = to_tf32(v0.w);
            As[d][ar][ak + 4] = to_tf32(v1.x); As[d][ar][ak + 5] = to_tf32(v1.y);
            As[d][ar][ak + 6] = to_tf32(v1.z); As[d][ar][ak + 7] = to_tf32(v1.w);
            Ws[d][wr][wk + 0] = to_tf32(wv.x); Ws[d][wr][wk + 1] = to_tf32(wv.y);
            Ws[d][wr][wk + 2] = to_tf32(wv.z); Ws[d][wr][wk + 3] = to_tf32(wv.w);
            __syncthreads();
            s = d;
        }
    }
    #pragma unroll
    for (int mi = 0; mi < 2; mi++) {
        #pragma unroll
        for (int ni = 0; ni < 4; ni++) {
            #pragma unroll
            for (int ci = 0; ci < 4; ci++) {
                int r = m0 + mw + mi * 16 + grp + ((ci >= 2) ? 8 : 0);
                int n = n0 + nw + ni * 8 + tig * 2 + (ci & 1);
                if (n < N)
                    C[(size_t)r * N + n] = fmaxf(acc[mi][ni][ci] + bias[n], 0.f);
            }
        }
    }
}

// ======================================================================
// 3xTF32 GEMM (encoder fc1): double-buffered smem, ONE sync per k-tile
// ======================================================================
__global__ void __launch_bounds__(256) gemm_tc3(
        const float* __restrict__ A,
        const float* __restrict__ W,
        const float* __restrict__ bias,
        float* __restrict__ C,
        int M, int N, int K) {
    __shared__ float As[2][128][17];
    __shared__ float Ws[2][64][17];
    int t = threadIdx.x, lane = t & 31, w = t >> 5;
    int grp = lane >> 2, tig = lane & 3;
    int m0 = blockIdx.x * 128, n0 = blockIdx.y * 64;
    int mw = (w & 3) * 32, nw = (w >> 2) * 32;
    float acc[2][4][4];
    #pragma unroll
    for (int mi = 0; mi < 2; mi++)
        #pragma unroll
        for (int ni = 0; ni < 4; ni++)
            #pragma unroll
            for (int c = 0; c < 4; c++) acc[mi][ni][c] = 0.f;

    int ar = t >> 1, ak = (t & 1) * 8;
    int wr = t >> 2, wk = (t & 3) * 4;
    const float* apb = A + (size_t)(m0 + ar) * K + ak;
    bool wval = (n0 + wr < N);
    const float* wpb = W + (size_t)(n0 + wr) * K + wk;

    float4 v0 = *(const float4*)apb;
    float4 v1 = *(const float4*)(apb + 4);
    float4 wv = wval ? *(const float4*)wpb : make_float4(0.f, 0.f, 0.f, 0.f);
    int s = 0;
    As[0][ar][ak + 0] = v0.x; As[0][ar][ak + 1] = v0.y;
    As[0][ar][ak + 2] = v0.z; As[0][ar][ak + 3] = v0.w;
    As[0][ar][ak + 4] = v1.x; As[0][ar][ak + 5] = v1.y;
    As[0][ar][ak + 6] = v1.z; As[0][ar][ak + 7] = v1.w;
    Ws[0][wr][wk + 0] = wv.x; Ws[0][wr][wk + 1] = wv.y;
    Ws[0][wr][wk + 2] = wv.z; Ws[0][wr][wk + 3] = wv.w;
    __syncthreads();

    for (int k0 = 0; k0 < K; k0 += 16) {
        bool more = (k0 + 16 < K);
        if (more) {
            v0 = *(const float4*)(apb + k0 + 16);
            v1 = *(const float4*)(apb + k0 + 20);
            wv = wval ? *(const float4*)(wpb + k0 + 16)
                      : make_float4(0.f, 0.f, 0.f, 0.f);
        }
        #pragma unroll
        for (int kk = 0; kk < 2; kk++) {
            int kb = kk * 8;
            unsigned ah[2][4], al[2][4];
            #pragma unroll
            for (int mi = 0; mi < 2; mi++) {
                int r = mw + mi * 16 + grp;
                split_tf32(As[s][r][kb + tig],         ah[mi][0], al[mi][0]);
                split_tf32(As[s][r + 8][kb + tig],     ah[mi][1], al[mi][1]);
                split_tf32(As[s][r][kb + tig + 4],     ah[mi][2], al[mi][2]);
                split_tf32(As[s][r + 8][kb + tig + 4], ah[mi][3], al[mi][3]);
            }
            #pragma unroll
            for (int ni = 0; ni < 4; ni++) {
                int n = nw + ni * 8 + grp;
                unsigned bh0, bl0, bh1, bl1;
                split_tf32(Ws[s][n][kb + tig],     bh0, bl0);
                split_tf32(Ws[s][n][kb + tig + 4], bh1, bl1);
                mma3(acc[0][ni], ah[0], al[0], bh0, bh1, bl0, bl1);
                mma3(acc[1][ni], ah[1], al[1], bh0, bh1, bl0, bl1);
            }
        }
        if (more) {
            int d = s ^ 1;
            As[d][ar][ak + 0] = v0.x; As[d][ar][ak + 1] = v0.y;
            As[d][ar][ak + 2] = v0.z; As[d][ar][ak + 3] = v0.w;
            As[d][ar][ak + 4] = v1.x; As[d][ar][ak + 5] = v1.y;
            As[d][ar][ak + 6] = v1.z; As[d][ar][ak + 7] = v1.w;
            Ws[d][wr][wk + 0] = wv.x; Ws[d][wr][wk + 1] = wv.y;
            Ws[d][wr][wk + 2] = wv.z; Ws[d][wr][wk + 3] = wv.w;
            __syncthreads();
            s = d;
        }
    }
    #pragma unroll
    for (int mi = 0; mi < 2; mi++) {
        #pragma unroll
        for (int ni = 0; ni < 4; ni++) {
            #pragma unroll
            for (int ci = 0; ci < 4; ci++) {
                int r = m0 + mw + mi * 16 + grp + ((ci >= 2) ? 8 : 0);
                int n = n0 + nw + ni * 8 + tig * 2 + (ci & 1);
                if (n < N)
                    C[(size_t)r * N + n] = fmaxf(acc[mi][ni][ci] + bias[n], 0.f);
            }
        }
    }
}

// ======================================================================
// convt2 inner body (compile-time tap tables)          [round-7 proven]
// ======================================================================
template<int DY0, int KY0, int DY1, int KY1,
         int DX0, int KX0, int DX1, int KX1>
__device__ __forceinline__ void ct2_body(
        const float* __restrict__ base, const float* __restrict__ w,
        float bv, float* __restrict__ outp, int m) {
    float acc[14];
    #pragma unroll
    for (int j = 0; j < 14; j++) acc[j] = bv;
    for (int ic = 0; ic < 16; ic++) {
        const float* xc = base + ic * 256;
        #pragma unroll
        for (int sy = 0; sy < 2; sy++) {
            int iy = m + (sy ? DY1 : DY0);
            float row[16];
            #pragma unroll
            for (int j = 0; j < 16; j++) row[j] = xc[(iy + 1) * 16 + j];
            {
                float wv = __ldg(w + ic * 16 + (sy ? KY1 : KY0) * 4 + KX0);
                #pragma unroll
                for (int n = 0; n < 14; n++) acc[n] += row[n + DX0 + 1] * wv;
            }
            {
                float wv = __ldg(w + ic * 16 + (sy ? KY1 : KY0) * 4 + KX1);
                #pragma unroll
                for (int n = 0; n < 14; n++) acc[n] += row[n + DX1 + 1] * wv;
            }
        }
    }
    #pragma unroll
    for (int n = 0; n < 14; n++) outp[2 * n] = acc[n];
}

// ======================================================================
// FUSED convt1+convt2 (decoder)                        [round-12 proven]
// ======================================================================
#define T12_IMSZ 2916
#define T12_ZB   6240
#define T12_XIN  6664
#define T12_W    T12_XIN
#define T12_HP   (T12_W + 16 * 32 * 24)
#define T12_TOT  (T12_HP + 2 * 4096)
#define T12_SMEM (T12_TOT * 4)

__global__ void __launch_bounds__(256) convt12_tc(
        const float* __restrict__ in,
        const float* __restrict__ w,
        const float* __restrict__ bias,
        const float* __restrict__ c2w,
        const float* __restrict__ c2b,
        float* __restrict__ out) {
    extern __shared__ float sm[];
    float* xin = sm;
    float* wt  = sm + T12_W;
    float* hp  = sm + T12_HP;
    int t = threadIdx.x;
    int b0 = blockIdx.x * 2;

    for (int i = t; i < T12_XIN; i += 256) xin[i] = 0.f;
    for (int i = t; i < 8192; i += 256) hp[i] = 0.f;
    __syncthreads();
    for (int i = t; i < 2 * 1568; i += 256) {
        int img = i / 1568, j = i % 1568;
        int ic = j / 49, p = j % 49, iy = p / 7, ix = p % 7;
        xin[img * T12_IMSZ + ((iy + 1) * 9 + (ix + 1)) * 36 + ic] =
            to_tf32(in[(size_t)(b0 + img) * 1568 + j]);
    }
    for (int i = t; i < 32 * 256; i += 256) {
        int ic = i / 256, r = i % 256, oc = r / 16, s = r % 16;
        wt[s * 768 + ic * 24 + oc] = to_tf32(w[i]);
    }
    __syncthreads();

    int lane = t & 31, wrp = t >> 5;
    int grp = lane >> 2, tig = lane & 3;
    int img = wrp >> 2, ph = wrp & 3;
    int a = ph >> 1, bp = ph & 1;
    int dyv[2], kyv[2], dxv[2], kxv[2];
    if (a == 0) { dyv[0] = 0; kyv[0] = 1; dyv[1] = -1; kyv[1] = 3; }
    else        { dyv[0] = 1; kyv[0] = 0; dyv[1] =  0; kyv[1] = 2; }
    if (bp == 0) { dxv[0] = 0; kxv[0] = 1; dxv[1] = -1; kxv[1] = 3; }
    else         { dxv[0] = 1; kxv[0] = 0; dxv[1] =  0; kxv[1] = 2; }

    int rb[4][2];
    #pragma unroll
    for (int mi = 0; mi < 4; mi++)
        #pragma unroll
        for (int h = 0; h < 2; h++) {
            int p = mi * 16 + grp + h * 8;
            rb[mi][h] = (p < 49)
                ? img * T12_IMSZ + ((p / 7 + 1) * 9 + (p % 7 + 1)) * 36
                : T12_ZB;
        }

    float acc[4][2][4];
    #pragma unroll
    for (int mi = 0; mi < 4; mi++)
        #pragma unroll
        for (int ni = 0; ni < 2; ni++)
            #pragma unroll
            for (int c = 0; c < 4; c++) acc[mi][ni][c] = 0.f;

    #pragma unroll
    for (int sy = 0; sy < 2; sy++) {
        #pragma unroll
        for (int sx = 0; sx < 2; sx++) {
            int soff = (dyv[sy] * 9 + dxv[sx]) * 36;
            const float* wsl = wt + (kyv[sy] * 4 + kxv[sx]) * 768;
            #pragma unroll
            for (int kk = 0; kk < 4; kk++) {
                int kb = kk * 8;
                unsigned afr[4][4];
                #pragma unroll
                for (int mi = 0; mi < 4; mi++) {
                    afr[mi][0] = __float_as_uint(xin[rb[mi][0] + soff + kb + tig]);
                    afr[mi][1] = __float_as_uint(xin[rb[mi][1] + soff + kb + tig]);
                    afr[mi][2] = __float_as_uint(xin[rb[mi][0] + soff + kb + tig + 4]);
                    afr[mi][3] = __float_as_uint(xin[rb[mi][1] + soff + kb + tig + 4]);
                }
                #pragma unroll
                for (int ni = 0; ni < 2; ni++) {
                    unsigned bb0 = __float_as_uint(wsl[(kb + tig) * 24 + ni * 8 + grp]);
                    unsigned bb1 = __float_as_uint(wsl[(kb + tig + 4) * 24 + ni * 8 + grp]);
                    #pragma unroll
                    for (int mi = 0; mi < 4; mi++)
                        mma_tf32(acc[mi][ni], afr[mi], bb0, bb1);
                }
            }
        }
    }

    #pragma unroll
    for (int mi = 0; mi < 4; mi++) {
        #pragma unroll
        for (int ni = 0; ni < 2; ni++) {
            #pragma unroll
            for (int ci = 0; ci < 4; ci++) {
                int p = mi * 16 + grp + ((ci >= 2) ? 8 : 0);
                if (p < 49) {
                    int m = p / 7, n = p % 7;
                    int oc = ni * 8 + tig * 2 + (ci & 1);
                    int oy = 2 * m + a, ox = 2 * n + bp;
                    float v = acc[mi][ni][ci] + __ldg(bias + oc);
                    hp[img * 4096 + oc * 256 + (oy + 1) * 16 + (ox + 1)] =
                        fmaxf(v, 0.f);
                }
            }
        }
    }
    __syncthreads();

    if (t < 112) {
        int ph2 = t / 28, r2 = t % 28;
        int img2 = r2 / 14, m2 = r2 % 14;
        int a2 = ph2 >> 1, b2 = ph2 & 1;
        const float* base2 = hp + img2 * 4096;
        float bv2 = c2b[0];
        float* outp = out + (size_t)(b0 + img2) * 784 + (2 * m2 + a2) * 28 + b2;
        if (ph2 == 0)      ct2_body<0, 1, -1, 3,  0, 1, -1, 3>(base2, c2w, bv2, outp, m2);
        else if (ph2 == 1) ct2_body<0, 1, -1, 3,  1, 0,  0, 2>(base2, c2w, bv2, outp, m2);
        else if (ph2 == 2) ct2_body<1, 0,  0, 2,  0, 1, -1, 3>(base2, c2w, bv2, outp, m2);
        else               ct2_body<1, 0,  0, 2,  1, 0,  0, 2>(base2, c2w, bv2, outp, m2);
    }
}

// ======================================================================
// fc2: z[B,32] = A[B,224] @ w^T + b  (fp32, feeds VQ)   [round-8]
// ======================================================================
__global__ void __launch_bounds__(256) fc2_kernel(
        const float* __restrict__ A,
        const float* __restrict__ w,
        const float* __restrict__ bias,
        float* __restrict__ out) {
    __shared__ float ws[32 * 224];
    int t = threadIdx.x;
    for (int i = t; i < 7168; i += 256) ws[i] = w[i];
    __syncthreads();
    int n = t & 31, r = t >> 5;
    float bv = bias[n];
    const float* wp = ws + n * 224;
    #pragma unroll
    for (int rr = 0; rr < 4; rr++) {
        int b = blockIdx.x * 32 + rr * 8 + r;
        const float* ap = A + (size_t)b * 224;
        float acc = bv;
        #pragma unroll 8
        for (int k = 0; k < 224; k++) acc += ap[k] * wp[k];
        out[(size_t)b * 32 + n] = acc;
    }
}

// ======================================================================
// VQ helpers (fp32 exact)
// ======================================================================
__global__ void enorm_kernel(const float* __restrict__ emb, float* __restrict__ enorm) {
    int e = blockIdx.x * blockDim.x + threadIdx.x;
    if (e < NE) {
        float s = 0.f;
        #pragma unroll
        for (int d = 0; d < ZD; d++) { float v = emb[e * ZD + d]; s += v * v; }
        enorm[e] = s;
    }
}

__global__ void zero_kernel(float* __restrict__ counts, float* __restrict__ sums,
                            float* __restrict__ loss) {
    int i = blockIdx.x * blockDim.x + threadIdx.x;
    if (i < NE) counts[i] = 0.f;
    if (i < NE * ZD) sums[i] = 0.f;
    if (i == 0) loss[0] = 0.f;
}

#define VQ_SMEM (NE * 36 * 4)

__global__ void __launch_bounds__(256) vq_kernel(
        const float* __restrict__ z,
        const float* __restrict__ emb,
        const float* __restrict__ enorm,
        int* __restrict__ idx,
        float* __restrict__ counts,
        float* __restrict__ sums,
        float* __restrict__ loss) {
    extern __shared__ float es[];          // [512][36]
    __shared__ float en[NE];
    __shared__ float zs[8][ZD];
    int t = threadIdx.x, lane = t & 31, wl = t >> 5;
    for (int i = t; i < NE * ZD; i += 256) {
        int e = i >> 5, d = i & 31;
        es[e * 36 + d] = emb[i];
    }
    for (int i = t; i < NE; i += 256) en[i] = enorm[i];
    __syncthreads();

    for (int rr = 0; rr < 8; rr++) {
        int row = blockIdx.x * 64 + wl * 8 + rr;
        zs[wl][lane] = z[(size_t)row * ZD + lane];
        __syncwarp();
        float best = 3.4e38f; int bi = NE;
        for (int e = lane; e < NE; e += 32) {
            const float* ep = es + e * 36;
            float dot = 0.f;
            #pragma unroll
            for (int d = 0; d < ZD; d += 4) {
                float4 v = *(const float4*)(ep + d);
                dot += zs[wl][d + 0] * v.x;
                dot += zs[wl][d + 1] * v.y;
                dot += zs[wl][d + 2] * v.z;
                dot += zs[wl][d + 3] * v.w;
            }
            float s = en[e] - 2.f * dot;
            if (s < best) { best = s; bi = e; }
        }
        #pragma unroll
        for (int off = 16; off; off >>= 1) {
            float ob = __shfl_xor_sync(0xffffffffu, best, off);
            int   oi = __shfl_xor_sync(0xffffffffu, bi, off);
            if (ob < best || (ob == best && oi < bi)) { best = ob; bi = oi; }
        }
        float zl = zs[wl][lane];
        float diff = es[bi * 36 + lane] - zl;
        float d2 = diff * diff;
        #pragma unroll
        for (int off = 16; off; off >>= 1)
            d2 += __shfl_xor_sync(0xffffffffu, d2, off);
        if (lane == 0) {
            idx[row] = bi;
            atomicAdd(&counts[bi], 1.f);
            atomicAdd(loss, d2);
        }
        atomicAdd(&sums[bi * ZD + lane], zl);
        __syncwarp();
    }
}

__global__ void embnew_kernel(const float* __restrict__ m_mat,
                              const float* __restrict__ n_mat,
                              const float* __restrict__ sums,
                              const float* __restrict__ counts,
                              float* __restrict__ out) {
    int i = blockIdx.x * blockDim.x + threadIdx.x;
    if (i < NE * ZD) {
        int e = i >> 5;
        float m = m_mat[i] * GAMMA + sums[i] * ONE_M_GAMMA;
        float n = n_mat[e] * GAMMA + counts[e] * ONE_M_GAMMA;
        out[i] = m / n;
    }
}

__global__ void finalize_kernel(const float* __restrict__ counts,
                                const float* __restrict__ loss,
                                float* __restrict__ out_scalars) {
    __shared__ float red[NE];
    int t = threadIdx.x;
    float c = counts[t];
    float em = c * (1.f / (float)BATCH);
    red[t] = em * logf(em + 1e-10f);
    __syncthreads();
    for (int s = 256; s; s >>= 1) {
        if (t < s) red[t] += red[t + s];
        __syncthreads();
    }
    if (t == 0) {
        float q = loss[0] * (1.f / ((float)BATCH * (float)ZD));
        out_scalars[0] = q;
        out_scalars[1] = BETA * q;
        out_scalars[2] = expf(-red[0]);
    }
}

// ======================================================================
// fc3 (fp32): 16 images/CTA                           [round-8, proven]
// ======================================================================
__global__ void __launch_bounds__(224) fc3_kernel(
        const float* __restrict__ emb,
        const int* __restrict__ idx,
        const float* __restrict__ w,
        const float* __restrict__ bias,
        float* __restrict__ out) {
    __shared__ float ws[224 * ZD];
    __shared__ float zq[16][ZD + 1];
    int b0 = blockIdx.x * 16, t = threadIdx.x;
    for (int i = t; i < 224 * ZD; i += 224) ws[i] = w[i];
    for (int i = t; i < 16 * ZD; i += 224) {
        int im = i >> 5, d = i & 31;
        zq[im][d] = emb[(size_t)idx[b0 + im] * ZD + d];
    }
    __syncthreads();
    float bv = bias[t];
    float wreg[ZD];
    const float* wp = ws + t * ZD;
    #pragma unroll
    for (int k = 0; k < ZD; k++) wreg[k] = wp[k];
    #pragma unroll 4
    for (int im = 0; im < 16; im++) {
        float acc = bv;
        #pragma unroll
        for (int k = 0; k < ZD; k++) acc += zq[im][k] * wreg[k];
        out[(size_t)(b0 + im) * 224 + t] = fmaxf(acc, 0.f);
    }
}

// ======================================================================
// launch
// ======================================================================
extern "C" void kernel_launch(void* const* d_in, const int* in_sizes, int n_in,
                              void* d_out, int out_size) {
    const float* x        = (const float*)d_in[0];
    const float* conv1_w  = (const float*)d_in[1];
    const float* conv1_b  = (const float*)d_in[2];
    const float* conv2_w  = (const float*)d_in[3];
    const float* conv2_b  = (const float*)d_in[4];
    const float* res1_w1  = (const float*)d_in[5];
    const float* res1_w2  = (const float*)d_in[6];
    const float* fc1_w    = (const float*)d_in[7];
    const float* fc1_b    = (const float*)d_in[8];
    const float* fc2_w    = (const float*)d_in[9];
    const float* fc2_b    = (const float*)d_in[10];
    const float* emb      = (const float*)d_in[11];
    const float* n_mat    = (const float*)d_in[12];
    const float* m_mat    = (const float*)d_in[13];
    const float* fc3_w    = (const float*)d_in[14];
    const float* fc3_b    = (const float*)d_in[15];
    const float* fc4_w    = (const float*)d_in[16];
    const float* fc4_b    = (const float*)d_in[17];
    const float* res2_w1  = (const float*)d_in[18];
    const float* res2_w2  = (const float*)d_in[19];
    const float* convt1_w = (const float*)d_in[20];
    const float* convt1_b = (const float*)d_in[21];
    const float* convt2_w = (const float*)d_in[22];
    const float* convt2_b = (const float*)d_in[23];
    float* out = (float*)d_out;

    float *h2, *a, *z, *enorm, *counts, *sums, *loss;
    int* idx;
    float2 *wf_r1, *wf_r2, *wf_c2;
    cudaGetSymbolAddress((void**)&h2,     g_h2);
    cudaGetSymbolAddress((void**)&a,      g_a);
    cudaGetSymbolAddress((void**)&z,      g_z);
    cudaGetSymbolAddress((void**)&idx,    g_idx);
    cudaGetSymbolAddress((void**)&enorm,  g_enorm);
    cudaGetSymbolAddress((void**)&counts, g_counts);
    cudaGetSymbolAddress((void**)&sums,   g_sums);
    cudaGetSymbolAddress((void**)&loss,   g_loss);
    cudaGetSymbolAddress((void**)&wf_r1,  g_wf_r1);
    cudaGetSymbolAddress((void**)&wf_r2,  g_wf_r2);
    cudaGetSymbolAddress((void**)&wf_c2,  g_wf_c2);

    cudaFuncSetAttribute(conv12_tc3,
                         cudaFuncAttributeMaxDynamicSharedMemorySize, C12_SMEM);
    cudaFuncSetAttribute(res_tc3,
                         cudaFuncAttributeMaxDynamicSharedMemorySize, E3_SMEM);
    cudaFuncSetAttribute(res_tcd,
                         cudaFuncAttributeMaxDynamicSharedMemorySize, D3_SMEM);
    cudaFuncSetAttribute(convt12_tc,
                         cudaFuncAttributeMaxDynamicSharedMemorySize, T12_SMEM);
    cudaFuncSetAttribute(vq_kernel,
                         cudaFuncAttributeMaxDynamicSharedMemorySize, VQ_SMEM);

    // weight repack (fragment-order textures)
    repack_res<<<36, 256>>>(res1_w1, wf_r1, 0);
    repack_res<<<36, 256>>>(res2_w1, wf_r2, 1);
    repack_c2 <<<16, 256>>>(conv2_w, wf_c2);

    // encoder (3xTF32 = fp32-class accuracy; VQ path preserved)
    conv12_tc3<<<BATCH / 2, 256, C12_SMEM>>>(x, conv1_w, conv1_b, wf_c2,
                                             conv2_b, h2);
    res_tc3  <<<BATCH / 2, 256, E3_SMEM>>>(h2, wf_r1, res1_w2);
    gemm_tc3<<<dim3(BATCH / 128, 4), 256>>>(h2, fc1_w, fc1_b, a,
                                            BATCH, 224, 1568);
    fc2_kernel<<<BATCH / 32, 256>>>(a, fc2_w, fc2_b, z);

    // VQ
    zero_kernel <<<(NE * ZD + 255) / 256, 256>>>(counts, sums, loss);
    enorm_kernel<<<2, 256>>>(emb, enorm);
    vq_kernel   <<<BATCH / 64, 256, VQ_SMEM>>>(z, emb, enorm, idx, counts,
                                               sums, loss);
    embnew_kernel  <<<(NE * ZD + 255) / 256, 256>>>(m_mat, n_mat, sums, counts,
                                                    out + OFF_SCAL + 3);
    finalize_kernel<<<1, NE>>>(counts, loss, out + OFF_SCAL);

    // decoder (single tf32)
    fc3_kernel<<<BATCH / 16, 224>>>(emb, idx, fc3_w, fc3_b, a);
    gemm_tc<<<dim3(BATCH / 128, 25), 256>>>(a, fc4_w, fc4_b, h2,
                                            BATCH, 1568, 224);
    res_tcd<<<BATCH / 2, 256, D3_SMEM>>>(h2, wf_r2, res2_w2);
    convt12_tc<<<BATCH / 2, 256, T12_SMEM>>>(h2, convt1_w, convt1_b,
                                             convt2_w, convt2_b, out);
}